// round 2
// baseline (speedup 1.0000x reference)
#include <cuda_runtime.h>
#include <cuda_bf16.h>
#include <cstdint>
#include <cstddef>

// ---------------------------------------------------------------------------
// Problem sizes: B=16, S=4096, D=1024, K=16, ITERS=3
// ---------------------------------------------------------------------------
#define SCALEF   0.03125f        /* 1024^-0.5 */
#define EPS_LN   1e-5f
#define EPS_ATTN 1e-8f

// scratch offsets (floats)
#define OFF_SLOTS 0u
#define OFF_LN    262144u
#define OFF_Q     524288u
#define OFF_Q2    786432u
#define OFF_UPD   1048576u
#define OFF_UN    1310720u
#define OFF_GI    1572864u
#define OFF_GH    2359296u
#define OFF_H1    3145728u
#define OFF_UPART 4194304u      /* 32 chunks * 256 rows * 1024 */
#define OFF_WKT   12582912u
#define OFF_CB    13631488u
#define OFF_BS    13631744u
#define OFF_RINV  13632000u
#define OFF_RP    13632256u     /* 256 rows * 32 chunks */
#define OFF_ATTN  13640448u
#define SCRATCH_N 14689024u

__device__ float g_scratch[SCRATCH_N];

__device__ __forceinline__ float geluf(float x) {
    return 0.5f * x * (1.0f + erff(x * 0.70710678118654752f));
}
__device__ __forceinline__ float sigmf(float x) {
    return 1.0f / (1.0f + __expf(-x));
}

// ---------------------------------------------------------------------------
// init: slots = broadcast(slot_mu)   (262144 elems)
// ---------------------------------------------------------------------------
__global__ __launch_bounds__(256) void init_slots_kernel(const float* __restrict__ mu) {
    unsigned idx = blockIdx.x * 256u + threadIdx.x;
    g_scratch[OFF_SLOTS + idx] = mu[idx & 16383u];
}

// ---------------------------------------------------------------------------
// transpose Wk (1024x1024) -> WkT in scratch
// ---------------------------------------------------------------------------
__global__ void transpose_kernel(const float* __restrict__ in) {
    __shared__ float t[32][33];
    int x  = blockIdx.x * 32 + threadIdx.x;
    int y0 = blockIdx.y * 32;
    #pragma unroll
    for (int j = threadIdx.y; j < 32; j += 8)
        t[j][threadIdx.x] = in[(size_t)(y0 + j) * 1024 + x];
    __syncthreads();
    int xo  = blockIdx.y * 32 + threadIdx.x;
    int yo0 = blockIdx.x * 32;
    #pragma unroll
    for (int j = threadIdx.y; j < 32; j += 8)
        g_scratch[OFF_WKT + (size_t)(yo0 + j) * 1024 + xo] = t[threadIdx.x][j];
}

// ---------------------------------------------------------------------------
// LayerNorm over D=1024; one block (256 thr) per row, 256 rows
// ---------------------------------------------------------------------------
__global__ __launch_bounds__(256) void ln_kernel(unsigned offX, unsigned offY,
                                                 const float* __restrict__ g,
                                                 const float* __restrict__ bt) {
    __shared__ float red[256];
    const float* X = g_scratch + offX;
    float* Y = g_scratch + offY;
    int row = blockIdx.x, tid = threadIdx.x;
    float4 x = ((const float4*)X)[row * 256 + tid];
    red[tid] = x.x + x.y + x.z + x.w;
    __syncthreads();
    for (int o = 128; o > 0; o >>= 1) { if (tid < o) red[tid] += red[tid + o]; __syncthreads(); }
    float mean = red[0] * (1.0f / 1024.0f);
    __syncthreads();
    float4 dx = { x.x - mean, x.y - mean, x.z - mean, x.w - mean };
    red[tid] = dx.x*dx.x + dx.y*dx.y + dx.z*dx.z + dx.w*dx.w;
    __syncthreads();
    for (int o = 128; o > 0; o >>= 1) { if (tid < o) red[tid] += red[tid + o]; __syncthreads(); }
    float rs = rsqrtf(red[0] * (1.0f / 1024.0f) + EPS_LN);
    float4 gg = ((const float4*)g)[tid], bb = ((const float4*)bt)[tid];
    float4 y = { dx.x*rs*gg.x + bb.x, dx.y*rs*gg.y + bb.y,
                 dx.z*rs*gg.z + bb.z, dx.w*rs*gg.w + bb.w };
    ((float4*)Y)[row * 256 + tid] = y;
}

// ---------------------------------------------------------------------------
// cb[row] = SCALE * dot(q[row,:], bk)
// ---------------------------------------------------------------------------
__global__ __launch_bounds__(256) void cbk_kernel(const float* __restrict__ bk) {
    __shared__ float red[256];
    int row = blockIdx.x, tid = threadIdx.x;
    const float* q = g_scratch + OFF_Q + (size_t)row * 1024;
    float p = 0.f;
    #pragma unroll
    for (int i = 0; i < 4; i++) { int d = tid + 256 * i; p = fmaf(q[d], bk[d], p); }
    red[tid] = p; __syncthreads();
    for (int o = 128; o > 0; o >>= 1) { if (tid < o) red[tid] += red[tid + o]; __syncthreads(); }
    if (tid == 0) g_scratch[OFF_CB + row] = SCALEF * red[0];
}

// ---------------------------------------------------------------------------
// GEMM: C[M,N] = A[M,KD] @ W[N,KD]^T (+ epilogue).  Tiles 32(M) x 64(N) x 16(K).
// 256 threads, each computes 2x4.
// ---------------------------------------------------------------------------
#define EPI_BIAS  0
#define EPI_BROW  1
#define EPI_GELU  2
#define EPI_RESID 3
#define EPI_SCALE 4

template<int EPI, int KD>
__global__ __launch_bounds__(256) void gemm_kernel(
    unsigned offA, const float* __restrict__ Wext, unsigned offW,
    const float* __restrict__ bias, unsigned offC, int N)
{
    __shared__ float As[16][36];
    __shared__ float Bs[16][68];
    float* S = g_scratch;
    const float* A = S + offA;
    const float* W = Wext ? Wext : (S + offW);
    float* C = S + offC;

    const int tid = threadIdx.x;
    const int bn = blockIdx.x * 64;
    const int bm = blockIdx.y * 32;
    const int tx = tid & 15, ty = tid >> 4;
    const int lrB = tid >> 2, lkB = (tid & 3) * 4;   // B tile: 64 rows x 16 k
    const int lrA = tid >> 3, lkA = (tid & 7) * 2;   // A tile: 32 rows x 16 k

    float acc[2][4];
    #pragma unroll
    for (int i = 0; i < 2; i++)
        #pragma unroll
        for (int j = 0; j < 4; j++) acc[i][j] = 0.f;

    for (int k0 = 0; k0 < KD; k0 += 16) {
        float2 av = *(const float2*)(A + (size_t)(bm + lrA) * KD + k0 + lkA);
        float4 wv = *(const float4*)(W + (size_t)(bn + lrB) * KD + k0 + lkB);
        __syncthreads();
        As[lkA + 0][lrA] = av.x; As[lkA + 1][lrA] = av.y;
        Bs[lkB + 0][lrB] = wv.x; Bs[lkB + 1][lrB] = wv.y;
        Bs[lkB + 2][lrB] = wv.z; Bs[lkB + 3][lrB] = wv.w;
        __syncthreads();
        #pragma unroll
        for (int kk = 0; kk < 16; kk++) {
            float2 a = *(const float2*)&As[kk][ty * 2];
            float4 b = *(const float4*)&Bs[kk][tx * 4];
            acc[0][0] = fmaf(a.x, b.x, acc[0][0]);
            acc[0][1] = fmaf(a.x, b.y, acc[0][1]);
            acc[0][2] = fmaf(a.x, b.z, acc[0][2]);
            acc[0][3] = fmaf(a.x, b.w, acc[0][3]);
            acc[1][0] = fmaf(a.y, b.x, acc[1][0]);
            acc[1][1] = fmaf(a.y, b.y, acc[1][1]);
            acc[1][2] = fmaf(a.y, b.z, acc[1][2]);
            acc[1][3] = fmaf(a.y, b.w, acc[1][3]);
        }
    }

    const int n = bn + tx * 4;
    #pragma unroll
    for (int i = 0; i < 2; i++) {
        const int m = bm + ty * 2 + i;
        float4 o = { acc[i][0], acc[i][1], acc[i][2], acc[i][3] };
        if (EPI == EPI_SCALE) {
            o.x *= SCALEF; o.y *= SCALEF; o.z *= SCALEF; o.w *= SCALEF;
        } else {
            float4 bb = *(const float4*)(bias + n);
            if (EPI == EPI_BROW) {
                float r = S[OFF_BS + m];
                o.x += bb.x * r; o.y += bb.y * r; o.z += bb.z * r; o.w += bb.w * r;
            } else {
                o.x += bb.x; o.y += bb.y; o.z += bb.z; o.w += bb.w;
            }
            if (EPI == EPI_GELU) {
                o.x = geluf(o.x); o.y = geluf(o.y); o.z = geluf(o.z); o.w = geluf(o.w);
            }
            if (EPI == EPI_RESID) {
                float4 c0 = *(const float4*)(C + (size_t)m * N + n);
                o.x += c0.x; o.y += c0.y; o.z += c0.z; o.w += c0.w;
            }
        }
        *(float4*)(C + (size_t)m * N + n) = o;
    }
}

// ---------------------------------------------------------------------------
// Fused token pass. grid = (32 chunks, 16 b), 128 threads, chunk = 128 tokens.
// Phase 1: logits = q2 . t + cb, softmax over K, store attn + rowsum partial.
// Phase 2: Upart[c] = attn_chunk @ tokens_chunk.
// ---------------------------------------------------------------------------
#define TSTR 36
__global__ __launch_bounds__(128) void pass_kernel(const float* __restrict__ tokens,
                                                   float* __restrict__ attn_ext)
{
    __shared__ float Td[128 * TSTR];
    __shared__ float Q2s[16 * TSTR];
    __shared__ float Att[16 * 128];
    const int tid = threadIdx.x;
    const int c = blockIdx.x;
    const int b = blockIdx.y;
    float* S = g_scratch;
    float* attn_out = attn_ext ? attn_ext : (S + OFF_ATTN);
    const float* q2 = S + OFF_Q2 + (size_t)b * 16384;
    const float* tokb = tokens + ((size_t)b * 4096 + (size_t)c * 128) * 1024;

    float lg[16];
    #pragma unroll
    for (int k = 0; k < 16; k++) lg[k] = S[OFF_CB + b * 16 + k];

    // ---- phase 1: logits ----
    for (int sl = 0; sl < 32; sl++) {
        __syncthreads();
        #pragma unroll
        for (int i = 0; i < 8; i++) {
            int id = tid + 128 * i;
            int row = id >> 3, c4 = (id & 7) << 2;
            *(float4*)&Td[row * TSTR + c4] =
                *(const float4*)(tokb + (size_t)row * 1024 + sl * 32 + c4);
        }
        {
            int row = tid >> 3, c4 = (tid & 7) << 2;
            *(float4*)&Q2s[row * TSTR + c4] =
                *(const float4*)(q2 + (size_t)row * 1024 + sl * 32 + c4);
        }
        __syncthreads();
        #pragma unroll
        for (int d4 = 0; d4 < 32; d4 += 4) {
            float4 tv = *(const float4*)&Td[tid * TSTR + d4];
            #pragma unroll
            for (int k = 0; k < 16; k++) {
                float4 qv = *(const float4*)&Q2s[k * TSTR + d4];
                lg[k] = fmaf(tv.x, qv.x, fmaf(tv.y, qv.y,
                        fmaf(tv.z, qv.z, fmaf(tv.w, qv.w, lg[k]))));
            }
        }
    }

    // ---- softmax over K (per token) ----
    float mx = lg[0];
    #pragma unroll
    for (int k = 1; k < 16; k++) mx = fmaxf(mx, lg[k]);
    float a[16], sum = 0.f;
    #pragma unroll
    for (int k = 0; k < 16; k++) { a[k] = __expf(lg[k] - mx); sum += a[k]; }
    float inv = 1.0f / sum;
    #pragma unroll
    for (int k = 0; k < 16; k++) {
        a[k] *= inv;
        Att[k * 128 + tid] = a[k];
        attn_out[((size_t)b * 16 + k) * 4096 + (size_t)c * 128 + tid] = a[k];
    }
    __syncthreads();
    if (tid < 16) {
        const float4* ap = (const float4*)&Att[tid * 128];
        float s2 = 0.f;
        #pragma unroll
        for (int i = 0; i < 32; i++) { float4 v = ap[i]; s2 += v.x + v.y + v.z + v.w; }
        S[OFF_RP + ((size_t)b * 16 + tid) * 32 + c] = s2;
    }

    // ---- phase 2: Upart = attn @ tokens ----
    const int kk = tid >> 3;
    const int dc = (tid & 7) << 2;
    float* up = S + OFF_UPART + (((size_t)c * 256) + b * 16 + kk) * 1024 + dc;
    const float* attk = &Att[kk * 128];
    for (int sl = 0; sl < 32; sl++) {
        __syncthreads();
        #pragma unroll
        for (int i = 0; i < 8; i++) {
            int id = tid + 128 * i;
            int row = id >> 3, c4 = (id & 7) << 2;
            *(float4*)&Td[row * TSTR + c4] =
                *(const float4*)(tokb + (size_t)row * 1024 + sl * 32 + c4);
        }
        __syncthreads();
        float4 acc = make_float4(0.f, 0.f, 0.f, 0.f);
        #pragma unroll 8
        for (int s = 0; s < 128; s += 4) {
            float4 a4 = *(const float4*)&attk[s];
            float4 t0 = *(const float4*)&Td[(s + 0) * TSTR + dc];
            float4 t1 = *(const float4*)&Td[(s + 1) * TSTR + dc];
            float4 t2 = *(const float4*)&Td[(s + 2) * TSTR + dc];
            float4 t3 = *(const float4*)&Td[(s + 3) * TSTR + dc];
            acc.x = fmaf(a4.x, t0.x, fmaf(a4.y, t1.x, fmaf(a4.z, t2.x, fmaf(a4.w, t3.x, acc.x))));
            acc.y = fmaf(a4.x, t0.y, fmaf(a4.y, t1.y, fmaf(a4.z, t2.y, fmaf(a4.w, t3.y, acc.y))));
            acc.z = fmaf(a4.x, t0.z, fmaf(a4.y, t1.z, fmaf(a4.z, t2.z, fmaf(a4.w, t3.z, acc.z))));
            acc.w = fmaf(a4.x, t0.w, fmaf(a4.y, t1.w, fmaf(a4.z, t2.w, fmaf(a4.w, t3.w, acc.w))));
        }
        *(float4*)(up + (size_t)sl * 32) = acc;
    }
}

// ---------------------------------------------------------------------------
// rowsum over chunks -> rinv, bscale
// ---------------------------------------------------------------------------
__global__ __launch_bounds__(256) void rowsum_kernel() {
    int row = threadIdx.x;
    float* S = g_scratch;
    float s = 0.f;
    #pragma unroll
    for (int cc = 0; cc < 32; cc++) s += S[OFF_RP + (size_t)row * 32 + cc];
    float ri = 1.0f / (s + EPS_ATTN);
    S[OFF_BS + row] = s * ri;
    S[OFF_RINV + row] = ri;
}

// ---------------------------------------------------------------------------
// Un[row][:] = rinv[row] * sum_chunks Upart
// ---------------------------------------------------------------------------
__global__ __launch_bounds__(256) void reduceU_kernel() {
    float* S = g_scratch;
    int row = blockIdx.x, tid = threadIdx.x;
    float ri = S[OFF_RINV + row];
    float4 acc = make_float4(0.f, 0.f, 0.f, 0.f);
    #pragma unroll 4
    for (int cc = 0; cc < 32; cc++) {
        float4 v = *(const float4*)&S[OFF_UPART + ((size_t)cc * 256 + row) * 1024 + tid * 4];
        acc.x += v.x; acc.y += v.y; acc.z += v.z; acc.w += v.w;
    }
    acc.x *= ri; acc.y *= ri; acc.z *= ri; acc.w *= ri;
    *(float4*)&S[OFF_UN + (size_t)row * 1024 + tid * 4] = acc;
}

// ---------------------------------------------------------------------------
// GRU gate combine, in-place slots update
// ---------------------------------------------------------------------------
__global__ __launch_bounds__(256) void gru_kernel() {
    float* S = g_scratch;
    unsigned idx = blockIdx.x * 256u + threadIdx.x;       // 0..262143
    unsigned row = idx >> 10, col = idx & 1023u;
    size_t gb = (size_t)row * 3072 + col;
    float ir = S[OFF_GI + gb], iz = S[OFF_GI + gb + 1024], in_ = S[OFF_GI + gb + 2048];
    float hr = S[OFF_GH + gb], hz = S[OFF_GH + gb + 1024], hn  = S[OFF_GH + gb + 2048];
    float r = sigmf(ir + hr);
    float z = sigmf(iz + hz);
    float n = tanhf(in_ + r * hn);
    float sp = S[OFF_SLOTS + idx];
    S[OFF_SLOTS + idx] = (1.0f - z) * n + z * sp;
}

// ---------------------------------------------------------------------------
// copy slots -> out[0:262144]
// ---------------------------------------------------------------------------
__global__ __launch_bounds__(256) void copy_out_kernel(float* __restrict__ out, int n) {
    int idx = blockIdx.x * 256 + threadIdx.x;
    if (idx < n) out[idx] = g_scratch[OFF_SLOTS + idx];
}

// ---------------------------------------------------------------------------
// host
// ---------------------------------------------------------------------------
extern "C" void kernel_launch(void* const* d_in, const int* in_sizes, int n_in,
                              void* d_out, int out_size) {
    const float* tokens = (const float*)d_in[0];
    const float* mu     = (const float*)d_in[1];
    const float* Wq  = (const float*)d_in[2];  const float* bq  = (const float*)d_in[3];
    const float* Wk  = (const float*)d_in[4];  const float* bk  = (const float*)d_in[5];
    const float* Wv  = (const float*)d_in[6];  const float* bv  = (const float*)d_in[7];
    const float* Wih = (const float*)d_in[8];  const float* bih = (const float*)d_in[9];
    const float* Whh = (const float*)d_in[10]; const float* bhh = (const float*)d_in[11];
    const float* W1  = (const float*)d_in[12]; const float* b1  = (const float*)d_in[13];
    const float* W2  = (const float*)d_in[14]; const float* b2  = (const float*)d_in[15];
    const float* gs  = (const float*)d_in[16]; const float* bs  = (const float*)d_in[17];
    const float* gm  = (const float*)d_in[18]; const float* bm  = (const float*)d_in[19];
    float* out = (float*)d_out;

    float* attnp = (out_size >= 1310720) ? (out + 262144) : nullptr;

    transpose_kernel<<<dim3(32, 32), dim3(32, 8)>>>(Wk);
    init_slots_kernel<<<1024, 256>>>(mu);

    for (int it = 0; it < 3; it++) {
        ln_kernel<<<256, 256>>>(OFF_SLOTS, OFF_LN, gs, bs);
        gemm_kernel<EPI_BIAS, 1024><<<dim3(16, 8), 256>>>(OFF_LN, Wq, 0, bq, OFF_Q, 1024);
        gemm_kernel<EPI_SCALE, 1024><<<dim3(16, 8), 256>>>(OFF_Q, nullptr, OFF_WKT, nullptr, OFF_Q2, 1024);
        cbk_kernel<<<256, 256>>>(bk);
        pass_kernel<<<dim3(32, 16), 128>>>(tokens, attnp);
        rowsum_kernel<<<1, 256>>>();
        reduceU_kernel<<<256, 256>>>();
        gemm_kernel<EPI_BROW, 1024><<<dim3(16, 8), 256>>>(OFF_UN, Wv, 0, bv, OFF_UPD, 1024);
        gemm_kernel<EPI_BIAS, 1024><<<dim3(48, 8), 256>>>(OFF_UPD, Wih, 0, bih, OFF_GI, 3072);
        gemm_kernel<EPI_BIAS, 1024><<<dim3(48, 8), 256>>>(OFF_SLOTS, Whh, 0, bhh, OFF_GH, 3072);
        gru_kernel<<<1024, 256>>>();
        ln_kernel<<<256, 256>>>(OFF_SLOTS, OFF_LN, gm, bm);
        gemm_kernel<EPI_GELU, 1024><<<dim3(64, 8), 256>>>(OFF_LN, W1, 0, b1, OFF_H1, 4096);
        gemm_kernel<EPI_RESID, 4096><<<dim3(16, 8), 256>>>(OFF_H1, W2, 0, b2, OFF_SLOTS, 1024);
    }

    int nslots = out_size < 262144 ? out_size : 262144;
    copy_out_kernel<<<1024, 256>>>(out, nslots);
}

// round 4
// speedup vs baseline: 1.0812x; 1.0812x over previous
#include <cuda_runtime.h>
#include <cuda_bf16.h>
#include <cstdint>
#include <cstddef>

// ---------------------------------------------------------------------------
// Problem sizes: B=16, S=4096, D=1024, K=16, ITERS=3
// ---------------------------------------------------------------------------
#define SCALEF   0.03125f        /* 1024^-0.5 */
#define EPS_LN   1e-5f
#define EPS_ATTN 1e-8f

// fp32 scratch offsets (floats)
#define OFF_SLOTS 0u
#define OFF_LN    262144u
#define OFF_Q     524288u
#define OFF_Q2    786432u
#define OFF_UPD   1048576u
#define OFF_UN    1310720u
#define OFF_GI    1572864u
#define OFF_GH    2359296u
#define OFF_H1    3145728u
#define OFF_UPART 4194304u      /* 32 chunks * 256 rows * 1024 */
#define OFF_WKT   12582912u
#define OFF_CB    13631488u
#define OFF_BS    13631744u
#define OFF_RINV  13632000u
#define OFF_RP    13632256u     /* 256 rows * 32 chunks */
#define OFF_ATTN  13640448u
#define SCRATCH_N 14689024u

__device__ float g_scratch[SCRATCH_N];

// bf16 split-weight buffers: W'[N][3K] with pattern [hi|lo|hi]
__device__ __nv_bfloat16 g_wq3 [1024u * 3072u];
__device__ __nv_bfloat16 g_wk3 [1024u * 3072u];   // from WkT
__device__ __nv_bfloat16 g_wv3 [1024u * 3072u];
__device__ __nv_bfloat16 g_wih3[3072u * 3072u];
__device__ __nv_bfloat16 g_whh3[3072u * 3072u];
__device__ __nv_bfloat16 g_w13 [4096u * 3072u];
__device__ __nv_bfloat16 g_w23 [1024u * 12288u];
// activation split buffer: A'[256][3K] with pattern [hi|hi|lo]
__device__ __nv_bfloat16 g_act3[256u * 12288u];

__device__ __forceinline__ float geluf(float x) {
    return 0.5f * x * (1.0f + erff(x * 0.70710678118654752f));
}
__device__ __forceinline__ float sigmf(float x) {
    return 1.0f / (1.0f + __expf(-x));
}

__device__ __forceinline__ uint32_t smem_u32(const void* p) {
    uint32_t a;
    asm("{ .reg .u64 t; cvta.to.shared.u64 t, %1; cvt.u32.u64 %0, t; }" : "=r"(a) : "l"(p));
    return a;
}
__device__ __forceinline__ void cp16s(uint32_t daddr, const void* src) {
    asm volatile("cp.async.cg.shared.global [%0], [%1], 16;" :: "r"(daddr), "l"(src));
}
__device__ __forceinline__ void ldm4(uint32_t* r, uint32_t addr) {
    asm volatile("ldmatrix.sync.aligned.m8n8.x4.shared.b16 {%0,%1,%2,%3}, [%4];"
        : "=r"(r[0]), "=r"(r[1]), "=r"(r[2]), "=r"(r[3]) : "r"(addr));
}
__device__ __forceinline__ void mma16816(float* c, const uint32_t* a, const uint32_t* b) {
    asm volatile(
        "mma.sync.aligned.m16n8k16.row.col.f32.bf16.bf16.f32 "
        "{%0,%1,%2,%3}, {%4,%5,%6,%7}, {%8,%9}, {%0,%1,%2,%3};"
        : "+f"(c[0]), "+f"(c[1]), "+f"(c[2]), "+f"(c[3])
        : "r"(a[0]), "r"(a[1]), "r"(a[2]), "r"(a[3]), "r"(b[0]), "r"(b[1]));
}

// ---------------------------------------------------------------------------
// init: slots = broadcast(slot_mu)
// ---------------------------------------------------------------------------
__global__ __launch_bounds__(256) void init_slots_kernel(const float* __restrict__ mu) {
    unsigned idx = blockIdx.x * 256u + threadIdx.x;
    g_scratch[OFF_SLOTS + idx] = mu[idx & 16383u];
}

// ---------------------------------------------------------------------------
// transpose Wk (1024x1024) -> WkT in scratch
// ---------------------------------------------------------------------------
__global__ void transpose_kernel(const float* __restrict__ in) {
    __shared__ float t[32][33];
    int x  = blockIdx.x * 32 + threadIdx.x;
    int y0 = blockIdx.y * 32;
    #pragma unroll
    for (int j = threadIdx.y; j < 32; j += 8)
        t[j][threadIdx.x] = in[(size_t)(y0 + j) * 1024 + x];
    __syncthreads();
    int xo  = blockIdx.y * 32 + threadIdx.x;
    int yo0 = blockIdx.x * 32;
    #pragma unroll
    for (int j = threadIdx.y; j < 32; j += 8)
        g_scratch[OFF_WKT + (size_t)(yo0 + j) * 1024 + xo] = t[threadIdx.x][j];
}

// ---------------------------------------------------------------------------
// weight split-convert: W (N x K fp32, row-major) -> dst (N x 3K bf16) [hi|lo|hi]
// ---------------------------------------------------------------------------
__global__ __launch_bounds__(256) void convw_kernel(const float* __restrict__ src,
                                                    unsigned srcOff,
                                                    __nv_bfloat16* __restrict__ dst,
                                                    int K) {
    unsigned idx = blockIdx.x * 256u + threadIdx.x;
    const float* S = src ? src : (g_scratch + srcOff);
    unsigned n = idx / (unsigned)K, k = idx % (unsigned)K;
    float x = S[idx];
    __nv_bfloat16 h = __float2bfloat16_rn(x);
    __nv_bfloat16 l = __float2bfloat16_rn(x - __bfloat162float(h));
    size_t base = (size_t)n * (3u * K);
    dst[base + k]         = h;
    dst[base + K + k]     = l;
    dst[base + 2u*K + k]  = h;
}

// ---------------------------------------------------------------------------
// activation split-convert: A (256 x K fp32) -> g_act3 (256 x 3K) [hi|hi|lo]
// ---------------------------------------------------------------------------
__global__ __launch_bounds__(256) void conva_kernel(unsigned srcOff, int K) {
    unsigned idx = blockIdx.x * 256u + threadIdx.x;   // < 256*K
    unsigned m = idx / (unsigned)K, k = idx % (unsigned)K;
    float x = g_scratch[srcOff + idx];
    __nv_bfloat16 h = __float2bfloat16_rn(x);
    __nv_bfloat16 l = __float2bfloat16_rn(x - __bfloat162float(h));
    size_t base = (size_t)m * (3u * K);
    g_act3[base + k]        = h;
    g_act3[base + K + k]    = h;
    g_act3[base + 2u*K + k] = l;
}

// ---------------------------------------------------------------------------
// HMMA GEMM: C[M=256, N] = A'[256,3K] (.) W'[N,3K]  (bf16 mma.sync -> fp32)
// Block 128(M) x 64(N), BK=32, 256 thr (8 warps, 4x2), double-buffered cp.async.
// smem K-major, row stride 40 elems (80B) -> conflict-free ldmatrix.
// ---------------------------------------------------------------------------
#define EPI_BIAS  0
#define EPI_BROW  1
#define EPI_GELU  2
#define EPI_RESID 3
#define EPI_SCALE 4

#define SAP 40

template<int EPI>
__global__ __launch_bounds__(256) void gemm_mma(const __nv_bfloat16* __restrict__ A3,
                                                const __nv_bfloat16* __restrict__ W3,
                                                const float* __restrict__ bias,
                                                unsigned offC, int N, int K3) {
    __shared__ __nv_bfloat16 As[2][128 * SAP];
    __shared__ __nv_bfloat16 Bs[2][64 * SAP];

    const int tid  = threadIdx.x;
    const int lane = tid & 31, wid = tid >> 5;
    const int wm = (wid & 3) * 32;          // warp m offset in tile
    const int wn = (wid >> 2) * 32;         // warp n offset in tile
    const int bn = blockIdx.x * 64, bm = blockIdx.y * 128;
    const int NC = K3 >> 5;

    // load mapping
    const int lrow = tid >> 2, lch = (tid & 3) * 8;     // chunk = 8 bf16 = 16B
    const __nv_bfloat16* agp0 = A3 + (size_t)(bm + lrow) * K3 + lch;
    const __nv_bfloat16* agp1 = A3 + (size_t)(bm + 64 + lrow) * K3 + lch;
    const __nv_bfloat16* bgp  = W3 + (size_t)(bn + lrow) * K3 + lch;
    const uint32_t asw0 = smem_u32(&As[0][lrow * SAP + lch]);
    const uint32_t asw1 = smem_u32(&As[0][(64 + lrow) * SAP + lch]);
    const uint32_t bsw  = smem_u32(&Bs[0][lrow * SAP + lch]);
    const uint32_t abufstep = (uint32_t)(128 * SAP * 2);
    const uint32_t bbufstep = (uint32_t)(64 * SAP * 2);

    // fragment smem addresses (per-lane, element offsets within buffer)
    const uint32_t a_base = smem_u32(&As[0][0]);
    const uint32_t b_base = smem_u32(&Bs[0][0]);
    const int a_row = wm + (lane & 15);                 // + mt*16
    const int a_col = (lane >> 4) * 8;                  // + ks*16
    const int b_row = wn + ((lane >> 4) & 1) * 8 + (lane & 7);  // + nt2*16
    const int b_col = ((lane >> 3) & 1) * 8;            // + ks*16

    float acc[2][4][4];
    #pragma unroll
    for (int i = 0; i < 2; i++)
        #pragma unroll
        for (int j = 0; j < 4; j++)
            #pragma unroll
            for (int e = 0; e < 4; e++) acc[i][j][e] = 0.f;

    // preload stage 0
    {
        cp16s(asw0, agp0);
        cp16s(asw1, agp1);
        cp16s(bsw,  bgp);
        asm volatile("cp.async.commit_group;" ::: "memory");
    }

    for (int c = 0; c < NC; c++) {
        const int buf = c & 1;
        if (c + 1 < NC) {
            const int nb = buf ^ 1;
            const size_t koff = (size_t)(c + 1) * 32;
            cp16s(asw0 + nb * abufstep, agp0 + koff);
            cp16s(asw1 + nb * abufstep, agp1 + koff);
            cp16s(bsw  + nb * bbufstep, bgp  + koff);
            asm volatile("cp.async.commit_group;" ::: "memory");
            asm volatile("cp.async.wait_group 1;" ::: "memory");
        } else {
            asm volatile("cp.async.wait_group 0;" ::: "memory");
        }
        __syncthreads();

        const uint32_t ab = a_base + buf * abufstep;
        const uint32_t bb = b_base + buf * bbufstep;
        #pragma unroll
        for (int ks = 0; ks < 2; ks++) {
            uint32_t af[2][4], bf[2][4];
            #pragma unroll
            for (int mt = 0; mt < 2; mt++)
                ldm4(af[mt], ab + (uint32_t)(((a_row + mt * 16) * SAP) + ks * 16 + a_col) * 2);
            #pragma unroll
            for (int nt2 = 0; nt2 < 2; nt2++)
                ldm4(bf[nt2], bb + (uint32_t)(((b_row + nt2 * 16) * SAP) + ks * 16 + b_col) * 2);
            #pragma unroll
            for (int mt = 0; mt < 2; mt++)
                #pragma unroll
                for (int nt = 0; nt < 4; nt++)
                    mma16816(acc[mt][nt], af[mt], &bf[nt >> 1][(nt & 1) * 2]);
        }
        __syncthreads();
    }

    // epilogue
    float* C = g_scratch + offC;
    const int mrow = lane >> 2, ncol2 = (lane & 3) * 2;
    #pragma unroll
    for (int mt = 0; mt < 2; mt++) {
        #pragma unroll
        for (int h = 0; h < 2; h++) {
            const int m = bm + wm + mt * 16 + mrow + h * 8;
            float brow = 0.f;
            if (EPI == EPI_BROW) brow = g_scratch[OFF_BS + m];
            #pragma unroll
            for (int nt = 0; nt < 4; nt++) {
                const int n0 = bn + wn + nt * 8 + ncol2;
                float ox = acc[mt][nt][h * 2], oy = acc[mt][nt][h * 2 + 1];
                if (EPI == EPI_SCALE) {
                    ox *= SCALEF; oy *= SCALEF;
                } else {
                    float2 bb = *(const float2*)(bias + n0);
                    if (EPI == EPI_BROW) { ox += bb.x * brow; oy += bb.y * brow; }
                    else                 { ox += bb.x;        oy += bb.y; }
                    if (EPI == EPI_GELU) { ox = geluf(ox); oy = geluf(oy); }
                    if (EPI == EPI_RESID) {
                        float2 c0 = *(const float2*)(C + (size_t)m * N + n0);
                        ox += c0.x; oy += c0.y;
                    }
                }
                *(float2*)(C + (size_t)m * N + n0) = make_float2(ox, oy);
            }
        }
    }
}

// ---------------------------------------------------------------------------
// LayerNorm over D=1024; one block (256 thr) per row, 256 rows
// ---------------------------------------------------------------------------
__global__ __launch_bounds__(256) void ln_kernel(unsigned offX, unsigned offY,
                                                 const float* __restrict__ g,
                                                 const float* __restrict__ bt) {
    __shared__ float red[256];
    const float* X = g_scratch + offX;
    float* Y = g_scratch + offY;
    int row = blockIdx.x, tid = threadIdx.x;
    float4 x = ((const float4*)X)[row * 256 + tid];
    red[tid] = x.x + x.y + x.z + x.w;
    __syncthreads();
    for (int o = 128; o > 0; o >>= 1) { if (tid < o) red[tid] += red[tid + o]; __syncthreads(); }
    float mean = red[0] * (1.0f / 1024.0f);
    __syncthreads();
    float4 dx = { x.x - mean, x.y - mean, x.z - mean, x.w - mean };
    red[tid] = dx.x*dx.x + dx.y*dx.y + dx.z*dx.z + dx.w*dx.w;
    __syncthreads();
    for (int o = 128; o > 0; o >>= 1) { if (tid < o) red[tid] += red[tid + o]; __syncthreads(); }
    float rs = rsqrtf(red[0] * (1.0f / 1024.0f) + EPS_LN);
    float4 gg = ((const float4*)g)[tid], bb = ((const float4*)bt)[tid];
    float4 y = { dx.x*rs*gg.x + bb.x, dx.y*rs*gg.y + bb.y,
                 dx.z*rs*gg.z + bb.z, dx.w*rs*gg.w + bb.w };
    ((float4*)Y)[row * 256 + tid] = y;
}

// ---------------------------------------------------------------------------
// cb[row] = SCALE * dot(q[row,:], bk)
// ---------------------------------------------------------------------------
__global__ __launch_bounds__(256) void cbk_kernel(const float* __restrict__ bk) {
    __shared__ float red[256];
    int row = blockIdx.x, tid = threadIdx.x;
    const float* q = g_scratch + OFF_Q + (size_t)row * 1024;
    float p = 0.f;
    #pragma unroll
    for (int i = 0; i < 4; i++) { int d = tid + 256 * i; p = fmaf(q[d], bk[d], p); }
    red[tid] = p; __syncthreads();
    for (int o = 128; o > 0; o >>= 1) { if (tid < o) red[tid] += red[tid + o]; __syncthreads(); }
    if (tid == 0) g_scratch[OFF_CB + row] = SCALEF * red[0];
}

// ---------------------------------------------------------------------------
// Fused token pass. grid = (32 chunks, 16 b), 128 threads, chunk = 128 tokens.
// ---------------------------------------------------------------------------
#define TSTR 36
__global__ __launch_bounds__(128) void pass_kernel(const float* __restrict__ tokens,
                                                   float* __restrict__ attn_ext)
{
    __shared__ float Td[128 * TSTR];
    __shared__ float Q2s[16 * TSTR];
    __shared__ float Att[16 * 128];
    const int tid = threadIdx.x;
    const int c = blockIdx.x;
    const int b = blockIdx.y;
    float* S = g_scratch;
    float* attn_out = attn_ext ? attn_ext : (S + OFF_ATTN);
    const float* q2 = S + OFF_Q2 + (size_t)b * 16384;
    const float* tokb = tokens + ((size_t)b * 4096 + (size_t)c * 128) * 1024;

    float lg[16];
    #pragma unroll
    for (int k = 0; k < 16; k++) lg[k] = S[OFF_CB + b * 16 + k];

    for (int sl = 0; sl < 32; sl++) {
        __syncthreads();
        #pragma unroll
        for (int i = 0; i < 8; i++) {
            int id = tid + 128 * i;
            int row = id >> 3, c4 = (id & 7) << 2;
            *(float4*)&Td[row * TSTR + c4] =
                *(const float4*)(tokb + (size_t)row * 1024 + sl * 32 + c4);
        }
        {
            int row = tid >> 3, c4 = (tid & 7) << 2;
            *(float4*)&Q2s[row * TSTR + c4] =
                *(const float4*)(q2 + (size_t)row * 1024 + sl * 32 + c4);
        }
        __syncthreads();
        #pragma unroll
        for (int d4 = 0; d4 < 32; d4 += 4) {
            float4 tv = *(const float4*)&Td[tid * TSTR + d4];
            #pragma unroll
            for (int k = 0; k < 16; k++) {
                float4 qv = *(const float4*)&Q2s[k * TSTR + d4];
                lg[k] = fmaf(tv.x, qv.x, fmaf(tv.y, qv.y,
                        fmaf(tv.z, qv.z, fmaf(tv.w, qv.w, lg[k]))));
            }
        }
    }

    float mx = lg[0];
    #pragma unroll
    for (int k = 1; k < 16; k++) mx = fmaxf(mx, lg[k]);
    float a[16], sum = 0.f;
    #pragma unroll
    for (int k = 0; k < 16; k++) { a[k] = __expf(lg[k] - mx); sum += a[k]; }
    float inv = 1.0f / sum;
    #pragma unroll
    for (int k = 0; k < 16; k++) {
        a[k] *= inv;
        Att[k * 128 + tid] = a[k];
        attn_out[((size_t)b * 16 + k) * 4096 + (size_t)c * 128 + tid] = a[k];
    }
    __syncthreads();
    if (tid < 16) {
        const float4* ap = (const float4*)&Att[tid * 128];
        float s2 = 0.f;
        #pragma unroll
        for (int i = 0; i < 32; i++) { float4 v = ap[i]; s2 += v.x + v.y + v.z + v.w; }
        S[OFF_RP + ((size_t)b * 16 + tid) * 32 + c] = s2;
    }

    const int kk = tid >> 3;
    const int dc = (tid & 7) << 2;
    float* up = S + OFF_UPART + (((size_t)c * 256) + b * 16 + kk) * 1024 + dc;
    const float* attk = &Att[kk * 128];
    for (int sl = 0; sl < 32; sl++) {
        __syncthreads();
        #pragma unroll
        for (int i = 0; i < 8; i++) {
            int id = tid + 128 * i;
            int row = id >> 3, c4 = (id & 7) << 2;
            *(float4*)&Td[row * TSTR + c4] =
                *(const float4*)(tokb + (size_t)row * 1024 + sl * 32 + c4);
        }
        __syncthreads();
        float4 acc = make_float4(0.f, 0.f, 0.f, 0.f);
        #pragma unroll 8
        for (int s = 0; s < 128; s += 4) {
            float4 a4 = *(const float4*)&attk[s];
            float4 t0 = *(const float4*)&Td[(s + 0) * TSTR + dc];
            float4 t1 = *(const float4*)&Td[(s + 1) * TSTR + dc];
            float4 t2 = *(const float4*)&Td[(s + 2) * TSTR + dc];
            float4 t3 = *(const float4*)&Td[(s + 3) * TSTR + dc];
            acc.x = fmaf(a4.x, t0.x, fmaf(a4.y, t1.x, fmaf(a4.z, t2.x, fmaf(a4.w, t3.x, acc.x))));
            acc.y = fmaf(a4.x, t0.y, fmaf(a4.y, t1.y, fmaf(a4.z, t2.y, fmaf(a4.w, t3.y, acc.y))));
            acc.z = fmaf(a4.x, t0.z, fmaf(a4.y, t1.z, fmaf(a4.z, t2.z, fmaf(a4.w, t3.z, acc.z))));
            acc.w = fmaf(a4.x, t0.w, fmaf(a4.y, t1.w, fmaf(a4.z, t2.w, fmaf(a4.w, t3.w, acc.w))));
        }
        *(float4*)(up + (size_t)sl * 32) = acc;
    }
}

// ---------------------------------------------------------------------------
// rowsum over chunks -> rinv, bscale
// ---------------------------------------------------------------------------
__global__ __launch_bounds__(256) void rowsum_kernel() {
    int row = threadIdx.x;
    float* S = g_scratch;
    float s = 0.f;
    #pragma unroll
    for (int cc = 0; cc < 32; cc++) s += S[OFF_RP + (size_t)row * 32 + cc];
    float ri = 1.0f / (s + EPS_ATTN);
    S[OFF_BS + row] = s * ri;
    S[OFF_RINV + row] = ri;
}

// ---------------------------------------------------------------------------
// Un[row][:] = rinv[row] * sum_chunks Upart
// ---------------------------------------------------------------------------
__global__ __launch_bounds__(256) void reduceU_kernel() {
    float* S = g_scratch;
    int row = blockIdx.x, tid = threadIdx.x;
    float ri = S[OFF_RINV + row];
    float4 acc = make_float4(0.f, 0.f, 0.f, 0.f);
    #pragma unroll 4
    for (int cc = 0; cc < 32; cc++) {
        float4 v = *(const float4*)&S[OFF_UPART + ((size_t)cc * 256 + row) * 1024 + tid * 4];
        acc.x += v.x; acc.y += v.y; acc.z += v.z; acc.w += v.w;
    }
    acc.x *= ri; acc.y *= ri; acc.z *= ri; acc.w *= ri;
    *(float4*)&S[OFF_UN + (size_t)row * 1024 + tid * 4] = acc;
}

// ---------------------------------------------------------------------------
// GRU gate combine, in-place slots update
// ---------------------------------------------------------------------------
__global__ __launch_bounds__(256) void gru_kernel() {
    float* S = g_scratch;
    unsigned idx = blockIdx.x * 256u + threadIdx.x;
    unsigned row = idx >> 10, col = idx & 1023u;
    size_t gb = (size_t)row * 3072 + col;
    float ir = S[OFF_GI + gb], iz = S[OFF_GI + gb + 1024], in_ = S[OFF_GI + gb + 2048];
    float hr = S[OFF_GH + gb], hz = S[OFF_GH + gb + 1024], hn  = S[OFF_GH + gb + 2048];
    float r = sigmf(ir + hr);
    float z = sigmf(iz + hz);
    float n = tanhf(in_ + r * hn);
    float sp = S[OFF_SLOTS + idx];
    S[OFF_SLOTS + idx] = (1.0f - z) * n + z * sp;
}

// ---------------------------------------------------------------------------
// copy slots -> out
// ---------------------------------------------------------------------------
__global__ __launch_bounds__(256) void copy_out_kernel(float* __restrict__ out, int n) {
    int idx = blockIdx.x * 256 + threadIdx.x;
    if (idx < n) out[idx] = g_scratch[OFF_SLOTS + idx];
}

// ---------------------------------------------------------------------------
// host
// ---------------------------------------------------------------------------
extern "C" void kernel_launch(void* const* d_in, const int* in_sizes, int n_in,
                              void* d_out, int out_size) {
    const float* tokens = (const float*)d_in[0];
    const float* mu     = (const float*)d_in[1];
    const float* Wq  = (const float*)d_in[2];  const float* bq  = (const float*)d_in[3];
    const float* Wk  = (const float*)d_in[4];  const float* bk  = (const float*)d_in[5];
    const float* Wv  = (const float*)d_in[6];  const float* bv  = (const float*)d_in[7];
    const float* Wih = (const float*)d_in[8];  const float* bih = (const float*)d_in[9];
    const float* Whh = (const float*)d_in[10]; const float* bhh = (const float*)d_in[11];
    const float* W1  = (const float*)d_in[12]; const float* b1  = (const float*)d_in[13];
    const float* W2  = (const float*)d_in[14]; const float* b2  = (const float*)d_in[15];
    const float* gs  = (const float*)d_in[16]; const float* bs  = (const float*)d_in[17];
    const float* gm  = (const float*)d_in[18]; const float* bm  = (const float*)d_in[19];
    float* out = (float*)d_out;

    float* attnp = (out_size >= 1310720) ? (out + 262144) : nullptr;

    __nv_bfloat16 *wq3, *wk3, *wv3, *wih3, *whh3, *w13, *w23, *act3;
    cudaGetSymbolAddress((void**)&wq3,  g_wq3);
    cudaGetSymbolAddress((void**)&wk3,  g_wk3);
    cudaGetSymbolAddress((void**)&wv3,  g_wv3);
    cudaGetSymbolAddress((void**)&wih3, g_wih3);
    cudaGetSymbolAddress((void**)&whh3, g_whh3);
    cudaGetSymbolAddress((void**)&w13,  g_w13);
    cudaGetSymbolAddress((void**)&w23,  g_w23);
    cudaGetSymbolAddress((void**)&act3, g_act3);

    // one-time per call: transpose Wk, convert weights, init slots
    transpose_kernel<<<dim3(32, 32), dim3(32, 8)>>>(Wk);
    convw_kernel<<<4096,  256>>>(Wq,      0, wq3,  1024);
    convw_kernel<<<4096,  256>>>(nullptr, OFF_WKT, wk3, 1024);
    convw_kernel<<<4096,  256>>>(Wv,      0, wv3,  1024);
    convw_kernel<<<12288, 256>>>(Wih,     0, wih3, 1024);
    convw_kernel<<<12288, 256>>>(Whh,     0, whh3, 1024);
    convw_kernel<<<16384, 256>>>(W1,      0, w13,  1024);
    convw_kernel<<<16384, 256>>>(W2,      0, w23,  4096);
    init_slots_kernel<<<1024, 256>>>(mu);

    for (int it = 0; it < 3; it++) {
        ln_kernel<<<256, 256>>>(OFF_SLOTS, OFF_LN, gs, bs);
        conva_kernel<<<1024, 256>>>(OFF_LN, 1024);
        gemm_mma<EPI_BIAS><<<dim3(16, 2), 256>>>(act3, wq3, bq, OFF_Q, 1024, 3072);
        conva_kernel<<<1024, 256>>>(OFF_Q, 1024);
        gemm_mma<EPI_SCALE><<<dim3(16, 2), 256>>>(act3, wk3, nullptr, OFF_Q2, 1024, 3072);
        cbk_kernel<<<256, 256>>>(bk);
        pass_kernel<<<dim3(32, 16), 128>>>(tokens, attnp);
        rowsum_kernel<<<1, 256>>>();
        reduceU_kernel<<<256, 256>>>();
        conva_kernel<<<1024, 256>>>(OFF_UN, 1024);
        gemm_mma<EPI_BROW><<<dim3(16, 2), 256>>>(act3, wv3, bv, OFF_UPD, 1024, 3072);
        conva_kernel<<<1024, 256>>>(OFF_UPD, 1024);
        gemm_mma<EPI_BIAS><<<dim3(48, 2), 256>>>(act3, wih3, bih, OFF_GI, 3072, 3072);
        conva_kernel<<<1024, 256>>>(OFF_SLOTS, 1024);
        gemm_mma<EPI_BIAS><<<dim3(48, 2), 256>>>(act3, whh3, bhh, OFF_GH, 3072, 3072);
        gru_kernel<<<1024, 256>>>();
        ln_kernel<<<256, 256>>>(OFF_SLOTS, OFF_LN, gm, bm);
        conva_kernel<<<1024, 256>>>(OFF_LN, 1024);
        gemm_mma<EPI_GELU><<<dim3(64, 2), 256>>>(act3, w13, b1, OFF_H1, 4096, 3072);
        conva_kernel<<<4096, 256>>>(OFF_H1, 4096);
        gemm_mma<EPI_RESID><<<dim3(16, 2), 256>>>(act3, w23, b2, OFF_SLOTS, 1024, 12288);
    }

    int nslots = out_size < 262144 ? out_size : 262144;
    copy_out_kernel<<<1024, 256>>>(out, nslots);
}

// round 5
// speedup vs baseline: 1.4666x; 1.3565x over previous
#include <cuda_runtime.h>
#include <cuda_bf16.h>
#include <cstdint>
#include <cstddef>

// ---------------------------------------------------------------------------
// Problem sizes: B=16, S=4096, D=1024, K=16, ITERS=3
// ---------------------------------------------------------------------------
#define SCALEF   0.03125f        /* 1024^-0.5 */
#define EPS_LN   1e-5f
#define EPS_ATTN 1e-8f

// fp32 scratch offsets (floats)
#define OFF_SLOTS 0u
#define OFF_Q     524288u
#define OFF_Q2    786432u
#define OFF_GI    1572864u
#define OFF_GH    2359296u
#define OFF_UPART 4194304u      /* 32 chunks * 256 rows * 1024 */
#define OFF_WKT   12582912u
#define OFF_CB    13631488u
#define OFF_BS    13631744u
#define OFF_RINV  13632000u
#define OFF_RP    13632256u     /* 256 rows * 32 chunks */
#define OFF_ATTN  13640448u
#define SCRATCH_N 14689024u

__device__ float g_scratch[SCRATCH_N];

// bf16 split-weight buffers: W'[N][3K] pattern [hi|lo|hi]
__device__ __nv_bfloat16 g_wq3 [1024u * 3072u];
__device__ __nv_bfloat16 g_wk3 [1024u * 3072u];   // from WkT
__device__ __nv_bfloat16 g_wv3 [1024u * 3072u];
__device__ __nv_bfloat16 g_wih3[3072u * 3072u];
__device__ __nv_bfloat16 g_whh3[3072u * 3072u];
__device__ __nv_bfloat16 g_w13 [4096u * 3072u];
__device__ __nv_bfloat16 g_w23 [1024u * 12288u];
// activation split buffers: [m][3K'] pattern [hi|hi|lo]
__device__ __nv_bfloat16 g_actA  [256u * 3072u];
__device__ __nv_bfloat16 g_actB  [256u * 3072u];
__device__ __nv_bfloat16 g_actS  [256u * 3072u];
__device__ __nv_bfloat16 g_actBig[256u * 12288u];

__device__ __forceinline__ float geluf(float x) {
    return 0.5f * x * (1.0f + erff(x * 0.70710678118654752f));
}
__device__ __forceinline__ float sigmf(float x) {
    return 1.0f / (1.0f + __expf(-x));
}

__device__ __forceinline__ uint32_t smem_u32(const void* p) {
    uint32_t a;
    asm("{ .reg .u64 t; cvta.to.shared.u64 t, %1; cvt.u32.u64 %0, t; }" : "=r"(a) : "l"(p));
    return a;
}
__device__ __forceinline__ void cp16s(uint32_t daddr, const void* src) {
    asm volatile("cp.async.cg.shared.global [%0], [%1], 16;" :: "r"(daddr), "l"(src));
}
__device__ __forceinline__ void cpcommit() {
    asm volatile("cp.async.commit_group;" ::: "memory");
}
__device__ __forceinline__ void cpwait_n(int n) {
    if (n <= 0)      asm volatile("cp.async.wait_group 0;" ::: "memory");
    else if (n == 1) asm volatile("cp.async.wait_group 1;" ::: "memory");
    else             asm volatile("cp.async.wait_group 2;" ::: "memory");
}
__device__ __forceinline__ void ldm4(uint32_t* r, uint32_t addr) {
    asm volatile("ldmatrix.sync.aligned.m8n8.x4.shared.b16 {%0,%1,%2,%3}, [%4];"
        : "=r"(r[0]), "=r"(r[1]), "=r"(r[2]), "=r"(r[3]) : "r"(addr));
}
__device__ __forceinline__ void mma16816(float* c, const uint32_t* a, const uint32_t* b) {
    asm volatile(
        "mma.sync.aligned.m16n8k16.row.col.f32.bf16.bf16.f32 "
        "{%0,%1,%2,%3}, {%4,%5,%6,%7}, {%8,%9}, {%0,%1,%2,%3};"
        : "+f"(c[0]), "+f"(c[1]), "+f"(c[2]), "+f"(c[3])
        : "r"(a[0]), "r"(a[1]), "r"(a[2]), "r"(a[3]), "r"(b[0]), "r"(b[1]));
}

// split helper: x -> (hi, lo) bf16
__device__ __forceinline__ void bsplit(float x, __nv_bfloat16& h, __nv_bfloat16& l) {
    h = __float2bfloat16_rn(x);
    l = __float2bfloat16_rn(x - __bfloat162float(h));
}

// ---------------------------------------------------------------------------
// init: slots = broadcast(slot_mu); also emit actS split (slots feed gh at it0)
// ---------------------------------------------------------------------------
__global__ __launch_bounds__(256) void init_slots_kernel(const float* __restrict__ mu) {
    unsigned idx = blockIdx.x * 256u + threadIdx.x;          // < 262144
    float x = mu[idx & 16383u];
    g_scratch[OFF_SLOTS + idx] = x;
    unsigned m = idx >> 10, k = idx & 1023u;
    __nv_bfloat16 h, l; bsplit(x, h, l);
    size_t base = (size_t)m * 3072u;
    g_actS[base + k] = h; g_actS[base + 1024u + k] = h; g_actS[base + 2048u + k] = l;
}

// ---------------------------------------------------------------------------
// transpose Wk (1024x1024) -> WkT in scratch
// ---------------------------------------------------------------------------
__global__ void transpose_kernel(const float* __restrict__ in) {
    __shared__ float t[32][33];
    int x  = blockIdx.x * 32 + threadIdx.x;
    int y0 = blockIdx.y * 32;
    #pragma unroll
    for (int j = threadIdx.y; j < 32; j += 8)
        t[j][threadIdx.x] = in[(size_t)(y0 + j) * 1024 + x];
    __syncthreads();
    int xo  = blockIdx.y * 32 + threadIdx.x;
    int yo0 = blockIdx.x * 32;
    #pragma unroll
    for (int j = threadIdx.y; j < 32; j += 8)
        g_scratch[OFF_WKT + (size_t)(yo0 + j) * 1024 + xo] = t[threadIdx.x][j];
}

// ---------------------------------------------------------------------------
// weight split-convert: W (N x K fp32 row-major) -> dst (N x 3K bf16) [hi|lo|hi]
// ---------------------------------------------------------------------------
__global__ __launch_bounds__(256) void convw_kernel(const float* __restrict__ src,
                                                    unsigned srcOff,
                                                    __nv_bfloat16* __restrict__ dst,
                                                    int K) {
    unsigned idx = blockIdx.x * 256u + threadIdx.x;
    const float* S = src ? src : (g_scratch + srcOff);
    unsigned n = idx / (unsigned)K, k = idx % (unsigned)K;
    float x = S[idx];
    __nv_bfloat16 h, l; bsplit(x, h, l);
    size_t base = (size_t)n * (3u * K);
    dst[base + k]        = h;
    dst[base + K + k]    = l;
    dst[base + 2u*K + k] = h;
}

// ---------------------------------------------------------------------------
// Unified HMMA GEMM core: C[M=*, N] = A'[.,3K] (.) W'[N,3K] bf16 -> fp32
// BM in {128, 64}, BN=64, BK=32, 4-stage cp.async pipeline, 256 threads.
// Runtime epilogue: epi 0=+bias, 2=gelu(+bias), 3=+bias+Cold(resid),
//                   4=*SCALE, 5=+bias*brow.  Optional act split output.
// ---------------------------------------------------------------------------
#define SAP 40

template<int BM>
__device__ __forceinline__ void gemm_core(char* sm,
    const __nv_bfloat16* __restrict__ A, const __nv_bfloat16* __restrict__ W,
    const float* __restrict__ bias, float* Cout, __nv_bfloat16* actout, int actK,
    int N, int K3, int epi)
{
    constexpr int NW_M = (BM == 128) ? 4 : 2;
    constexpr int WTN  = (BM == 128) ? 32 : 16;
    constexpr int NT   = WTN / 8;
    constexpr uint32_t ASTG = BM * SAP * 2;
    constexpr uint32_t BSTG = 64 * SAP * 2;

    const int tid  = threadIdx.x;
    const int lane = tid & 31, wid = tid >> 5;
    const int wm = (wid % NW_M) * 32;
    const int wn = (wid / NW_M) * WTN;
    const int bn = blockIdx.x * 64, bm = blockIdx.y * BM;
    const int NC = K3 >> 5;

    const uint32_t smb = smem_u32(sm);
    const uint32_t aS = smb;                 // 4 stages of A
    const uint32_t bS = smb + 4 * ASTG;      // 4 stages of B

    const int lrow = tid >> 2, lch = (tid & 3) * 8;
    const __nv_bfloat16* agp0 = A + (size_t)(bm + lrow) * K3 + lch;
    const __nv_bfloat16* agp1 = A + (size_t)(bm + 64 + lrow) * K3 + lch;   // BM=128 only
    const __nv_bfloat16* bgp  = W + (size_t)(bn + lrow) * K3 + lch;
    const uint32_t aoff = (uint32_t)(lrow * SAP + lch) * 2;
    const uint32_t aoff1 = (uint32_t)((64 + lrow) * SAP + lch) * 2;

    // frag addressing
    const int a_row = wm + (lane & 15);
    const int a_col = (lane >> 4) * 8;
    const int b_row = wn + ((lane >> 4) & 1) * 8 + (lane & 7);
    const int b_col = ((lane >> 3) & 1) * 8;

    float acc[2][NT][4];
    #pragma unroll
    for (int i = 0; i < 2; i++)
        #pragma unroll
        for (int j = 0; j < NT; j++)
            #pragma unroll
            for (int e = 0; e < 4; e++) acc[i][j][e] = 0.f;

    // prologue: stages 0..2
    #pragma unroll
    for (int s = 0; s < 3; s++) {
        const size_t ko = (size_t)s * 32;
        cp16s(aS + s * ASTG + aoff, agp0 + ko);
        if (BM == 128) cp16s(aS + s * ASTG + aoff1, agp1 + ko);
        cp16s(bS + s * BSTG + aoff, bgp + ko);
        cpcommit();
    }

    for (int c = 0; c < NC; c++) {
        int bnd = NC - 1 - c; if (bnd > 2) bnd = 2;
        cpwait_n(bnd);
        __syncthreads();
        if (c + 3 < NC) {
            const int s = (c + 3) & 3;
            const size_t ko = (size_t)(c + 3) * 32;
            cp16s(aS + s * ASTG + aoff, agp0 + ko);
            if (BM == 128) cp16s(aS + s * ASTG + aoff1, agp1 + ko);
            cp16s(bS + s * BSTG + aoff, bgp + ko);
            cpcommit();
        }
        const uint32_t ab = aS + (c & 3) * ASTG;
        const uint32_t bb = bS + (c & 3) * BSTG;
        #pragma unroll
        for (int ks = 0; ks < 2; ks++) {
            uint32_t af[2][4], bf[2][4];
            #pragma unroll
            for (int mt = 0; mt < 2; mt++)
                ldm4(af[mt], ab + (uint32_t)(((a_row + mt * 16) * SAP) + ks * 16 + a_col) * 2);
            #pragma unroll
            for (int nb = 0; nb < NT / 2 + (NT & 1); nb++)   // NT=4 -> 2 ldm, NT=2 -> 1 ldm
                ldm4(bf[nb], bb + (uint32_t)(((b_row + nb * 16) * SAP) + ks * 16 + b_col) * 2);
            #pragma unroll
            for (int mt = 0; mt < 2; mt++)
                #pragma unroll
                for (int nt = 0; nt < NT; nt++)
                    mma16816(acc[mt][nt], af[mt], &bf[nt >> 1][(nt & 1) * 2]);
        }
    }

    // epilogue
    const int mrow = lane >> 2, ncol2 = (lane & 3) * 2;
    #pragma unroll
    for (int mt = 0; mt < 2; mt++) {
        #pragma unroll
        for (int h = 0; h < 2; h++) {
            const int m = bm + wm + mt * 16 + mrow + h * 8;
            float brow = 0.f;
            if (epi == 5) brow = g_scratch[OFF_BS + m];
            #pragma unroll
            for (int nt = 0; nt < NT; nt++) {
                const int n0 = bn + wn + nt * 8 + ncol2;
                float ox = acc[mt][nt][h * 2], oy = acc[mt][nt][h * 2 + 1];
                if (epi == 4) { ox *= SCALEF; oy *= SCALEF; }
                else {
                    float2 bb = *(const float2*)(bias + n0);
                    if (epi == 5)      { ox += bb.x * brow; oy += bb.y * brow; }
                    else               { ox += bb.x;        oy += bb.y; }
                    if (epi == 2)      { ox = geluf(ox); oy = geluf(oy); }
                    if (epi == 3) {
                        float2 c0 = *(const float2*)(Cout + (size_t)m * N + n0);
                        ox += c0.x; oy += c0.y;
                    }
                }
                if (Cout) *(float2*)(Cout + (size_t)m * N + n0) = make_float2(ox, oy);
                if (actout) {
                    __nv_bfloat16 hh, ll;
                    size_t base = (size_t)m * (3u * (unsigned)actK);
                    bsplit(ox, hh, ll);
                    actout[base + n0] = hh; actout[base + actK + n0] = hh;
                    actout[base + 2 * actK + n0] = ll;
                    bsplit(oy, hh, ll);
                    actout[base + n0 + 1] = hh; actout[base + actK + n0 + 1] = hh;
                    actout[base + 2 * actK + n0 + 1] = ll;
                }
            }
        }
    }
}

template<int BM>
__global__ __launch_bounds__(256) void gemm_k(const __nv_bfloat16* __restrict__ A,
                                              const __nv_bfloat16* __restrict__ W,
                                              const float* __restrict__ bias,
                                              float* Cout, __nv_bfloat16* actout, int actK,
                                              int N, int K3, int epi) {
    extern __shared__ char sm[];
    gemm_core<BM>(sm, A, W, bias, Cout, actout, actK, N, K3, epi);
}

// merged GRU gemms: z=0 -> gi = actB @ Wih^T + bih ; z=1 -> gh = actS @ Whh^T + bhh
__global__ __launch_bounds__(256) void gru_gemm_k(const float* __restrict__ bih,
                                                  const float* __restrict__ bhh) {
    extern __shared__ char sm[];
    if (blockIdx.z == 0)
        gemm_core<128>(sm, g_actB, g_wih3, bih, g_scratch + OFF_GI, nullptr, 0, 3072, 3072, 0);
    else
        gemm_core<128>(sm, g_actS, g_whh3, bhh, g_scratch + OFF_GH, nullptr, 0, 3072, 3072, 0);
}

// ---------------------------------------------------------------------------
// LayerNorm over D=1024 -> act split only. one block per row, 256 rows.
// ---------------------------------------------------------------------------
__global__ __launch_bounds__(256) void ln_kernel(unsigned offX,
                                                 const float* __restrict__ g,
                                                 const float* __restrict__ bt,
                                                 __nv_bfloat16* __restrict__ actout) {
    __shared__ float red[256];
    const float* X = g_scratch + offX;
    int row = blockIdx.x, tid = threadIdx.x;
    float4 x = ((const float4*)X)[row * 256 + tid];
    red[tid] = x.x + x.y + x.z + x.w;
    __syncthreads();
    for (int o = 128; o > 0; o >>= 1) { if (tid < o) red[tid] += red[tid + o]; __syncthreads(); }
    float mean = red[0] * (1.0f / 1024.0f);
    __syncthreads();
    float4 dx = { x.x - mean, x.y - mean, x.z - mean, x.w - mean };
    red[tid] = dx.x*dx.x + dx.y*dx.y + dx.z*dx.z + dx.w*dx.w;
    __syncthreads();
    for (int o = 128; o > 0; o >>= 1) { if (tid < o) red[tid] += red[tid + o]; __syncthreads(); }
    float rs = rsqrtf(red[0] * (1.0f / 1024.0f) + EPS_LN);
    float4 gg = ((const float4*)g)[tid], bb = ((const float4*)bt)[tid];
    float y[4] = { dx.x*rs*gg.x + bb.x, dx.y*rs*gg.y + bb.y,
                   dx.z*rs*gg.z + bb.z, dx.w*rs*gg.w + bb.w };
    size_t base = (size_t)row * 3072u;
    #pragma unroll
    for (int j = 0; j < 4; j++) {
        int k = tid * 4 + j;
        __nv_bfloat16 h, l; bsplit(y[j], h, l);
        actout[base + k] = h; actout[base + 1024 + k] = h; actout[base + 2048 + k] = l;
    }
}

// ---------------------------------------------------------------------------
// cb[row] = SCALE * dot(q[row,:], bk)
// ---------------------------------------------------------------------------
__global__ __launch_bounds__(256) void cbk_kernel(const float* __restrict__ bk) {
    __shared__ float red[256];
    int row = blockIdx.x, tid = threadIdx.x;
    const float* q = g_scratch + OFF_Q + (size_t)row * 1024;
    float p = 0.f;
    #pragma unroll
    for (int i = 0; i < 4; i++) { int d = tid + 256 * i; p = fmaf(q[d], bk[d], p); }
    red[tid] = p; __syncthreads();
    for (int o = 128; o > 0; o >>= 1) { if (tid < o) red[tid] += red[tid + o]; __syncthreads(); }
    if (tid == 0) g_scratch[OFF_CB + row] = SCALEF * red[0];
}

// ---------------------------------------------------------------------------
// Fused token pass. grid = (32 chunks, 16 b), 128 threads, chunk = 128 tokens.
// ---------------------------------------------------------------------------
#define TSTR 36
__global__ __launch_bounds__(128) void pass_kernel(const float* __restrict__ tokens,
                                                   float* __restrict__ attn_ext)
{
    __shared__ float Td[128 * TSTR];
    __shared__ float Q2s[16 * TSTR];
    __shared__ float Att[16 * 128];
    const int tid = threadIdx.x;
    const int c = blockIdx.x;
    const int b = blockIdx.y;
    float* S = g_scratch;
    float* attn_out = attn_ext ? attn_ext : (S + OFF_ATTN);
    const float* q2 = S + OFF_Q2 + (size_t)b * 16384;
    const float* tokb = tokens + ((size_t)b * 4096 + (size_t)c * 128) * 1024;

    float lg[16];
    #pragma unroll
    for (int k = 0; k < 16; k++) lg[k] = S[OFF_CB + b * 16 + k];

    for (int sl = 0; sl < 32; sl++) {
        __syncthreads();
        #pragma unroll
        for (int i = 0; i < 8; i++) {
            int id = tid + 128 * i;
            int row = id >> 3, c4 = (id & 7) << 2;
            *(float4*)&Td[row * TSTR + c4] =
                *(const float4*)(tokb + (size_t)row * 1024 + sl * 32 + c4);
        }
        {
            int row = tid >> 3, c4 = (tid & 7) << 2;
            *(float4*)&Q2s[row * TSTR + c4] =
                *(const float4*)(q2 + (size_t)row * 1024 + sl * 32 + c4);
        }
        __syncthreads();
        #pragma unroll
        for (int d4 = 0; d4 < 32; d4 += 4) {
            float4 tv = *(const float4*)&Td[tid * TSTR + d4];
            #pragma unroll
            for (int k = 0; k < 16; k++) {
                float4 qv = *(const float4*)&Q2s[k * TSTR + d4];
                lg[k] = fmaf(tv.x, qv.x, fmaf(tv.y, qv.y,
                        fmaf(tv.z, qv.z, fmaf(tv.w, qv.w, lg[k]))));
            }
        }
    }

    float mx = lg[0];
    #pragma unroll
    for (int k = 1; k < 16; k++) mx = fmaxf(mx, lg[k]);
    float a[16], sum = 0.f;
    #pragma unroll
    for (int k = 0; k < 16; k++) { a[k] = __expf(lg[k] - mx); sum += a[k]; }
    float inv = 1.0f / sum;
    #pragma unroll
    for (int k = 0; k < 16; k++) {
        a[k] *= inv;
        Att[k * 128 + tid] = a[k];
        attn_out[((size_t)b * 16 + k) * 4096 + (size_t)c * 128 + tid] = a[k];
    }
    __syncthreads();
    if (tid < 16) {
        const float4* ap = (const float4*)&Att[tid * 128];
        float s2 = 0.f;
        #pragma unroll
        for (int i = 0; i < 32; i++) { float4 v = ap[i]; s2 += v.x + v.y + v.z + v.w; }
        S[OFF_RP + ((size_t)b * 16 + tid) * 32 + c] = s2;
    }

    const int kk = tid >> 3;
    const int dc = (tid & 7) << 2;
    float* up = S + OFF_UPART + (((size_t)c * 256) + b * 16 + kk) * 1024 + dc;
    const float* attk = &Att[kk * 128];
    for (int sl = 0; sl < 32; sl++) {
        __syncthreads();
        #pragma unroll
        for (int i = 0; i < 8; i++) {
            int id = tid + 128 * i;
            int row = id >> 3, c4 = (id & 7) << 2;
            *(float4*)&Td[row * TSTR + c4] =
                *(const float4*)(tokb + (size_t)row * 1024 + sl * 32 + c4);
        }
        __syncthreads();
        float4 acc = make_float4(0.f, 0.f, 0.f, 0.f);
        #pragma unroll 8
        for (int s = 0; s < 128; s += 4) {
            float4 a4 = *(const float4*)&attk[s];
            float4 t0 = *(const float4*)&Td[(s + 0) * TSTR + dc];
            float4 t1 = *(const float4*)&Td[(s + 1) * TSTR + dc];
            float4 t2 = *(const float4*)&Td[(s + 2) * TSTR + dc];
            float4 t3 = *(const float4*)&Td[(s + 3) * TSTR + dc];
            acc.x = fmaf(a4.x, t0.x, fmaf(a4.y, t1.x, fmaf(a4.z, t2.x, fmaf(a4.w, t3.x, acc.x))));
            acc.y = fmaf(a4.x, t0.y, fmaf(a4.y, t1.y, fmaf(a4.z, t2.y, fmaf(a4.w, t3.y, acc.y))));
            acc.z = fmaf(a4.x, t0.z, fmaf(a4.y, t1.z, fmaf(a4.z, t2.z, fmaf(a4.w, t3.z, acc.z))));
            acc.w = fmaf(a4.x, t0.w, fmaf(a4.y, t1.w, fmaf(a4.z, t2.w, fmaf(a4.w, t3.w, acc.w))));
        }
        *(float4*)(up + (size_t)sl * 32) = acc;
    }
}

// ---------------------------------------------------------------------------
// rowsum over chunks -> rinv, bscale
// ---------------------------------------------------------------------------
__global__ __launch_bounds__(256) void rowsum_kernel() {
    int row = threadIdx.x;
    float* S = g_scratch;
    float s = 0.f;
    #pragma unroll
    for (int cc = 0; cc < 32; cc++) s += S[OFF_RP + (size_t)row * 32 + cc];
    float ri = 1.0f / (s + EPS_ATTN);
    S[OFF_BS + row] = s * ri;
    S[OFF_RINV + row] = ri;
}

// ---------------------------------------------------------------------------
// Un[row][:] = rinv[row] * sum_chunks Upart -> actA split directly
// ---------------------------------------------------------------------------
__global__ __launch_bounds__(256) void reduceU_kernel() {
    float* S = g_scratch;
    int row = blockIdx.x, tid = threadIdx.x;
    float ri = S[OFF_RINV + row];
    float4 acc = make_float4(0.f, 0.f, 0.f, 0.f);
    #pragma unroll 4
    for (int cc = 0; cc < 32; cc++) {
        float4 v = *(const float4*)&S[OFF_UPART + ((size_t)cc * 256 + row) * 1024 + tid * 4];
        acc.x += v.x; acc.y += v.y; acc.z += v.z; acc.w += v.w;
    }
    float y[4] = { acc.x * ri, acc.y * ri, acc.z * ri, acc.w * ri };
    size_t base = (size_t)row * 3072u;
    #pragma unroll
    for (int j = 0; j < 4; j++) {
        int k = tid * 4 + j;
        __nv_bfloat16 h, l; bsplit(y[j], h, l);
        g_actA[base + k] = h; g_actA[base + 1024 + k] = h; g_actA[base + 2048 + k] = l;
    }
}

// ---------------------------------------------------------------------------
// GRU gate combine, in-place slots update
// ---------------------------------------------------------------------------
__global__ __launch_bounds__(256) void gru_kernel() {
    float* S = g_scratch;
    unsigned idx = blockIdx.x * 256u + threadIdx.x;
    unsigned row = idx >> 10, col = idx & 1023u;
    size_t gb = (size_t)row * 3072 + col;
    float ir = S[OFF_GI + gb], iz = S[OFF_GI + gb + 1024], in_ = S[OFF_GI + gb + 2048];
    float hr = S[OFF_GH + gb], hz = S[OFF_GH + gb + 1024], hn  = S[OFF_GH + gb + 2048];
    float r = sigmf(ir + hr);
    float z = sigmf(iz + hz);
    float n = tanhf(in_ + r * hn);
    float sp = S[OFF_SLOTS + idx];
    S[OFF_SLOTS + idx] = (1.0f - z) * n + z * sp;
}

// ---------------------------------------------------------------------------
// copy slots -> out
// ---------------------------------------------------------------------------
__global__ __launch_bounds__(256) void copy_out_kernel(float* __restrict__ out, int n) {
    int idx = blockIdx.x * 256 + threadIdx.x;
    if (idx < n) out[idx] = g_scratch[OFF_SLOTS + idx];
}

// ---------------------------------------------------------------------------
// host
// ---------------------------------------------------------------------------
#define SMEM128 (4 * (128 + 64) * SAP * 2)
#define SMEM64  (4 * (64 + 64) * SAP * 2)

extern "C" void kernel_launch(void* const* d_in, const int* in_sizes, int n_in,
                              void* d_out, int out_size) {
    const float* tokens = (const float*)d_in[0];
    const float* mu     = (const float*)d_in[1];
    const float* Wq  = (const float*)d_in[2];  const float* bq  = (const float*)d_in[3];
    const float* Wk  = (const float*)d_in[4];  const float* bk  = (const float*)d_in[5];
    const float* Wv  = (const float*)d_in[6];  const float* bv  = (const float*)d_in[7];
    const float* Wih = (const float*)d_in[8];  const float* bih = (const float*)d_in[9];
    const float* Whh = (const float*)d_in[10]; const float* bhh = (const float*)d_in[11];
    const float* W1  = (const float*)d_in[12]; const float* b1  = (const float*)d_in[13];
    const float* W2  = (const float*)d_in[14]; const float* b2  = (const float*)d_in[15];
    const float* gs  = (const float*)d_in[16]; const float* bs  = (const float*)d_in[17];
    const float* gm  = (const float*)d_in[18]; const float* bm  = (const float*)d_in[19];
    float* out = (float*)d_out;

    float* attnp = (out_size >= 1310720) ? (out + 262144) : nullptr;

    cudaFuncSetAttribute((const void*)gemm_k<128>, cudaFuncAttributeMaxDynamicSharedMemorySize, SMEM128);
    cudaFuncSetAttribute((const void*)gemm_k<64>,  cudaFuncAttributeMaxDynamicSharedMemorySize, SMEM64);
    cudaFuncSetAttribute((const void*)gru_gemm_k,  cudaFuncAttributeMaxDynamicSharedMemorySize, SMEM128);

    __nv_bfloat16 *wq3, *wk3, *wv3, *wih3, *whh3, *w13, *w23, *actA, *actB, *actS, *actBig;
    cudaGetSymbolAddress((void**)&wq3,  g_wq3);
    cudaGetSymbolAddress((void**)&wk3,  g_wk3);
    cudaGetSymbolAddress((void**)&wv3,  g_wv3);
    cudaGetSymbolAddress((void**)&wih3, g_wih3);
    cudaGetSymbolAddress((void**)&whh3, g_whh3);
    cudaGetSymbolAddress((void**)&w13,  g_w13);
    cudaGetSymbolAddress((void**)&w23,  g_w23);
    cudaGetSymbolAddress((void**)&actA, g_actA);
    cudaGetSymbolAddress((void**)&actB, g_actB);
    cudaGetSymbolAddress((void**)&actS, g_actS);
    cudaGetSymbolAddress((void**)&actBig, g_actBig);
    float* scr;
    cudaGetSymbolAddress((void**)&scr, g_scratch);

    // one-time per call
    transpose_kernel<<<dim3(32, 32), dim3(32, 8)>>>(Wk);
    convw_kernel<<<4096,  256>>>(Wq,      0, wq3,  1024);
    convw_kernel<<<4096,  256>>>(nullptr, OFF_WKT, wk3, 1024);
    convw_kernel<<<4096,  256>>>(Wv,      0, wv3,  1024);
    convw_kernel<<<12288, 256>>>(Wih,     0, wih3, 1024);
    convw_kernel<<<12288, 256>>>(Whh,     0, whh3, 1024);
    convw_kernel<<<16384, 256>>>(W1,      0, w13,  1024);
    convw_kernel<<<16384, 256>>>(W2,      0, w23,  4096);
    init_slots_kernel<<<1024, 256>>>(mu);

    for (int it = 0; it < 3; it++) {
        ln_kernel<<<256, 256>>>(OFF_SLOTS, gs, bs, actA);
        gemm_k<64><<<dim3(16, 4), 256, SMEM64>>>(actA, wq3, bq, scr + OFF_Q, actB, 1024,
                                                 1024, 3072, 0);
        cbk_kernel<<<256, 256>>>(bk);
        gemm_k<64><<<dim3(16, 4), 256, SMEM64>>>(actB, wk3, nullptr, scr + OFF_Q2, nullptr, 0,
                                                 1024, 3072, 4);
        pass_kernel<<<dim3(32, 16), 128>>>(tokens, attnp);
        rowsum_kernel<<<1, 256>>>();
        reduceU_kernel<<<256, 256>>>();
        gemm_k<64><<<dim3(16, 4), 256, SMEM64>>>(actA, wv3, bv, nullptr, actB, 1024,
                                                 1024, 3072, 5);
        gru_gemm_k<<<dim3(48, 2, 2), 256, SMEM128>>>(bih, bhh);
        gru_kernel<<<1024, 256>>>();
        ln_kernel<<<256, 256>>>(OFF_SLOTS, gm, bm, actA);
        gemm_k<128><<<dim3(64, 2), 256, SMEM128>>>(actA, w13, b1, nullptr, actBig, 4096,
                                                   4096, 3072, 2);
        gemm_k<64><<<dim3(16, 4), 256, SMEM64>>>(actBig, w23, b2, scr + OFF_SLOTS, actS, 1024,
                                                 1024, 12288, 3);
    }

    int nslots = out_size < 262144 ? out_size : 262144;
    copy_out_kernel<<<1024, 256>>>(out, nslots);
}

// round 6
// speedup vs baseline: 1.7680x; 1.2055x over previous
#include <cuda_runtime.h>
#include <cuda_bf16.h>
#include <cstdint>
#include <cstddef>

// ---------------------------------------------------------------------------
// Problem sizes: B=16, S=4096, D=1024, K=16, ITERS=3
// ---------------------------------------------------------------------------
#define SCALEF   0.03125f        /* 1024^-0.5 */
#define EPS_LN   1e-5f
#define EPS_ATTN 1e-8f

// fp32 scratch offsets (floats)
#define OFF_SLOTS 0u
#define OFF_Q     524288u
#define OFF_GI    1572864u
#define OFF_GH    2359296u
#define OFF_WKT   12582912u
#define OFF_CB    13631488u
#define OFF_BS    13631744u
#define OFF_RINV  13632000u
#define OFF_RP    13632256u     /* 256 rows * 32 chunks */
#define OFF_ATTN  13640448u
#define SCRATCH_N 14689024u

__device__ float g_scratch[SCRATCH_N];

// bf16 split-weight buffers: W'[N][3K] pattern [hi|lo|hi]
__device__ __nv_bfloat16 g_wq3 [1024u * 3072u];
__device__ __nv_bfloat16 g_wk3 [1024u * 3072u];   // from WkT
__device__ __nv_bfloat16 g_wv3 [1024u * 3072u];
__device__ __nv_bfloat16 g_wih3[3072u * 3072u];
__device__ __nv_bfloat16 g_whh3[3072u * 3072u];
__device__ __nv_bfloat16 g_w13 [4096u * 3072u];
__device__ __nv_bfloat16 g_w23 [1024u * 12288u];
// activation split buffers: [m][3K'] pattern [hi|hi|lo]
__device__ __nv_bfloat16 g_actA  [256u * 3072u];
__device__ __nv_bfloat16 g_actB  [256u * 3072u];
__device__ __nv_bfloat16 g_actS  [256u * 3072u];
__device__ __nv_bfloat16 g_actBig[256u * 12288u];
// token planes (hi/lo) normal [b][s][d] and transposed [b][d][s]
__device__ __nv_bfloat16 g_tokh [16u * 4096u * 1024u];
__device__ __nv_bfloat16 g_tokl [16u * 4096u * 1024u];
__device__ __nv_bfloat16 g_tokhT[16u * 1024u * 4096u];
__device__ __nv_bfloat16 g_toklT[16u * 1024u * 4096u];
// q2 planes [256][1024], attn planes [256][4096]
__device__ __nv_bfloat16 g_q2h[256u * 1024u];
__device__ __nv_bfloat16 g_q2l[256u * 1024u];
__device__ __nv_bfloat16 g_ath[256u * 4096u];
__device__ __nv_bfloat16 g_atl[256u * 4096u];

__device__ __forceinline__ float geluf(float x) {
    return 0.5f * x * (1.0f + erff(x * 0.70710678118654752f));
}
__device__ __forceinline__ float sigmf(float x) {
    return 1.0f / (1.0f + __expf(-x));
}

__device__ __forceinline__ uint32_t smem_u32(const void* p) {
    uint32_t a;
    asm("{ .reg .u64 t; cvta.to.shared.u64 t, %1; cvt.u32.u64 %0, t; }" : "=r"(a) : "l"(p));
    return a;
}
__device__ __forceinline__ void cp16s(uint32_t daddr, const void* src) {
    asm volatile("cp.async.cg.shared.global [%0], [%1], 16;" :: "r"(daddr), "l"(src));
}
__device__ __forceinline__ void cpcommit() {
    asm volatile("cp.async.commit_group;" ::: "memory");
}
__device__ __forceinline__ void cpwait_n(int n) {
    if (n <= 0)      asm volatile("cp.async.wait_group 0;" ::: "memory");
    else if (n == 1) asm volatile("cp.async.wait_group 1;" ::: "memory");
    else             asm volatile("cp.async.wait_group 2;" ::: "memory");
}
__device__ __forceinline__ void ldm4(uint32_t* r, uint32_t addr) {
    asm volatile("ldmatrix.sync.aligned.m8n8.x4.shared.b16 {%0,%1,%2,%3}, [%4];"
        : "=r"(r[0]), "=r"(r[1]), "=r"(r[2]), "=r"(r[3]) : "r"(addr));
}
__device__ __forceinline__ void mma16816(float* c, const uint32_t* a, const uint32_t* b) {
    asm volatile(
        "mma.sync.aligned.m16n8k16.row.col.f32.bf16.bf16.f32 "
        "{%0,%1,%2,%3}, {%4,%5,%6,%7}, {%8,%9}, {%0,%1,%2,%3};"
        : "+f"(c[0]), "+f"(c[1]), "+f"(c[2]), "+f"(c[3])
        : "r"(a[0]), "r"(a[1]), "r"(a[2]), "r"(a[3]), "r"(b[0]), "r"(b[1]));
}

__device__ __forceinline__ void bsplit(float x, __nv_bfloat16& h, __nv_bfloat16& l) {
    h = __float2bfloat16_rn(x);
    l = __float2bfloat16_rn(x - __bfloat162float(h));
}

// ---------------------------------------------------------------------------
// init: slots = broadcast(slot_mu); also emit actS split (slots feed gh at it0)
// ---------------------------------------------------------------------------
__global__ __launch_bounds__(256) void init_slots_kernel(const float* __restrict__ mu) {
    unsigned idx = blockIdx.x * 256u + threadIdx.x;          // < 262144
    float x = mu[idx & 16383u];
    g_scratch[OFF_SLOTS + idx] = x;
    unsigned m = idx >> 10, k = idx & 1023u;
    __nv_bfloat16 h, l; bsplit(x, h, l);
    size_t base = (size_t)m * 3072u;
    g_actS[base + k] = h; g_actS[base + 1024u + k] = h; g_actS[base + 2048u + k] = l;
}

// ---------------------------------------------------------------------------
// transpose Wk (1024x1024) -> WkT in scratch
// ---------------------------------------------------------------------------
__global__ void transpose_kernel(const float* __restrict__ in) {
    __shared__ float t[32][33];
    int x  = blockIdx.x * 32 + threadIdx.x;
    int y0 = blockIdx.y * 32;
    #pragma unroll
    for (int j = threadIdx.y; j < 32; j += 8)
        t[j][threadIdx.x] = in[(size_t)(y0 + j) * 1024 + x];
    __syncthreads();
    int xo  = blockIdx.y * 32 + threadIdx.x;
    int yo0 = blockIdx.x * 32;
    #pragma unroll
    for (int j = threadIdx.y; j < 32; j += 8)
        g_scratch[OFF_WKT + (size_t)(yo0 + j) * 1024 + xo] = t[threadIdx.x][j];
}

// ---------------------------------------------------------------------------
// tokens -> bf16 hi/lo planes + transposed planes.  grid (32, 128, 16), blk (32,8)
// ---------------------------------------------------------------------------
__global__ void tcnv_kernel(const float* __restrict__ tokens) {
    __shared__ __nv_bfloat16 th[32][33], tl[32][33];
    const int d0 = blockIdx.x * 32, s0 = blockIdx.y * 32, b = blockIdx.z;
    #pragma unroll
    for (int j = threadIdx.y; j < 32; j += 8) {
        size_t o = ((size_t)b * 4096 + s0 + j) * 1024 + d0 + threadIdx.x;
        float x = tokens[o];
        __nv_bfloat16 h, l; bsplit(x, h, l);
        g_tokh[o] = h; g_tokl[o] = l;
        th[j][threadIdx.x] = h; tl[j][threadIdx.x] = l;
    }
    __syncthreads();
    #pragma unroll
    for (int j = threadIdx.y; j < 32; j += 8) {
        size_t o = ((size_t)b * 1024 + d0 + j) * 4096 + s0 + threadIdx.x;
        g_tokhT[o] = th[threadIdx.x][j];
        g_toklT[o] = tl[threadIdx.x][j];
    }
}

// ---------------------------------------------------------------------------
// weight split-convert (vectorized x4): W (N x K fp32) -> dst (N x 3K) [hi|lo|hi]
// ---------------------------------------------------------------------------
__global__ __launch_bounds__(256) void convw_kernel(const float* __restrict__ src,
                                                    unsigned srcOff,
                                                    __nv_bfloat16* __restrict__ dst,
                                                    int K) {
    unsigned idx4 = blockIdx.x * 256u + threadIdx.x;
    const float* S = src ? src : (g_scratch + srcOff);
    unsigned K4 = (unsigned)K >> 2;
    unsigned n = idx4 / K4, k = (idx4 % K4) * 4u;
    float4 x = *(const float4*)(S + (size_t)n * K + k);
    __nv_bfloat16 h0,h1,h2,h3,l0,l1,l2,l3;
    bsplit(x.x,h0,l0); bsplit(x.y,h1,l1); bsplit(x.z,h2,l2); bsplit(x.w,h3,l3);
    size_t base = (size_t)n * (3u * K);
    *(__nv_bfloat162*)(dst + base + k)           = __nv_bfloat162(h0, h1);
    *(__nv_bfloat162*)(dst + base + k + 2)       = __nv_bfloat162(h2, h3);
    *(__nv_bfloat162*)(dst + base + K + k)       = __nv_bfloat162(l0, l1);
    *(__nv_bfloat162*)(dst + base + K + k + 2)   = __nv_bfloat162(l2, l3);
    *(__nv_bfloat162*)(dst + base + 2*K + k)     = __nv_bfloat162(h0, h1);
    *(__nv_bfloat162*)(dst + base + 2*K + k + 2) = __nv_bfloat162(h2, h3);
}

// ---------------------------------------------------------------------------
// Unified HMMA GEMM core (as round 5) + optional 2-plane output (ph/pl)
// ---------------------------------------------------------------------------
#define SAP 40

template<int BM>
__device__ __forceinline__ void gemm_core(char* sm,
    const __nv_bfloat16* __restrict__ A, const __nv_bfloat16* __restrict__ W,
    const float* __restrict__ bias, float* Cout, __nv_bfloat16* actout, int actK,
    __nv_bfloat16* ph, __nv_bfloat16* pl,
    int N, int K3, int epi)
{
    constexpr int NW_M = (BM == 128) ? 4 : 2;
    constexpr int WTN  = (BM == 128) ? 32 : 16;
    constexpr int NT   = WTN / 8;
    constexpr uint32_t ASTG = BM * SAP * 2;
    constexpr uint32_t BSTG = 64 * SAP * 2;

    const int tid  = threadIdx.x;
    const int lane = tid & 31, wid = tid >> 5;
    const int wm = (wid % NW_M) * 32;
    const int wn = (wid / NW_M) * WTN;
    const int bn = blockIdx.x * 64, bm = blockIdx.y * BM;
    const int NC = K3 >> 5;

    const uint32_t smb = smem_u32(sm);
    const uint32_t aS = smb;
    const uint32_t bS = smb + 4 * ASTG;

    const int lrow = tid >> 2, lch = (tid & 3) * 8;
    const __nv_bfloat16* agp0 = A + (size_t)(bm + lrow) * K3 + lch;
    const __nv_bfloat16* agp1 = A + (size_t)(bm + 64 + lrow) * K3 + lch;
    const __nv_bfloat16* bgp  = W + (size_t)(bn + lrow) * K3 + lch;
    const uint32_t aoff  = (uint32_t)(lrow * SAP + lch) * 2;
    const uint32_t aoff1 = (uint32_t)((64 + lrow) * SAP + lch) * 2;

    const int a_row = wm + (lane & 15);
    const int a_col = (lane >> 4) * 8;
    const int b_row = wn + ((lane >> 4) & 1) * 8 + (lane & 7);
    const int b_col = ((lane >> 3) & 1) * 8;

    float acc[2][NT][4];
    #pragma unroll
    for (int i = 0; i < 2; i++)
        #pragma unroll
        for (int j = 0; j < NT; j++)
            #pragma unroll
            for (int e = 0; e < 4; e++) acc[i][j][e] = 0.f;

    #pragma unroll
    for (int s = 0; s < 3; s++) {
        const size_t ko = (size_t)s * 32;
        cp16s(aS + s * ASTG + aoff, agp0 + ko);
        if (BM == 128) cp16s(aS + s * ASTG + aoff1, agp1 + ko);
        cp16s(bS + s * BSTG + aoff, bgp + ko);
        cpcommit();
    }

    for (int c = 0; c < NC; c++) {
        int bnd = NC - 1 - c; if (bnd > 2) bnd = 2;
        cpwait_n(bnd);
        __syncthreads();
        if (c + 3 < NC) {
            const int s = (c + 3) & 3;
            const size_t ko = (size_t)(c + 3) * 32;
            cp16s(aS + s * ASTG + aoff, agp0 + ko);
            if (BM == 128) cp16s(aS + s * ASTG + aoff1, agp1 + ko);
            cp16s(bS + s * BSTG + aoff, bgp + ko);
            cpcommit();
        }
        const uint32_t ab = aS + (c & 3) * ASTG;
        const uint32_t bb = bS + (c & 3) * BSTG;
        #pragma unroll
        for (int ks = 0; ks < 2; ks++) {
            uint32_t af[2][4], bf[2][4];
            #pragma unroll
            for (int mt = 0; mt < 2; mt++)
                ldm4(af[mt], ab + (uint32_t)(((a_row + mt * 16) * SAP) + ks * 16 + a_col) * 2);
            #pragma unroll
            for (int nb = 0; nb < NT / 2 + (NT & 1); nb++)
                ldm4(bf[nb], bb + (uint32_t)(((b_row + nb * 16) * SAP) + ks * 16 + b_col) * 2);
            #pragma unroll
            for (int mt = 0; mt < 2; mt++)
                #pragma unroll
                for (int nt = 0; nt < NT; nt++)
                    mma16816(acc[mt][nt], af[mt], &bf[nt >> 1][(nt & 1) * 2]);
        }
    }

    const int mrow = lane >> 2, ncol2 = (lane & 3) * 2;
    #pragma unroll
    for (int mt = 0; mt < 2; mt++) {
        #pragma unroll
        for (int h = 0; h < 2; h++) {
            const int m = bm + wm + mt * 16 + mrow + h * 8;
            float brow = 0.f;
            if (epi == 5) brow = g_scratch[OFF_BS + m];
            #pragma unroll
            for (int nt = 0; nt < NT; nt++) {
                const int n0 = bn + wn + nt * 8 + ncol2;
                float ox = acc[mt][nt][h * 2], oy = acc[mt][nt][h * 2 + 1];
                if (epi == 4) { ox *= SCALEF; oy *= SCALEF; }
                else {
                    float2 bb = *(const float2*)(bias + n0);
                    if (epi == 5)      { ox += bb.x * brow; oy += bb.y * brow; }
                    else               { ox += bb.x;        oy += bb.y; }
                    if (epi == 2)      { ox = geluf(ox); oy = geluf(oy); }
                    if (epi == 3) {
                        float2 c0 = *(const float2*)(Cout + (size_t)m * N + n0);
                        ox += c0.x; oy += c0.y;
                    }
                }
                if (Cout) *(float2*)(Cout + (size_t)m * N + n0) = make_float2(ox, oy);
                if (ph) {
                    __nv_bfloat16 hh, ll;
                    bsplit(ox, hh, ll);
                    ph[(size_t)m * N + n0] = hh; pl[(size_t)m * N + n0] = ll;
                    bsplit(oy, hh, ll);
                    ph[(size_t)m * N + n0 + 1] = hh; pl[(size_t)m * N + n0 + 1] = ll;
                }
                if (actout) {
                    __nv_bfloat16 hh, ll;
                    size_t base = (size_t)m * (3u * (unsigned)actK);
                    bsplit(ox, hh, ll);
                    actout[base + n0] = hh; actout[base + actK + n0] = hh;
                    actout[base + 2 * actK + n0] = ll;
                    bsplit(oy, hh, ll);
                    actout[base + n0 + 1] = hh; actout[base + actK + n0 + 1] = hh;
                    actout[base + 2 * actK + n0 + 1] = ll;
                }
            }
        }
    }
}

template<int BM>
__global__ __launch_bounds__(256) void gemm_k(const __nv_bfloat16* __restrict__ A,
                                              const __nv_bfloat16* __restrict__ W,
                                              const float* __restrict__ bias,
                                              float* Cout, __nv_bfloat16* actout, int actK,
                                              __nv_bfloat16* ph, __nv_bfloat16* pl,
                                              int N, int K3, int epi) {
    extern __shared__ char sm[];
    gemm_core<BM>(sm, A, W, bias, Cout, actout, actK, ph, pl, N, K3, epi);
}

__global__ __launch_bounds__(256) void gru_gemm_k(const float* __restrict__ bih,
                                                  const float* __restrict__ bhh) {
    extern __shared__ char sm[];
    if (blockIdx.z == 0)
        gemm_core<128>(sm, g_actB, g_wih3, bih, g_scratch + OFF_GI, nullptr, 0,
                       nullptr, nullptr, 3072, 3072, 0);
    else
        gemm_core<128>(sm, g_actS, g_whh3, bhh, g_scratch + OFF_GH, nullptr, 0,
                       nullptr, nullptr, 3072, 3072, 0);
}

// ---------------------------------------------------------------------------
// Phase 1: logits via HMMA + softmax over K.  grid (32 chunks, 16 b), 128 thr.
// A = token planes [128 tok x 1024], B = q2 planes (resident, N=16).
// ---------------------------------------------------------------------------
#define P1_SMEM 147968   /* Qh 33024 + Ql 33024 + 4 stages * 20480 */
__global__ __launch_bounds__(128) void logits_kernel(float* __restrict__ attn_out) {
    extern __shared__ char sm[];
    __shared__ float LgAtt[2176];
    __shared__ float cbs[16];
    const int tid = threadIdx.x;
    const int lane = tid & 31, wid = tid >> 5;
    const int sc = blockIdx.x, b = blockIdx.y;
    const int wm = wid * 32;

    const uint32_t smb = smem_u32(sm);
    const uint32_t Qh = smb, Ql = smb + 33024u;
    const uint32_t Tb = smb + 66048u;           // 4 stages of (Th 10240 | Tl 10240)

    if (tid < 16) cbs[tid] = g_scratch[OFF_CB + b * 16 + tid];

    const size_t tokbase = ((size_t)b * 4096 + (size_t)sc * 128) * 1024;

    // stage 0 + Q planes in the first commit group
    {
        #pragma unroll
        for (int i = 0; i < 16; i++) {
            int id = tid + 128 * i;
            int row = id >> 7, j = id & 127;
            cp16s(Qh + (uint32_t)(row * 1032 + j * 8) * 2,
                  g_q2h + (size_t)(b * 16 + row) * 1024 + j * 8);
            cp16s(Ql + (uint32_t)(row * 1032 + j * 8) * 2,
                  g_q2l + (size_t)(b * 16 + row) * 1024 + j * 8);
        }
        #pragma unroll
        for (int i = 0; i < 4; i++) {
            int id = tid + 128 * i;
            int row = id >> 2, j = id & 3;
            cp16s(Tb + (uint32_t)(row * 40 + j * 8) * 2,
                  g_tokh + tokbase + (size_t)row * 1024 + j * 8);
            cp16s(Tb + 10240u + (uint32_t)(row * 40 + j * 8) * 2,
                  g_tokl + tokbase + (size_t)row * 1024 + j * 8);
        }
        cpcommit();
        for (int s = 1; s < 3; s++) {
            #pragma unroll
            for (int i = 0; i < 4; i++) {
                int id = tid + 128 * i;
                int row = id >> 2, j = id & 3;
                cp16s(Tb + (uint32_t)s * 20480u + (uint32_t)(row * 40 + j * 8) * 2,
                      g_tokh + tokbase + (size_t)row * 1024 + s * 32 + j * 8);
                cp16s(Tb + (uint32_t)s * 20480u + 10240u + (uint32_t)(row * 40 + j * 8) * 2,
                      g_tokl + tokbase + (size_t)row * 1024 + s * 32 + j * 8);
            }
            cpcommit();
        }
    }

    float acc[2][2][4];
    #pragma unroll
    for (int i = 0; i < 2; i++)
        #pragma unroll
        for (int j = 0; j < 2; j++)
            #pragma unroll
            for (int e = 0; e < 4; e++) acc[i][j][e] = 0.f;

    const int a_rb = wm + (lane & 15);
    const int a_cb = (lane >> 4) * 8;
    const int b_rb = ((lane >> 4) & 1) * 8 + (lane & 7);
    const int b_cb = ((lane >> 3) & 1) * 8;

    for (int c = 0; c < 32; c++) {
        int bnd = 31 - c; if (bnd > 2) bnd = 2;
        cpwait_n(bnd);
        __syncthreads();
        if (c + 3 < 32) {
            const int s = (c + 3) & 3;
            #pragma unroll
            for (int i = 0; i < 4; i++) {
                int id = tid + 128 * i;
                int row = id >> 2, j = id & 3;
                cp16s(Tb + (uint32_t)s * 20480u + (uint32_t)(row * 40 + j * 8) * 2,
                      g_tokh + tokbase + (size_t)row * 1024 + (c + 3) * 32 + j * 8);
                cp16s(Tb + (uint32_t)s * 20480u + 10240u + (uint32_t)(row * 40 + j * 8) * 2,
                      g_tokl + tokbase + (size_t)row * 1024 + (c + 3) * 32 + j * 8);
            }
            cpcommit();
        }
        const uint32_t Th_ = Tb + (uint32_t)(c & 3) * 20480u;
        const uint32_t Tl_ = Th_ + 10240u;
        const int qcol = c * 32;
        #pragma unroll
        for (int ks = 0; ks < 2; ks++) {
            uint32_t afh[2][4], afl[2][4], bfh[4], bfl[4];
            #pragma unroll
            for (int mt = 0; mt < 2; mt++) {
                uint32_t ao = (uint32_t)(((a_rb + mt * 16) * 40) + ks * 16 + a_cb) * 2;
                ldm4(afh[mt], Th_ + ao);
                ldm4(afl[mt], Tl_ + ao);
            }
            uint32_t bo = (uint32_t)(b_rb * 1032 + qcol + ks * 16 + b_cb) * 2;
            ldm4(bfh, Qh + bo);
            ldm4(bfl, Ql + bo);
            #pragma unroll
            for (int mt = 0; mt < 2; mt++)
                #pragma unroll
                for (int nt = 0; nt < 2; nt++) {
                    mma16816(acc[mt][nt], afh[mt], &bfh[nt * 2]);
                    mma16816(acc[mt][nt], afh[mt], &bfl[nt * 2]);
                    mma16816(acc[mt][nt], afl[mt], &bfh[nt * 2]);
                }
        }
    }

    // dump logits to smem [tok][16]
    #pragma unroll
    for (int mt = 0; mt < 2; mt++)
        #pragma unroll
        for (int nt = 0; nt < 2; nt++)
            #pragma unroll
            for (int e = 0; e < 4; e++) {
                int row = wm + mt * 16 + (lane >> 2) + (e >> 1) * 8;
                int col = nt * 8 + (lane & 3) * 2 + (e & 1);
                LgAtt[row * 17 + col] = acc[mt][nt][e];
            }
    __syncthreads();

    // per-token softmax over K=16 (thread t = token t)
    float a[16];
    {
        float mx = -1e30f;
        #pragma unroll
        for (int k = 0; k < 16; k++) { a[k] = LgAtt[tid * 17 + k] + cbs[k]; mx = fmaxf(mx, a[k]); }
        float sum = 0.f;
        #pragma unroll
        for (int k = 0; k < 16; k++) { a[k] = __expf(a[k] - mx); sum += a[k]; }
        float inv = 1.0f / sum;
        #pragma unroll
        for (int k = 0; k < 16; k++) a[k] *= inv;
    }
    __syncthreads();
    #pragma unroll
    for (int k = 0; k < 16; k++) {
        size_t o = (size_t)(b * 16 + k) * 4096 + (size_t)sc * 128 + tid;
        attn_out[o] = a[k];
        __nv_bfloat16 h, l; bsplit(a[k], h, l);
        g_ath[o] = h; g_atl[o] = l;
        LgAtt[k * 136 + tid] = a[k];
    }
    __syncthreads();
    if (tid < 16) {
        float s2 = 0.f;
        #pragma unroll 16
        for (int t = 0; t < 128; t++) s2 += LgAtt[tid * 136 + t];
        g_scratch[OFF_RP + (size_t)(b * 16 + tid) * 32 + sc] = s2;
    }
}

// ---------------------------------------------------------------------------
// Phase 2: updates via HMMA.  grid (16 dblk, 16 b), 128 thr.
// U[16, d64] = attn[16, 4096] @ tokT[d64, 4096]^T ; epilogue: *rinv -> actA split
// ---------------------------------------------------------------------------
#define P2_SMEM 51200   /* 4 stages * (Ah 1280 | Al 1280 | Bh 5120 | Bl 5120) */
__global__ __launch_bounds__(128) void updates_kernel() {
    extern __shared__ char sm[];
    const int tid = threadIdx.x;
    const int lane = tid & 31, wid = tid >> 5;
    const int dblk = blockIdx.x, b = blockIdx.y;

    const uint32_t smb = smem_u32(sm);
    const size_t abase = (size_t)b * 16 * 4096;
    const size_t bbase = ((size_t)b * 1024 + (size_t)dblk * 64) * 4096;

    auto load_stage = [&](int st, int c) {
        const uint32_t S = smb + (uint32_t)st * 12800u;
        const int s0 = c * 32;
        {   // A tiles: 16 rows x 32 cols per plane
            int t2 = tid & 63;
            int row = t2 >> 2, j = t2 & 3;
            const __nv_bfloat16* src = (tid < 64) ? g_ath : g_atl;
            uint32_t dst = S + ((tid < 64) ? 0u : 1280u);
            cp16s(dst + (uint32_t)(row * 40 + j * 8) * 2,
                  src + abase + (size_t)row * 4096 + s0 + j * 8);
        }
        #pragma unroll
        for (int i = 0; i < 2; i++) {   // B tiles: 64 rows x 32 cols
            int id = tid + 128 * i;
            int row = id >> 2, j = id & 3;
            cp16s(S + 2560u + (uint32_t)(row * 40 + j * 8) * 2,
                  g_tokhT + bbase + (size_t)row * 4096 + s0 + j * 8);
            cp16s(S + 7680u + (uint32_t)(row * 40 + j * 8) * 2,
                  g_toklT + bbase + (size_t)row * 4096 + s0 + j * 8);
        }
        cpcommit();
    };

    #pragma unroll
    for (int s = 0; s < 3; s++) load_stage(s, s);

    float acc[2][4];
    #pragma unroll
    for (int j = 0; j < 2; j++)
        #pragma unroll
        for (int e = 0; e < 4; e++) acc[j][e] = 0.f;

    const int a_rb = lane & 15;
    const int a_cb = (lane >> 4) * 8;
    const int b_rb = wid * 16 + ((lane >> 4) & 1) * 8 + (lane & 7);
    const int b_cb = ((lane >> 3) & 1) * 8;

    for (int c = 0; c < 128; c++) {
        int bnd = 127 - c; if (bnd > 2) bnd = 2;
        cpwait_n(bnd);
        __syncthreads();
        if (c + 3 < 128) load_stage((c + 3) & 3, c + 3);
        const uint32_t S = smb + (uint32_t)(c & 3) * 12800u;
        #pragma unroll
        for (int ks = 0; ks < 2; ks++) {
            uint32_t afh[4], afl[4], bfh[4], bfl[4];
            uint32_t ao = (uint32_t)(a_rb * 40 + ks * 16 + a_cb) * 2;
            ldm4(afh, S + ao);
            ldm4(afl, S + 1280u + ao);
            uint32_t bo = (uint32_t)(b_rb * 40 + ks * 16 + b_cb) * 2;
            ldm4(bfh, S + 2560u + bo);
            ldm4(bfl, S + 7680u + bo);
            #pragma unroll
            for (int nt = 0; nt < 2; nt++) {
                mma16816(acc[nt], afh, &bfh[nt * 2]);
                mma16816(acc[nt], afh, &bfl[nt * 2]);
                mma16816(acc[nt], afl, &bfh[nt * 2]);
            }
        }
    }

    // epilogue: un = U * rinv -> actA 3-plane split
    #pragma unroll
    for (int nt = 0; nt < 2; nt++)
        #pragma unroll
        for (int e = 0; e < 4; e++) {
            int slot = (lane >> 2) + (e >> 1) * 8;
            int row = b * 16 + slot;
            int col = dblk * 64 + wid * 16 + nt * 8 + (lane & 3) * 2 + (e & 1);
            float un = acc[nt][e] * g_scratch[OFF_RINV + row];
            __nv_bfloat16 h, l; bsplit(un, h, l);
            size_t base = (size_t)row * 3072u;
            g_actA[base + col] = h; g_actA[base + 1024 + col] = h; g_actA[base + 2048 + col] = l;
        }
}

// ---------------------------------------------------------------------------
// LayerNorm over D=1024 -> act split only. one block per row, 256 rows.
// ---------------------------------------------------------------------------
__global__ __launch_bounds__(256) void ln_kernel(unsigned offX,
                                                 const float* __restrict__ g,
                                                 const float* __restrict__ bt,
                                                 __nv_bfloat16* __restrict__ actout) {
    __shared__ float red[256];
    const float* X = g_scratch + offX;
    int row = blockIdx.x, tid = threadIdx.x;
    float4 x = ((const float4*)X)[row * 256 + tid];
    red[tid] = x.x + x.y + x.z + x.w;
    __syncthreads();
    for (int o = 128; o > 0; o >>= 1) { if (tid < o) red[tid] += red[tid + o]; __syncthreads(); }
    float mean = red[0] * (1.0f / 1024.0f);
    __syncthreads();
    float4 dx = { x.x - mean, x.y - mean, x.z - mean, x.w - mean };
    red[tid] = dx.x*dx.x + dx.y*dx.y + dx.z*dx.z + dx.w*dx.w;
    __syncthreads();
    for (int o = 128; o > 0; o >>= 1) { if (tid < o) red[tid] += red[tid + o]; __syncthreads(); }
    float rs = rsqrtf(red[0] * (1.0f / 1024.0f) + EPS_LN);
    float4 gg = ((const float4*)g)[tid], bb = ((const float4*)bt)[tid];
    float y[4] = { dx.x*rs*gg.x + bb.x, dx.y*rs*gg.y + bb.y,
                   dx.z*rs*gg.z + bb.z, dx.w*rs*gg.w + bb.w };
    size_t base = (size_t)row * 3072u;
    #pragma unroll
    for (int j = 0; j < 4; j++) {
        int k = tid * 4 + j;
        __nv_bfloat16 h, l; bsplit(y[j], h, l);
        actout[base + k] = h; actout[base + 1024 + k] = h; actout[base + 2048 + k] = l;
    }
}

// ---------------------------------------------------------------------------
// cb[row] = SCALE * dot(q[row,:], bk)
// ---------------------------------------------------------------------------
__global__ __launch_bounds__(256) void cbk_kernel(const float* __restrict__ bk) {
    __shared__ float red[256];
    int row = blockIdx.x, tid = threadIdx.x;
    const float* q = g_scratch + OFF_Q + (size_t)row * 1024;
    float p = 0.f;
    #pragma unroll
    for (int i = 0; i < 4; i++) { int d = tid + 256 * i; p = fmaf(q[d], bk[d], p); }
    red[tid] = p; __syncthreads();
    for (int o = 128; o > 0; o >>= 1) { if (tid < o) red[tid] += red[tid + o]; __syncthreads(); }
    if (tid == 0) g_scratch[OFF_CB + row] = SCALEF * red[0];
}

// ---------------------------------------------------------------------------
// rowsum over chunks -> rinv, bscale
// ---------------------------------------------------------------------------
__global__ __launch_bounds__(256) void rowsum_kernel() {
    int row = threadIdx.x;
    float* S = g_scratch;
    float s = 0.f;
    #pragma unroll
    for (int cc = 0; cc < 32; cc++) s += S[OFF_RP + (size_t)row * 32 + cc];
    float ri = 1.0f / (s + EPS_ATTN);
    S[OFF_BS + row] = s * ri;
    S[OFF_RINV + row] = ri;
}

// ---------------------------------------------------------------------------
// GRU gate combine, in-place slots update
// ---------------------------------------------------------------------------
__global__ __launch_bounds__(256) void gru_kernel() {
    float* S = g_scratch;
    unsigned idx = blockIdx.x * 256u + threadIdx.x;
    unsigned row = idx >> 10, col = idx & 1023u;
    size_t gb = (size_t)row * 3072 + col;
    float ir = S[OFF_GI + gb], iz = S[OFF_GI + gb + 1024], in_ = S[OFF_GI + gb + 2048];
    float hr = S[OFF_GH + gb], hz = S[OFF_GH + gb + 1024], hn  = S[OFF_GH + gb + 2048];
    float r = sigmf(ir + hr);
    float z = sigmf(iz + hz);
    float n = tanhf(in_ + r * hn);
    float sp = S[OFF_SLOTS + idx];
    S[OFF_SLOTS + idx] = (1.0f - z) * n + z * sp;
}

// ---------------------------------------------------------------------------
// copy slots -> out
// ---------------------------------------------------------------------------
__global__ __launch_bounds__(256) void copy_out_kernel(float* __restrict__ out, int n) {
    int idx = blockIdx.x * 256 + threadIdx.x;
    if (idx < n) out[idx] = g_scratch[OFF_SLOTS + idx];
}

// ---------------------------------------------------------------------------
// host
// ---------------------------------------------------------------------------
#define SMEM128 (4 * (128 + 64) * SAP * 2)
#define SMEM64  (4 * (64 + 64) * SAP * 2)

extern "C" void kernel_launch(void* const* d_in, const int* in_sizes, int n_in,
                              void* d_out, int out_size) {
    const float* tokens = (const float*)d_in[0];
    const float* mu     = (const float*)d_in[1];
    const float* Wq  = (const float*)d_in[2];  const float* bq  = (const float*)d_in[3];
    const float* Wk  = (const float*)d_in[4];  const float* bk  = (const float*)d_in[5];
    const float* Wv  = (const float*)d_in[6];  const float* bv  = (const float*)d_in[7];
    const float* Wih = (const float*)d_in[8];  const float* bih = (const float*)d_in[9];
    const float* Whh = (const float*)d_in[10]; const float* bhh = (const float*)d_in[11];
    const float* W1  = (const float*)d_in[12]; const float* b1  = (const float*)d_in[13];
    const float* W2  = (const float*)d_in[14]; const float* b2  = (const float*)d_in[15];
    const float* gs  = (const float*)d_in[16]; const float* bs  = (const float*)d_in[17];
    const float* gm  = (const float*)d_in[18]; const float* bm  = (const float*)d_in[19];
    float* out = (float*)d_out;

    cudaFuncSetAttribute((const void*)gemm_k<128>, cudaFuncAttributeMaxDynamicSharedMemorySize, SMEM128);
    cudaFuncSetAttribute((const void*)gemm_k<64>,  cudaFuncAttributeMaxDynamicSharedMemorySize, SMEM64);
    cudaFuncSetAttribute((const void*)gru_gemm_k,  cudaFuncAttributeMaxDynamicSharedMemorySize, SMEM128);
    cudaFuncSetAttribute((const void*)logits_kernel,  cudaFuncAttributeMaxDynamicSharedMemorySize, P1_SMEM);
    cudaFuncSetAttribute((const void*)updates_kernel, cudaFuncAttributeMaxDynamicSharedMemorySize, P2_SMEM);

    __nv_bfloat16 *wq3, *wk3, *wv3, *wih3, *whh3, *w13, *w23, *actA, *actB, *actS, *actBig;
    __nv_bfloat16 *q2h, *q2l;
    cudaGetSymbolAddress((void**)&wq3,  g_wq3);
    cudaGetSymbolAddress((void**)&wk3,  g_wk3);
    cudaGetSymbolAddress((void**)&wv3,  g_wv3);
    cudaGetSymbolAddress((void**)&wih3, g_wih3);
    cudaGetSymbolAddress((void**)&whh3, g_whh3);
    cudaGetSymbolAddress((void**)&w13,  g_w13);
    cudaGetSymbolAddress((void**)&w23,  g_w23);
    cudaGetSymbolAddress((void**)&actA, g_actA);
    cudaGetSymbolAddress((void**)&actB, g_actB);
    cudaGetSymbolAddress((void**)&actS, g_actS);
    cudaGetSymbolAddress((void**)&actBig, g_actBig);
    cudaGetSymbolAddress((void**)&q2h, g_q2h);
    cudaGetSymbolAddress((void**)&q2l, g_q2l);
    float* scr;
    cudaGetSymbolAddress((void**)&scr, g_scratch);

    float* attnp = (out_size >= 1310720) ? (out + 262144) : (scr + OFF_ATTN);

    // one-time per call
    transpose_kernel<<<dim3(32, 32), dim3(32, 8)>>>(Wk);
    tcnv_kernel<<<dim3(32, 128, 16), dim3(32, 8)>>>(tokens);
    convw_kernel<<<1024, 256>>>(Wq,      0, wq3,  1024);
    convw_kernel<<<1024, 256>>>(nullptr, OFF_WKT, wk3, 1024);
    convw_kernel<<<1024, 256>>>(Wv,      0, wv3,  1024);
    convw_kernel<<<3072, 256>>>(Wih,     0, wih3, 1024);
    convw_kernel<<<3072, 256>>>(Whh,     0, whh3, 1024);
    convw_kernel<<<4096, 256>>>(W1,      0, w13,  1024);
    convw_kernel<<<4096, 256>>>(W2,      0, w23,  4096);
    init_slots_kernel<<<1024, 256>>>(mu);

    for (int it = 0; it < 3; it++) {
        ln_kernel<<<256, 256>>>(OFF_SLOTS, gs, bs, actA);
        gemm_k<64><<<dim3(16, 4), 256, SMEM64>>>(actA, wq3, bq, scr + OFF_Q, actB, 1024,
                                                 nullptr, nullptr, 1024, 3072, 0);
        cbk_kernel<<<256, 256>>>(bk);
        gemm_k<64><<<dim3(16, 4), 256, SMEM64>>>(actB, wk3, nullptr, nullptr, nullptr, 0,
                                                 q2h, q2l, 1024, 3072, 4);
        logits_kernel<<<dim3(32, 16), 128, P1_SMEM>>>(attnp);
        rowsum_kernel<<<1, 256>>>();
        updates_kernel<<<dim3(16, 16), 128, P2_SMEM>>>();
        gemm_k<64><<<dim3(16, 4), 256, SMEM64>>>(actA, wv3, bv, nullptr, actB, 1024,
                                                 nullptr, nullptr, 1024, 3072, 5);
        gru_gemm_k<<<dim3(48, 2, 2), 256, SMEM128>>>(bih, bhh);
        gru_kernel<<<1024, 256>>>();
        ln_kernel<<<256, 256>>>(OFF_SLOTS, gm, bm, actA);
        gemm_k<128><<<dim3(64, 2), 256, SMEM128>>>(actA, w13, b1, nullptr, actBig, 4096,
                                                   nullptr, nullptr, 4096, 3072, 2);
        gemm_k<64><<<dim3(16, 4), 256, SMEM64>>>(actBig, w23, b2, scr + OFF_SLOTS, actS, 1024,
                                                 nullptr, nullptr, 1024, 12288, 3);
    }

    int nslots = out_size < 262144 ? out_size : 262144;
    copy_out_kernel<<<1024, 256>>>(out, nslots);
}

// round 7
// speedup vs baseline: 1.8615x; 1.0529x over previous
#include <cuda_runtime.h>
#include <cuda_bf16.h>
#include <cstdint>
#include <cstddef>

// ---------------------------------------------------------------------------
// Problem sizes: B=16, S=4096, D=1024, K=16, ITERS=3
// ---------------------------------------------------------------------------
#define SCALEF   0.03125f        /* 1024^-0.5 */
#define EPS_LN   1e-5f
#define EPS_ATTN 1e-8f

// fp32 scratch offsets (floats)
#define OFF_SLOTS 0u
#define OFF_Q     524288u
#define OFF_GI    1572864u
#define OFF_GH    2359296u
#define OFF_UPART 4194304u      /* 32 chunks * 256 rows * 1024 */
#define OFF_WKT   12582912u
#define OFF_CB    13631488u
#define OFF_BS    13631744u
#define OFF_RP    13632256u     /* 256 rows * 32 chunks */
#define OFF_ATTN  13640448u
#define SCRATCH_N 14689024u

__device__ float g_scratch[SCRATCH_N];

// bf16 split-weight buffers: W'[N][3K] pattern [hi|lo|hi]
__device__ __nv_bfloat16 g_wq3 [1024u * 3072u];
__device__ __nv_bfloat16 g_wk3 [1024u * 3072u];   // from WkT
__device__ __nv_bfloat16 g_wv3 [1024u * 3072u];
__device__ __nv_bfloat16 g_wih3[3072u * 3072u];
__device__ __nv_bfloat16 g_whh3[3072u * 3072u];
__device__ __nv_bfloat16 g_w13 [4096u * 3072u];
__device__ __nv_bfloat16 g_w23 [1024u * 12288u];
// activation split buffers: [m][3K'] pattern [hi|hi|lo]
__device__ __nv_bfloat16 g_actA  [256u * 3072u];
__device__ __nv_bfloat16 g_actB  [256u * 3072u];
__device__ __nv_bfloat16 g_actS  [256u * 3072u];
__device__ __nv_bfloat16 g_actBig[256u * 12288u];
// token planes (hi/lo) [b][s][d]
__device__ __nv_bfloat16 g_tokh [16u * 4096u * 1024u];
__device__ __nv_bfloat16 g_tokl [16u * 4096u * 1024u];
// q2 planes [256][1024]
__device__ __nv_bfloat16 g_q2h[256u * 1024u];
__device__ __nv_bfloat16 g_q2l[256u * 1024u];

__device__ __forceinline__ float geluf(float x) {
    return 0.5f * x * (1.0f + erff(x * 0.70710678118654752f));
}
__device__ __forceinline__ float sigmf(float x) {
    return 1.0f / (1.0f + __expf(-x));
}

__device__ __forceinline__ uint32_t smem_u32(const void* p) {
    uint32_t a;
    asm("{ .reg .u64 t; cvta.to.shared.u64 t, %1; cvt.u32.u64 %0, t; }" : "=r"(a) : "l"(p));
    return a;
}
__device__ __forceinline__ void cp16s(uint32_t daddr, const void* src) {
    asm volatile("cp.async.cg.shared.global [%0], [%1], 16;" :: "r"(daddr), "l"(src));
}
__device__ __forceinline__ void cpcommit() {
    asm volatile("cp.async.commit_group;" ::: "memory");
}
__device__ __forceinline__ void cpwait_n(int n) {
    if (n <= 0)      asm volatile("cp.async.wait_group 0;" ::: "memory");
    else if (n == 1) asm volatile("cp.async.wait_group 1;" ::: "memory");
    else             asm volatile("cp.async.wait_group 2;" ::: "memory");
}
__device__ __forceinline__ void ldm4(uint32_t* r, uint32_t addr) {
    asm volatile("ldmatrix.sync.aligned.m8n8.x4.shared.b16 {%0,%1,%2,%3}, [%4];"
        : "=r"(r[0]), "=r"(r[1]), "=r"(r[2]), "=r"(r[3]) : "r"(addr));
}
__device__ __forceinline__ void ldm2t(uint32_t* r, uint32_t addr) {
    asm volatile("ldmatrix.sync.aligned.m8n8.x2.trans.shared.b16 {%0,%1}, [%2];"
        : "=r"(r[0]), "=r"(r[1]) : "r"(addr));
}
__device__ __forceinline__ void mma16816(float* c, const uint32_t* a, const uint32_t* b) {
    asm volatile(
        "mma.sync.aligned.m16n8k16.row.col.f32.bf16.bf16.f32 "
        "{%0,%1,%2,%3}, {%4,%5,%6,%7}, {%8,%9}, {%0,%1,%2,%3};"
        : "+f"(c[0]), "+f"(c[1]), "+f"(c[2]), "+f"(c[3])
        : "r"(a[0]), "r"(a[1]), "r"(a[2]), "r"(a[3]), "r"(b[0]), "r"(b[1]));
}

__device__ __forceinline__ void bsplit(float x, __nv_bfloat16& h, __nv_bfloat16& l) {
    h = __float2bfloat16_rn(x);
    l = __float2bfloat16_rn(x - __bfloat162float(h));
}

// ---------------------------------------------------------------------------
// init: slots = broadcast(slot_mu); also emit actS split (slots feed gh at it0)
// ---------------------------------------------------------------------------
__global__ __launch_bounds__(256) void init_slots_kernel(const float* __restrict__ mu) {
    unsigned idx = blockIdx.x * 256u + threadIdx.x;          // < 262144
    float x = mu[idx & 16383u];
    g_scratch[OFF_SLOTS + idx] = x;
    unsigned m = idx >> 10, k = idx & 1023u;
    __nv_bfloat16 h, l; bsplit(x, h, l);
    size_t base = (size_t)m * 3072u;
    g_actS[base + k] = h; g_actS[base + 1024u + k] = h; g_actS[base + 2048u + k] = l;
}

// ---------------------------------------------------------------------------
// transpose Wk (1024x1024) -> WkT in scratch
// ---------------------------------------------------------------------------
__global__ void transpose_kernel(const float* __restrict__ in) {
    __shared__ float t[32][33];
    int x  = blockIdx.x * 32 + threadIdx.x;
    int y0 = blockIdx.y * 32;
    #pragma unroll
    for (int j = threadIdx.y; j < 32; j += 8)
        t[j][threadIdx.x] = in[(size_t)(y0 + j) * 1024 + x];
    __syncthreads();
    int xo  = blockIdx.y * 32 + threadIdx.x;
    int yo0 = blockIdx.x * 32;
    #pragma unroll
    for (int j = threadIdx.y; j < 32; j += 8)
        g_scratch[OFF_WKT + (size_t)(yo0 + j) * 1024 + xo] = t[threadIdx.x][j];
}

// ---------------------------------------------------------------------------
// tokens -> bf16 hi/lo planes (elementwise, float4-vectorized)
// ---------------------------------------------------------------------------
__global__ __launch_bounds__(256) void tcnv_kernel(const float* __restrict__ tokens) {
    size_t idx4 = (size_t)blockIdx.x * 256u + threadIdx.x;   // < 16*4096*1024/4
    float4 x = ((const float4*)tokens)[idx4];
    __nv_bfloat16 h0,h1,h2,h3,l0,l1,l2,l3;
    bsplit(x.x,h0,l0); bsplit(x.y,h1,l1); bsplit(x.z,h2,l2); bsplit(x.w,h3,l3);
    size_t k = idx4 * 4;
    *(__nv_bfloat162*)(g_tokh + k)     = __nv_bfloat162(h0, h1);
    *(__nv_bfloat162*)(g_tokh + k + 2) = __nv_bfloat162(h2, h3);
    *(__nv_bfloat162*)(g_tokl + k)     = __nv_bfloat162(l0, l1);
    *(__nv_bfloat162*)(g_tokl + k + 2) = __nv_bfloat162(l2, l3);
}

// ---------------------------------------------------------------------------
// weight split-convert (vectorized x4): W (N x K fp32) -> dst (N x 3K) [hi|lo|hi]
// ---------------------------------------------------------------------------
__global__ __launch_bounds__(256) void convw_kernel(const float* __restrict__ src,
                                                    unsigned srcOff,
                                                    __nv_bfloat16* __restrict__ dst,
                                                    int K) {
    unsigned idx4 = blockIdx.x * 256u + threadIdx.x;
    const float* S = src ? src : (g_scratch + srcOff);
    unsigned K4 = (unsigned)K >> 2;
    unsigned n = idx4 / K4, k = (idx4 % K4) * 4u;
    float4 x = *(const float4*)(S + (size_t)n * K + k);
    __nv_bfloat16 h0,h1,h2,h3,l0,l1,l2,l3;
    bsplit(x.x,h0,l0); bsplit(x.y,h1,l1); bsplit(x.z,h2,l2); bsplit(x.w,h3,l3);
    size_t base = (size_t)n * (3u * K);
    *(__nv_bfloat162*)(dst + base + k)           = __nv_bfloat162(h0, h1);
    *(__nv_bfloat162*)(dst + base + k + 2)       = __nv_bfloat162(h2, h3);
    *(__nv_bfloat162*)(dst + base + K + k)       = __nv_bfloat162(l0, l1);
    *(__nv_bfloat162*)(dst + base + K + k + 2)   = __nv_bfloat162(l2, l3);
    *(__nv_bfloat162*)(dst + base + 2*K + k)     = __nv_bfloat162(h0, h1);
    *(__nv_bfloat162*)(dst + base + 2*K + k + 2) = __nv_bfloat162(h2, h3);
}

// ---------------------------------------------------------------------------
// Unified HMMA GEMM core + optional 2-plane output (ph/pl)
// ---------------------------------------------------------------------------
#define SAP 40

template<int BM>
__device__ __forceinline__ void gemm_core(char* sm,
    const __nv_bfloat16* __restrict__ A, const __nv_bfloat16* __restrict__ W,
    const float* __restrict__ bias, float* Cout, __nv_bfloat16* actout, int actK,
    __nv_bfloat16* ph, __nv_bfloat16* pl,
    int N, int K3, int epi)
{
    constexpr int NW_M = (BM == 128) ? 4 : 2;
    constexpr int WTN  = (BM == 128) ? 32 : 16;
    constexpr int NT   = WTN / 8;
    constexpr uint32_t ASTG = BM * SAP * 2;
    constexpr uint32_t BSTG = 64 * SAP * 2;

    const int tid  = threadIdx.x;
    const int lane = tid & 31, wid = tid >> 5;
    const int wm = (wid % NW_M) * 32;
    const int wn = (wid / NW_M) * WTN;
    const int bn = blockIdx.x * 64, bm = blockIdx.y * BM;
    const int NC = K3 >> 5;

    const uint32_t smb = smem_u32(sm);
    const uint32_t aS = smb;
    const uint32_t bS = smb + 4 * ASTG;

    const int lrow = tid >> 2, lch = (tid & 3) * 8;
    const __nv_bfloat16* agp0 = A + (size_t)(bm + lrow) * K3 + lch;
    const __nv_bfloat16* agp1 = A + (size_t)(bm + 64 + lrow) * K3 + lch;
    const __nv_bfloat16* bgp  = W + (size_t)(bn + lrow) * K3 + lch;
    const uint32_t aoff  = (uint32_t)(lrow * SAP + lch) * 2;
    const uint32_t aoff1 = (uint32_t)((64 + lrow) * SAP + lch) * 2;

    const int a_row = wm + (lane & 15);
    const int a_col = (lane >> 4) * 8;
    const int b_row = wn + ((lane >> 4) & 1) * 8 + (lane & 7);
    const int b_col = ((lane >> 3) & 1) * 8;

    float acc[2][NT][4];
    #pragma unroll
    for (int i = 0; i < 2; i++)
        #pragma unroll
        for (int j = 0; j < NT; j++)
            #pragma unroll
            for (int e = 0; e < 4; e++) acc[i][j][e] = 0.f;

    #pragma unroll
    for (int s = 0; s < 3; s++) {
        const size_t ko = (size_t)s * 32;
        cp16s(aS + s * ASTG + aoff, agp0 + ko);
        if (BM == 128) cp16s(aS + s * ASTG + aoff1, agp1 + ko);
        cp16s(bS + s * BSTG + aoff, bgp + ko);
        cpcommit();
    }

    for (int c = 0; c < NC; c++) {
        int bnd = NC - 1 - c; if (bnd > 2) bnd = 2;
        cpwait_n(bnd);
        __syncthreads();
        if (c + 3 < NC) {
            const int s = (c + 3) & 3;
            const size_t ko = (size_t)(c + 3) * 32;
            cp16s(aS + s * ASTG + aoff, agp0 + ko);
            if (BM == 128) cp16s(aS + s * ASTG + aoff1, agp1 + ko);
            cp16s(bS + s * BSTG + aoff, bgp + ko);
            cpcommit();
        }
        const uint32_t ab = aS + (c & 3) * ASTG;
        const uint32_t bb = bS + (c & 3) * BSTG;
        #pragma unroll
        for (int ks = 0; ks < 2; ks++) {
            uint32_t af[2][4], bf[2][4];
            #pragma unroll
            for (int mt = 0; mt < 2; mt++)
                ldm4(af[mt], ab + (uint32_t)(((a_row + mt * 16) * SAP) + ks * 16 + a_col) * 2);
            #pragma unroll
            for (int nb = 0; nb < NT / 2 + (NT & 1); nb++)
                ldm4(bf[nb], bb + (uint32_t)(((b_row + nb * 16) * SAP) + ks * 16 + b_col) * 2);
            #pragma unroll
            for (int mt = 0; mt < 2; mt++)
                #pragma unroll
                for (int nt = 0; nt < NT; nt++)
                    mma16816(acc[mt][nt], af[mt], &bf[nt >> 1][(nt & 1) * 2]);
        }
    }

    const int mrow = lane >> 2, ncol2 = (lane & 3) * 2;
    #pragma unroll
    for (int mt = 0; mt < 2; mt++) {
        #pragma unroll
        for (int h = 0; h < 2; h++) {
            const int m = bm + wm + mt * 16 + mrow + h * 8;
            float brow = 0.f;
            if (epi == 5) brow = g_scratch[OFF_BS + m];
            #pragma unroll
            for (int nt = 0; nt < NT; nt++) {
                const int n0 = bn + wn + nt * 8 + ncol2;
                float ox = acc[mt][nt][h * 2], oy = acc[mt][nt][h * 2 + 1];
                if (epi == 4) { ox *= SCALEF; oy *= SCALEF; }
                else {
                    float2 bb = *(const float2*)(bias + n0);
                    if (epi == 5)      { ox += bb.x * brow; oy += bb.y * brow; }
                    else               { ox += bb.x;        oy += bb.y; }
                    if (epi == 2)      { ox = geluf(ox); oy = geluf(oy); }
                    if (epi == 3) {
                        float2 c0 = *(const float2*)(Cout + (size_t)m * N + n0);
                        ox += c0.x; oy += c0.y;
                    }
                }
                if (Cout) *(float2*)(Cout + (size_t)m * N + n0) = make_float2(ox, oy);
                if (ph) {
                    __nv_bfloat16 hh, ll;
                    bsplit(ox, hh, ll);
                    ph[(size_t)m * N + n0] = hh; pl[(size_t)m * N + n0] = ll;
                    bsplit(oy, hh, ll);
                    ph[(size_t)m * N + n0 + 1] = hh; pl[(size_t)m * N + n0 + 1] = ll;
                }
                if (actout) {
                    __nv_bfloat16 hh, ll;
                    size_t base = (size_t)m * (3u * (unsigned)actK);
                    bsplit(ox, hh, ll);
                    actout[base + n0] = hh; actout[base + actK + n0] = hh;
                    actout[base + 2 * actK + n0] = ll;
                    bsplit(oy, hh, ll);
                    actout[base + n0 + 1] = hh; actout[base + actK + n0 + 1] = hh;
                    actout[base + 2 * actK + n0 + 1] = ll;
                }
            }
        }
    }
}

template<int BM>
__global__ __launch_bounds__(256) void gemm_k(const __nv_bfloat16* __restrict__ A,
                                              const __nv_bfloat16* __restrict__ W,
                                              const float* __restrict__ bias,
                                              float* Cout, __nv_bfloat16* actout, int actK,
                                              __nv_bfloat16* ph, __nv_bfloat16* pl,
                                              int N, int K3, int epi) {
    extern __shared__ char sm[];
    gemm_core<BM>(sm, A, W, bias, Cout, actout, actK, ph, pl, N, K3, epi);
}

__global__ __launch_bounds__(256) void gru_gemm_k(const float* __restrict__ bih,
                                                  const float* __restrict__ bhh) {
    extern __shared__ char sm[];
    if (blockIdx.z == 0)
        gemm_core<128>(sm, g_actB, g_wih3, bih, g_scratch + OFF_GI, nullptr, 0,
                       nullptr, nullptr, 3072, 3072, 0);
    else
        gemm_core<128>(sm, g_actS, g_whh3, bhh, g_scratch + OFF_GH, nullptr, 0,
                       nullptr, nullptr, 3072, 3072, 0);
}

// ---------------------------------------------------------------------------
// Fused pass: logits (HMMA) + softmax over K + updates (HMMA, ldmatrix.trans).
// grid (32 chunks, 16 b), 128 threads (4 warps). chunk = 128 tokens.
// Part A: logits[128 tok, 16 slots] = tok . q2 (3-term split), softmax, attn->smem.
// Part B: Upart[16 slots, 1024 d] = attn @ tok  (token tiles re-streamed, L2-hot).
// ---------------------------------------------------------------------------
#define FP_SMEM 147968   /* Qh 33024 + Ql 33024 + 4 stages * 20480 */
__global__ __launch_bounds__(128) void fused_pass_kernel(float* __restrict__ attn_out) {
    extern __shared__ char sm[];
    __shared__ float LgAtt[2176];
    __shared__ __nv_bfloat16 AttH[2176], AttL[2176];
    __shared__ float cbs[16];
    const int tid = threadIdx.x;
    const int lane = tid & 31, wid = tid >> 5;
    const int sc = blockIdx.x, b = blockIdx.y;
    const int wm = wid * 32;

    const uint32_t smb = smem_u32(sm);
    const uint32_t Qh = smb, Ql = smb + 33024u;
    const uint32_t Tb = smb + 66048u;           // 4 stages of (Th 10240 | Tl 10240)

    if (tid < 16) cbs[tid] = g_scratch[OFF_CB + b * 16 + tid];

    const size_t tokbase = ((size_t)b * 4096 + (size_t)sc * 128) * 1024;

    // token stage loader (stage st <- d-chunk c)
    auto load_stage = [&](int st, int c) {
        #pragma unroll
        for (int i = 0; i < 4; i++) {
            int id = tid + 128 * i;
            int row = id >> 2, j = id & 3;
            cp16s(Tb + (uint32_t)st * 20480u + (uint32_t)(row * 40 + j * 8) * 2,
                  g_tokh + tokbase + (size_t)row * 1024 + c * 32 + j * 8);
            cp16s(Tb + (uint32_t)st * 20480u + 10240u + (uint32_t)(row * 40 + j * 8) * 2,
                  g_tokl + tokbase + (size_t)row * 1024 + c * 32 + j * 8);
        }
        cpcommit();
    };

    // prologue: Q planes + stage 0 in first group; stages 1,2
    {
        #pragma unroll
        for (int i = 0; i < 16; i++) {
            int id = tid + 128 * i;
            int row = id >> 7, j = id & 127;
            cp16s(Qh + (uint32_t)(row * 1032 + j * 8) * 2,
                  g_q2h + (size_t)(b * 16 + row) * 1024 + j * 8);
            cp16s(Ql + (uint32_t)(row * 1032 + j * 8) * 2,
                  g_q2l + (size_t)(b * 16 + row) * 1024 + j * 8);
        }
        load_stage(0, 0);
        load_stage(1, 1);
        load_stage(2, 2);
    }

    float acc[2][2][4];
    #pragma unroll
    for (int i = 0; i < 2; i++)
        #pragma unroll
        for (int j = 0; j < 2; j++)
            #pragma unroll
            for (int e = 0; e < 4; e++) acc[i][j][e] = 0.f;

    const int a_rb = wm + (lane & 15);
    const int a_cb = (lane >> 4) * 8;
    const int b_rb = ((lane >> 4) & 1) * 8 + (lane & 7);
    const int b_cb = ((lane >> 3) & 1) * 8;

    // ---- Part A: logits over 32 d-chunks ----
    for (int c = 0; c < 32; c++) {
        int bnd = 31 - c; if (bnd > 2) bnd = 2;
        cpwait_n(bnd);
        __syncthreads();
        if (c + 3 < 32) load_stage((c + 3) & 3, c + 3);
        const uint32_t Th_ = Tb + (uint32_t)(c & 3) * 20480u;
        const uint32_t Tl_ = Th_ + 10240u;
        const int qcol = c * 32;
        #pragma unroll
        for (int ks = 0; ks < 2; ks++) {
            uint32_t afh[2][4], afl[2][4], bfh[4], bfl[4];
            #pragma unroll
            for (int mt = 0; mt < 2; mt++) {
                uint32_t ao = (uint32_t)(((a_rb + mt * 16) * 40) + ks * 16 + a_cb) * 2;
                ldm4(afh[mt], Th_ + ao);
                ldm4(afl[mt], Tl_ + ao);
            }
            uint32_t bo = (uint32_t)(b_rb * 1032 + qcol + ks * 16 + b_cb) * 2;
            ldm4(bfh, Qh + bo);
            ldm4(bfl, Ql + bo);
            #pragma unroll
            for (int mt = 0; mt < 2; mt++)
                #pragma unroll
                for (int nt = 0; nt < 2; nt++) {
                    mma16816(acc[mt][nt], afh[mt], &bfh[nt * 2]);
                    mma16816(acc[mt][nt], afh[mt], &bfl[nt * 2]);
                    mma16816(acc[mt][nt], afl[mt], &bfh[nt * 2]);
                }
        }
    }

    // dump logits to smem [tok][16]
    #pragma unroll
    for (int mt = 0; mt < 2; mt++)
        #pragma unroll
        for (int nt = 0; nt < 2; nt++)
            #pragma unroll
            for (int e = 0; e < 4; e++) {
                int row = wm + mt * 16 + (lane >> 2) + (e >> 1) * 8;
                int col = nt * 8 + (lane & 3) * 2 + (e & 1);
                LgAtt[row * 17 + col] = acc[mt][nt][e];
            }
    __syncthreads();

    // per-token softmax over K=16 (thread t = token t)
    float a[16];
    {
        float mx = -1e30f;
        #pragma unroll
        for (int k = 0; k < 16; k++) { a[k] = LgAtt[tid * 17 + k] + cbs[k]; mx = fmaxf(mx, a[k]); }
        float sum = 0.f;
        #pragma unroll
        for (int k = 0; k < 16; k++) { a[k] = __expf(a[k] - mx); sum += a[k]; }
        float inv = 1.0f / sum;
        #pragma unroll
        for (int k = 0; k < 16; k++) a[k] *= inv;
    }
    __syncthreads();
    #pragma unroll
    for (int k = 0; k < 16; k++) {
        size_t o = (size_t)(b * 16 + k) * 4096 + (size_t)sc * 128 + tid;
        attn_out[o] = a[k];
        __nv_bfloat16 h, l; bsplit(a[k], h, l);
        AttH[k * 136 + tid] = h; AttL[k * 136 + tid] = l;
        LgAtt[k * 136 + tid] = a[k];
    }
    __syncthreads();
    if (tid < 16) {
        float s2 = 0.f;
        #pragma unroll 16
        for (int t = 0; t < 128; t++) s2 += LgAtt[tid * 136 + t];
        g_scratch[OFF_RP + (size_t)(b * 16 + tid) * 32 + sc] = s2;
    }

    // ---- Part B: Upart = attn @ tok ----
    // preload attn A-fragments (m16 k16, 8 k-steps over 128 tokens)
    uint32_t ah[8][4], al[8][4];
    {
        const uint32_t AHb = smem_u32(AttH), ALb = smem_u32(AttL);
        #pragma unroll
        for (int ks = 0; ks < 8; ks++) {
            uint32_t ao = (uint32_t)((lane & 15) * 136 + ks * 16 + (lane >> 4) * 8) * 2;
            ldm4(ah[ks], AHb + ao);
            ldm4(al[ks], ALb + ao);
        }
    }

    // restart token pipeline
    load_stage(0, 0);
    load_stage(1, 1);
    load_stage(2, 2);

    const size_t ubase = OFF_UPART + ((size_t)sc * 256 + (size_t)b * 16) * 1024;
    const int slot0 = lane >> 2;
    for (int c = 0; c < 32; c++) {
        int bnd = 31 - c; if (bnd > 2) bnd = 2;
        cpwait_n(bnd);
        __syncthreads();
        if (c + 3 < 32) load_stage((c + 3) & 3, c + 3);
        const uint32_t Th_ = Tb + (uint32_t)(c & 3) * 20480u;
        const uint32_t Tl_ = Th_ + 10240u;
        float uacc[4] = {0.f, 0.f, 0.f, 0.f};
        #pragma unroll
        for (int ks = 0; ks < 8; ks++) {
            uint32_t bh[2], bl[2];
            uint32_t bo = (uint32_t)((ks * 16 + (lane & 15)) * 40 + wid * 8) * 2;
            ldm2t(bh, Th_ + bo);
            ldm2t(bl, Tl_ + bo);
            mma16816(uacc, ah[ks], bh);
            mma16816(uacc, ah[ks], bl);
            mma16816(uacc, al[ks], bh);
        }
        const int d0 = c * 32 + wid * 8 + (lane & 3) * 2;
        *(float2*)&g_scratch[ubase + (size_t)slot0 * 1024 + d0] =
            make_float2(uacc[0], uacc[1]);
        *(float2*)&g_scratch[ubase + (size_t)(slot0 + 8) * 1024 + d0] =
            make_float2(uacc[2], uacc[3]);
    }
}

// ---------------------------------------------------------------------------
// LayerNorm over D=1024 -> act split only. one block per row, 256 rows.
// ---------------------------------------------------------------------------
__global__ __launch_bounds__(256) void ln_kernel(unsigned offX,
                                                 const float* __restrict__ g,
                                                 const float* __restrict__ bt,
                                                 __nv_bfloat16* __restrict__ actout) {
    __shared__ float red[256];
    const float* X = g_scratch + offX;
    int row = blockIdx.x, tid = threadIdx.x;
    float4 x = ((const float4*)X)[row * 256 + tid];
    red[tid] = x.x + x.y + x.z + x.w;
    __syncthreads();
    for (int o = 128; o > 0; o >>= 1) { if (tid < o) red[tid] += red[tid + o]; __syncthreads(); }
    float mean = red[0] * (1.0f / 1024.0f);
    __syncthreads();
    float4 dx = { x.x - mean, x.y - mean, x.z - mean, x.w - mean };
    red[tid] = dx.x*dx.x + dx.y*dx.y + dx.z*dx.z + dx.w*dx.w;
    __syncthreads();
    for (int o = 128; o > 0; o >>= 1) { if (tid < o) red[tid] += red[tid + o]; __syncthreads(); }
    float rs = rsqrtf(red[0] * (1.0f / 1024.0f) + EPS_LN);
    float4 gg = ((const float4*)g)[tid], bb = ((const float4*)bt)[tid];
    float y[4] = { dx.x*rs*gg.x + bb.x, dx.y*rs*gg.y + bb.y,
                   dx.z*rs*gg.z + bb.z, dx.w*rs*gg.w + bb.w };
    size_t base = (size_t)row * 3072u;
    #pragma unroll
    for (int j = 0; j < 4; j++) {
        int k = tid * 4 + j;
        __nv_bfloat16 h, l; bsplit(y[j], h, l);
        actout[base + k] = h; actout[base + 1024 + k] = h; actout[base + 2048 + k] = l;
    }
}

// ---------------------------------------------------------------------------
// cb[row] = SCALE * dot(q[row,:], bk)
// ---------------------------------------------------------------------------
__global__ __launch_bounds__(256) void cbk_kernel(const float* __restrict__ bk) {
    __shared__ float red[256];
    int row = blockIdx.x, tid = threadIdx.x;
    const float* q = g_scratch + OFF_Q + (size_t)row * 1024;
    float p = 0.f;
    #pragma unroll
    for (int i = 0; i < 4; i++) { int d = tid + 256 * i; p = fmaf(q[d], bk[d], p); }
    red[tid] = p; __syncthreads();
    for (int o = 128; o > 0; o >>= 1) { if (tid < o) red[tid] += red[tid + o]; __syncthreads(); }
    if (tid == 0) g_scratch[OFF_CB + row] = SCALEF * red[0];
}

// ---------------------------------------------------------------------------
// reduceU (+fused rowsum): Un[row][:] = sum_chunks Upart / rowsum -> actA split
// ---------------------------------------------------------------------------
__global__ __launch_bounds__(256) void reduceU_kernel() {
    float* S = g_scratch;
    int row = blockIdx.x, tid = threadIdx.x;
    float s = 0.f;
    #pragma unroll
    for (int cc = 0; cc < 32; cc++) s += S[OFF_RP + (size_t)row * 32 + cc];
    float ri = 1.0f / (s + EPS_ATTN);
    if (tid == 0) S[OFF_BS + row] = s * ri;
    float4 acc = make_float4(0.f, 0.f, 0.f, 0.f);
    #pragma unroll 4
    for (int cc = 0; cc < 32; cc++) {
        float4 v = *(const float4*)&S[OFF_UPART + ((size_t)cc * 256 + row) * 1024 + tid * 4];
        acc.x += v.x; acc.y += v.y; acc.z += v.z; acc.w += v.w;
    }
    float y[4] = { acc.x * ri, acc.y * ri, acc.z * ri, acc.w * ri };
    size_t base = (size_t)row * 3072u;
    #pragma unroll
    for (int j = 0; j < 4; j++) {
        int k = tid * 4 + j;
        __nv_bfloat16 h, l; bsplit(y[j], h, l);
        g_actA[base + k] = h; g_actA[base + 1024 + k] = h; g_actA[base + 2048 + k] = l;
    }
}

// ---------------------------------------------------------------------------
// GRU gate combine, in-place slots update
// ---------------------------------------------------------------------------
__global__ __launch_bounds__(256) void gru_kernel() {
    float* S = g_scratch;
    unsigned idx = blockIdx.x * 256u + threadIdx.x;
    unsigned row = idx >> 10, col = idx & 1023u;
    size_t gb = (size_t)row * 3072 + col;
    float ir = S[OFF_GI + gb], iz = S[OFF_GI + gb + 1024], in_ = S[OFF_GI + gb + 2048];
    float hr = S[OFF_GH + gb], hz = S[OFF_GH + gb + 1024], hn  = S[OFF_GH + gb + 2048];
    float r = sigmf(ir + hr);
    float z = sigmf(iz + hz);
    float n = tanhf(in_ + r * hn);
    float sp = S[OFF_SLOTS + idx];
    S[OFF_SLOTS + idx] = (1.0f - z) * n + z * sp;
}

// ---------------------------------------------------------------------------
// copy slots -> out
// ---------------------------------------------------------------------------
__global__ __launch_bounds__(256) void copy_out_kernel(float* __restrict__ out, int n) {
    int idx = blockIdx.x * 256 + threadIdx.x;
    if (idx < n) out[idx] = g_scratch[OFF_SLOTS + idx];
}

// ---------------------------------------------------------------------------
// host
// ---------------------------------------------------------------------------
#define SMEM128 (4 * (128 + 64) * SAP * 2)
#define SMEM64  (4 * (64 + 64) * SAP * 2)

extern "C" void kernel_launch(void* const* d_in, const int* in_sizes, int n_in,
                              void* d_out, int out_size) {
    const float* tokens = (const float*)d_in[0];
    const float* mu     = (const float*)d_in[1];
    const float* Wq  = (const float*)d_in[2];  const float* bq  = (const float*)d_in[3];
    const float* Wk  = (const float*)d_in[4];  const float* bk  = (const float*)d_in[5];
    const float* Wv  = (const float*)d_in[6];  const float* bv  = (const float*)d_in[7];
    const float* Wih = (const float*)d_in[8];  const float* bih = (const float*)d_in[9];
    const float* Whh = (const float*)d_in[10]; const float* bhh = (const float*)d_in[11];
    const float* W1  = (const float*)d_in[12]; const float* b1  = (const float*)d_in[13];
    const float* W2  = (const float*)d_in[14]; const float* b2  = (const float*)d_in[15];
    const float* gs  = (const float*)d_in[16]; const float* bs  = (const float*)d_in[17];
    const float* gm  = (const float*)d_in[18]; const float* bm  = (const float*)d_in[19];
    float* out = (float*)d_out;

    cudaFuncSetAttribute((const void*)gemm_k<128>, cudaFuncAttributeMaxDynamicSharedMemorySize, SMEM128);
    cudaFuncSetAttribute((const void*)gemm_k<64>,  cudaFuncAttributeMaxDynamicSharedMemorySize, SMEM64);
    cudaFuncSetAttribute((const void*)gru_gemm_k,  cudaFuncAttributeMaxDynamicSharedMemorySize, SMEM128);
    cudaFuncSetAttribute((const void*)fused_pass_kernel, cudaFuncAttributeMaxDynamicSharedMemorySize, FP_SMEM);

    __nv_bfloat16 *wq3, *wk3, *wv3, *wih3, *whh3, *w13, *w23, *actA, *actB, *actS, *actBig;
    __nv_bfloat16 *q2h, *q2l;
    cudaGetSymbolAddress((void**)&wq3,  g_wq3);
    cudaGetSymbolAddress((void**)&wk3,  g_wk3);
    cudaGetSymbolAddress((void**)&wv3,  g_wv3);
    cudaGetSymbolAddress((void**)&wih3, g_wih3);
    cudaGetSymbolAddress((void**)&whh3, g_whh3);
    cudaGetSymbolAddress((void**)&w13,  g_w13);
    cudaGetSymbolAddress((void**)&w23,  g_w23);
    cudaGetSymbolAddress((void**)&actA, g_actA);
    cudaGetSymbolAddress((void**)&actB, g_actB);
    cudaGetSymbolAddress((void**)&actS, g_actS);
    cudaGetSymbolAddress((void**)&actBig, g_actBig);
    cudaGetSymbolAddress((void**)&q2h, g_q2h);
    cudaGetSymbolAddress((void**)&q2l, g_q2l);
    float* scr;
    cudaGetSymbolAddress((void**)&scr, g_scratch);

    float* attnp = (out_size >= 1310720) ? (out + 262144) : (scr + OFF_ATTN);

    // one-time per call
    transpose_kernel<<<dim3(32, 32), dim3(32, 8)>>>(Wk);
    tcnv_kernel<<<65536, 256>>>(tokens);
    convw_kernel<<<1024, 256>>>(Wq,      0, wq3,  1024);
    convw_kernel<<<1024, 256>>>(nullptr, OFF_WKT, wk3, 1024);
    convw_kernel<<<1024, 256>>>(Wv,      0, wv3,  1024);
    convw_kernel<<<3072, 256>>>(Wih,     0, wih3, 1024);
    convw_kernel<<<3072, 256>>>(Whh,     0, whh3, 1024);
    convw_kernel<<<4096, 256>>>(W1,      0, w13,  1024);
    convw_kernel<<<4096, 256>>>(W2,      0, w23,  4096);
    init_slots_kernel<<<1024, 256>>>(mu);

    for (int it = 0; it < 3; it++) {
        ln_kernel<<<256, 256>>>(OFF_SLOTS, gs, bs, actA);
        gemm_k<64><<<dim3(16, 4), 256, SMEM64>>>(actA, wq3, bq, scr + OFF_Q, actB, 1024,
                                                 nullptr, nullptr, 1024, 3072, 0);
        cbk_kernel<<<256, 256>>>(bk);
        gemm_k<64><<<dim3(16, 4), 256, SMEM64>>>(actB, wk3, nullptr, nullptr, nullptr, 0,
                                                 q2h, q2l, 1024, 3072, 4);
        fused_pass_kernel<<<dim3(32, 16), 128, FP_SMEM>>>(attnp);
        reduceU_kernel<<<256, 256>>>();
        gemm_k<64><<<dim3(16, 4), 256, SMEM64>>>(actA, wv3, bv, nullptr, actB, 1024,
                                                 nullptr, nullptr, 1024, 3072, 5);
        gru_gemm_k<<<dim3(48, 2, 2), 256, SMEM128>>>(bih, bhh);
        gru_kernel<<<1024, 256>>>();
        ln_kernel<<<256, 256>>>(OFF_SLOTS, gm, bm, actA);
        gemm_k<128><<<dim3(64, 2), 256, SMEM128>>>(actA, w13, b1, nullptr, actBig, 4096,
                                                   nullptr, nullptr, 4096, 3072, 2);
        gemm_k<64><<<dim3(16, 4), 256, SMEM64>>>(actBig, w23, b2, scr + OFF_SLOTS, actS, 1024,
                                                 nullptr, nullptr, 1024, 12288, 3);
    }

    int nslots = out_size < 262144 ? out_size : 262144;
    copy_out_kernel<<<1024, 256>>>(out, nslots);
}

// round 8
// speedup vs baseline: 1.9729x; 1.0598x over previous
#include <cuda_runtime.h>
#include <cuda_bf16.h>
#include <cstdint>
#include <cstddef>

// ---------------------------------------------------------------------------
// Problem sizes: B=16, S=4096, D=1024, K=16, ITERS=3
// ---------------------------------------------------------------------------
#define SCALEF   0.03125f        /* 1024^-0.5 */
#define EPS_LN   1e-5f
#define EPS_ATTN 1e-8f

// fp32 scratch offsets (floats)
#define OFF_SLOTS 0u
#define OFF_GI    1572864u
#define OFF_GH    2359296u
#define OFF_WQT   4194304u
#define OFF_WVT   5242880u
#define OFF_MFP   6291456u
#define OFF_WVIH  7340032u      /* 3145728 floats */
#define OFF_U     10485760u     /* 262144 floats (atomic accum) */
#define OFF_WCB   10747904u
#define OFF_V2    10748928u
#define OFF_BVW   10749952u
#define OFF_C0    10753024u
#define OFF_WKT   12582912u
#define OFF_CB    13631488u
#define OFF_BS    13631744u
#define OFF_RP    13632256u     /* 256 rows * 32 chunks */
#define OFF_ATTN  13640448u
#define SCRATCH_N 14689024u

__device__ float g_scratch[SCRATCH_N];

// bf16 split buffers.  Weight pattern [hi|lo|hi], act pattern [hi|hi|lo].
__device__ __nv_bfloat16 g_wq3  [1024u * 3072u];   // Mw3 (weight pattern)
__device__ __nv_bfloat16 g_wk3  [1024u * 3072u];   // one-time: WqT weight-split
__device__ __nv_bfloat16 g_wv3  [1024u * 3072u];   // one-time: WvT weight-split
__device__ __nv_bfloat16 g_wih3 [3072u * 3072u];   // one-time: Wih act-split
__device__ __nv_bfloat16 g_wvih3[3072u * 3072u];   // Wvih3 (weight pattern)
__device__ __nv_bfloat16 g_whh3 [3072u * 3072u];
__device__ __nv_bfloat16 g_w13  [4096u * 3072u];
__device__ __nv_bfloat16 g_w23  [1024u * 12288u];
// activation split buffers (act pattern)
__device__ __nv_bfloat16 g_actA  [256u * 3072u];
__device__ __nv_bfloat16 g_actS  [256u * 3072u];
__device__ __nv_bfloat16 g_actBig[256u * 12288u];  // also one-time: WkT act-split (1024x3072)
// token planes (hi/lo) [b][s][d]
__device__ __nv_bfloat16 g_tokh [16u * 4096u * 1024u];
__device__ __nv_bfloat16 g_tokl [16u * 4096u * 1024u];
// q2 planes [256][1024]
__device__ __nv_bfloat16 g_q2h[256u * 1024u];
__device__ __nv_bfloat16 g_q2l[256u * 1024u];

__device__ __forceinline__ float geluf(float x) {
    return 0.5f * x * (1.0f + erff(x * 0.70710678118654752f));
}
__device__ __forceinline__ float sigmf(float x) {
    return 1.0f / (1.0f + __expf(-x));
}

__device__ __forceinline__ uint32_t smem_u32(const void* p) {
    uint32_t a;
    asm("{ .reg .u64 t; cvta.to.shared.u64 t, %1; cvt.u32.u64 %0, t; }" : "=r"(a) : "l"(p));
    return a;
}
__device__ __forceinline__ void cp16s(uint32_t daddr, const void* src) {
    asm volatile("cp.async.cg.shared.global [%0], [%1], 16;" :: "r"(daddr), "l"(src));
}
__device__ __forceinline__ void cpcommit() {
    asm volatile("cp.async.commit_group;" ::: "memory");
}
__device__ __forceinline__ void cpwait_n(int n) {
    if (n <= 0)      asm volatile("cp.async.wait_group 0;" ::: "memory");
    else if (n == 1) asm volatile("cp.async.wait_group 1;" ::: "memory");
    else             asm volatile("cp.async.wait_group 2;" ::: "memory");
}
__device__ __forceinline__ void ldm4(uint32_t* r, uint32_t addr) {
    asm volatile("ldmatrix.sync.aligned.m8n8.x4.shared.b16 {%0,%1,%2,%3}, [%4];"
        : "=r"(r[0]), "=r"(r[1]), "=r"(r[2]), "=r"(r[3]) : "r"(addr));
}
__device__ __forceinline__ void ldm2t(uint32_t* r, uint32_t addr) {
    asm volatile("ldmatrix.sync.aligned.m8n8.x2.trans.shared.b16 {%0,%1}, [%2];"
        : "=r"(r[0]), "=r"(r[1]) : "r"(addr));
}
__device__ __forceinline__ void mma16816(float* c, const uint32_t* a, const uint32_t* b) {
    asm volatile(
        "mma.sync.aligned.m16n8k16.row.col.f32.bf16.bf16.f32 "
        "{%0,%1,%2,%3}, {%4,%5,%6,%7}, {%8,%9}, {%0,%1,%2,%3};"
        : "+f"(c[0]), "+f"(c[1]), "+f"(c[2]), "+f"(c[3])
        : "r"(a[0]), "r"(a[1]), "r"(a[2]), "r"(a[3]), "r"(b[0]), "r"(b[1]));
}

__device__ __forceinline__ void bsplit(float x, __nv_bfloat16& h, __nv_bfloat16& l) {
    h = __float2bfloat16_rn(x);
    l = __float2bfloat16_rn(x - __bfloat162float(h));
}

// ---------------------------------------------------------------------------
// init: slots = broadcast(slot_mu); also emit actS split (slots feed gh at it0)
// ---------------------------------------------------------------------------
__global__ __launch_bounds__(256) void init_slots_kernel(const float* __restrict__ mu) {
    unsigned idx = blockIdx.x * 256u + threadIdx.x;          // < 262144
    float x = mu[idx & 16383u];
    g_scratch[OFF_SLOTS + idx] = x;
    unsigned m = idx >> 10, k = idx & 1023u;
    __nv_bfloat16 h, l; bsplit(x, h, l);
    size_t base = (size_t)m * 3072u;
    g_actS[base + k] = h; g_actS[base + 1024u + k] = h; g_actS[base + 2048u + k] = l;
}

// ---------------------------------------------------------------------------
// transpose 1024x1024 fp32: in -> g_scratch[dstOff]
// ---------------------------------------------------------------------------
__global__ void transpose_kernel(const float* __restrict__ in, unsigned dstOff) {
    __shared__ float t[32][33];
    int x  = blockIdx.x * 32 + threadIdx.x;
    int y0 = blockIdx.y * 32;
    #pragma unroll
    for (int j = threadIdx.y; j < 32; j += 8)
        t[j][threadIdx.x] = in[(size_t)(y0 + j) * 1024 + x];
    __syncthreads();
    int xo  = blockIdx.y * 32 + threadIdx.x;
    int yo0 = blockIdx.x * 32;
    #pragma unroll
    for (int j = threadIdx.y; j < 32; j += 8)
        g_scratch[dstOff + (size_t)(yo0 + j) * 1024 + xo] = t[threadIdx.x][j];
}

// ---------------------------------------------------------------------------
// tokens -> bf16 hi/lo planes (elementwise, float4-vectorized)
// ---------------------------------------------------------------------------
__global__ __launch_bounds__(256) void tcnv_kernel(const float* __restrict__ tokens) {
    size_t idx4 = (size_t)blockIdx.x * 256u + threadIdx.x;
    float4 x = ((const float4*)tokens)[idx4];
    __nv_bfloat16 h0,h1,h2,h3,l0,l1,l2,l3;
    bsplit(x.x,h0,l0); bsplit(x.y,h1,l1); bsplit(x.z,h2,l2); bsplit(x.w,h3,l3);
    size_t k = idx4 * 4;
    *(__nv_bfloat162*)(g_tokh + k)     = __nv_bfloat162(h0, h1);
    *(__nv_bfloat162*)(g_tokh + k + 2) = __nv_bfloat162(h2, h3);
    *(__nv_bfloat162*)(g_tokl + k)     = __nv_bfloat162(l0, l1);
    *(__nv_bfloat162*)(g_tokl + k + 2) = __nv_bfloat162(l2, l3);
}

// ---------------------------------------------------------------------------
// split-convert: src (N x K fp32) -> dst (N x 3K bf16)
// actpat=0: [hi|lo|hi] (weight side)  actpat=1: [hi|hi|lo] (A side)
// ---------------------------------------------------------------------------
__global__ __launch_bounds__(256) void convw_kernel(const float* __restrict__ src,
                                                    unsigned srcOff,
                                                    __nv_bfloat16* __restrict__ dst,
                                                    int K, int actpat) {
    unsigned idx4 = blockIdx.x * 256u + threadIdx.x;
    const float* S = src ? src : (g_scratch + srcOff);
    unsigned K4 = (unsigned)K >> 2;
    unsigned n = idx4 / K4, k = (idx4 % K4) * 4u;
    float4 x = *(const float4*)(S + (size_t)n * K + k);
    __nv_bfloat16 h0,h1,h2,h3,l0,l1,l2,l3;
    bsplit(x.x,h0,l0); bsplit(x.y,h1,l1); bsplit(x.z,h2,l2); bsplit(x.w,h3,l3);
    size_t base = (size_t)n * (3u * K);
    unsigned midoff = actpat ? 0u : (unsigned)K;     // plane1: act->hi, weight->lo
    unsigned lastoff = actpat ? 2u*(unsigned)K : 2u*(unsigned)K;
    // plane0 = hi
    *(__nv_bfloat162*)(dst + base + k)           = __nv_bfloat162(h0, h1);
    *(__nv_bfloat162*)(dst + base + k + 2)       = __nv_bfloat162(h2, h3);
    if (actpat) {
        *(__nv_bfloat162*)(dst + base + K + k)       = __nv_bfloat162(h0, h1);
        *(__nv_bfloat162*)(dst + base + K + k + 2)   = __nv_bfloat162(h2, h3);
        *(__nv_bfloat162*)(dst + base + 2*K + k)     = __nv_bfloat162(l0, l1);
        *(__nv_bfloat162*)(dst + base + 2*K + k + 2) = __nv_bfloat162(l2, l3);
    } else {
        *(__nv_bfloat162*)(dst + base + K + k)       = __nv_bfloat162(l0, l1);
        *(__nv_bfloat162*)(dst + base + K + k + 2)   = __nv_bfloat162(l2, l3);
        *(__nv_bfloat162*)(dst + base + 2*K + k)     = __nv_bfloat162(h0, h1);
        *(__nv_bfloat162*)(dst + base + 2*K + k + 2) = __nv_bfloat162(h2, h3);
    }
}

// ---------------------------------------------------------------------------
// gemv: out[row] = scale * dot(M[row, 0:len], v)
// ---------------------------------------------------------------------------
__global__ __launch_bounds__(256) void gemv_kernel(const float* __restrict__ M,
                                                   unsigned moff,
                                                   const float* __restrict__ v,
                                                   unsigned outoff, int len, float scale) {
    __shared__ float red[256];
    const float* Mr = (M ? M : g_scratch + moff) + (size_t)blockIdx.x * len;
    int tid = threadIdx.x;
    float p = 0.f;
    for (int i = tid * 4; i < len; i += 1024) {
        float4 a = *(const float4*)(Mr + i);
        float4 b = *(const float4*)(v + i);
        p += a.x*b.x + a.y*b.y + a.z*b.z + a.w*b.w;
    }
    red[tid] = p; __syncthreads();
    for (int o = 128; o > 0; o >>= 1) { if (tid < o) red[tid] += red[tid + o]; __syncthreads(); }
    if (tid == 0) g_scratch[outoff + blockIdx.x] = scale * red[0];
}

// ---------------------------------------------------------------------------
// Unified HMMA GEMM core + optional 2-plane output (ph/pl)
// epi: 0=+bias  2=gelu(+bias)  3=+bias+resid  4=*SCALE  6=raw  7=+bias+brow*bias2
// ---------------------------------------------------------------------------
#define SAP 40

template<int BM>
__device__ __forceinline__ void gemm_core(char* sm,
    const __nv_bfloat16* __restrict__ A, const __nv_bfloat16* __restrict__ W,
    const float* __restrict__ bias, const float* __restrict__ bias2,
    float* Cout, __nv_bfloat16* actout, int actK,
    __nv_bfloat16* ph, __nv_bfloat16* pl,
    int N, int K3, int epi)
{
    constexpr int NW_M = (BM == 128) ? 4 : 2;
    constexpr int WTN  = (BM == 128) ? 32 : 16;
    constexpr int NT   = WTN / 8;
    constexpr uint32_t ASTG = BM * SAP * 2;
    constexpr uint32_t BSTG = 64 * SAP * 2;

    const int tid  = threadIdx.x;
    const int lane = tid & 31, wid = tid >> 5;
    const int wm = (wid % NW_M) * 32;
    const int wn = (wid / NW_M) * WTN;
    const int bn = blockIdx.x * 64, bm = blockIdx.y * BM;
    const int NC = K3 >> 5;

    const uint32_t smb = smem_u32(sm);
    const uint32_t aS = smb;
    const uint32_t bS = smb + 4 * ASTG;

    const int lrow = tid >> 2, lch = (tid & 3) * 8;
    const __nv_bfloat16* agp0 = A + (size_t)(bm + lrow) * K3 + lch;
    const __nv_bfloat16* agp1 = A + (size_t)(bm + 64 + lrow) * K3 + lch;
    const __nv_bfloat16* bgp  = W + (size_t)(bn + lrow) * K3 + lch;
    const uint32_t aoff  = (uint32_t)(lrow * SAP + lch) * 2;
    const uint32_t aoff1 = (uint32_t)((64 + lrow) * SAP + lch) * 2;

    const int a_row = wm + (lane & 15);
    const int a_col = (lane >> 4) * 8;
    const int b_row = wn + ((lane >> 4) & 1) * 8 + (lane & 7);
    const int b_col = ((lane >> 3) & 1) * 8;

    float acc[2][NT][4];
    #pragma unroll
    for (int i = 0; i < 2; i++)
        #pragma unroll
        for (int j = 0; j < NT; j++)
            #pragma unroll
            for (int e = 0; e < 4; e++) acc[i][j][e] = 0.f;

    #pragma unroll
    for (int s = 0; s < 3; s++) {
        const size_t ko = (size_t)s * 32;
        cp16s(aS + s * ASTG + aoff, agp0 + ko);
        if (BM == 128) cp16s(aS + s * ASTG + aoff1, agp1 + ko);
        cp16s(bS + s * BSTG + aoff, bgp + ko);
        cpcommit();
    }

    for (int c = 0; c < NC; c++) {
        int bnd = NC - 1 - c; if (bnd > 2) bnd = 2;
        cpwait_n(bnd);
        __syncthreads();
        if (c + 3 < NC) {
            const int s = (c + 3) & 3;
            const size_t ko = (size_t)(c + 3) * 32;
            cp16s(aS + s * ASTG + aoff, agp0 + ko);
            if (BM == 128) cp16s(aS + s * ASTG + aoff1, agp1 + ko);
            cp16s(bS + s * BSTG + aoff, bgp + ko);
            cpcommit();
        }
        const uint32_t ab = aS + (c & 3) * ASTG;
        const uint32_t bb = bS + (c & 3) * BSTG;
        #pragma unroll
        for (int ks = 0; ks < 2; ks++) {
            uint32_t af[2][4], bf[2][4];
            #pragma unroll
            for (int mt = 0; mt < 2; mt++)
                ldm4(af[mt], ab + (uint32_t)(((a_row + mt * 16) * SAP) + ks * 16 + a_col) * 2);
            #pragma unroll
            for (int nb = 0; nb < NT / 2 + (NT & 1); nb++)
                ldm4(bf[nb], bb + (uint32_t)(((b_row + nb * 16) * SAP) + ks * 16 + b_col) * 2);
            #pragma unroll
            for (int mt = 0; mt < 2; mt++)
                #pragma unroll
                for (int nt = 0; nt < NT; nt++)
                    mma16816(acc[mt][nt], af[mt], &bf[nt >> 1][(nt & 1) * 2]);
        }
    }

    const int mrow = lane >> 2, ncol2 = (lane & 3) * 2;
    #pragma unroll
    for (int mt = 0; mt < 2; mt++) {
        #pragma unroll
        for (int h = 0; h < 2; h++) {
            const int m = bm + wm + mt * 16 + mrow + h * 8;
            float brow = 0.f;
            if (epi == 7) brow = g_scratch[OFF_BS + m];
            #pragma unroll
            for (int nt = 0; nt < NT; nt++) {
                const int n0 = bn + wn + nt * 8 + ncol2;
                float ox = acc[mt][nt][h * 2], oy = acc[mt][nt][h * 2 + 1];
                if (epi == 4) { ox *= SCALEF; oy *= SCALEF; }
                else if (epi == 6) { /* raw */ }
                else {
                    float2 bb = *(const float2*)(bias + n0);
                    if (epi == 7) {
                        float2 b2 = *(const float2*)(bias2 + n0);
                        ox += bb.x + brow * b2.x; oy += bb.y + brow * b2.y;
                    } else { ox += bb.x; oy += bb.y; }
                    if (epi == 2) { ox = geluf(ox); oy = geluf(oy); }
                    if (epi == 3) {
                        float2 c0 = *(const float2*)(Cout + (size_t)m * N + n0);
                        ox += c0.x; oy += c0.y;
                    }
                }
                if (Cout) *(float2*)(Cout + (size_t)m * N + n0) = make_float2(ox, oy);
                if (ph) {
                    __nv_bfloat16 hh, ll;
                    bsplit(ox, hh, ll);
                    ph[(size_t)m * N + n0] = hh; pl[(size_t)m * N + n0] = ll;
                    bsplit(oy, hh, ll);
                    ph[(size_t)m * N + n0 + 1] = hh; pl[(size_t)m * N + n0 + 1] = ll;
                }
                if (actout) {
                    __nv_bfloat16 hh, ll;
                    size_t base = (size_t)m * (3u * (unsigned)actK);
                    bsplit(ox, hh, ll);
                    actout[base + n0] = hh; actout[base + actK + n0] = hh;
                    actout[base + 2 * actK + n0] = ll;
                    bsplit(oy, hh, ll);
                    actout[base + n0 + 1] = hh; actout[base + actK + n0 + 1] = hh;
                    actout[base + 2 * actK + n0 + 1] = ll;
                }
            }
        }
    }
}

template<int BM>
__global__ __launch_bounds__(256) void gemm_k(const __nv_bfloat16* __restrict__ A,
                                              const __nv_bfloat16* __restrict__ W,
                                              const float* __restrict__ bias,
                                              const float* __restrict__ bias2,
                                              float* Cout, __nv_bfloat16* actout, int actK,
                                              __nv_bfloat16* ph, __nv_bfloat16* pl,
                                              int N, int K3, int epi) {
    extern __shared__ char sm[];
    gemm_core<BM>(sm, A, W, bias, bias2, Cout, actout, actK, ph, pl, N, K3, epi);
}

// merged GRU gemms: z0: gi = actA @ Wvih^T + bih + brow*bvWih ; z1: gh = actS @ Whh^T + bhh
__global__ __launch_bounds__(256) void gru_gemm_k(const float* __restrict__ bih,
                                                  const float* __restrict__ bhh) {
    extern __shared__ char sm[];
    if (blockIdx.z == 0)
        gemm_core<128>(sm, g_actA, g_wvih3, bih, g_scratch + OFF_BVW,
                       g_scratch + OFF_GI, nullptr, 0, nullptr, nullptr, 3072, 3072, 7);
    else
        gemm_core<128>(sm, g_actS, g_whh3, bhh, nullptr,
                       g_scratch + OFF_GH, nullptr, 0, nullptr, nullptr, 3072, 3072, 0);
}

// ---------------------------------------------------------------------------
// Fused pass: logits (HMMA) + softmax over K + updates (HMMA, ldmatrix.trans,
// atomicAdd accumulate).  grid (32 chunks, 16 b), 128 threads.
// ---------------------------------------------------------------------------
#define FP_SMEM 147968   /* Qh 33024 + Ql 33024 + 4 stages * 20480 */
__global__ __launch_bounds__(128) void fused_pass_kernel(float* __restrict__ attn_out) {
    extern __shared__ char sm[];
    __shared__ float LgAtt[2176];
    __shared__ __nv_bfloat16 AttH[2176], AttL[2176];
    __shared__ float cbs[16];
    const int tid = threadIdx.x;
    const int lane = tid & 31, wid = tid >> 5;
    const int sc = blockIdx.x, b = blockIdx.y;
    const int wm = wid * 32;

    const uint32_t smb = smem_u32(sm);
    const uint32_t Qh = smb, Ql = smb + 33024u;
    const uint32_t Tb = smb + 66048u;

    if (tid < 16) cbs[tid] = g_scratch[OFF_CB + b * 16 + tid];

    const size_t tokbase = ((size_t)b * 4096 + (size_t)sc * 128) * 1024;

    auto load_stage = [&](int st, int c) {
        #pragma unroll
        for (int i = 0; i < 4; i++) {
            int id = tid + 128 * i;
            int row = id >> 2, j = id & 3;
            cp16s(Tb + (uint32_t)st * 20480u + (uint32_t)(row * 40 + j * 8) * 2,
                  g_tokh + tokbase + (size_t)row * 1024 + c * 32 + j * 8);
            cp16s(Tb + (uint32_t)st * 20480u + 10240u + (uint32_t)(row * 40 + j * 8) * 2,
                  g_tokl + tokbase + (size_t)row * 1024 + c * 32 + j * 8);
        }
        cpcommit();
    };

    {
        #pragma unroll
        for (int i = 0; i < 16; i++) {
            int id = tid + 128 * i;
            int row = id >> 7, j = id & 127;
            cp16s(Qh + (uint32_t)(row * 1032 + j * 8) * 2,
                  g_q2h + (size_t)(b * 16 + row) * 1024 + j * 8);
            cp16s(Ql + (uint32_t)(row * 1032 + j * 8) * 2,
                  g_q2l + (size_t)(b * 16 + row) * 1024 + j * 8);
        }
        load_stage(0, 0);
        load_stage(1, 1);
        load_stage(2, 2);
    }

    float acc[2][2][4];
    #pragma unroll
    for (int i = 0; i < 2; i++)
        #pragma unroll
        for (int j = 0; j < 2; j++)
            #pragma unroll
            for (int e = 0; e < 4; e++) acc[i][j][e] = 0.f;

    const int a_rb = wm + (lane & 15);
    const int a_cb = (lane >> 4) * 8;
    const int b_rb = ((lane >> 4) & 1) * 8 + (lane & 7);
    const int b_cb = ((lane >> 3) & 1) * 8;

    for (int c = 0; c < 32; c++) {
        int bnd = 31 - c; if (bnd > 2) bnd = 2;
        cpwait_n(bnd);
        __syncthreads();
        if (c + 3 < 32) load_stage((c + 3) & 3, c + 3);
        const uint32_t Th_ = Tb + (uint32_t)(c & 3) * 20480u;
        const uint32_t Tl_ = Th_ + 10240u;
        const int qcol = c * 32;
        #pragma unroll
        for (int ks = 0; ks < 2; ks++) {
            uint32_t afh[2][4], afl[2][4], bfh[4], bfl[4];
            #pragma unroll
            for (int mt = 0; mt < 2; mt++) {
                uint32_t ao = (uint32_t)(((a_rb + mt * 16) * 40) + ks * 16 + a_cb) * 2;
                ldm4(afh[mt], Th_ + ao);
                ldm4(afl[mt], Tl_ + ao);
            }
            uint32_t bo = (uint32_t)(b_rb * 1032 + qcol + ks * 16 + b_cb) * 2;
            ldm4(bfh, Qh + bo);
            ldm4(bfl, Ql + bo);
            #pragma unroll
            for (int mt = 0; mt < 2; mt++)
                #pragma unroll
                for (int nt = 0; nt < 2; nt++) {
                    mma16816(acc[mt][nt], afh[mt], &bfh[nt * 2]);
                    mma16816(acc[mt][nt], afh[mt], &bfl[nt * 2]);
                    mma16816(acc[mt][nt], afl[mt], &bfh[nt * 2]);
                }
        }
    }

    #pragma unroll
    for (int mt = 0; mt < 2; mt++)
        #pragma unroll
        for (int nt = 0; nt < 2; nt++)
            #pragma unroll
            for (int e = 0; e < 4; e++) {
                int row = wm + mt * 16 + (lane >> 2) + (e >> 1) * 8;
                int col = nt * 8 + (lane & 3) * 2 + (e & 1);
                LgAtt[row * 17 + col] = acc[mt][nt][e];
            }
    __syncthreads();

    float a[16];
    {
        float mx = -1e30f;
        #pragma unroll
        for (int k = 0; k < 16; k++) { a[k] = LgAtt[tid * 17 + k] + cbs[k]; mx = fmaxf(mx, a[k]); }
        float sum = 0.f;
        #pragma unroll
        for (int k = 0; k < 16; k++) { a[k] = __expf(a[k] - mx); sum += a[k]; }
        float inv = 1.0f / sum;
        #pragma unroll
        for (int k = 0; k < 16; k++) a[k] *= inv;
    }
    __syncthreads();
    #pragma unroll
    for (int k = 0; k < 16; k++) {
        size_t o = (size_t)(b * 16 + k) * 4096 + (size_t)sc * 128 + tid;
        attn_out[o] = a[k];
        __nv_bfloat16 h, l; bsplit(a[k], h, l);
        AttH[k * 136 + tid] = h; AttL[k * 136 + tid] = l;
        LgAtt[k * 136 + tid] = a[k];
    }
    __syncthreads();
    if (tid < 16) {
        float s2 = 0.f;
        #pragma unroll 16
        for (int t = 0; t < 128; t++) s2 += LgAtt[tid * 136 + t];
        g_scratch[OFF_RP + (size_t)(b * 16 + tid) * 32 + sc] = s2;
    }

    // ---- Part B: U += attn @ tok (atomic accumulate) ----
    uint32_t ah[8][4], al[8][4];
    {
        const uint32_t AHb = smem_u32(AttH), ALb = smem_u32(AttL);
        #pragma unroll
        for (int ks = 0; ks < 8; ks++) {
            uint32_t ao = (uint32_t)((lane & 15) * 136 + ks * 16 + (lane >> 4) * 8) * 2;
            ldm4(ah[ks], AHb + ao);
            ldm4(al[ks], ALb + ao);
        }
    }

    load_stage(0, 0);
    load_stage(1, 1);
    load_stage(2, 2);

    float* Ub = g_scratch + OFF_U + (size_t)(b * 16) * 1024;
    const int slot0 = lane >> 2;
    for (int c = 0; c < 32; c++) {
        int bnd = 31 - c; if (bnd > 2) bnd = 2;
        cpwait_n(bnd);
        __syncthreads();
        if (c + 3 < 32) load_stage((c + 3) & 3, c + 3);
        const uint32_t Th_ = Tb + (uint32_t)(c & 3) * 20480u;
        const uint32_t Tl_ = Th_ + 10240u;
        float uacc[4] = {0.f, 0.f, 0.f, 0.f};
        #pragma unroll
        for (int ks = 0; ks < 8; ks++) {
            uint32_t bh[2], bl[2];
            uint32_t bo = (uint32_t)((ks * 16 + (lane & 15)) * 40 + wid * 8) * 2;
            ldm2t(bh, Th_ + bo);
            ldm2t(bl, Tl_ + bo);
            mma16816(uacc, ah[ks], bh);
            mma16816(uacc, ah[ks], bl);
            mma16816(uacc, al[ks], bh);
        }
        const int d0 = c * 32 + wid * 8 + (lane & 3) * 2;
        atomicAdd(&Ub[(size_t)slot0 * 1024 + d0],       uacc[0]);
        atomicAdd(&Ub[(size_t)slot0 * 1024 + d0 + 1],   uacc[1]);
        atomicAdd(&Ub[(size_t)(slot0 + 8) * 1024 + d0],     uacc[2]);
        atomicAdd(&Ub[(size_t)(slot0 + 8) * 1024 + d0 + 1], uacc[3]);
    }
}

// ---------------------------------------------------------------------------
// LayerNorm (slots) -> actA split; optional cb + zero-U (docb=1 for ln_s)
// ---------------------------------------------------------------------------
__global__ __launch_bounds__(256) void ln_kernel(unsigned offX,
                                                 const float* __restrict__ g,
                                                 const float* __restrict__ bt,
                                                 __nv_bfloat16* __restrict__ actout,
                                                 int docb) {
    __shared__ float red[256];
    const float* X = g_scratch + offX;
    int row = blockIdx.x, tid = threadIdx.x;
    float4 x = ((const float4*)X)[row * 256 + tid];
    red[tid] = x.x + x.y + x.z + x.w;
    __syncthreads();
    for (int o = 128; o > 0; o >>= 1) { if (tid < o) red[tid] += red[tid + o]; __syncthreads(); }
    float mean = red[0] * (1.0f / 1024.0f);
    __syncthreads();
    float4 dx = { x.x - mean, x.y - mean, x.z - mean, x.w - mean };
    red[tid] = dx.x*dx.x + dx.y*dx.y + dx.z*dx.z + dx.w*dx.w;
    __syncthreads();
    for (int o = 128; o > 0; o >>= 1) { if (tid < o) red[tid] += red[tid + o]; __syncthreads(); }
    float rs = rsqrtf(red[0] * (1.0f / 1024.0f) + EPS_LN);
    float4 gg = ((const float4*)g)[tid], bb = ((const float4*)bt)[tid];
    float y[4] = { dx.x*rs*gg.x + bb.x, dx.y*rs*gg.y + bb.y,
                   dx.z*rs*gg.z + bb.z, dx.w*rs*gg.w + bb.w };
    size_t base = (size_t)row * 3072u;
    #pragma unroll
    for (int j = 0; j < 4; j++) {
        int k = tid * 4 + j;
        __nv_bfloat16 h, l; bsplit(y[j], h, l);
        actout[base + k] = h; actout[base + 1024 + k] = h; actout[base + 2048 + k] = l;
    }
    if (docb) {
        // zero U row for this iteration's fused pass
        *(float4*)&g_scratch[OFF_U + (size_t)row * 1024 + tid * 4] =
            make_float4(0.f, 0.f, 0.f, 0.f);
        float p = 0.f;
        #pragma unroll
        for (int j = 0; j < 4; j++) p += y[j] * g_scratch[OFF_WCB + tid * 4 + j];
        __syncthreads();
        red[tid] = p; __syncthreads();
        for (int o = 128; o > 0; o >>= 1) { if (tid < o) red[tid] += red[tid + o]; __syncthreads(); }
        if (tid == 0)
            g_scratch[OFF_CB + row] = SCALEF * (red[0] + g_scratch[OFF_C0]);
    }
}

// ---------------------------------------------------------------------------
// reduceU (+rowsum): Un[row] = U[row]/rowsum -> actA split; BS=brow
// ---------------------------------------------------------------------------
__global__ __launch_bounds__(256) void reduceU_kernel() {
    float* S = g_scratch;
    int row = blockIdx.x, tid = threadIdx.x;
    float s = 0.f;
    #pragma unroll
    for (int cc = 0; cc < 32; cc++) s += S[OFF_RP + (size_t)row * 32 + cc];
    float ri = 1.0f / (s + EPS_ATTN);
    if (tid == 0) S[OFF_BS + row] = s * ri;
    float4 v = *(const float4*)&S[OFF_U + (size_t)row * 1024 + tid * 4];
    float y[4] = { v.x * ri, v.y * ri, v.z * ri, v.w * ri };
    size_t base = (size_t)row * 3072u;
    #pragma unroll
    for (int j = 0; j < 4; j++) {
        int k = tid * 4 + j;
        __nv_bfloat16 h, l; bsplit(y[j], h, l);
        g_actA[base + k] = h; g_actA[base + 1024 + k] = h; g_actA[base + 2048 + k] = l;
    }
}

// ---------------------------------------------------------------------------
// Fused GRU combine + LayerNorm(mlp) -> slots, actA.  block = row.
// ---------------------------------------------------------------------------
__global__ __launch_bounds__(256) void gru_ln_kernel(const float* __restrict__ gm,
                                                     const float* __restrict__ bm) {
    __shared__ float red[256];
    float* S = g_scratch;
    int row = blockIdx.x, tid = threadIdx.x;
    size_t gb = (size_t)row * 3072 + tid * 4;
    float4 ir = *(const float4*)&S[OFF_GI + gb];
    float4 iz = *(const float4*)&S[OFF_GI + gb + 1024];
    float4 in_ = *(const float4*)&S[OFF_GI + gb + 2048];
    float4 hr = *(const float4*)&S[OFF_GH + gb];
    float4 hz = *(const float4*)&S[OFF_GH + gb + 1024];
    float4 hn = *(const float4*)&S[OFF_GH + gb + 2048];
    float4 sp = *(const float4*)&S[OFF_SLOTS + (size_t)row * 1024 + tid * 4];
    float ns[4];
    {
        float r0 = sigmf(ir.x + hr.x), z0 = sigmf(iz.x + hz.x);
        ns[0] = (1.f - z0) * tanhf(in_.x + r0 * hn.x) + z0 * sp.x;
        float r1 = sigmf(ir.y + hr.y), z1 = sigmf(iz.y + hz.y);
        ns[1] = (1.f - z1) * tanhf(in_.y + r1 * hn.y) + z1 * sp.y;
        float r2 = sigmf(ir.z + hr.z), z2 = sigmf(iz.z + hz.z);
        ns[2] = (1.f - z2) * tanhf(in_.z + r2 * hn.z) + z2 * sp.z;
        float r3 = sigmf(ir.w + hr.w), z3 = sigmf(iz.w + hz.w);
        ns[3] = (1.f - z3) * tanhf(in_.w + r3 * hn.w) + z3 * sp.w;
    }
    *(float4*)&S[OFF_SLOTS + (size_t)row * 1024 + tid * 4] =
        make_float4(ns[0], ns[1], ns[2], ns[3]);
    // LN over ns
    red[tid] = ns[0] + ns[1] + ns[2] + ns[3];
    __syncthreads();
    for (int o = 128; o > 0; o >>= 1) { if (tid < o) red[tid] += red[tid + o]; __syncthreads(); }
    float mean = red[0] * (1.0f / 1024.0f);
    __syncthreads();
    float dx[4] = { ns[0]-mean, ns[1]-mean, ns[2]-mean, ns[3]-mean };
    red[tid] = dx[0]*dx[0] + dx[1]*dx[1] + dx[2]*dx[2] + dx[3]*dx[3];
    __syncthreads();
    for (int o = 128; o > 0; o >>= 1) { if (tid < o) red[tid] += red[tid + o]; __syncthreads(); }
    float rs = rsqrtf(red[0] * (1.0f / 1024.0f) + EPS_LN);
    float4 gg = ((const float4*)gm)[tid], bb = ((const float4*)bm)[tid];
    float y[4] = { dx[0]*rs*gg.x + bb.x, dx[1]*rs*gg.y + bb.y,
                   dx[2]*rs*gg.z + bb.z, dx[3]*rs*gg.w + bb.w };
    size_t base = (size_t)row * 3072u;
    #pragma unroll
    for (int j = 0; j < 4; j++) {
        int k = tid * 4 + j;
        __nv_bfloat16 h, l; bsplit(y[j], h, l);
        g_actA[base + k] = h; g_actA[base + 1024 + k] = h; g_actA[base + 2048 + k] = l;
    }
}

// ---------------------------------------------------------------------------
// copy slots -> out
// ---------------------------------------------------------------------------
__global__ __launch_bounds__(256) void copy_out_kernel(float* __restrict__ out, int n) {
    int idx = blockIdx.x * 256 + threadIdx.x;
    if (idx < n) out[idx] = g_scratch[OFF_SLOTS + idx];
}

// ---------------------------------------------------------------------------
// host
// ---------------------------------------------------------------------------
#define SMEM128 (4 * (128 + 64) * SAP * 2)
#define SMEM64  (4 * (64 + 64) * SAP * 2)

extern "C" void kernel_launch(void* const* d_in, const int* in_sizes, int n_in,
                              void* d_out, int out_size) {
    const float* tokens = (const float*)d_in[0];
    const float* mu     = (const float*)d_in[1];
    const float* Wq  = (const float*)d_in[2];  const float* bq  = (const float*)d_in[3];
    const float* Wk  = (const float*)d_in[4];  const float* bk  = (const float*)d_in[5];
    const float* Wv  = (const float*)d_in[6];  const float* bv  = (const float*)d_in[7];
    const float* Wih = (const float*)d_in[8];  const float* bih = (const float*)d_in[9];
    const float* Whh = (const float*)d_in[10]; const float* bhh = (const float*)d_in[11];
    const float* W1  = (const float*)d_in[12]; const float* b1  = (const float*)d_in[13];
    const float* W2  = (const float*)d_in[14]; const float* b2  = (const float*)d_in[15];
    const float* gs  = (const float*)d_in[16]; const float* bs  = (const float*)d_in[17];
    const float* gm  = (const float*)d_in[18]; const float* bm  = (const float*)d_in[19];
    float* out = (float*)d_out;

    cudaFuncSetAttribute((const void*)gemm_k<128>, cudaFuncAttributeMaxDynamicSharedMemorySize, SMEM128);
    cudaFuncSetAttribute((const void*)gemm_k<64>,  cudaFuncAttributeMaxDynamicSharedMemorySize, SMEM64);
    cudaFuncSetAttribute((const void*)gru_gemm_k,  cudaFuncAttributeMaxDynamicSharedMemorySize, SMEM128);
    cudaFuncSetAttribute((const void*)fused_pass_kernel, cudaFuncAttributeMaxDynamicSharedMemorySize, FP_SMEM);

    __nv_bfloat16 *wq3, *wk3, *wv3, *wih3, *wvih3, *whh3, *w13, *w23;
    __nv_bfloat16 *actA, *actS, *actBig, *q2h, *q2l;
    cudaGetSymbolAddress((void**)&wq3,   g_wq3);
    cudaGetSymbolAddress((void**)&wk3,   g_wk3);
    cudaGetSymbolAddress((void**)&wv3,   g_wv3);
    cudaGetSymbolAddress((void**)&wih3,  g_wih3);
    cudaGetSymbolAddress((void**)&wvih3, g_wvih3);
    cudaGetSymbolAddress((void**)&whh3,  g_whh3);
    cudaGetSymbolAddress((void**)&w13,   g_w13);
    cudaGetSymbolAddress((void**)&w23,   g_w23);
    cudaGetSymbolAddress((void**)&actA,  g_actA);
    cudaGetSymbolAddress((void**)&actS,  g_actS);
    cudaGetSymbolAddress((void**)&actBig, g_actBig);
    cudaGetSymbolAddress((void**)&q2h, g_q2h);
    cudaGetSymbolAddress((void**)&q2l, g_q2l);
    float* scr;
    cudaGetSymbolAddress((void**)&scr, g_scratch);

    float* attnp = (out_size >= 1310720) ? (out + 262144) : (scr + OFF_ATTN);

    // ---- one-time ----
    transpose_kernel<<<dim3(32, 32), dim3(32, 8)>>>(Wk, OFF_WKT);
    transpose_kernel<<<dim3(32, 32), dim3(32, 8)>>>(Wq, OFF_WQT);
    transpose_kernel<<<dim3(32, 32), dim3(32, 8)>>>(Wv, OFF_WVT);
    tcnv_kernel<<<65536, 256>>>(tokens);
    convw_kernel<<<1024, 256>>>(nullptr, OFF_WQT, wk3, 1024, 0);      // WqT weight-split
    convw_kernel<<<1024, 256>>>(nullptr, OFF_WKT, actBig, 1024, 1);   // WkT act-split
    convw_kernel<<<3072, 256>>>(Wih, 0, wih3, 1024, 1);               // Wih act-split
    convw_kernel<<<1024, 256>>>(nullptr, OFF_WVT, wv3, 1024, 0);      // WvT weight-split
    gemv_kernel<<<1024, 256>>>(nullptr, OFF_WQT, bk, OFF_WCB, 1024, 1.0f);
    gemv_kernel<<<1024, 256>>>(nullptr, OFF_WKT, bq, OFF_V2, 1024, SCALEF);
    gemv_kernel<<<3072, 256>>>(Wih, 0, bv, OFF_BVW, 1024, 1.0f);
    gemv_kernel<<<1, 256>>>(bq, 0, bk, OFF_C0, 1024, 1.0f);
    // Mw = SCALE * WkT (.) WqT   [1024 x 1024]
    gemm_k<128><<<dim3(16, 8), 256, SMEM128>>>(actBig, wk3, nullptr, nullptr,
                                               scr + OFF_MFP, nullptr, 0,
                                               nullptr, nullptr, 1024, 3072, 4);
    // Wvih = Wih (.) WvT         [3072 x 1024]
    gemm_k<128><<<dim3(16, 24), 256, SMEM128>>>(wih3, wv3, nullptr, nullptr,
                                                scr + OFF_WVIH, nullptr, 0,
                                                nullptr, nullptr, 1024, 3072, 6);
    convw_kernel<<<1024, 256>>>(nullptr, OFF_MFP,  wq3,   1024, 0);   // Mw3
    convw_kernel<<<3072, 256>>>(nullptr, OFF_WVIH, wvih3, 1024, 0);   // Wvih3
    convw_kernel<<<3072, 256>>>(Whh, 0, whh3, 1024, 0);
    convw_kernel<<<4096, 256>>>(W1,  0, w13,  1024, 0);
    convw_kernel<<<4096, 256>>>(W2,  0, w23,  4096, 0);
    init_slots_kernel<<<1024, 256>>>(mu);

    for (int it = 0; it < 3; it++) {
        ln_kernel<<<256, 256>>>(OFF_SLOTS, gs, bs, actA, 1);
        // q2 = ln (.) Mw3 + v2  -> q2 planes
        gemm_k<64><<<dim3(16, 4), 256, SMEM64>>>(actA, wq3, scr + OFF_V2, nullptr,
                                                 nullptr, nullptr, 0,
                                                 q2h, q2l, 1024, 3072, 0);
        fused_pass_kernel<<<dim3(32, 16), 128, FP_SMEM>>>(attnp);
        reduceU_kernel<<<256, 256>>>();
        gru_gemm_k<<<dim3(48, 2, 2), 256, SMEM128>>>(bih, bhh);
        gru_ln_kernel<<<256, 256>>>(gm, bm);
        gemm_k<128><<<dim3(64, 2), 256, SMEM128>>>(actA, w13, b1, nullptr,
                                                   nullptr, actBig, 4096,
                                                   nullptr, nullptr, 4096, 3072, 2);
        gemm_k<64><<<dim3(16, 4), 256, SMEM64>>>(actBig, w23, b2, nullptr,
                                                 scr + OFF_SLOTS, actS, 1024,
                                                 nullptr, nullptr, 1024, 12288, 3);
    }

    int nslots = out_size < 262144 ? out_size : 262144;
    copy_out_kernel<<<1024, 256>>>(out, nslots);
}

// round 9
// speedup vs baseline: 2.3261x; 1.1791x over previous
#include <cuda_runtime.h>
#include <cuda_bf16.h>
#include <cstdint>
#include <cstddef>

// ---------------------------------------------------------------------------
// Problem sizes: B=16, S=4096, D=1024, K=16, ITERS=3
// ---------------------------------------------------------------------------
#define SCALEF   0.03125f        /* 1024^-0.5 */
#define EPS_LN   1e-5f
#define EPS_ATTN 1e-8f

// fp32 scratch offsets (floats)
#define OFF_SLOTS 0u
#define OFF_GI    1572864u
#define OFF_GH    2359296u
#define OFF_WQT   4194304u
#define OFF_WVT   5242880u
#define OFF_MFP   6291456u
#define OFF_WVIH  7340032u      /* 3145728 floats */
#define OFF_U     10485760u     /* 262144 floats (atomic accum) */
#define OFF_WCB   10747904u
#define OFF_V2    10748928u
#define OFF_BVW   10749952u
#define OFF_C0    10753024u
#define OFF_WKT   12582912u
#define OFF_CB    13631488u
#define OFF_BS    13631744u
#define OFF_RP    13632256u     /* 256 rows * 32 chunks */
#define OFF_ATTN  13640448u
#define SCRATCH_N 14689024u

__device__ float g_scratch[SCRATCH_N];

// bf16 2-plane weight buffers: [hi plane | lo plane], each N*K
__device__ __nv_bfloat16 g_wMw  [2u * 1024u * 1024u];
__device__ __nv_bfloat16 g_wVih [2u * 3072u * 1024u];
__device__ __nv_bfloat16 g_wHh  [2u * 3072u * 1024u];
__device__ __nv_bfloat16 g_w1   [2u * 4096u * 1024u];
__device__ __nv_bfloat16 g_w2   [2u * 1024u * 4096u];
// one-time composition operands
__device__ __nv_bfloat16 g_wWqT [2u * 1024u * 1024u];
__device__ __nv_bfloat16 g_wWkT [2u * 1024u * 1024u];
__device__ __nv_bfloat16 g_wWvT [2u * 1024u * 1024u];
__device__ __nv_bfloat16 g_wWihA[2u * 3072u * 1024u];
// activation plane pairs
__device__ __nv_bfloat16 g_actAh[256u * 1024u], g_actAl[256u * 1024u];
__device__ __nv_bfloat16 g_actSh[256u * 1024u], g_actSl[256u * 1024u];
__device__ __nv_bfloat16 g_actBh[256u * 4096u], g_actBl[256u * 4096u];
// token planes [b][s][d]
__device__ __nv_bfloat16 g_tokh [16u * 4096u * 1024u];
__device__ __nv_bfloat16 g_tokl [16u * 4096u * 1024u];
// q2 planes [256][1024]
__device__ __nv_bfloat16 g_q2h[256u * 1024u];
__device__ __nv_bfloat16 g_q2l[256u * 1024u];

__device__ __forceinline__ float geluf(float x) {
    return 0.5f * x * (1.0f + erff(x * 0.70710678118654752f));
}
__device__ __forceinline__ float sigmf(float x) {
    return 1.0f / (1.0f + __expf(-x));
}

__device__ __forceinline__ uint32_t smem_u32(const void* p) {
    uint32_t a;
    asm("{ .reg .u64 t; cvta.to.shared.u64 t, %1; cvt.u32.u64 %0, t; }" : "=r"(a) : "l"(p));
    return a;
}
__device__ __forceinline__ void cp16s(uint32_t daddr, const void* src) {
    asm volatile("cp.async.cg.shared.global [%0], [%1], 16;" :: "r"(daddr), "l"(src));
}
__device__ __forceinline__ void cpcommit() {
    asm volatile("cp.async.commit_group;" ::: "memory");
}
__device__ __forceinline__ void cpwait_n(int n) {
    if (n <= 0)      asm volatile("cp.async.wait_group 0;" ::: "memory");
    else if (n == 1) asm volatile("cp.async.wait_group 1;" ::: "memory");
    else             asm volatile("cp.async.wait_group 2;" ::: "memory");
}
__device__ __forceinline__ void ldm4(uint32_t* r, uint32_t addr) {
    asm volatile("ldmatrix.sync.aligned.m8n8.x4.shared.b16 {%0,%1,%2,%3}, [%4];"
        : "=r"(r[0]), "=r"(r[1]), "=r"(r[2]), "=r"(r[3]) : "r"(addr));
}
__device__ __forceinline__ void ldm2t(uint32_t* r, uint32_t addr) {
    asm volatile("ldmatrix.sync.aligned.m8n8.x2.trans.shared.b16 {%0,%1}, [%2];"
        : "=r"(r[0]), "=r"(r[1]) : "r"(addr));
}
__device__ __forceinline__ void mma16816(float* c, const uint32_t* a, const uint32_t* b) {
    asm volatile(
        "mma.sync.aligned.m16n8k16.row.col.f32.bf16.bf16.f32 "
        "{%0,%1,%2,%3}, {%4,%5,%6,%7}, {%8,%9}, {%0,%1,%2,%3};"
        : "+f"(c[0]), "+f"(c[1]), "+f"(c[2]), "+f"(c[3])
        : "r"(a[0]), "r"(a[1]), "r"(a[2]), "r"(a[3]), "r"(b[0]), "r"(b[1]));
}

__device__ __forceinline__ void bsplit(float x, __nv_bfloat16& h, __nv_bfloat16& l) {
    h = __float2bfloat16_rn(x);
    l = __float2bfloat16_rn(x - __bfloat162float(h));
}

// ---------------------------------------------------------------------------
// init: slots = broadcast(slot_mu); emit actS planes (slots feed gh at it0)
// ---------------------------------------------------------------------------
__global__ __launch_bounds__(256) void init_slots_kernel(const float* __restrict__ mu) {
    unsigned idx = blockIdx.x * 256u + threadIdx.x;          // < 262144
    float x = mu[idx & 16383u];
    g_scratch[OFF_SLOTS + idx] = x;
    __nv_bfloat16 h, l; bsplit(x, h, l);
    g_actSh[idx] = h; g_actSl[idx] = l;
}

// ---------------------------------------------------------------------------
// transpose 1024x1024 fp32: in -> g_scratch[dstOff]
// ---------------------------------------------------------------------------
__global__ void transpose_kernel(const float* __restrict__ in, unsigned dstOff) {
    __shared__ float t[32][33];
    int x  = blockIdx.x * 32 + threadIdx.x;
    int y0 = blockIdx.y * 32;
    #pragma unroll
    for (int j = threadIdx.y; j < 32; j += 8)
        t[j][threadIdx.x] = in[(size_t)(y0 + j) * 1024 + x];
    __syncthreads();
    int xo  = blockIdx.y * 32 + threadIdx.x;
    int yo0 = blockIdx.x * 32;
    #pragma unroll
    for (int j = threadIdx.y; j < 32; j += 8)
        g_scratch[dstOff + (size_t)(yo0 + j) * 1024 + xo] = t[threadIdx.x][j];
}

// ---------------------------------------------------------------------------
// tokens -> bf16 hi/lo planes
// ---------------------------------------------------------------------------
__global__ __launch_bounds__(256) void tcnv_kernel(const float* __restrict__ tokens) {
    size_t idx4 = (size_t)blockIdx.x * 256u + threadIdx.x;
    float4 x = ((const float4*)tokens)[idx4];
    __nv_bfloat16 h0,h1,h2,h3,l0,l1,l2,l3;
    bsplit(x.x,h0,l0); bsplit(x.y,h1,l1); bsplit(x.z,h2,l2); bsplit(x.w,h3,l3);
    size_t k = idx4 * 4;
    *(__nv_bfloat162*)(g_tokh + k)     = __nv_bfloat162(h0, h1);
    *(__nv_bfloat162*)(g_tokh + k + 2) = __nv_bfloat162(h2, h3);
    *(__nv_bfloat162*)(g_tokl + k)     = __nv_bfloat162(l0, l1);
    *(__nv_bfloat162*)(g_tokl + k + 2) = __nv_bfloat162(l2, l3);
}

// ---------------------------------------------------------------------------
// split-convert to 2 planes: src (flat fp32, n elems) -> dh, dl
// ---------------------------------------------------------------------------
__global__ __launch_bounds__(256) void convw2_kernel(const float* __restrict__ src,
                                                     unsigned srcOff,
                                                     __nv_bfloat16* __restrict__ dh,
                                                     __nv_bfloat16* __restrict__ dl) {
    size_t idx4 = (size_t)blockIdx.x * 256u + threadIdx.x;
    const float* S = src ? src : (g_scratch + srcOff);
    float4 x = *(const float4*)(S + idx4 * 4);
    __nv_bfloat16 h0,h1,h2,h3,l0,l1,l2,l3;
    bsplit(x.x,h0,l0); bsplit(x.y,h1,l1); bsplit(x.z,h2,l2); bsplit(x.w,h3,l3);
    size_t k = idx4 * 4;
    *(__nv_bfloat162*)(dh + k)     = __nv_bfloat162(h0, h1);
    *(__nv_bfloat162*)(dh + k + 2) = __nv_bfloat162(h2, h3);
    *(__nv_bfloat162*)(dl + k)     = __nv_bfloat162(l0, l1);
    *(__nv_bfloat162*)(dl + k + 2) = __nv_bfloat162(l2, l3);
}

// ---------------------------------------------------------------------------
// gemv: out[row] = scale * dot(M[row, 0:len], v)
// ---------------------------------------------------------------------------
__global__ __launch_bounds__(256) void gemv_kernel(const float* __restrict__ M,
                                                   unsigned moff,
                                                   const float* __restrict__ v,
                                                   unsigned outoff, int len, float scale) {
    __shared__ float red[256];
    const float* Mr = (M ? M : g_scratch + moff) + (size_t)blockIdx.x * len;
    int tid = threadIdx.x;
    float p = 0.f;
    for (int i = tid * 4; i < len; i += 1024) {
        float4 a = *(const float4*)(Mr + i);
        float4 b = *(const float4*)(v + i);
        p += a.x*b.x + a.y*b.y + a.z*b.z + a.w*b.w;
    }
    red[tid] = p; __syncthreads();
    for (int o = 128; o > 0; o >>= 1) { if (tid < o) red[tid] += red[tid + o]; __syncthreads(); }
    if (tid == 0) g_scratch[outoff + blockIdx.x] = scale * red[0];
}

// ---------------------------------------------------------------------------
// 2-plane HMMA GEMM: C = (Ah+Al) (.) (Wh+Wl)^T  via Ah*Wh + Ah*Wl + Al*Wh.
// BM in {128,64}, BN=64, chunk=32 K, 4-stage cp.async, 256 threads.
// epi: 0=+bias  2=gelu(+bias)  3=+bias+resid  4=*SCALE  6=raw  7=+bias+brow*bias2
// ---------------------------------------------------------------------------
#define SAP 40

template<int BM>
__device__ __forceinline__ void gemm2_core(char* sm,
    const __nv_bfloat16* __restrict__ Ah, const __nv_bfloat16* __restrict__ Al,
    const __nv_bfloat16* __restrict__ Wh, const __nv_bfloat16* __restrict__ Wl,
    const float* __restrict__ bias, const float* __restrict__ bias2,
    float* Cout, __nv_bfloat16* ph, __nv_bfloat16* pl,
    int N, int K, int epi)
{
    constexpr int NW_M = (BM == 128) ? 4 : 2;
    constexpr int WTN  = (BM == 128) ? 32 : 16;
    constexpr int NT   = WTN / 8;
    constexpr uint32_t AP  = BM * SAP * 2;      // bytes per A plane tile
    constexpr uint32_t WP  = 64 * SAP * 2;
    constexpr uint32_t STG = 2 * AP + 2 * WP;

    const int tid  = threadIdx.x;
    const int lane = tid & 31, wid = tid >> 5;
    const int wm = (wid % NW_M) * 32;
    const int wn = (wid / NW_M) * WTN;
    const int bn = blockIdx.x * 64, bm = blockIdx.y * BM;
    const int NC = K >> 5;

    const uint32_t smb = smem_u32(sm);

    const int lrow = tid >> 2, lch = (tid & 3) * 8;
    const uint32_t aoff  = (uint32_t)(lrow * SAP + lch) * 2;
    const uint32_t aoff1 = (uint32_t)((64 + lrow) * SAP + lch) * 2;
    const __nv_bfloat16* agh0 = Ah + (size_t)(bm + lrow) * K + lch;
    const __nv_bfloat16* agl0 = Al + (size_t)(bm + lrow) * K + lch;
    const __nv_bfloat16* agh1 = Ah + (size_t)(bm + 64 + lrow) * K + lch;
    const __nv_bfloat16* agl1 = Al + (size_t)(bm + 64 + lrow) * K + lch;
    const __nv_bfloat16* wgh  = Wh + (size_t)(bn + lrow) * K + lch;
    const __nv_bfloat16* wgl  = Wl + (size_t)(bn + lrow) * K + lch;

    const int a_row = wm + (lane & 15);
    const int a_col = (lane >> 4) * 8;
    const int b_row = wn + ((lane >> 4) & 1) * 8 + (lane & 7);
    const int b_col = ((lane >> 3) & 1) * 8;

    float acc[2][NT][4];
    #pragma unroll
    for (int i = 0; i < 2; i++)
        #pragma unroll
        for (int j = 0; j < NT; j++)
            #pragma unroll
            for (int e = 0; e < 4; e++) acc[i][j][e] = 0.f;

    auto load_stage = [&](int st, int c) {
        const uint32_t S = smb + (uint32_t)st * STG;
        const int ko = c * 32;
        cp16s(S + aoff, agh0 + ko);
        cp16s(S + AP + aoff, agl0 + ko);
        if (BM == 128) {
            cp16s(S + aoff1, agh1 + ko);
            cp16s(S + AP + aoff1, agl1 + ko);
        }
        cp16s(S + 2 * AP + aoff, wgh + ko);
        cp16s(S + 2 * AP + WP + aoff, wgl + ko);
        cpcommit();
    };

    load_stage(0, 0);
    load_stage(1, 1);
    load_stage(2, 2);

    for (int c = 0; c < NC; c++) {
        int bnd = NC - 1 - c; if (bnd > 2) bnd = 2;
        cpwait_n(bnd);
        __syncthreads();
        if (c + 3 < NC) load_stage((c + 3) & 3, c + 3);
        const uint32_t S = smb + (uint32_t)(c & 3) * STG;
        const uint32_t abh = S, abl = S + AP;
        const uint32_t wbh = S + 2 * AP, wbl = S + 2 * AP + WP;
        #pragma unroll
        for (int ks = 0; ks < 2; ks++) {
            uint32_t afh[2][4], afl[2][4], bfh[2][4], bfl[2][4];
            #pragma unroll
            for (int mt = 0; mt < 2; mt++) {
                uint32_t ao = (uint32_t)(((a_row + mt * 16) * SAP) + ks * 16 + a_col) * 2;
                ldm4(afh[mt], abh + ao);
                ldm4(afl[mt], abl + ao);
            }
            #pragma unroll
            for (int nb = 0; nb < NT / 2 + (NT & 1); nb++) {
                uint32_t bo = (uint32_t)(((b_row + nb * 16) * SAP) + ks * 16 + b_col) * 2;
                ldm4(bfh[nb], wbh + bo);
                ldm4(bfl[nb], wbl + bo);
            }
            #pragma unroll
            for (int mt = 0; mt < 2; mt++)
                #pragma unroll
                for (int nt = 0; nt < NT; nt++) {
                    const uint32_t* bh = &bfh[nt >> 1][(nt & 1) * 2];
                    const uint32_t* bl = &bfl[nt >> 1][(nt & 1) * 2];
                    mma16816(acc[mt][nt], afh[mt], bh);
                    mma16816(acc[mt][nt], afh[mt], bl);
                    mma16816(acc[mt][nt], afl[mt], bh);
                }
        }
    }

    const int mrow = lane >> 2, ncol2 = (lane & 3) * 2;
    #pragma unroll
    for (int mt = 0; mt < 2; mt++) {
        #pragma unroll
        for (int h = 0; h < 2; h++) {
            const int m = bm + wm + mt * 16 + mrow + h * 8;
            float brow = 0.f;
            if (epi == 7) brow = g_scratch[OFF_BS + m];
            #pragma unroll
            for (int nt = 0; nt < NT; nt++) {
                const int n0 = bn + wn + nt * 8 + ncol2;
                float ox = acc[mt][nt][h * 2], oy = acc[mt][nt][h * 2 + 1];
                if (epi == 4) { ox *= SCALEF; oy *= SCALEF; }
                else if (epi == 6) { }
                else {
                    float2 bb = *(const float2*)(bias + n0);
                    if (epi == 7) {
                        float2 b2 = *(const float2*)(bias2 + n0);
                        ox += bb.x + brow * b2.x; oy += bb.y + brow * b2.y;
                    } else { ox += bb.x; oy += bb.y; }
                    if (epi == 2) { ox = geluf(ox); oy = geluf(oy); }
                    if (epi == 3) {
                        float2 c0 = *(const float2*)(Cout + (size_t)m * N + n0);
                        ox += c0.x; oy += c0.y;
                    }
                }
                if (Cout) *(float2*)(Cout + (size_t)m * N + n0) = make_float2(ox, oy);
                if (ph) {
                    __nv_bfloat16 hx, lx, hy, ly;
                    bsplit(ox, hx, lx); bsplit(oy, hy, ly);
                    *(__nv_bfloat162*)(ph + (size_t)m * N + n0) = __nv_bfloat162(hx, hy);
                    *(__nv_bfloat162*)(pl + (size_t)m * N + n0) = __nv_bfloat162(lx, ly);
                }
            }
        }
    }
}

template<int BM>
__global__ __launch_bounds__(256) void gemm2_k(const __nv_bfloat16* __restrict__ Ah,
                                               const __nv_bfloat16* __restrict__ Al,
                                               const __nv_bfloat16* __restrict__ Wh,
                                               const __nv_bfloat16* __restrict__ Wl,
                                               const float* __restrict__ bias,
                                               const float* __restrict__ bias2,
                                               float* Cout, __nv_bfloat16* ph, __nv_bfloat16* pl,
                                               int N, int K, int epi) {
    extern __shared__ char sm[];
    gemm2_core<BM>(sm, Ah, Al, Wh, Wl, bias, bias2, Cout, ph, pl, N, K, epi);
}

// merged GRU gemms: z0: gi = actA @ Wvih^T + bih + brow*bvWih ; z1: gh = actS @ Whh^T + bhh
__global__ __launch_bounds__(256) void gru_gemm_k(const float* __restrict__ bih,
                                                  const float* __restrict__ bhh) {
    extern __shared__ char sm[];
    if (blockIdx.z == 0)
        gemm2_core<128>(sm, g_actAh, g_actAl, g_wVih, g_wVih + 3072u*1024u,
                        bih, g_scratch + OFF_BVW, g_scratch + OFF_GI,
                        nullptr, nullptr, 3072, 1024, 7);
    else
        gemm2_core<128>(sm, g_actSh, g_actSl, g_wHh, g_wHh + 3072u*1024u,
                        bhh, nullptr, g_scratch + OFF_GH,
                        nullptr, nullptr, 3072, 1024, 0);
}

// ---------------------------------------------------------------------------
// Fused pass: logits (HMMA) + softmax over K + updates (HMMA, ldmatrix.trans,
// atomicAdd accumulate).  grid (32 chunks, 16 b), 128 threads.
// ---------------------------------------------------------------------------
#define FP_SMEM 147968   /* Qh 33024 + Ql 33024 + 4 stages * 20480 */
__global__ __launch_bounds__(128) void fused_pass_kernel(float* __restrict__ attn_out) {
    extern __shared__ char sm[];
    __shared__ float LgAtt[2176];
    __shared__ __nv_bfloat16 AttH[2176], AttL[2176];
    __shared__ float cbs[16];
    const int tid = threadIdx.x;
    const int lane = tid & 31, wid = tid >> 5;
    const int sc = blockIdx.x, b = blockIdx.y;
    const int wm = wid * 32;

    const uint32_t smb = smem_u32(sm);
    const uint32_t Qh = smb, Ql = smb + 33024u;
    const uint32_t Tb = smb + 66048u;

    if (tid < 16) cbs[tid] = g_scratch[OFF_CB + b * 16 + tid];

    const size_t tokbase = ((size_t)b * 4096 + (size_t)sc * 128) * 1024;

    auto load_stage = [&](int st, int c) {
        #pragma unroll
        for (int i = 0; i < 4; i++) {
            int id = tid + 128 * i;
            int row = id >> 2, j = id & 3;
            cp16s(Tb + (uint32_t)st * 20480u + (uint32_t)(row * 40 + j * 8) * 2,
                  g_tokh + tokbase + (size_t)row * 1024 + c * 32 + j * 8);
            cp16s(Tb + (uint32_t)st * 20480u + 10240u + (uint32_t)(row * 40 + j * 8) * 2,
                  g_tokl + tokbase + (size_t)row * 1024 + c * 32 + j * 8);
        }
        cpcommit();
    };

    {
        #pragma unroll
        for (int i = 0; i < 16; i++) {
            int id = tid + 128 * i;
            int row = id >> 7, j = id & 127;
            cp16s(Qh + (uint32_t)(row * 1032 + j * 8) * 2,
                  g_q2h + (size_t)(b * 16 + row) * 1024 + j * 8);
            cp16s(Ql + (uint32_t)(row * 1032 + j * 8) * 2,
                  g_q2l + (size_t)(b * 16 + row) * 1024 + j * 8);
        }
        load_stage(0, 0);
        load_stage(1, 1);
        load_stage(2, 2);
    }

    float acc[2][2][4];
    #pragma unroll
    for (int i = 0; i < 2; i++)
        #pragma unroll
        for (int j = 0; j < 2; j++)
            #pragma unroll
            for (int e = 0; e < 4; e++) acc[i][j][e] = 0.f;

    const int a_rb = wm + (lane & 15);
    const int a_cb = (lane >> 4) * 8;
    const int b_rb = ((lane >> 4) & 1) * 8 + (lane & 7);
    const int b_cb = ((lane >> 3) & 1) * 8;

    for (int c = 0; c < 32; c++) {
        int bnd = 31 - c; if (bnd > 2) bnd = 2;
        cpwait_n(bnd);
        __syncthreads();
        if (c + 3 < 32) load_stage((c + 3) & 3, c + 3);
        const uint32_t Th_ = Tb + (uint32_t)(c & 3) * 20480u;
        const uint32_t Tl_ = Th_ + 10240u;
        const int qcol = c * 32;
        #pragma unroll
        for (int ks = 0; ks < 2; ks++) {
            uint32_t afh[2][4], afl[2][4], bfh[4], bfl[4];
            #pragma unroll
            for (int mt = 0; mt < 2; mt++) {
                uint32_t ao = (uint32_t)(((a_rb + mt * 16) * 40) + ks * 16 + a_cb) * 2;
                ldm4(afh[mt], Th_ + ao);
                ldm4(afl[mt], Tl_ + ao);
            }
            uint32_t bo = (uint32_t)(b_rb * 1032 + qcol + ks * 16 + b_cb) * 2;
            ldm4(bfh, Qh + bo);
            ldm4(bfl, Ql + bo);
            #pragma unroll
            for (int mt = 0; mt < 2; mt++)
                #pragma unroll
                for (int nt = 0; nt < 2; nt++) {
                    mma16816(acc[mt][nt], afh[mt], &bfh[nt * 2]);
                    mma16816(acc[mt][nt], afh[mt], &bfl[nt * 2]);
                    mma16816(acc[mt][nt], afl[mt], &bfh[nt * 2]);
                }
        }
    }

    #pragma unroll
    for (int mt = 0; mt < 2; mt++)
        #pragma unroll
        for (int nt = 0; nt < 2; nt++)
            #pragma unroll
            for (int e = 0; e < 4; e++) {
                int row = wm + mt * 16 + (lane >> 2) + (e >> 1) * 8;
                int col = nt * 8 + (lane & 3) * 2 + (e & 1);
                LgAtt[row * 17 + col] = acc[mt][nt][e];
            }
    __syncthreads();

    float a[16];
    {
        float mx = -1e30f;
        #pragma unroll
        for (int k = 0; k < 16; k++) { a[k] = LgAtt[tid * 17 + k] + cbs[k]; mx = fmaxf(mx, a[k]); }
        float sum = 0.f;
        #pragma unroll
        for (int k = 0; k < 16; k++) { a[k] = __expf(a[k] - mx); sum += a[k]; }
        float inv = 1.0f / sum;
        #pragma unroll
        for (int k = 0; k < 16; k++) a[k] *= inv;
    }
    __syncthreads();
    #pragma unroll
    for (int k = 0; k < 16; k++) {
        size_t o = (size_t)(b * 16 + k) * 4096 + (size_t)sc * 128 + tid;
        attn_out[o] = a[k];
        __nv_bfloat16 h, l; bsplit(a[k], h, l);
        AttH[k * 136 + tid] = h; AttL[k * 136 + tid] = l;
        LgAtt[k * 136 + tid] = a[k];
    }
    __syncthreads();
    if (tid < 16) {
        float s2 = 0.f;
        #pragma unroll 16
        for (int t = 0; t < 128; t++) s2 += LgAtt[tid * 136 + t];
        g_scratch[OFF_RP + (size_t)(b * 16 + tid) * 32 + sc] = s2;
    }

    // ---- Part B: U += attn @ tok (atomic accumulate) ----
    uint32_t ah[8][4], al[8][4];
    {
        const uint32_t AHb = smem_u32(AttH), ALb = smem_u32(AttL);
        #pragma unroll
        for (int ks = 0; ks < 8; ks++) {
            uint32_t ao = (uint32_t)((lane & 15) * 136 + ks * 16 + (lane >> 4) * 8) * 2;
            ldm4(ah[ks], AHb + ao);
            ldm4(al[ks], ALb + ao);
        }
    }

    load_stage(0, 0);
    load_stage(1, 1);
    load_stage(2, 2);

    float* Ub = g_scratch + OFF_U + (size_t)(b * 16) * 1024;
    const int slot0 = lane >> 2;
    for (int c = 0; c < 32; c++) {
        int bnd = 31 - c; if (bnd > 2) bnd = 2;
        cpwait_n(bnd);
        __syncthreads();
        if (c + 3 < 32) load_stage((c + 3) & 3, c + 3);
        const uint32_t Th_ = Tb + (uint32_t)(c & 3) * 20480u;
        const uint32_t Tl_ = Th_ + 10240u;
        float uacc[4] = {0.f, 0.f, 0.f, 0.f};
        #pragma unroll
        for (int ks = 0; ks < 8; ks++) {
            uint32_t bh[2], bl[2];
            uint32_t bo = (uint32_t)((ks * 16 + (lane & 15)) * 40 + wid * 8) * 2;
            ldm2t(bh, Th_ + bo);
            ldm2t(bl, Tl_ + bo);
            mma16816(uacc, ah[ks], bh);
            mma16816(uacc, ah[ks], bl);
            mma16816(uacc, al[ks], bh);
        }
        const int d0 = c * 32 + wid * 8 + (lane & 3) * 2;
        atomicAdd(&Ub[(size_t)slot0 * 1024 + d0],       uacc[0]);
        atomicAdd(&Ub[(size_t)slot0 * 1024 + d0 + 1],   uacc[1]);
        atomicAdd(&Ub[(size_t)(slot0 + 8) * 1024 + d0],     uacc[2]);
        atomicAdd(&Ub[(size_t)(slot0 + 8) * 1024 + d0 + 1], uacc[3]);
    }
}

// ---------------------------------------------------------------------------
// LayerNorm (slots) -> actA planes; docb=1: also cb + zero-U
// ---------------------------------------------------------------------------
__global__ __launch_bounds__(256) void ln_kernel(unsigned offX,
                                                 const float* __restrict__ g,
                                                 const float* __restrict__ bt,
                                                 int docb) {
    __shared__ float red[256];
    const float* X = g_scratch + offX;
    int row = blockIdx.x, tid = threadIdx.x;
    float4 x = ((const float4*)X)[row * 256 + tid];
    red[tid] = x.x + x.y + x.z + x.w;
    __syncthreads();
    for (int o = 128; o > 0; o >>= 1) { if (tid < o) red[tid] += red[tid + o]; __syncthreads(); }
    float mean = red[0] * (1.0f / 1024.0f);
    __syncthreads();
    float4 dx = { x.x - mean, x.y - mean, x.z - mean, x.w - mean };
    red[tid] = dx.x*dx.x + dx.y*dx.y + dx.z*dx.z + dx.w*dx.w;
    __syncthreads();
    for (int o = 128; o > 0; o >>= 1) { if (tid < o) red[tid] += red[tid + o]; __syncthreads(); }
    float rs = rsqrtf(red[0] * (1.0f / 1024.0f) + EPS_LN);
    float4 gg = ((const float4*)g)[tid], bb = ((const float4*)bt)[tid];
    float y[4] = { dx.x*rs*gg.x + bb.x, dx.y*rs*gg.y + bb.y,
                   dx.z*rs*gg.z + bb.z, dx.w*rs*gg.w + bb.w };
    size_t base = (size_t)row * 1024u + tid * 4;
    #pragma unroll
    for (int j = 0; j < 4; j++) {
        __nv_bfloat16 h, l; bsplit(y[j], h, l);
        g_actAh[base + j] = h; g_actAl[base + j] = l;
    }
    if (docb) {
        *(float4*)&g_scratch[OFF_U + base] = make_float4(0.f, 0.f, 0.f, 0.f);
        float p = 0.f;
        #pragma unroll
        for (int j = 0; j < 4; j++) p += y[j] * g_scratch[OFF_WCB + tid * 4 + j];
        __syncthreads();
        red[tid] = p; __syncthreads();
        for (int o = 128; o > 0; o >>= 1) { if (tid < o) red[tid] += red[tid + o]; __syncthreads(); }
        if (tid == 0)
            g_scratch[OFF_CB + row] = SCALEF * (red[0] + g_scratch[OFF_C0]);
    }
}

// ---------------------------------------------------------------------------
// reduceU (+rowsum): Un[row] = U[row]/rowsum -> actA planes; BS=brow
// ---------------------------------------------------------------------------
__global__ __launch_bounds__(256) void reduceU_kernel() {
    float* S = g_scratch;
    int row = blockIdx.x, tid = threadIdx.x;
    float s = 0.f;
    #pragma unroll
    for (int cc = 0; cc < 32; cc++) s += S[OFF_RP + (size_t)row * 32 + cc];
    float ri = 1.0f / (s + EPS_ATTN);
    if (tid == 0) S[OFF_BS + row] = s * ri;
    size_t base = (size_t)row * 1024u + tid * 4;
    float4 v = *(const float4*)&S[OFF_U + base];
    float y[4] = { v.x * ri, v.y * ri, v.z * ri, v.w * ri };
    #pragma unroll
    for (int j = 0; j < 4; j++) {
        __nv_bfloat16 h, l; bsplit(y[j], h, l);
        g_actAh[base + j] = h; g_actAl[base + j] = l;
    }
}

// ---------------------------------------------------------------------------
// Fused GRU combine + LayerNorm(mlp) -> slots, actA planes.  block = row.
// ---------------------------------------------------------------------------
__global__ __launch_bounds__(256) void gru_ln_kernel(const float* __restrict__ gm,
                                                     const float* __restrict__ bm) {
    __shared__ float red[256];
    float* S = g_scratch;
    int row = blockIdx.x, tid = threadIdx.x;
    size_t gb = (size_t)row * 3072 + tid * 4;
    float4 ir = *(const float4*)&S[OFF_GI + gb];
    float4 iz = *(const float4*)&S[OFF_GI + gb + 1024];
    float4 in_ = *(const float4*)&S[OFF_GI + gb + 2048];
    float4 hr = *(const float4*)&S[OFF_GH + gb];
    float4 hz = *(const float4*)&S[OFF_GH + gb + 1024];
    float4 hn = *(const float4*)&S[OFF_GH + gb + 2048];
    float4 sp = *(const float4*)&S[OFF_SLOTS + (size_t)row * 1024 + tid * 4];
    float ns[4];
    {
        float r0 = sigmf(ir.x + hr.x), z0 = sigmf(iz.x + hz.x);
        ns[0] = (1.f - z0) * tanhf(in_.x + r0 * hn.x) + z0 * sp.x;
        float r1 = sigmf(ir.y + hr.y), z1 = sigmf(iz.y + hz.y);
        ns[1] = (1.f - z1) * tanhf(in_.y + r1 * hn.y) + z1 * sp.y;
        float r2 = sigmf(ir.z + hr.z), z2 = sigmf(iz.z + hz.z);
        ns[2] = (1.f - z2) * tanhf(in_.z + r2 * hn.z) + z2 * sp.z;
        float r3 = sigmf(ir.w + hr.w), z3 = sigmf(iz.w + hz.w);
        ns[3] = (1.f - z3) * tanhf(in_.w + r3 * hn.w) + z3 * sp.w;
    }
    *(float4*)&S[OFF_SLOTS + (size_t)row * 1024 + tid * 4] =
        make_float4(ns[0], ns[1], ns[2], ns[3]);
    red[tid] = ns[0] + ns[1] + ns[2] + ns[3];
    __syncthreads();
    for (int o = 128; o > 0; o >>= 1) { if (tid < o) red[tid] += red[tid + o]; __syncthreads(); }
    float mean = red[0] * (1.0f / 1024.0f);
    __syncthreads();
    float dx[4] = { ns[0]-mean, ns[1]-mean, ns[2]-mean, ns[3]-mean };
    red[tid] = dx[0]*dx[0] + dx[1]*dx[1] + dx[2]*dx[2] + dx[3]*dx[3];
    __syncthreads();
    for (int o = 128; o > 0; o >>= 1) { if (tid < o) red[tid] += red[tid + o]; __syncthreads(); }
    float rs = rsqrtf(red[0] * (1.0f / 1024.0f) + EPS_LN);
    float4 gg = ((const float4*)gm)[tid], bb = ((const float4*)bm)[tid];
    float y[4] = { dx[0]*rs*gg.x + bb.x, dx[1]*rs*gg.y + bb.y,
                   dx[2]*rs*gg.z + bb.z, dx[3]*rs*gg.w + bb.w };
    size_t base = (size_t)row * 1024u + tid * 4;
    #pragma unroll
    for (int j = 0; j < 4; j++) {
        __nv_bfloat16 h, l; bsplit(y[j], h, l);
        g_actAh[base + j] = h; g_actAl[base + j] = l;
    }
}

// ---------------------------------------------------------------------------
// copy slots -> out
// ---------------------------------------------------------------------------
__global__ __launch_bounds__(256) void copy_out_kernel(float* __restrict__ out, int n) {
    int idx = blockIdx.x * 256 + threadIdx.x;
    if (idx < n) out[idx] = g_scratch[OFF_SLOTS + idx];
}

// ---------------------------------------------------------------------------
// host
// ---------------------------------------------------------------------------
#define SMEM128 (4 * (2*128 + 2*64) * SAP * 2)   /* 122880 */
#define SMEM64  (4 * (2*64 + 2*64) * SAP * 2)    /* 81920 */

extern "C" void kernel_launch(void* const* d_in, const int* in_sizes, int n_in,
                              void* d_out, int out_size) {
    const float* tokens = (const float*)d_in[0];
    const float* mu     = (const float*)d_in[1];
    const float* Wq  = (const float*)d_in[2];  const float* bq  = (const float*)d_in[3];
    const float* Wk  = (const float*)d_in[4];  const float* bk  = (const float*)d_in[5];
    const float* Wv  = (const float*)d_in[6];  const float* bv  = (const float*)d_in[7];
    const float* Wih = (const float*)d_in[8];  const float* bih = (const float*)d_in[9];
    const float* Whh = (const float*)d_in[10]; const float* bhh = (const float*)d_in[11];
    const float* W1  = (const float*)d_in[12]; const float* b1  = (const float*)d_in[13];
    const float* W2  = (const float*)d_in[14]; const float* b2  = (const float*)d_in[15];
    const float* gs  = (const float*)d_in[16]; const float* bs  = (const float*)d_in[17];
    const float* gm  = (const float*)d_in[18]; const float* bm  = (const float*)d_in[19];
    float* out = (float*)d_out;

    cudaFuncSetAttribute((const void*)gemm2_k<128>, cudaFuncAttributeMaxDynamicSharedMemorySize, SMEM128);
    cudaFuncSetAttribute((const void*)gemm2_k<64>,  cudaFuncAttributeMaxDynamicSharedMemorySize, SMEM64);
    cudaFuncSetAttribute((const void*)gru_gemm_k,   cudaFuncAttributeMaxDynamicSharedMemorySize, SMEM128);
    cudaFuncSetAttribute((const void*)fused_pass_kernel, cudaFuncAttributeMaxDynamicSharedMemorySize, FP_SMEM);

    __nv_bfloat16 *wMw, *wVih, *wHh, *w1, *w2, *wWqT, *wWkT, *wWvT, *wWihA;
    __nv_bfloat16 *actAh, *actAl, *actSh, *actSl, *actBh, *actBl, *q2h, *q2l;
    cudaGetSymbolAddress((void**)&wMw,   g_wMw);
    cudaGetSymbolAddress((void**)&wVih,  g_wVih);
    cudaGetSymbolAddress((void**)&wHh,   g_wHh);
    cudaGetSymbolAddress((void**)&w1,    g_w1);
    cudaGetSymbolAddress((void**)&w2,    g_w2);
    cudaGetSymbolAddress((void**)&wWqT,  g_wWqT);
    cudaGetSymbolAddress((void**)&wWkT,  g_wWkT);
    cudaGetSymbolAddress((void**)&wWvT,  g_wWvT);
    cudaGetSymbolAddress((void**)&wWihA, g_wWihA);
    cudaGetSymbolAddress((void**)&actAh, g_actAh);
    cudaGetSymbolAddress((void**)&actAl, g_actAl);
    cudaGetSymbolAddress((void**)&actSh, g_actSh);
    cudaGetSymbolAddress((void**)&actSl, g_actSl);
    cudaGetSymbolAddress((void**)&actBh, g_actBh);
    cudaGetSymbolAddress((void**)&actBl, g_actBl);
    cudaGetSymbolAddress((void**)&q2h, g_q2h);
    cudaGetSymbolAddress((void**)&q2l, g_q2l);
    float* scr;
    cudaGetSymbolAddress((void**)&scr, g_scratch);

    float* attnp = (out_size >= 1310720) ? (out + 262144) : (scr + OFF_ATTN);

    const size_t P1M = 1024u * 1024u;
    const size_t P3M = 3072u * 1024u;
    const size_t P4M = 4096u * 1024u;

    // ---- one-time ----
    transpose_kernel<<<dim3(32, 32), dim3(32, 8)>>>(Wk, OFF_WKT);
    transpose_kernel<<<dim3(32, 32), dim3(32, 8)>>>(Wq, OFF_WQT);
    transpose_kernel<<<dim3(32, 32), dim3(32, 8)>>>(Wv, OFF_WVT);
    tcnv_kernel<<<65536, 256>>>(tokens);
    convw2_kernel<<<1024, 256>>>(nullptr, OFF_WQT, wWqT, wWqT + P1M);
    convw2_kernel<<<1024, 256>>>(nullptr, OFF_WKT, wWkT, wWkT + P1M);
    convw2_kernel<<<1024, 256>>>(nullptr, OFF_WVT, wWvT, wWvT + P1M);
    convw2_kernel<<<3072, 256>>>(Wih, 0, wWihA, wWihA + P3M);
    gemv_kernel<<<1024, 256>>>(nullptr, OFF_WQT, bk, OFF_WCB, 1024, 1.0f);
    gemv_kernel<<<1024, 256>>>(nullptr, OFF_WKT, bq, OFF_V2, 1024, SCALEF);
    gemv_kernel<<<3072, 256>>>(Wih, 0, bv, OFF_BVW, 1024, 1.0f);
    gemv_kernel<<<1, 256>>>(bq, 0, bk, OFF_C0, 1024, 1.0f);
    // Mw = SCALE * WkT (.) WqT^T   [1024 x 1024]
    gemm2_k<128><<<dim3(16, 8), 256, SMEM128>>>(wWkT, wWkT + P1M, wWqT, wWqT + P1M,
                                                nullptr, nullptr, scr + OFF_MFP,
                                                nullptr, nullptr, 1024, 1024, 4);
    // Wvih = Wih (.) WvT^T         [3072 x 1024]
    gemm2_k<128><<<dim3(16, 24), 256, SMEM128>>>(wWihA, wWihA + P3M, wWvT, wWvT + P1M,
                                                 nullptr, nullptr, scr + OFF_WVIH,
                                                 nullptr, nullptr, 1024, 1024, 6);
    convw2_kernel<<<1024, 256>>>(nullptr, OFF_MFP,  wMw,  wMw + P1M);
    convw2_kernel<<<3072, 256>>>(nullptr, OFF_WVIH, wVih, wVih + P3M);
    convw2_kernel<<<3072, 256>>>(Whh, 0, wHh, wHh + P3M);
    convw2_kernel<<<4096, 256>>>(W1,  0, w1,  w1 + P4M);
    convw2_kernel<<<4096, 256>>>(W2,  0, w2,  w2 + P4M);
    init_slots_kernel<<<1024, 256>>>(mu);

    for (int it = 0; it < 3; it++) {
        ln_kernel<<<256, 256>>>(OFF_SLOTS, gs, bs, 1);
        // q2 = ln (.) Mw + v2 -> q2 planes
        gemm2_k<64><<<dim3(16, 4), 256, SMEM64>>>(actAh, actAl, wMw, wMw + P1M,
                                                  scr + OFF_V2, nullptr, nullptr,
                                                  q2h, q2l, 1024, 1024, 0);
        fused_pass_kernel<<<dim3(32, 16), 128, FP_SMEM>>>(attnp);
        reduceU_kernel<<<256, 256>>>();
        gru_gemm_k<<<dim3(48, 2, 2), 256, SMEM128>>>(bih, bhh);
        gru_ln_kernel<<<256, 256>>>(gm, bm);
        gemm2_k<128><<<dim3(64, 2), 256, SMEM128>>>(actAh, actAl, w1, w1 + P4M,
                                                    b1, nullptr, nullptr,
                                                    actBh, actBl, 4096, 1024, 2);
        gemm2_k<64><<<dim3(16, 4), 256, SMEM64>>>(actBh, actBl, w2, w2 + P4M,
                                                  b2, nullptr, scr + OFF_SLOTS,
                                                  actSh, actSl, 1024, 4096, 3);
    }

    int nslots = out_size < 262144 ? out_size : 262144;
    copy_out_kernel<<<1024, 256>>>(out, nslots);
}

// round 10
// speedup vs baseline: 2.3476x; 1.0092x over previous
#include <cuda_runtime.h>
#include <cuda_bf16.h>
#include <cstdint>
#include <cstddef>

// ---------------------------------------------------------------------------
// Problem sizes: B=16, S=4096, D=1024, K=16, ITERS=3
// ---------------------------------------------------------------------------
#define SCALEF   0.03125f        /* 1024^-0.5 */
#define EPS_LN   1e-5f
#define EPS_ATTN 1e-8f

// fp32 scratch offsets (floats)
#define OFF_SLOTS 0u
#define OFF_GI    1572864u
#define OFF_GH    2359296u
#define OFF_WQT   4194304u
#define OFF_WVT   5242880u
#define OFF_MFP   6291456u
#define OFF_WVIH  7340032u      /* 3145728 floats */
#define OFF_U     10485760u     /* 262144 floats (atomic accum) */
#define OFF_WCB   10747904u
#define OFF_V2    10748928u
#define OFF_BVW   10749952u
#define OFF_C0    10753024u
#define OFF_WKT   12582912u
#define OFF_CB    13631488u
#define OFF_BS    13631744u
#define OFF_RP    13632256u     /* 256 rows * 32 chunks */
#define OFF_ATTN  13640448u
#define SCRATCH_N 14689024u

__device__ float g_scratch[SCRATCH_N];

// bf16 2-plane weight buffers: [hi plane | lo plane], each N*K
__device__ __nv_bfloat16 g_wMw  [2u * 1024u * 1024u];
__device__ __nv_bfloat16 g_wVih [2u * 3072u * 1024u];
__device__ __nv_bfloat16 g_wHh  [2u * 3072u * 1024u];
__device__ __nv_bfloat16 g_w1   [2u * 4096u * 1024u];
__device__ __nv_bfloat16 g_w2   [2u * 1024u * 4096u];
// one-time composition operands
__device__ __nv_bfloat16 g_wWqT [2u * 1024u * 1024u];
__device__ __nv_bfloat16 g_wWkT [2u * 1024u * 1024u];
__device__ __nv_bfloat16 g_wWvT [2u * 1024u * 1024u];
__device__ __nv_bfloat16 g_wWihA[2u * 3072u * 1024u];
// activation plane pairs
__device__ __nv_bfloat16 g_actAh[256u * 1024u], g_actAl[256u * 1024u];
__device__ __nv_bfloat16 g_actSh[256u * 1024u], g_actSl[256u * 1024u];
__device__ __nv_bfloat16 g_actBh[256u * 4096u], g_actBl[256u * 4096u];
// token planes [b][s][d]
__device__ __nv_bfloat16 g_tokh [16u * 4096u * 1024u];
__device__ __nv_bfloat16 g_tokl [16u * 4096u * 1024u];
// q2 planes [256][1024]
__device__ __nv_bfloat16 g_q2h[256u * 1024u];
__device__ __nv_bfloat16 g_q2l[256u * 1024u];

__device__ __forceinline__ float geluf(float x) {
    return 0.5f * x * (1.0f + erff(x * 0.70710678118654752f));
}
__device__ __forceinline__ float sigmf(float x) {
    return 1.0f / (1.0f + __expf(-x));
}

__device__ __forceinline__ uint32_t smem_u32(const void* p) {
    uint32_t a;
    asm("{ .reg .u64 t; cvta.to.shared.u64 t, %1; cvt.u32.u64 %0, t; }" : "=r"(a) : "l"(p));
    return a;
}
__device__ __forceinline__ void cp16s(uint32_t daddr, const void* src) {
    asm volatile("cp.async.cg.shared.global [%0], [%1], 16;" :: "r"(daddr), "l"(src));
}
__device__ __forceinline__ void cpcommit() {
    asm volatile("cp.async.commit_group;" ::: "memory");
}
__device__ __forceinline__ void cpwait_n(int n) {
    if (n <= 0)      asm volatile("cp.async.wait_group 0;" ::: "memory");
    else if (n == 1) asm volatile("cp.async.wait_group 1;" ::: "memory");
    else             asm volatile("cp.async.wait_group 2;" ::: "memory");
}
__device__ __forceinline__ void ldm4(uint32_t* r, uint32_t addr) {
    asm volatile("ldmatrix.sync.aligned.m8n8.x4.shared.b16 {%0,%1,%2,%3}, [%4];"
        : "=r"(r[0]), "=r"(r[1]), "=r"(r[2]), "=r"(r[3]) : "r"(addr));
}
__device__ __forceinline__ void ldm2t(uint32_t* r, uint32_t addr) {
    asm volatile("ldmatrix.sync.aligned.m8n8.x2.trans.shared.b16 {%0,%1}, [%2];"
        : "=r"(r[0]), "=r"(r[1]) : "r"(addr));
}
__device__ __forceinline__ void mma16816(float* c, const uint32_t* a, const uint32_t* b) {
    asm volatile(
        "mma.sync.aligned.m16n8k16.row.col.f32.bf16.bf16.f32 "
        "{%0,%1,%2,%3}, {%4,%5,%6,%7}, {%8,%9}, {%0,%1,%2,%3};"
        : "+f"(c[0]), "+f"(c[1]), "+f"(c[2]), "+f"(c[3])
        : "r"(a[0]), "r"(a[1]), "r"(a[2]), "r"(a[3]), "r"(b[0]), "r"(b[1]));
}

__device__ __forceinline__ void bsplit(float x, __nv_bfloat16& h, __nv_bfloat16& l) {
    h = __float2bfloat16_rn(x);
    l = __float2bfloat16_rn(x - __bfloat162float(h));
}

// ---------------------------------------------------------------------------
// init: slots = broadcast(slot_mu); emit actS planes (slots feed gh at it0)
// ---------------------------------------------------------------------------
__global__ __launch_bounds__(256) void init_slots_kernel(const float* __restrict__ mu) {
    unsigned idx = blockIdx.x * 256u + threadIdx.x;          // < 262144
    float x = mu[idx & 16383u];
    g_scratch[OFF_SLOTS + idx] = x;
    __nv_bfloat16 h, l; bsplit(x, h, l);
    g_actSh[idx] = h; g_actSl[idx] = l;
}

// ---------------------------------------------------------------------------
// transpose 1024x1024 fp32: in -> g_scratch[dstOff]
// ---------------------------------------------------------------------------
__global__ void transpose_kernel(const float* __restrict__ in, unsigned dstOff) {
    __shared__ float t[32][33];
    int x  = blockIdx.x * 32 + threadIdx.x;
    int y0 = blockIdx.y * 32;
    #pragma unroll
    for (int j = threadIdx.y; j < 32; j += 8)
        t[j][threadIdx.x] = in[(size_t)(y0 + j) * 1024 + x];
    __syncthreads();
    int xo  = blockIdx.y * 32 + threadIdx.x;
    int yo0 = blockIdx.x * 32;
    #pragma unroll
    for (int j = threadIdx.y; j < 32; j += 8)
        g_scratch[dstOff + (size_t)(yo0 + j) * 1024 + xo] = t[threadIdx.x][j];
}

// ---------------------------------------------------------------------------
// tokens -> bf16 hi/lo planes
// ---------------------------------------------------------------------------
__global__ __launch_bounds__(256) void tcnv_kernel(const float* __restrict__ tokens) {
    size_t idx4 = (size_t)blockIdx.x * 256u + threadIdx.x;
    float4 x = ((const float4*)tokens)[idx4];
    __nv_bfloat16 h0,h1,h2,h3,l0,l1,l2,l3;
    bsplit(x.x,h0,l0); bsplit(x.y,h1,l1); bsplit(x.z,h2,l2); bsplit(x.w,h3,l3);
    size_t k = idx4 * 4;
    *(__nv_bfloat162*)(g_tokh + k)     = __nv_bfloat162(h0, h1);
    *(__nv_bfloat162*)(g_tokh + k + 2) = __nv_bfloat162(h2, h3);
    *(__nv_bfloat162*)(g_tokl + k)     = __nv_bfloat162(l0, l1);
    *(__nv_bfloat162*)(g_tokl + k + 2) = __nv_bfloat162(l2, l3);
}

// ---------------------------------------------------------------------------
// split-convert to 2 planes: src (flat fp32) -> dh, dl
// ---------------------------------------------------------------------------
__global__ __launch_bounds__(256) void convw2_kernel(const float* __restrict__ src,
                                                     unsigned srcOff,
                                                     __nv_bfloat16* __restrict__ dh,
                                                     __nv_bfloat16* __restrict__ dl) {
    size_t idx4 = (size_t)blockIdx.x * 256u + threadIdx.x;
    const float* S = src ? src : (g_scratch + srcOff);
    float4 x = *(const float4*)(S + idx4 * 4);
    __nv_bfloat16 h0,h1,h2,h3,l0,l1,l2,l3;
    bsplit(x.x,h0,l0); bsplit(x.y,h1,l1); bsplit(x.z,h2,l2); bsplit(x.w,h3,l3);
    size_t k = idx4 * 4;
    *(__nv_bfloat162*)(dh + k)     = __nv_bfloat162(h0, h1);
    *(__nv_bfloat162*)(dh + k + 2) = __nv_bfloat162(h2, h3);
    *(__nv_bfloat162*)(dl + k)     = __nv_bfloat162(l0, l1);
    *(__nv_bfloat162*)(dl + k + 2) = __nv_bfloat162(l2, l3);
}

// ---------------------------------------------------------------------------
// gemv: out[row] = scale * dot(M[row, 0:len], v)
// ---------------------------------------------------------------------------
__global__ __launch_bounds__(256) void gemv_kernel(const float* __restrict__ M,
                                                   unsigned moff,
                                                   const float* __restrict__ v,
                                                   unsigned outoff, int len, float scale) {
    __shared__ float red[256];
    const float* Mr = (M ? M : g_scratch + moff) + (size_t)blockIdx.x * len;
    int tid = threadIdx.x;
    float p = 0.f;
    for (int i = tid * 4; i < len; i += 1024) {
        float4 a = *(const float4*)(Mr + i);
        float4 b = *(const float4*)(v + i);
        p += a.x*b.x + a.y*b.y + a.z*b.z + a.w*b.w;
    }
    red[tid] = p; __syncthreads();
    for (int o = 128; o > 0; o >>= 1) { if (tid < o) red[tid] += red[tid + o]; __syncthreads(); }
    if (tid == 0) g_scratch[outoff + blockIdx.x] = scale * red[0];
}

// ---------------------------------------------------------------------------
// 2-plane HMMA GEMM: C = (Ah+Al) (.) (Wh+Wl)^T  via Ah*Wh + Ah*Wl + Al*Wh.
// ---------------------------------------------------------------------------
#define SAP 40

template<int BM>
__device__ __forceinline__ void gemm2_core(char* sm,
    const __nv_bfloat16* __restrict__ Ah, const __nv_bfloat16* __restrict__ Al,
    const __nv_bfloat16* __restrict__ Wh, const __nv_bfloat16* __restrict__ Wl,
    const float* __restrict__ bias, const float* __restrict__ bias2,
    float* Cout, __nv_bfloat16* ph, __nv_bfloat16* pl,
    int N, int K, int epi)
{
    constexpr int NW_M = (BM == 128) ? 4 : 2;
    constexpr int WTN  = (BM == 128) ? 32 : 16;
    constexpr int NT   = WTN / 8;
    constexpr uint32_t AP  = BM * SAP * 2;
    constexpr uint32_t WP  = 64 * SAP * 2;
    constexpr uint32_t STG = 2 * AP + 2 * WP;

    const int tid  = threadIdx.x;
    const int lane = tid & 31, wid = tid >> 5;
    const int wm = (wid % NW_M) * 32;
    const int wn = (wid / NW_M) * WTN;
    const int bn = blockIdx.x * 64, bm = blockIdx.y * BM;
    const int NC = K >> 5;

    const uint32_t smb = smem_u32(sm);

    const int lrow = tid >> 2, lch = (tid & 3) * 8;
    const uint32_t aoff  = (uint32_t)(lrow * SAP + lch) * 2;
    const uint32_t aoff1 = (uint32_t)((64 + lrow) * SAP + lch) * 2;
    const __nv_bfloat16* agh0 = Ah + (size_t)(bm + lrow) * K + lch;
    const __nv_bfloat16* agl0 = Al + (size_t)(bm + lrow) * K + lch;
    const __nv_bfloat16* agh1 = Ah + (size_t)(bm + 64 + lrow) * K + lch;
    const __nv_bfloat16* agl1 = Al + (size_t)(bm + 64 + lrow) * K + lch;
    const __nv_bfloat16* wgh  = Wh + (size_t)(bn + lrow) * K + lch;
    const __nv_bfloat16* wgl  = Wl + (size_t)(bn + lrow) * K + lch;

    const int a_row = wm + (lane & 15);
    const int a_col = (lane >> 4) * 8;
    const int b_row = wn + ((lane >> 4) & 1) * 8 + (lane & 7);
    const int b_col = ((lane >> 3) & 1) * 8;

    float acc[2][NT][4];
    #pragma unroll
    for (int i = 0; i < 2; i++)
        #pragma unroll
        for (int j = 0; j < NT; j++)
            #pragma unroll
            for (int e = 0; e < 4; e++) acc[i][j][e] = 0.f;

    auto load_stage = [&](int st, int c) {
        const uint32_t S = smb + (uint32_t)st * STG;
        const int ko = c * 32;
        cp16s(S + aoff, agh0 + ko);
        cp16s(S + AP + aoff, agl0 + ko);
        if (BM == 128) {
            cp16s(S + aoff1, agh1 + ko);
            cp16s(S + AP + aoff1, agl1 + ko);
        }
        cp16s(S + 2 * AP + aoff, wgh + ko);
        cp16s(S + 2 * AP + WP + aoff, wgl + ko);
        cpcommit();
    };

    load_stage(0, 0);
    load_stage(1, 1);
    load_stage(2, 2);

    for (int c = 0; c < NC; c++) {
        int bnd = NC - 1 - c; if (bnd > 2) bnd = 2;
        cpwait_n(bnd);
        __syncthreads();
        if (c + 3 < NC) load_stage((c + 3) & 3, c + 3);
        const uint32_t S = smb + (uint32_t)(c & 3) * STG;
        const uint32_t abh = S, abl = S + AP;
        const uint32_t wbh = S + 2 * AP, wbl = S + 2 * AP + WP;
        #pragma unroll
        for (int ks = 0; ks < 2; ks++) {
            uint32_t afh[2][4], afl[2][4], bfh[2][4], bfl[2][4];
            #pragma unroll
            for (int mt = 0; mt < 2; mt++) {
                uint32_t ao = (uint32_t)(((a_row + mt * 16) * SAP) + ks * 16 + a_col) * 2;
                ldm4(afh[mt], abh + ao);
                ldm4(afl[mt], abl + ao);
            }
            #pragma unroll
            for (int nb = 0; nb < NT / 2 + (NT & 1); nb++) {
                uint32_t bo = (uint32_t)(((b_row + nb * 16) * SAP) + ks * 16 + b_col) * 2;
                ldm4(bfh[nb], wbh + bo);
                ldm4(bfl[nb], wbl + bo);
            }
            #pragma unroll
            for (int mt = 0; mt < 2; mt++)
                #pragma unroll
                for (int nt = 0; nt < NT; nt++) {
                    const uint32_t* bh = &bfh[nt >> 1][(nt & 1) * 2];
                    const uint32_t* bl = &bfl[nt >> 1][(nt & 1) * 2];
                    mma16816(acc[mt][nt], afh[mt], bh);
                    mma16816(acc[mt][nt], afh[mt], bl);
                    mma16816(acc[mt][nt], afl[mt], bh);
                }
        }
    }

    const int mrow = lane >> 2, ncol2 = (lane & 3) * 2;
    #pragma unroll
    for (int mt = 0; mt < 2; mt++) {
        #pragma unroll
        for (int h = 0; h < 2; h++) {
            const int m = bm + wm + mt * 16 + mrow + h * 8;
            float brow = 0.f;
            if (epi == 7) brow = g_scratch[OFF_BS + m];
            #pragma unroll
            for (int nt = 0; nt < NT; nt++) {
                const int n0 = bn + wn + nt * 8 + ncol2;
                float ox = acc[mt][nt][h * 2], oy = acc[mt][nt][h * 2 + 1];
                if (epi == 4) { ox *= SCALEF; oy *= SCALEF; }
                else if (epi == 6) { }
                else {
                    float2 bb = *(const float2*)(bias + n0);
                    if (epi == 7) {
                        float2 b2 = *(const float2*)(bias2 + n0);
                        ox += bb.x + brow * b2.x; oy += bb.y + brow * b2.y;
                    } else { ox += bb.x; oy += bb.y; }
                    if (epi == 2) { ox = geluf(ox); oy = geluf(oy); }
                    if (epi == 3) {
                        float2 c0 = *(const float2*)(Cout + (size_t)m * N + n0);
                        ox += c0.x; oy += c0.y;
                    }
                }
                if (Cout) *(float2*)(Cout + (size_t)m * N + n0) = make_float2(ox, oy);
                if (ph) {
                    __nv_bfloat16 hx, lx, hy, ly;
                    bsplit(ox, hx, lx); bsplit(oy, hy, ly);
                    *(__nv_bfloat162*)(ph + (size_t)m * N + n0) = __nv_bfloat162(hx, hy);
                    *(__nv_bfloat162*)(pl + (size_t)m * N + n0) = __nv_bfloat162(lx, ly);
                }
            }
        }
    }
}

template<int BM>
__global__ __launch_bounds__(256) void gemm2_k(const __nv_bfloat16* __restrict__ Ah,
                                               const __nv_bfloat16* __restrict__ Al,
                                               const __nv_bfloat16* __restrict__ Wh,
                                               const __nv_bfloat16* __restrict__ Wl,
                                               const float* __restrict__ bias,
                                               const float* __restrict__ bias2,
                                               float* Cout, __nv_bfloat16* ph, __nv_bfloat16* pl,
                                               int N, int K, int epi) {
    extern __shared__ char sm[];
    gemm2_core<BM>(sm, Ah, Al, Wh, Wl, bias, bias2, Cout, ph, pl, N, K, epi);
}

// merged GRU gemms
__global__ __launch_bounds__(256) void gru_gemm_k(const float* __restrict__ bih,
                                                  const float* __restrict__ bhh) {
    extern __shared__ char sm[];
    if (blockIdx.z == 0)
        gemm2_core<128>(sm, g_actAh, g_actAl, g_wVih, g_wVih + 3072u*1024u,
                        bih, g_scratch + OFF_BVW, g_scratch + OFF_GI,
                        nullptr, nullptr, 3072, 1024, 7);
    else
        gemm2_core<128>(sm, g_actSh, g_actSl, g_wHh, g_wHh + 3072u*1024u,
                        bhh, nullptr, g_scratch + OFF_GH,
                        nullptr, nullptr, 3072, 1024, 0);
}

// ---------------------------------------------------------------------------
// Fused pass (256 threads, 8 warps): logits + softmax over K + updates.
// Part A: warp w -> tokens [16w,16w+16).  Part B: warp = (n-tile, k-half).
// grid (32 chunks, 16 b).
// ---------------------------------------------------------------------------
#define FP_SMEM 147968   /* Qh 33024 + Ql 33024 + 4 stages * 20480 */
__global__ __launch_bounds__(256) void fused_pass_kernel(float* __restrict__ attn_out,
                                                         int wlast) {
    extern __shared__ char sm[];
    __shared__ float LgAtt[2176];
    __shared__ __nv_bfloat16 AttH[2176], AttL[2176];
    __shared__ float cbs[16];
    const int tid = threadIdx.x;
    const int lane = tid & 31, wid = tid >> 5;
    const int sc = blockIdx.x, b = blockIdx.y;

    const uint32_t smb = smem_u32(sm);
    const uint32_t Qh = smb, Ql = smb + 33024u;
    const uint32_t Tb = smb + 66048u;

    if (tid < 16) cbs[tid] = g_scratch[OFF_CB + b * 16 + tid];

    const size_t tokbase = ((size_t)b * 4096 + (size_t)sc * 128) * 1024;

    auto load_stage = [&](int st, int c) {
        #pragma unroll
        for (int i = 0; i < 2; i++) {
            int id = tid + 256 * i;
            int row = id >> 2, j = id & 3;
            cp16s(Tb + (uint32_t)st * 20480u + (uint32_t)(row * 40 + j * 8) * 2,
                  g_tokh + tokbase + (size_t)row * 1024 + c * 32 + j * 8);
            cp16s(Tb + (uint32_t)st * 20480u + 10240u + (uint32_t)(row * 40 + j * 8) * 2,
                  g_tokl + tokbase + (size_t)row * 1024 + c * 32 + j * 8);
        }
        cpcommit();
    };

    {
        #pragma unroll
        for (int i = 0; i < 8; i++) {
            int id = tid + 256 * i;
            int row = id >> 7, j = id & 127;
            cp16s(Qh + (uint32_t)(row * 1032 + j * 8) * 2,
                  g_q2h + (size_t)(b * 16 + row) * 1024 + j * 8);
            cp16s(Ql + (uint32_t)(row * 1032 + j * 8) * 2,
                  g_q2l + (size_t)(b * 16 + row) * 1024 + j * 8);
        }
        load_stage(0, 0);
        load_stage(1, 1);
        load_stage(2, 2);
    }

    float acc[2][4];
    #pragma unroll
    for (int j = 0; j < 2; j++)
        #pragma unroll
        for (int e = 0; e < 4; e++) acc[j][e] = 0.f;

    const int a_rb = wid * 16 + (lane & 15);          // token row (m16 per warp)
    const int a_cb = (lane >> 4) * 8;
    const int b_rb = ((lane >> 4) & 1) * 8 + (lane & 7);
    const int b_cb = ((lane >> 3) & 1) * 8;

    // ---- Part A: logits over 32 d-chunks ----
    for (int c = 0; c < 32; c++) {
        int bnd = 31 - c; if (bnd > 2) bnd = 2;
        cpwait_n(bnd);
        __syncthreads();
        if (c + 3 < 32) load_stage((c + 3) & 3, c + 3);
        const uint32_t Th_ = Tb + (uint32_t)(c & 3) * 20480u;
        const uint32_t Tl_ = Th_ + 10240u;
        const int qcol = c * 32;
        #pragma unroll
        for (int ks = 0; ks < 2; ks++) {
            uint32_t afh[4], afl[4], bfh[4], bfl[4];
            uint32_t ao = (uint32_t)((a_rb * 40) + ks * 16 + a_cb) * 2;
            ldm4(afh, Th_ + ao);
            ldm4(afl, Tl_ + ao);
            uint32_t bo = (uint32_t)(b_rb * 1032 + qcol + ks * 16 + b_cb) * 2;
            ldm4(bfh, Qh + bo);
            ldm4(bfl, Ql + bo);
            #pragma unroll
            for (int nt = 0; nt < 2; nt++) {
                mma16816(acc[nt], afh, &bfh[nt * 2]);
                mma16816(acc[nt], afh, &bfl[nt * 2]);
                mma16816(acc[nt], afl, &bfh[nt * 2]);
            }
        }
    }

    // dump logits [tok][16]
    #pragma unroll
    for (int nt = 0; nt < 2; nt++)
        #pragma unroll
        for (int e = 0; e < 4; e++) {
            int row = wid * 16 + (lane >> 2) + (e >> 1) * 8;
            int col = nt * 8 + (lane & 3) * 2 + (e & 1);
            LgAtt[row * 17 + col] = acc[nt][e];
        }
    __syncthreads();

    // per-token softmax over K=16 (threads 0..127)
    float a[16];
    if (tid < 128) {
        float mx = -1e30f;
        #pragma unroll
        for (int k = 0; k < 16; k++) { a[k] = LgAtt[tid * 17 + k] + cbs[k]; mx = fmaxf(mx, a[k]); }
        float sum = 0.f;
        #pragma unroll
        for (int k = 0; k < 16; k++) { a[k] = __expf(a[k] - mx); sum += a[k]; }
        float inv = 1.0f / sum;
        #pragma unroll
        for (int k = 0; k < 16; k++) a[k] *= inv;
    }
    __syncthreads();
    if (tid < 128) {
        #pragma unroll
        for (int k = 0; k < 16; k++) {
            if (wlast) {
                size_t o = (size_t)(b * 16 + k) * 4096 + (size_t)sc * 128 + tid;
                attn_out[o] = a[k];
            }
            __nv_bfloat16 h, l; bsplit(a[k], h, l);
            AttH[k * 136 + tid] = h; AttL[k * 136 + tid] = l;
            LgAtt[k * 136 + tid] = a[k];
        }
    }
    __syncthreads();
    if (tid < 16) {
        float s2 = 0.f;
        #pragma unroll 16
        for (int t = 0; t < 128; t++) s2 += LgAtt[tid * 136 + t];
        g_scratch[OFF_RP + (size_t)(b * 16 + tid) * 32 + sc] = s2;
    }

    // ---- Part B: U += attn @ tok (8 warps: nq = n-tile, kh = k-half) ----
    const int nq = wid & 3;          // d-subtile (8 d)
    const int kh = wid >> 2;         // token half (64 tokens)
    uint32_t ah[4][4], al[4][4];
    {
        const uint32_t AHb = smem_u32(AttH), ALb = smem_u32(AttL);
        #pragma unroll
        for (int ks = 0; ks < 4; ks++) {
            int gks = kh * 4 + ks;
            uint32_t ao = (uint32_t)((lane & 15) * 136 + gks * 16 + (lane >> 4) * 8) * 2;
            ldm4(ah[ks], AHb + ao);
            ldm4(al[ks], ALb + ao);
        }
    }

    load_stage(0, 0);
    load_stage(1, 1);
    load_stage(2, 2);

    float* Ub = g_scratch + OFF_U + (size_t)(b * 16) * 1024;
    const int slot0 = lane >> 2;
    for (int c = 0; c < 32; c++) {
        int bnd = 31 - c; if (bnd > 2) bnd = 2;
        cpwait_n(bnd);
        __syncthreads();
        if (c + 3 < 32) load_stage((c + 3) & 3, c + 3);
        const uint32_t Th_ = Tb + (uint32_t)(c & 3) * 20480u;
        const uint32_t Tl_ = Th_ + 10240u;
        float uacc[4] = {0.f, 0.f, 0.f, 0.f};
        #pragma unroll
        for (int ks = 0; ks < 4; ks++) {
            int gks = kh * 4 + ks;
            uint32_t bh[2], bl[2];
            uint32_t bo = (uint32_t)((gks * 16 + (lane & 15)) * 40 + nq * 8) * 2;
            ldm2t(bh, Th_ + bo);
            ldm2t(bl, Tl_ + bo);
            mma16816(uacc, ah[ks], bh);
            mma16816(uacc, ah[ks], bl);
            mma16816(uacc, al[ks], bh);
        }
        const int d0 = c * 32 + nq * 8 + (lane & 3) * 2;
        atomicAdd(&Ub[(size_t)slot0 * 1024 + d0],       uacc[0]);
        atomicAdd(&Ub[(size_t)slot0 * 1024 + d0 + 1],   uacc[1]);
        atomicAdd(&Ub[(size_t)(slot0 + 8) * 1024 + d0],     uacc[2]);
        atomicAdd(&Ub[(size_t)(slot0 + 8) * 1024 + d0 + 1], uacc[3]);
    }
}

// ---------------------------------------------------------------------------
// LayerNorm (slots) -> actA planes; docb=1: also cb + zero-U
// ---------------------------------------------------------------------------
__global__ __launch_bounds__(256) void ln_kernel(unsigned offX,
                                                 const float* __restrict__ g,
                                                 const float* __restrict__ bt,
                                                 int docb) {
    __shared__ float red[256];
    const float* X = g_scratch + offX;
    int row = blockIdx.x, tid = threadIdx.x;
    float4 x = ((const float4*)X)[row * 256 + tid];
    red[tid] = x.x + x.y + x.z + x.w;
    __syncthreads();
    for (int o = 128; o > 0; o >>= 1) { if (tid < o) red[tid] += red[tid + o]; __syncthreads(); }
    float mean = red[0] * (1.0f / 1024.0f);
    __syncthreads();
    float4 dx = { x.x - mean, x.y - mean, x.z - mean, x.w - mean };
    red[tid] = dx.x*dx.x + dx.y*dx.y + dx.z*dx.z + dx.w*dx.w;
    __syncthreads();
    for (int o = 128; o > 0; o >>= 1) { if (tid < o) red[tid] += red[tid + o]; __syncthreads(); }
    float rs = rsqrtf(red[0] * (1.0f / 1024.0f) + EPS_LN);
    float4 gg = ((const float4*)g)[tid], bb = ((const float4*)bt)[tid];
    float y[4] = { dx.x*rs*gg.x + bb.x, dx.y*rs*gg.y + bb.y,
                   dx.z*rs*gg.z + bb.z, dx.w*rs*gg.w + bb.w };
    size_t base = (size_t)row * 1024u + tid * 4;
    #pragma unroll
    for (int j = 0; j < 4; j++) {
        __nv_bfloat16 h, l; bsplit(y[j], h, l);
        g_actAh[base + j] = h; g_actAl[base + j] = l;
    }
    if (docb) {
        *(float4*)&g_scratch[OFF_U + base] = make_float4(0.f, 0.f, 0.f, 0.f);
        float p = 0.f;
        #pragma unroll
        for (int j = 0; j < 4; j++) p += y[j] * g_scratch[OFF_WCB + tid * 4 + j];
        __syncthreads();
        red[tid] = p; __syncthreads();
        for (int o = 128; o > 0; o >>= 1) { if (tid < o) red[tid] += red[tid + o]; __syncthreads(); }
        if (tid == 0)
            g_scratch[OFF_CB + row] = SCALEF * (red[0] + g_scratch[OFF_C0]);
    }
}

// ---------------------------------------------------------------------------
// reduceU (+rowsum): Un[row] = U[row]/rowsum -> actA planes; BS=brow
// ---------------------------------------------------------------------------
__global__ __launch_bounds__(256) void reduceU_kernel() {
    float* S = g_scratch;
    int row = blockIdx.x, tid = threadIdx.x;
    float s = 0.f;
    #pragma unroll
    for (int cc = 0; cc < 32; cc++) s += S[OFF_RP + (size_t)row * 32 + cc];
    float ri = 1.0f / (s + EPS_ATTN);
    if (tid == 0) S[OFF_BS + row] = s * ri;
    size_t base = (size_t)row * 1024u + tid * 4;
    float4 v = *(const float4*)&S[OFF_U + base];
    float y[4] = { v.x * ri, v.y * ri, v.z * ri, v.w * ri };
    #pragma unroll
    for (int j = 0; j < 4; j++) {
        __nv_bfloat16 h, l; bsplit(y[j], h, l);
        g_actAh[base + j] = h; g_actAl[base + j] = l;
    }
}

// ---------------------------------------------------------------------------
// Fused GRU combine + LayerNorm(mlp) -> slots, actA planes.  block = row.
// ---------------------------------------------------------------------------
__global__ __launch_bounds__(256) void gru_ln_kernel(const float* __restrict__ gm,
                                                     const float* __restrict__ bm) {
    __shared__ float red[256];
    float* S = g_scratch;
    int row = blockIdx.x, tid = threadIdx.x;
    size_t gb = (size_t)row * 3072 + tid * 4;
    float4 ir = *(const float4*)&S[OFF_GI + gb];
    float4 iz = *(const float4*)&S[OFF_GI + gb + 1024];
    float4 in_ = *(const float4*)&S[OFF_GI + gb + 2048];
    float4 hr = *(const float4*)&S[OFF_GH + gb];
    float4 hz = *(const float4*)&S[OFF_GH + gb + 1024];
    float4 hn = *(const float4*)&S[OFF_GH + gb + 2048];
    float4 sp = *(const float4*)&S[OFF_SLOTS + (size_t)row * 1024 + tid * 4];
    float ns[4];
    {
        float r0 = sigmf(ir.x + hr.x), z0 = sigmf(iz.x + hz.x);
        ns[0] = (1.f - z0) * tanhf(in_.x + r0 * hn.x) + z0 * sp.x;
        float r1 = sigmf(ir.y + hr.y), z1 = sigmf(iz.y + hz.y);
        ns[1] = (1.f - z1) * tanhf(in_.y + r1 * hn.y) + z1 * sp.y;
        float r2 = sigmf(ir.z + hr.z), z2 = sigmf(iz.z + hz.z);
        ns[2] = (1.f - z2) * tanhf(in_.z + r2 * hn.z) + z2 * sp.z;
        float r3 = sigmf(ir.w + hr.w), z3 = sigmf(iz.w + hz.w);
        ns[3] = (1.f - z3) * tanhf(in_.w + r3 * hn.w) + z3 * sp.w;
    }
    *(float4*)&S[OFF_SLOTS + (size_t)row * 1024 + tid * 4] =
        make_float4(ns[0], ns[1], ns[2], ns[3]);
    red[tid] = ns[0] + ns[1] + ns[2] + ns[3];
    __syncthreads();
    for (int o = 128; o > 0; o >>= 1) { if (tid < o) red[tid] += red[tid + o]; __syncthreads(); }
    float mean = red[0] * (1.0f / 1024.0f);
    __syncthreads();
    float dx[4] = { ns[0]-mean, ns[1]-mean, ns[2]-mean, ns[3]-mean };
    red[tid] = dx[0]*dx[0] + dx[1]*dx[1] + dx[2]*dx[2] + dx[3]*dx[3];
    __syncthreads();
    for (int o = 128; o > 0; o >>= 1) { if (tid < o) red[tid] += red[tid + o]; __syncthreads(); }
    float rs = rsqrtf(red[0] * (1.0f / 1024.0f) + EPS_LN);
    float4 gg = ((const float4*)gm)[tid], bb = ((const float4*)bm)[tid];
    float y[4] = { dx[0]*rs*gg.x + bb.x, dx[1]*rs*gg.y + bb.y,
                   dx[2]*rs*gg.z + bb.z, dx[3]*rs*gg.w + bb.w };
    size_t base = (size_t)row * 1024u + tid * 4;
    #pragma unroll
    for (int j = 0; j < 4; j++) {
        __nv_bfloat16 h, l; bsplit(y[j], h, l);
        g_actAh[base + j] = h; g_actAl[base + j] = l;
    }
}

// ---------------------------------------------------------------------------
// copy slots -> out
// ---------------------------------------------------------------------------
__global__ __launch_bounds__(256) void copy_out_kernel(float* __restrict__ out, int n) {
    int idx = blockIdx.x * 256 + threadIdx.x;
    if (idx < n) out[idx] = g_scratch[OFF_SLOTS + idx];
}

// ---------------------------------------------------------------------------
// host
// ---------------------------------------------------------------------------
#define SMEM128 (4 * (2*128 + 2*64) * SAP * 2)   /* 122880 */
#define SMEM64  (4 * (2*64 + 2*64) * SAP * 2)    /* 81920 */

extern "C" void kernel_launch(void* const* d_in, const int* in_sizes, int n_in,
                              void* d_out, int out_size) {
    const float* tokens = (const float*)d_in[0];
    const float* mu     = (const float*)d_in[1];
    const float* Wq  = (const float*)d_in[2];  const float* bq  = (const float*)d_in[3];
    const float* Wk  = (const float*)d_in[4];  const float* bk  = (const float*)d_in[5];
    const float* Wv  = (const float*)d_in[6];  const float* bv  = (const float*)d_in[7];
    const float* Wih = (const float*)d_in[8];  const float* bih = (const float*)d_in[9];
    const float* Whh = (const float*)d_in[10]; const float* bhh = (const float*)d_in[11];
    const float* W1  = (const float*)d_in[12]; const float* b1  = (const float*)d_in[13];
    const float* W2  = (const float*)d_in[14]; const float* b2  = (const float*)d_in[15];
    const float* gs  = (const float*)d_in[16]; const float* bs  = (const float*)d_in[17];
    const float* gm  = (const float*)d_in[18]; const float* bm  = (const float*)d_in[19];
    float* out = (float*)d_out;

    cudaFuncSetAttribute((const void*)gemm2_k<128>, cudaFuncAttributeMaxDynamicSharedMemorySize, SMEM128);
    cudaFuncSetAttribute((const void*)gemm2_k<64>,  cudaFuncAttributeMaxDynamicSharedMemorySize, SMEM64);
    cudaFuncSetAttribute((const void*)gru_gemm_k,   cudaFuncAttributeMaxDynamicSharedMemorySize, SMEM128);
    cudaFuncSetAttribute((const void*)fused_pass_kernel, cudaFuncAttributeMaxDynamicSharedMemorySize, FP_SMEM);

    __nv_bfloat16 *wMw, *wVih, *wHh, *w1, *w2, *wWqT, *wWkT, *wWvT, *wWihA;
    __nv_bfloat16 *actAh, *actAl, *actSh, *actSl, *actBh, *actBl, *q2h, *q2l;
    cudaGetSymbolAddress((void**)&wMw,   g_wMw);
    cudaGetSymbolAddress((void**)&wVih,  g_wVih);
    cudaGetSymbolAddress((void**)&wHh,   g_wHh);
    cudaGetSymbolAddress((void**)&w1,    g_w1);
    cudaGetSymbolAddress((void**)&w2,    g_w2);
    cudaGetSymbolAddress((void**)&wWqT,  g_wWqT);
    cudaGetSymbolAddress((void**)&wWkT,  g_wWkT);
    cudaGetSymbolAddress((void**)&wWvT,  g_wWvT);
    cudaGetSymbolAddress((void**)&wWihA, g_wWihA);
    cudaGetSymbolAddress((void**)&actAh, g_actAh);
    cudaGetSymbolAddress((void**)&actAl, g_actAl);
    cudaGetSymbolAddress((void**)&actSh, g_actSh);
    cudaGetSymbolAddress((void**)&actSl, g_actSl);
    cudaGetSymbolAddress((void**)&actBh, g_actBh);
    cudaGetSymbolAddress((void**)&actBl, g_actBl);
    cudaGetSymbolAddress((void**)&q2h, g_q2h);
    cudaGetSymbolAddress((void**)&q2l, g_q2l);
    float* scr;
    cudaGetSymbolAddress((void**)&scr, g_scratch);

    float* attnp = (out_size >= 1310720) ? (out + 262144) : (scr + OFF_ATTN);

    const size_t P1M = 1024u * 1024u;
    const size_t P3M = 3072u * 1024u;
    const size_t P4M = 4096u * 1024u;

    // ---- one-time ----
    transpose_kernel<<<dim3(32, 32), dim3(32, 8)>>>(Wk, OFF_WKT);
    transpose_kernel<<<dim3(32, 32), dim3(32, 8)>>>(Wq, OFF_WQT);
    transpose_kernel<<<dim3(32, 32), dim3(32, 8)>>>(Wv, OFF_WVT);
    tcnv_kernel<<<65536, 256>>>(tokens);
    convw2_kernel<<<1024, 256>>>(nullptr, OFF_WQT, wWqT, wWqT + P1M);
    convw2_kernel<<<1024, 256>>>(nullptr, OFF_WKT, wWkT, wWkT + P1M);
    convw2_kernel<<<1024, 256>>>(nullptr, OFF_WVT, wWvT, wWvT + P1M);
    convw2_kernel<<<3072, 256>>>(Wih, 0, wWihA, wWihA + P3M);
    gemv_kernel<<<1024, 256>>>(nullptr, OFF_WQT, bk, OFF_WCB, 1024, 1.0f);
    gemv_kernel<<<1024, 256>>>(nullptr, OFF_WKT, bq, OFF_V2, 1024, SCALEF);
    gemv_kernel<<<3072, 256>>>(Wih, 0, bv, OFF_BVW, 1024, 1.0f);
    gemv_kernel<<<1, 256>>>(bq, 0, bk, OFF_C0, 1024, 1.0f);
    gemm2_k<128><<<dim3(16, 8), 256, SMEM128>>>(wWkT, wWkT + P1M, wWqT, wWqT + P1M,
                                                nullptr, nullptr, scr + OFF_MFP,
                                                nullptr, nullptr, 1024, 1024, 4);
    gemm2_k<128><<<dim3(16, 24), 256, SMEM128>>>(wWihA, wWihA + P3M, wWvT, wWvT + P1M,
                                                 nullptr, nullptr, scr + OFF_WVIH,
                                                 nullptr, nullptr, 1024, 1024, 6);
    convw2_kernel<<<1024, 256>>>(nullptr, OFF_MFP,  wMw,  wMw + P1M);
    convw2_kernel<<<3072, 256>>>(nullptr, OFF_WVIH, wVih, wVih + P3M);
    convw2_kernel<<<3072, 256>>>(Whh, 0, wHh, wHh + P3M);
    convw2_kernel<<<4096, 256>>>(W1,  0, w1,  w1 + P4M);
    convw2_kernel<<<4096, 256>>>(W2,  0, w2,  w2 + P4M);
    init_slots_kernel<<<1024, 256>>>(mu);

    for (int it = 0; it < 3; it++) {
        ln_kernel<<<256, 256>>>(OFF_SLOTS, gs, bs, 1);
        gemm2_k<64><<<dim3(16, 4), 256, SMEM64>>>(actAh, actAl, wMw, wMw + P1M,
                                                  scr + OFF_V2, nullptr, nullptr,
                                                  q2h, q2l, 1024, 1024, 0);
        fused_pass_kernel<<<dim3(32, 16), 256, FP_SMEM>>>(attnp, it == 2 ? 1 : 0);
        reduceU_kernel<<<256, 256>>>();
        gru_gemm_k<<<dim3(48, 2, 2), 256, SMEM128>>>(bih, bhh);
        gru_ln_kernel<<<256, 256>>>(gm, bm);
        gemm2_k<128><<<dim3(64, 2), 256, SMEM128>>>(actAh, actAl, w1, w1 + P4M,
                                                    b1, nullptr, nullptr,
                                                    actBh, actBl, 4096, 1024, 2);
        gemm2_k<64><<<dim3(16, 4), 256, SMEM64>>>(actBh, actBl, w2, w2 + P4M,
                                                  b2, nullptr, scr + OFF_SLOTS,
                                                  actSh, actSl, 1024, 4096, 3);
    }

    int nslots = out_size < 262144 ? out_size : 262144;
    copy_out_kernel<<<1024, 256>>>(out, nslots);
}

// round 11
// speedup vs baseline: 2.6065x; 1.1103x over previous
#include <cuda_runtime.h>
#include <cuda_bf16.h>
#include <cstdint>
#include <cstddef>

// ---------------------------------------------------------------------------
// Problem sizes: B=16, S=4096, D=1024, K=16, ITERS=3
// ---------------------------------------------------------------------------
#define SCALEF   0.03125f        /* 1024^-0.5 */
#define EPS_LN   1e-5f
#define EPS_ATTN 1e-8f

// fp32 scratch offsets (floats)
#define OFF_SLOTS 0u
#define OFF_GI    1572864u
#define OFF_GH    2359296u
#define OFF_WQT   4194304u
#define OFF_WVT   5242880u
#define OFF_MFP   6291456u
#define OFF_WVIH  7340032u      /* 3145728 floats */
#define OFF_U     10485760u     /* 262144 floats (atomic accum) */
#define OFF_WCB   10747904u
#define OFF_V2    10748928u
#define OFF_BVW   10749952u
#define OFF_C0    10753024u
#define OFF_WKT   12582912u
#define OFF_CB    13631488u
#define OFF_BS    13631744u
#define OFF_RP    13632256u     /* 256 rows * 32 chunks */
#define OFF_ATTN  13640448u
#define SCRATCH_N 14689024u

__device__ float g_scratch[SCRATCH_N];

// bf16 2-plane weight buffers: [hi plane | lo plane], each N*K
__device__ __nv_bfloat16 g_wMw  [2u * 1024u * 1024u];
__device__ __nv_bfloat16 g_wVih [2u * 3072u * 1024u];
__device__ __nv_bfloat16 g_wHh  [2u * 3072u * 1024u];
__device__ __nv_bfloat16 g_w1   [2u * 4096u * 1024u];
__device__ __nv_bfloat16 g_w2   [2u * 1024u * 4096u];
// one-time composition operands
__device__ __nv_bfloat16 g_wWqT [2u * 1024u * 1024u];
__device__ __nv_bfloat16 g_wWkT [2u * 1024u * 1024u];
__device__ __nv_bfloat16 g_wWvT [2u * 1024u * 1024u];
__device__ __nv_bfloat16 g_wWihA[2u * 3072u * 1024u];
// activation plane pairs
__device__ __nv_bfloat16 g_actAh[256u * 1024u], g_actAl[256u * 1024u];
__device__ __nv_bfloat16 g_actSh[256u * 1024u], g_actSl[256u * 1024u];
__device__ __nv_bfloat16 g_actBh[256u * 4096u], g_actBl[256u * 4096u];
// token planes [b][s][d]
__device__ __nv_bfloat16 g_tokh [16u * 4096u * 1024u];
__device__ __nv_bfloat16 g_tokl [16u * 4096u * 1024u];
// q2 planes [256][1024]
__device__ __nv_bfloat16 g_q2h[256u * 1024u];
__device__ __nv_bfloat16 g_q2l[256u * 1024u];

__device__ __forceinline__ float geluf(float x) {
    return 0.5f * x * (1.0f + erff(x * 0.70710678118654752f));
}
__device__ __forceinline__ float sigmf(float x) {
    return 1.0f / (1.0f + __expf(-x));
}

__device__ __forceinline__ uint32_t smem_u32(const void* p) {
    uint32_t a;
    asm("{ .reg .u64 t; cvta.to.shared.u64 t, %1; cvt.u32.u64 %0, t; }" : "=r"(a) : "l"(p));
    return a;
}
__device__ __forceinline__ void cp16s(uint32_t daddr, const void* src) {
    asm volatile("cp.async.cg.shared.global [%0], [%1], 16;" :: "r"(daddr), "l"(src));
}
__device__ __forceinline__ void cpcommit() {
    asm volatile("cp.async.commit_group;" ::: "memory");
}
__device__ __forceinline__ void cpwait_n(int n) {
    if (n <= 0)      asm volatile("cp.async.wait_group 0;" ::: "memory");
    else if (n == 1) asm volatile("cp.async.wait_group 1;" ::: "memory");
    else             asm volatile("cp.async.wait_group 2;" ::: "memory");
}
__device__ __forceinline__ void ldm4(uint32_t* r, uint32_t addr) {
    asm volatile("ldmatrix.sync.aligned.m8n8.x4.shared.b16 {%0,%1,%2,%3}, [%4];"
        : "=r"(r[0]), "=r"(r[1]), "=r"(r[2]), "=r"(r[3]) : "r"(addr));
}
__device__ __forceinline__ void ldm2t(uint32_t* r, uint32_t addr) {
    asm volatile("ldmatrix.sync.aligned.m8n8.x2.trans.shared.b16 {%0,%1}, [%2];"
        : "=r"(r[0]), "=r"(r[1]) : "r"(addr));
}
__device__ __forceinline__ void mma16816(float* c, const uint32_t* a, const uint32_t* b) {
    asm volatile(
        "mma.sync.aligned.m16n8k16.row.col.f32.bf16.bf16.f32 "
        "{%0,%1,%2,%3}, {%4,%5,%6,%7}, {%8,%9}, {%0,%1,%2,%3};"
        : "+f"(c[0]), "+f"(c[1]), "+f"(c[2]), "+f"(c[3])
        : "r"(a[0]), "r"(a[1]), "r"(a[2]), "r"(a[3]), "r"(b[0]), "r"(b[1]));
}

__device__ __forceinline__ void bsplit(float x, __nv_bfloat16& h, __nv_bfloat16& l) {
    h = __float2bfloat16_rn(x);
    l = __float2bfloat16_rn(x - __bfloat162float(h));
}

// ---------------------------------------------------------------------------
// init: slots = broadcast(slot_mu); emit actS planes (slots feed gh at it0)
// ---------------------------------------------------------------------------
__global__ __launch_bounds__(256) void init_slots_kernel(const float* __restrict__ mu) {
    unsigned idx = blockIdx.x * 256u + threadIdx.x;          // < 262144
    float x = mu[idx & 16383u];
    g_scratch[OFF_SLOTS + idx] = x;
    __nv_bfloat16 h, l; bsplit(x, h, l);
    g_actSh[idx] = h; g_actSl[idx] = l;
}

// ---------------------------------------------------------------------------
// transpose 1024x1024 fp32: in -> g_scratch[dstOff]
// ---------------------------------------------------------------------------
__global__ void transpose_kernel(const float* __restrict__ in, unsigned dstOff) {
    __shared__ float t[32][33];
    int x  = blockIdx.x * 32 + threadIdx.x;
    int y0 = blockIdx.y * 32;
    #pragma unroll
    for (int j = threadIdx.y; j < 32; j += 8)
        t[j][threadIdx.x] = in[(size_t)(y0 + j) * 1024 + x];
    __syncthreads();
    int xo  = blockIdx.y * 32 + threadIdx.x;
    int yo0 = blockIdx.x * 32;
    #pragma unroll
    for (int j = threadIdx.y; j < 32; j += 8)
        g_scratch[dstOff + (size_t)(yo0 + j) * 1024 + xo] = t[threadIdx.x][j];
}

// ---------------------------------------------------------------------------
// tokens -> bf16 hi/lo planes
// ---------------------------------------------------------------------------
__global__ __launch_bounds__(256) void tcnv_kernel(const float* __restrict__ tokens) {
    size_t idx4 = (size_t)blockIdx.x * 256u + threadIdx.x;
    float4 x = ((const float4*)tokens)[idx4];
    __nv_bfloat16 h0,h1,h2,h3,l0,l1,l2,l3;
    bsplit(x.x,h0,l0); bsplit(x.y,h1,l1); bsplit(x.z,h2,l2); bsplit(x.w,h3,l3);
    size_t k = idx4 * 4;
    *(__nv_bfloat162*)(g_tokh + k)     = __nv_bfloat162(h0, h1);
    *(__nv_bfloat162*)(g_tokh + k + 2) = __nv_bfloat162(h2, h3);
    *(__nv_bfloat162*)(g_tokl + k)     = __nv_bfloat162(l0, l1);
    *(__nv_bfloat162*)(g_tokl + k + 2) = __nv_bfloat162(l2, l3);
}

// ---------------------------------------------------------------------------
// split-convert to 2 planes: src (flat fp32) -> dh, dl
// ---------------------------------------------------------------------------
__global__ __launch_bounds__(256) void convw2_kernel(const float* __restrict__ src,
                                                     unsigned srcOff,
                                                     __nv_bfloat16* __restrict__ dh,
                                                     __nv_bfloat16* __restrict__ dl) {
    size_t idx4 = (size_t)blockIdx.x * 256u + threadIdx.x;
    const float* S = src ? src : (g_scratch + srcOff);
    float4 x = *(const float4*)(S + idx4 * 4);
    __nv_bfloat16 h0,h1,h2,h3,l0,l1,l2,l3;
    bsplit(x.x,h0,l0); bsplit(x.y,h1,l1); bsplit(x.z,h2,l2); bsplit(x.w,h3,l3);
    size_t k = idx4 * 4;
    *(__nv_bfloat162*)(dh + k)     = __nv_bfloat162(h0, h1);
    *(__nv_bfloat162*)(dh + k + 2) = __nv_bfloat162(h2, h3);
    *(__nv_bfloat162*)(dl + k)     = __nv_bfloat162(l0, l1);
    *(__nv_bfloat162*)(dl + k + 2) = __nv_bfloat162(l2, l3);
}

// ---------------------------------------------------------------------------
// gemv: out[row] = scale * dot(M[row, 0:len], v)
// ---------------------------------------------------------------------------
__global__ __launch_bounds__(256) void gemv_kernel(const float* __restrict__ M,
                                                   unsigned moff,
                                                   const float* __restrict__ v,
                                                   unsigned outoff, int len, float scale) {
    __shared__ float red[256];
    const float* Mr = (M ? M : g_scratch + moff) + (size_t)blockIdx.x * len;
    int tid = threadIdx.x;
    float p = 0.f;
    for (int i = tid * 4; i < len; i += 1024) {
        float4 a = *(const float4*)(Mr + i);
        float4 b = *(const float4*)(v + i);
        p += a.x*b.x + a.y*b.y + a.z*b.z + a.w*b.w;
    }
    red[tid] = p; __syncthreads();
    for (int o = 128; o > 0; o >>= 1) { if (tid < o) red[tid] += red[tid + o]; __syncthreads(); }
    if (tid == 0) g_scratch[outoff + blockIdx.x] = scale * red[0];
}

// ---------------------------------------------------------------------------
// 2-plane HMMA GEMM: C = (Ah+Al) (.) (Wh+Wl)^T  via Ah*Wh + Ah*Wl + Al*Wh.
// ---------------------------------------------------------------------------
#define SAP 40

template<int BM>
__device__ __forceinline__ void gemm2_core(char* sm,
    const __nv_bfloat16* __restrict__ Ah, const __nv_bfloat16* __restrict__ Al,
    const __nv_bfloat16* __restrict__ Wh, const __nv_bfloat16* __restrict__ Wl,
    const float* __restrict__ bias, const float* __restrict__ bias2,
    float* Cout, __nv_bfloat16* ph, __nv_bfloat16* pl,
    int N, int K, int epi)
{
    constexpr int NW_M = (BM == 128) ? 4 : 2;
    constexpr int WTN  = (BM == 128) ? 32 : 16;
    constexpr int NT   = WTN / 8;
    constexpr uint32_t AP  = BM * SAP * 2;
    constexpr uint32_t WP  = 64 * SAP * 2;
    constexpr uint32_t STG = 2 * AP + 2 * WP;

    const int tid  = threadIdx.x;
    const int lane = tid & 31, wid = tid >> 5;
    const int wm = (wid % NW_M) * 32;
    const int wn = (wid / NW_M) * WTN;
    const int bn = blockIdx.x * 64, bm = blockIdx.y * BM;
    const int NC = K >> 5;

    const uint32_t smb = smem_u32(sm);

    const int lrow = tid >> 2, lch = (tid & 3) * 8;
    const uint32_t aoff  = (uint32_t)(lrow * SAP + lch) * 2;
    const uint32_t aoff1 = (uint32_t)((64 + lrow) * SAP + lch) * 2;
    const __nv_bfloat16* agh0 = Ah + (size_t)(bm + lrow) * K + lch;
    const __nv_bfloat16* agl0 = Al + (size_t)(bm + lrow) * K + lch;
    const __nv_bfloat16* agh1 = Ah + (size_t)(bm + 64 + lrow) * K + lch;
    const __nv_bfloat16* agl1 = Al + (size_t)(bm + 64 + lrow) * K + lch;
    const __nv_bfloat16* wgh  = Wh + (size_t)(bn + lrow) * K + lch;
    const __nv_bfloat16* wgl  = Wl + (size_t)(bn + lrow) * K + lch;

    const int a_row = wm + (lane & 15);
    const int a_col = (lane >> 4) * 8;
    const int b_row = wn + ((lane >> 4) & 1) * 8 + (lane & 7);
    const int b_col = ((lane >> 3) & 1) * 8;

    float acc[2][NT][4];
    #pragma unroll
    for (int i = 0; i < 2; i++)
        #pragma unroll
        for (int j = 0; j < NT; j++)
            #pragma unroll
            for (int e = 0; e < 4; e++) acc[i][j][e] = 0.f;

    auto load_stage = [&](int st, int c) {
        const uint32_t S = smb + (uint32_t)st * STG;
        const int ko = c * 32;
        cp16s(S + aoff, agh0 + ko);
        cp16s(S + AP + aoff, agl0 + ko);
        if (BM == 128) {
            cp16s(S + aoff1, agh1 + ko);
            cp16s(S + AP + aoff1, agl1 + ko);
        }
        cp16s(S + 2 * AP + aoff, wgh + ko);
        cp16s(S + 2 * AP + WP + aoff, wgl + ko);
        cpcommit();
    };

    load_stage(0, 0);
    load_stage(1, 1);
    load_stage(2, 2);

    for (int c = 0; c < NC; c++) {
        int bnd = NC - 1 - c; if (bnd > 2) bnd = 2;
        cpwait_n(bnd);
        __syncthreads();
        if (c + 3 < NC) load_stage((c + 3) & 3, c + 3);
        const uint32_t S = smb + (uint32_t)(c & 3) * STG;
        const uint32_t abh = S, abl = S + AP;
        const uint32_t wbh = S + 2 * AP, wbl = S + 2 * AP + WP;
        #pragma unroll
        for (int ks = 0; ks < 2; ks++) {
            uint32_t afh[2][4], afl[2][4], bfh[2][4], bfl[2][4];
            #pragma unroll
            for (int mt = 0; mt < 2; mt++) {
                uint32_t ao = (uint32_t)(((a_row + mt * 16) * SAP) + ks * 16 + a_col) * 2;
                ldm4(afh[mt], abh + ao);
                ldm4(afl[mt], abl + ao);
            }
            #pragma unroll
            for (int nb = 0; nb < NT / 2 + (NT & 1); nb++) {
                uint32_t bo = (uint32_t)(((b_row + nb * 16) * SAP) + ks * 16 + b_col) * 2;
                ldm4(bfh[nb], wbh + bo);
                ldm4(bfl[nb], wbl + bo);
            }
            #pragma unroll
            for (int mt = 0; mt < 2; mt++)
                #pragma unroll
                for (int nt = 0; nt < NT; nt++) {
                    const uint32_t* bh = &bfh[nt >> 1][(nt & 1) * 2];
                    const uint32_t* bl = &bfl[nt >> 1][(nt & 1) * 2];
                    mma16816(acc[mt][nt], afh[mt], bh);
                    mma16816(acc[mt][nt], afh[mt], bl);
                    mma16816(acc[mt][nt], afl[mt], bh);
                }
        }
    }

    const int mrow = lane >> 2, ncol2 = (lane & 3) * 2;
    #pragma unroll
    for (int mt = 0; mt < 2; mt++) {
        #pragma unroll
        for (int h = 0; h < 2; h++) {
            const int m = bm + wm + mt * 16 + mrow + h * 8;
            float brow = 0.f;
            if (epi == 7) brow = g_scratch[OFF_BS + m];
            #pragma unroll
            for (int nt = 0; nt < NT; nt++) {
                const int n0 = bn + wn + nt * 8 + ncol2;
                float ox = acc[mt][nt][h * 2], oy = acc[mt][nt][h * 2 + 1];
                if (epi == 4) { ox *= SCALEF; oy *= SCALEF; }
                else if (epi == 6) { }
                else {
                    float2 bb = *(const float2*)(bias + n0);
                    if (epi == 7) {
                        float2 b2 = *(const float2*)(bias2 + n0);
                        ox += bb.x + brow * b2.x; oy += bb.y + brow * b2.y;
                    } else { ox += bb.x; oy += bb.y; }
                    if (epi == 2) { ox = geluf(ox); oy = geluf(oy); }
                    if (epi == 3) {
                        float2 c0 = *(const float2*)(Cout + (size_t)m * N + n0);
                        ox += c0.x; oy += c0.y;
                    }
                }
                if (Cout) *(float2*)(Cout + (size_t)m * N + n0) = make_float2(ox, oy);
                if (ph) {
                    __nv_bfloat16 hx, lx, hy, ly;
                    bsplit(ox, hx, lx); bsplit(oy, hy, ly);
                    *(__nv_bfloat162*)(ph + (size_t)m * N + n0) = __nv_bfloat162(hx, hy);
                    *(__nv_bfloat162*)(pl + (size_t)m * N + n0) = __nv_bfloat162(lx, ly);
                }
            }
        }
    }
}

template<int BM>
__global__ __launch_bounds__(256) void gemm2_k(const __nv_bfloat16* __restrict__ Ah,
                                               const __nv_bfloat16* __restrict__ Al,
                                               const __nv_bfloat16* __restrict__ Wh,
                                               const __nv_bfloat16* __restrict__ Wl,
                                               const float* __restrict__ bias,
                                               const float* __restrict__ bias2,
                                               float* Cout, __nv_bfloat16* ph, __nv_bfloat16* pl,
                                               int N, int K, int epi) {
    extern __shared__ char sm[];
    gemm2_core<BM>(sm, Ah, Al, Wh, Wl, bias, bias2, Cout, ph, pl, N, K, epi);
}

// merged GRU gemms
__global__ __launch_bounds__(256) void gru_gemm_k(const float* __restrict__ bih,
                                                  const float* __restrict__ bhh) {
    extern __shared__ char sm[];
    if (blockIdx.z == 0)
        gemm2_core<128>(sm, g_actAh, g_actAl, g_wVih, g_wVih + 3072u*1024u,
                        bih, g_scratch + OFF_BVW, g_scratch + OFF_GI,
                        nullptr, nullptr, 3072, 1024, 7);
    else
        gemm2_core<128>(sm, g_actSh, g_actSl, g_wHh, g_wHh + 3072u*1024u,
                        bhh, nullptr, g_scratch + OFF_GH,
                        nullptr, nullptr, 3072, 1024, 0);
}

// ---------------------------------------------------------------------------
// Single-read fused pass (256 threads): per 16-token group -- load tok strip
// once, logits (k split over 8 warps) + softmax + updates vs the SAME strip.
// U accumulated in registers across groups; one atomicAdd set per CTA.
// grid (32 chunks of 128 tokens, 16 b).
// smem: Q planes 66048 + 2 group buffers (each hi 33024 | lo 33024) = 198144.
// ---------------------------------------------------------------------------
#define FP_SMEM 198144
__global__ __launch_bounds__(256) void fused_pass_kernel(float* __restrict__ attn_out,
                                                         int wlast) {
    extern __shared__ char sm[];
    __shared__ float Lg[8][16][17];
    __shared__ float Att32[16][17];                 // [token][slot]
    __shared__ __nv_bfloat16 ATh[16][24], ATl[16][24];  // [slot][token]
    __shared__ float cbs[16], rs[16];
    const int tid = threadIdx.x;
    const int lane = tid & 31, wid = tid >> 5;
    const int sc = blockIdx.x, b = blockIdx.y;

    const uint32_t smb = smem_u32(sm);
    const uint32_t Qh = smb, Ql = smb + 33024u;
    const uint32_t TB = smb + 66048u;               // 2 buffers x 66048

    if (tid < 16) { cbs[tid] = g_scratch[OFF_CB + b * 16 + tid]; rs[tid] = 0.f; }

    const size_t tokbase = ((size_t)b * 4096 + (size_t)sc * 128) * 1024;

    auto load_group = [&](int buf, int g) {
        const uint32_t Bs = TB + (uint32_t)buf * 66048u;
        #pragma unroll
        for (int i = 0; i < 8; i++) {
            int idx = tid + 256 * i;
            int row = idx >> 7, j = idx & 127;
            cp16s(Bs + (uint32_t)(row * 1032 + j * 8) * 2,
                  g_tokh + tokbase + (size_t)(g * 16 + row) * 1024 + j * 8);
            cp16s(Bs + 33024u + (uint32_t)(row * 1032 + j * 8) * 2,
                  g_tokl + tokbase + (size_t)(g * 16 + row) * 1024 + j * 8);
        }
        cpcommit();
    };

    // Q planes + first group
    {
        #pragma unroll
        for (int i = 0; i < 8; i++) {
            int id = tid + 256 * i;
            int row = id >> 7, j = id & 127;
            cp16s(Qh + (uint32_t)(row * 1032 + j * 8) * 2,
                  g_q2h + (size_t)(b * 16 + row) * 1024 + j * 8);
            cp16s(Ql + (uint32_t)(row * 1032 + j * 8) * 2,
                  g_q2l + (size_t)(b * 16 + row) * 1024 + j * 8);
        }
        cpcommit();
        load_group(0, 0);
    }

    // persistent U accumulators: warp wid owns d slice [wid*128, wid*128+128)
    float uacc[16][4];
    #pragma unroll
    for (int nt = 0; nt < 16; nt++)
        #pragma unroll
        for (int e = 0; e < 4; e++) uacc[nt][e] = 0.f;

    const int kw = wid * 128;               // this warp's k-slice for logits
    const int a_r = lane & 15;              // token row
    const int a_c = (lane >> 4) * 8;
    const int b_r = ((lane >> 4) & 1) * 8 + (lane & 7);
    const int b_c = ((lane >> 3) & 1) * 8;
    const uint32_t ATHb = smem_u32(&ATh[0][0]);
    const uint32_t ATLb = smem_u32(&ATl[0][0]);
    const uint32_t at_off = (uint32_t)((lane & 15) * 24 + (lane >> 4) * 8) * 2;

    for (int g = 0; g < 8; g++) {
        cpwait_n(0);
        __syncthreads();
        if (g + 1 < 8) load_group((g + 1) & 1, g + 1);
        const uint32_t Bs = TB + (uint32_t)(g & 1) * 66048u;
        const uint32_t Bh = Bs, Bl = Bs + 33024u;

        // ---- logits: warp k-slice, m16 (tokens) x n16 (slots) ----
        float la[2][4];
        #pragma unroll
        for (int nt = 0; nt < 2; nt++)
            #pragma unroll
            for (int e = 0; e < 4; e++) la[nt][e] = 0.f;
        #pragma unroll
        for (int ks = 0; ks < 8; ks++) {
            const int col = kw + ks * 16;
            uint32_t afh[4], afl[4], bfh[4], bfl[4];
            uint32_t ao = (uint32_t)(a_r * 1032 + col + a_c) * 2;
            ldm4(afh, Bh + ao);
            ldm4(afl, Bl + ao);
            uint32_t bo = (uint32_t)(b_r * 1032 + col + b_c) * 2;
            ldm4(bfh, Qh + bo);
            ldm4(bfl, Ql + bo);
            #pragma unroll
            for (int nt = 0; nt < 2; nt++) {
                mma16816(la[nt], afh, &bfh[nt * 2]);
                mma16816(la[nt], afh, &bfl[nt * 2]);
                mma16816(la[nt], afl, &bfh[nt * 2]);
            }
        }
        #pragma unroll
        for (int nt = 0; nt < 2; nt++)
            #pragma unroll
            for (int e = 0; e < 4; e++) {
                int row = (lane >> 2) + (e >> 1) * 8;
                int col = nt * 8 + (lane & 3) * 2 + (e & 1);
                Lg[wid][row][col] = la[nt][e];
            }
        __syncthreads();

        // reduce over 8 warps (256 threads, one (tok, slot) each)
        {
            int tok = tid >> 4, s = tid & 15;
            float v = cbs[s];
            #pragma unroll
            for (int w = 0; w < 8; w++) v += Lg[w][tok][s];
            Att32[tok][s] = v;
        }
        __syncthreads();

        // softmax per token (threads 0..15)
        if (tid < 16) {
            float a[16];
            float mx = -1e30f;
            #pragma unroll
            for (int k = 0; k < 16; k++) { a[k] = Att32[tid][k]; mx = fmaxf(mx, a[k]); }
            float sum = 0.f;
            #pragma unroll
            for (int k = 0; k < 16; k++) { a[k] = __expf(a[k] - mx); sum += a[k]; }
            float inv = 1.0f / sum;
            #pragma unroll
            for (int k = 0; k < 16; k++) {
                a[k] *= inv;
                Att32[tid][k] = a[k];
                __nv_bfloat16 h, l; bsplit(a[k], h, l);
                ATh[k][tid] = h; ATl[k][tid] = l;
                if (wlast)
                    attn_out[(size_t)(b * 16 + k) * 4096 + (size_t)sc * 128 + g * 16 + tid] = a[k];
            }
        }
        __syncthreads();

        // rowsum partial (threads 16..31, slot = tid-16)
        if (tid >= 16 && tid < 32) {
            int s = tid - 16;
            float t = 0.f;
            #pragma unroll
            for (int tok = 0; tok < 16; tok++) t += Att32[tok][s];
            rs[s] += t;
        }

        // ---- updates: U[slots][d-slice] += attnT @ tok  (same strip) ----
        uint32_t ath[4], atl[4];
        ldm4(ath, ATHb + at_off);
        ldm4(atl, ATLb + at_off);
        #pragma unroll
        for (int nt = 0; nt < 16; nt++) {
            const int d0 = kw + nt * 8;
            uint32_t bh[2], bl[2];
            uint32_t bo = (uint32_t)((lane & 15) * 1032 + d0) * 2;
            ldm2t(bh, Bh + bo);
            ldm2t(bl, Bl + bo);
            mma16816(uacc[nt], ath, bh);
            mma16816(uacc[nt], ath, bl);
            mma16816(uacc[nt], atl, bh);
        }
    }

    __syncthreads();
    if (tid < 16)
        g_scratch[OFF_RP + (size_t)(b * 16 + tid) * 32 + sc] = rs[tid];

    // one atomic accumulation per CTA
    float* Ub = g_scratch + OFF_U + (size_t)(b * 16) * 1024;
    const int slot0 = lane >> 2;
    #pragma unroll
    for (int nt = 0; nt < 16; nt++) {
        const int d0 = kw + nt * 8 + (lane & 3) * 2;
        atomicAdd(&Ub[(size_t)slot0 * 1024 + d0],           uacc[nt][0]);
        atomicAdd(&Ub[(size_t)slot0 * 1024 + d0 + 1],       uacc[nt][1]);
        atomicAdd(&Ub[(size_t)(slot0 + 8) * 1024 + d0],     uacc[nt][2]);
        atomicAdd(&Ub[(size_t)(slot0 + 8) * 1024 + d0 + 1], uacc[nt][3]);
    }
}

// ---------------------------------------------------------------------------
// LayerNorm (slots) -> actA planes; docb=1: also cb + zero-U
// ---------------------------------------------------------------------------
__global__ __launch_bounds__(256) void ln_kernel(unsigned offX,
                                                 const float* __restrict__ g,
                                                 const float* __restrict__ bt,
                                                 int docb) {
    __shared__ float red[256];
    const float* X = g_scratch + offX;
    int row = blockIdx.x, tid = threadIdx.x;
    float4 x = ((const float4*)X)[row * 256 + tid];
    red[tid] = x.x + x.y + x.z + x.w;
    __syncthreads();
    for (int o = 128; o > 0; o >>= 1) { if (tid < o) red[tid] += red[tid + o]; __syncthreads(); }
    float mean = red[0] * (1.0f / 1024.0f);
    __syncthreads();
    float4 dx = { x.x - mean, x.y - mean, x.z - mean, x.w - mean };
    red[tid] = dx.x*dx.x + dx.y*dx.y + dx.z*dx.z + dx.w*dx.w;
    __syncthreads();
    for (int o = 128; o > 0; o >>= 1) { if (tid < o) red[tid] += red[tid + o]; __syncthreads(); }
    float rs = rsqrtf(red[0] * (1.0f / 1024.0f) + EPS_LN);
    float4 gg = ((const float4*)g)[tid], bb = ((const float4*)bt)[tid];
    float y[4] = { dx.x*rs*gg.x + bb.x, dx.y*rs*gg.y + bb.y,
                   dx.z*rs*gg.z + bb.z, dx.w*rs*gg.w + bb.w };
    size_t base = (size_t)row * 1024u + tid * 4;
    #pragma unroll
    for (int j = 0; j < 4; j++) {
        __nv_bfloat16 h, l; bsplit(y[j], h, l);
        g_actAh[base + j] = h; g_actAl[base + j] = l;
    }
    if (docb) {
        *(float4*)&g_scratch[OFF_U + base] = make_float4(0.f, 0.f, 0.f, 0.f);
        float p = 0.f;
        #pragma unroll
        for (int j = 0; j < 4; j++) p += y[j] * g_scratch[OFF_WCB + tid * 4 + j];
        __syncthreads();
        red[tid] = p; __syncthreads();
        for (int o = 128; o > 0; o >>= 1) { if (tid < o) red[tid] += red[tid + o]; __syncthreads(); }
        if (tid == 0)
            g_scratch[OFF_CB + row] = SCALEF * (red[0] + g_scratch[OFF_C0]);
    }
}

// ---------------------------------------------------------------------------
// reduceU (+rowsum): Un[row] = U[row]/rowsum -> actA planes; BS=brow
// ---------------------------------------------------------------------------
__global__ __launch_bounds__(256) void reduceU_kernel() {
    float* S = g_scratch;
    int row = blockIdx.x, tid = threadIdx.x;
    float s = 0.f;
    #pragma unroll
    for (int cc = 0; cc < 32; cc++) s += S[OFF_RP + (size_t)row * 32 + cc];
    float ri = 1.0f / (s + EPS_ATTN);
    if (tid == 0) S[OFF_BS + row] = s * ri;
    size_t base = (size_t)row * 1024u + tid * 4;
    float4 v = *(const float4*)&S[OFF_U + base];
    float y[4] = { v.x * ri, v.y * ri, v.z * ri, v.w * ri };
    #pragma unroll
    for (int j = 0; j < 4; j++) {
        __nv_bfloat16 h, l; bsplit(y[j], h, l);
        g_actAh[base + j] = h; g_actAl[base + j] = l;
    }
}

// ---------------------------------------------------------------------------
// Fused GRU combine + LayerNorm(mlp) -> slots, actA planes.  block = row.
// ---------------------------------------------------------------------------
__global__ __launch_bounds__(256) void gru_ln_kernel(const float* __restrict__ gm,
                                                     const float* __restrict__ bm) {
    __shared__ float red[256];
    float* S = g_scratch;
    int row = blockIdx.x, tid = threadIdx.x;
    size_t gb = (size_t)row * 3072 + tid * 4;
    float4 ir = *(const float4*)&S[OFF_GI + gb];
    float4 iz = *(const float4*)&S[OFF_GI + gb + 1024];
    float4 in_ = *(const float4*)&S[OFF_GI + gb + 2048];
    float4 hr = *(const float4*)&S[OFF_GH + gb];
    float4 hz = *(const float4*)&S[OFF_GH + gb + 1024];
    float4 hn = *(const float4*)&S[OFF_GH + gb + 2048];
    float4 sp = *(const float4*)&S[OFF_SLOTS + (size_t)row * 1024 + tid * 4];
    float ns[4];
    {
        float r0 = sigmf(ir.x + hr.x), z0 = sigmf(iz.x + hz.x);
        ns[0] = (1.f - z0) * tanhf(in_.x + r0 * hn.x) + z0 * sp.x;
        float r1 = sigmf(ir.y + hr.y), z1 = sigmf(iz.y + hz.y);
        ns[1] = (1.f - z1) * tanhf(in_.y + r1 * hn.y) + z1 * sp.y;
        float r2 = sigmf(ir.z + hr.z), z2 = sigmf(iz.z + hz.z);
        ns[2] = (1.f - z2) * tanhf(in_.z + r2 * hn.z) + z2 * sp.z;
        float r3 = sigmf(ir.w + hr.w), z3 = sigmf(iz.w + hz.w);
        ns[3] = (1.f - z3) * tanhf(in_.w + r3 * hn.w) + z3 * sp.w;
    }
    *(float4*)&S[OFF_SLOTS + (size_t)row * 1024 + tid * 4] =
        make_float4(ns[0], ns[1], ns[2], ns[3]);
    red[tid] = ns[0] + ns[1] + ns[2] + ns[3];
    __syncthreads();
    for (int o = 128; o > 0; o >>= 1) { if (tid < o) red[tid] += red[tid + o]; __syncthreads(); }
    float mean = red[0] * (1.0f / 1024.0f);
    __syncthreads();
    float dx[4] = { ns[0]-mean, ns[1]-mean, ns[2]-mean, ns[3]-mean };
    red[tid] = dx[0]*dx[0] + dx[1]*dx[1] + dx[2]*dx[2] + dx[3]*dx[3];
    __syncthreads();
    for (int o = 128; o > 0; o >>= 1) { if (tid < o) red[tid] += red[tid + o]; __syncthreads(); }
    float rs = rsqrtf(red[0] * (1.0f / 1024.0f) + EPS_LN);
    float4 gg = ((const float4*)gm)[tid], bb = ((const float4*)bm)[tid];
    float y[4] = { dx[0]*rs*gg.x + bb.x, dx[1]*rs*gg.y + bb.y,
                   dx[2]*rs*gg.z + bb.z, dx[3]*rs*gg.w + bb.w };
    size_t base = (size_t)row * 1024u + tid * 4;
    #pragma unroll
    for (int j = 0; j < 4; j++) {
        __nv_bfloat16 h, l; bsplit(y[j], h, l);
        g_actAh[base + j] = h; g_actAl[base + j] = l;
    }
}

// ---------------------------------------------------------------------------
// copy slots -> out
// ---------------------------------------------------------------------------
__global__ __launch_bounds__(256) void copy_out_kernel(float* __restrict__ out, int n) {
    int idx = blockIdx.x * 256 + threadIdx.x;
    if (idx < n) out[idx] = g_scratch[OFF_SLOTS + idx];
}

// ---------------------------------------------------------------------------
// host
// ---------------------------------------------------------------------------
#define SMEM128 (4 * (2*128 + 2*64) * SAP * 2)   /* 122880 */
#define SMEM64  (4 * (2*64 + 2*64) * SAP * 2)    /* 81920 */

extern "C" void kernel_launch(void* const* d_in, const int* in_sizes, int n_in,
                              void* d_out, int out_size) {
    const float* tokens = (const float*)d_in[0];
    const float* mu     = (const float*)d_in[1];
    const float* Wq  = (const float*)d_in[2];  const float* bq  = (const float*)d_in[3];
    const float* Wk  = (const float*)d_in[4];  const float* bk  = (const float*)d_in[5];
    const float* Wv  = (const float*)d_in[6];  const float* bv  = (const float*)d_in[7];
    const float* Wih = (const float*)d_in[8];  const float* bih = (const float*)d_in[9];
    const float* Whh = (const float*)d_in[10]; const float* bhh = (const float*)d_in[11];
    const float* W1  = (const float*)d_in[12]; const float* b1  = (const float*)d_in[13];
    const float* W2  = (const float*)d_in[14]; const float* b2  = (const float*)d_in[15];
    const float* gs  = (const float*)d_in[16]; const float* bs  = (const float*)d_in[17];
    const float* gm  = (const float*)d_in[18]; const float* bm  = (const float*)d_in[19];
    float* out = (float*)d_out;

    cudaFuncSetAttribute((const void*)gemm2_k<128>, cudaFuncAttributeMaxDynamicSharedMemorySize, SMEM128);
    cudaFuncSetAttribute((const void*)gemm2_k<64>,  cudaFuncAttributeMaxDynamicSharedMemorySize, SMEM64);
    cudaFuncSetAttribute((const void*)gru_gemm_k,   cudaFuncAttributeMaxDynamicSharedMemorySize, SMEM128);
    cudaFuncSetAttribute((const void*)fused_pass_kernel, cudaFuncAttributeMaxDynamicSharedMemorySize, FP_SMEM);

    __nv_bfloat16 *wMw, *wVih, *wHh, *w1, *w2, *wWqT, *wWkT, *wWvT, *wWihA;
    __nv_bfloat16 *actAh, *actAl, *actBh, *actBl, *q2h, *q2l;
    cudaGetSymbolAddress((void**)&wMw,   g_wMw);
    cudaGetSymbolAddress((void**)&wVih,  g_wVih);
    cudaGetSymbolAddress((void**)&wHh,   g_wHh);
    cudaGetSymbolAddress((void**)&w1,    g_w1);
    cudaGetSymbolAddress((void**)&w2,    g_w2);
    cudaGetSymbolAddress((void**)&wWqT,  g_wWqT);
    cudaGetSymbolAddress((void**)&wWkT,  g_wWkT);
    cudaGetSymbolAddress((void**)&wWvT,  g_wWvT);
    cudaGetSymbolAddress((void**)&wWihA, g_wWihA);
    cudaGetSymbolAddress((void**)&actAh, g_actAh);
    cudaGetSymbolAddress((void**)&actAl, g_actAl);
    cudaGetSymbolAddress((void**)&actBh, g_actBh);
    cudaGetSymbolAddress((void**)&actBl, g_actBl);
    cudaGetSymbolAddress((void**)&q2h, g_q2h);
    cudaGetSymbolAddress((void**)&q2l, g_q2l);
    __nv_bfloat16 *actSh, *actSl;
    cudaGetSymbolAddress((void**)&actSh, g_actSh);
    cudaGetSymbolAddress((void**)&actSl, g_actSl);
    float* scr;
    cudaGetSymbolAddress((void**)&scr, g_scratch);

    float* attnp = (out_size >= 1310720) ? (out + 262144) : (scr + OFF_ATTN);

    const size_t P1M = 1024u * 1024u;
    const size_t P3M = 3072u * 1024u;
    const size_t P4M = 4096u * 1024u;

    // ---- one-time ----
    transpose_kernel<<<dim3(32, 32), dim3(32, 8)>>>(Wk, OFF_WKT);
    transpose_kernel<<<dim3(32, 32), dim3(32, 8)>>>(Wq, OFF_WQT);
    transpose_kernel<<<dim3(32, 32), dim3(32, 8)>>>(Wv, OFF_WVT);
    tcnv_kernel<<<65536, 256>>>(tokens);
    convw2_kernel<<<1024, 256>>>(nullptr, OFF_WQT, wWqT, wWqT + P1M);
    convw2_kernel<<<1024, 256>>>(nullptr, OFF_WKT, wWkT, wWkT + P1M);
    convw2_kernel<<<1024, 256>>>(nullptr, OFF_WVT, wWvT, wWvT + P1M);
    convw2_kernel<<<3072, 256>>>(Wih, 0, wWihA, wWihA + P3M);
    gemv_kernel<<<1024, 256>>>(nullptr, OFF_WQT, bk, OFF_WCB, 1024, 1.0f);
    gemv_kernel<<<1024, 256>>>(nullptr, OFF_WKT, bq, OFF_V2, 1024, SCALEF);
    gemv_kernel<<<3072, 256>>>(Wih, 0, bv, OFF_BVW, 1024, 1.0f);
    gemv_kernel<<<1, 256>>>(bq, 0, bk, OFF_C0, 1024, 1.0f);
    gemm2_k<128><<<dim3(16, 8), 256, SMEM128>>>(wWkT, wWkT + P1M, wWqT, wWqT + P1M,
                                                nullptr, nullptr, scr + OFF_MFP,
                                                nullptr, nullptr, 1024, 1024, 4);
    gemm2_k<128><<<dim3(16, 24), 256, SMEM128>>>(wWihA, wWihA + P3M, wWvT, wWvT + P1M,
                                                 nullptr, nullptr, scr + OFF_WVIH,
                                                 nullptr, nullptr, 1024, 1024, 6);
    convw2_kernel<<<1024, 256>>>(nullptr, OFF_MFP,  wMw,  wMw + P1M);
    convw2_kernel<<<3072, 256>>>(nullptr, OFF_WVIH, wVih, wVih + P3M);
    convw2_kernel<<<3072, 256>>>(Whh, 0, wHh, wHh + P3M);
    convw2_kernel<<<4096, 256>>>(W1,  0, w1,  w1 + P4M);
    convw2_kernel<<<4096, 256>>>(W2,  0, w2,  w2 + P4M);
    init_slots_kernel<<<1024, 256>>>(mu);

    for (int it = 0; it < 3; it++) {
        ln_kernel<<<256, 256>>>(OFF_SLOTS, gs, bs, 1);
        gemm2_k<64><<<dim3(16, 4), 256, SMEM64>>>(actAh, actAl, wMw, wMw + P1M,
                                                  scr + OFF_V2, nullptr, nullptr,
                                                  q2h, q2l, 1024, 1024, 0);
        fused_pass_kernel<<<dim3(32, 16), 256, FP_SMEM>>>(attnp, it == 2 ? 1 : 0);
        reduceU_kernel<<<256, 256>>>();
        gru_gemm_k<<<dim3(48, 2, 2), 256, SMEM128>>>(bih, bhh);
        gru_ln_kernel<<<256, 256>>>(gm, bm);
        gemm2_k<128><<<dim3(64, 2), 256, SMEM128>>>(actAh, actAl, w1, w1 + P4M,
                                                    b1, nullptr, nullptr,
                                                    actBh, actBl, 4096, 1024, 2);
        gemm2_k<64><<<dim3(16, 4), 256, SMEM64>>>(actBh, actBl, w2, w2 + P4M,
                                                  b2, nullptr, scr + OFF_SLOTS,
                                                  actSh, actSl, 1024, 4096, 3);
    }

    int nslots = out_size < 262144 ? out_size : 262144;
    copy_out_kernel<<<1024, 256>>>(out, nslots);
}

// round 13
// speedup vs baseline: 2.7331x; 1.0486x over previous
#include <cuda_runtime.h>
#include <cuda_bf16.h>
#include <cstdint>
#include <cstddef>

// ---------------------------------------------------------------------------
// Problem sizes: B=16, S=4096, D=1024, K=16, ITERS=3
// ---------------------------------------------------------------------------
#define SCALEF   0.03125f        /* 1024^-0.5 */
#define EPS_LN   1e-5f
#define EPS_ATTN 1e-8f

// fp32 scratch offsets (floats)
#define OFF_SLOTS 0u
#define OFF_GI    1572864u
#define OFF_GH    2359296u
#define OFF_WQT   4194304u
#define OFF_WVT   5242880u
#define OFF_MFP   6291456u
#define OFF_WVIH  7340032u      /* 3145728 floats */
#define OFF_U     10485760u     /* 262144 floats (atomic accum) */
#define OFF_WCB   10747904u
#define OFF_V2    10748928u
#define OFF_BVW   10749952u
#define OFF_C0    10753024u
#define OFF_WKT   12582912u
#define OFF_CB    13631488u
#define OFF_BS    13631744u
#define OFF_RP    13632256u     /* 256 rows * 32 chunks */
#define OFF_ATTN  13640448u
#define SCRATCH_N 14689024u

__device__ float g_scratch[SCRATCH_N];

// bf16 2-plane weight buffers: [hi plane | lo plane], each N*K
__device__ __nv_bfloat16 g_wMw  [2u * 1024u * 1024u];
__device__ __nv_bfloat16 g_wVih [2u * 3072u * 1024u];
__device__ __nv_bfloat16 g_wHh  [2u * 3072u * 1024u];
__device__ __nv_bfloat16 g_w1   [2u * 4096u * 1024u];
__device__ __nv_bfloat16 g_w2   [2u * 1024u * 4096u];
// one-time composition operands
__device__ __nv_bfloat16 g_wWqT [2u * 1024u * 1024u];
__device__ __nv_bfloat16 g_wWkT [2u * 1024u * 1024u];
__device__ __nv_bfloat16 g_wWvT [2u * 1024u * 1024u];
__device__ __nv_bfloat16 g_wWihA[2u * 3072u * 1024u];
// activation plane pairs
__device__ __nv_bfloat16 g_actAh[256u * 1024u], g_actAl[256u * 1024u];
__device__ __nv_bfloat16 g_actSh[256u * 1024u], g_actSl[256u * 1024u];
__device__ __nv_bfloat16 g_actBh[256u * 4096u], g_actBl[256u * 4096u];
// token planes [b][s][d]
__device__ __nv_bfloat16 g_tokh [16u * 4096u * 1024u];
__device__ __nv_bfloat16 g_tokl [16u * 4096u * 1024u];
// q2 planes [256][1024]
__device__ __nv_bfloat16 g_q2h[256u * 1024u];
__device__ __nv_bfloat16 g_q2l[256u * 1024u];

__device__ __forceinline__ float geluf(float x) {
    return 0.5f * x * (1.0f + erff(x * 0.70710678118654752f));
}
__device__ __forceinline__ float sigmf(float x) {
    return 1.0f / (1.0f + __expf(-x));
}

__device__ __forceinline__ uint32_t smem_u32(const void* p) {
    uint32_t a;
    asm("{ .reg .u64 t; cvta.to.shared.u64 t, %1; cvt.u32.u64 %0, t; }" : "=r"(a) : "l"(p));
    return a;
}
__device__ __forceinline__ void cp16s(uint32_t daddr, const void* src) {
    asm volatile("cp.async.cg.shared.global [%0], [%1], 16;" :: "r"(daddr), "l"(src));
}
__device__ __forceinline__ void cpcommit() {
    asm volatile("cp.async.commit_group;" ::: "memory");
}
__device__ __forceinline__ void cpwait_n(int n) {
    if (n <= 0)      asm volatile("cp.async.wait_group 0;" ::: "memory");
    else if (n == 1) asm volatile("cp.async.wait_group 1;" ::: "memory");
    else             asm volatile("cp.async.wait_group 2;" ::: "memory");
}
__device__ __forceinline__ void ldm4(uint32_t* r, uint32_t addr) {
    asm volatile("ldmatrix.sync.aligned.m8n8.x4.shared.b16 {%0,%1,%2,%3}, [%4];"
        : "=r"(r[0]), "=r"(r[1]), "=r"(r[2]), "=r"(r[3]) : "r"(addr));
}
__device__ __forceinline__ void ldm2(uint32_t* r, uint32_t addr) {
    asm volatile("ldmatrix.sync.aligned.m8n8.x2.shared.b16 {%0,%1}, [%2];"
        : "=r"(r[0]), "=r"(r[1]) : "r"(addr));
}
__device__ __forceinline__ void ldm2t(uint32_t* r, uint32_t addr) {
    asm volatile("ldmatrix.sync.aligned.m8n8.x2.trans.shared.b16 {%0,%1}, [%2];"
        : "=r"(r[0]), "=r"(r[1]) : "r"(addr));
}
__device__ __forceinline__ void mma16816(float* c, const uint32_t* a, const uint32_t* b) {
    asm volatile(
        "mma.sync.aligned.m16n8k16.row.col.f32.bf16.bf16.f32 "
        "{%0,%1,%2,%3}, {%4,%5,%6,%7}, {%8,%9}, {%0,%1,%2,%3};"
        : "+f"(c[0]), "+f"(c[1]), "+f"(c[2]), "+f"(c[3])
        : "r"(a[0]), "r"(a[1]), "r"(a[2]), "r"(a[3]), "r"(b[0]), "r"(b[1]));
}

__device__ __forceinline__ void bsplit(float x, __nv_bfloat16& h, __nv_bfloat16& l) {
    h = __float2bfloat16_rn(x);
    l = __float2bfloat16_rn(x - __bfloat162float(h));
}

// ---------------------------------------------------------------------------
// init: slots = broadcast(slot_mu); emit actS planes (slots feed gh at it0)
// ---------------------------------------------------------------------------
__global__ __launch_bounds__(256) void init_slots_kernel(const float* __restrict__ mu) {
    unsigned idx = blockIdx.x * 256u + threadIdx.x;          // < 262144
    float x = mu[idx & 16383u];
    g_scratch[OFF_SLOTS + idx] = x;
    __nv_bfloat16 h, l; bsplit(x, h, l);
    g_actSh[idx] = h; g_actSl[idx] = l;
}

// ---------------------------------------------------------------------------
// transpose 1024x1024 fp32: in -> g_scratch[dstOff]
// ---------------------------------------------------------------------------
__global__ void transpose_kernel(const float* __restrict__ in, unsigned dstOff) {
    __shared__ float t[32][33];
    int x  = blockIdx.x * 32 + threadIdx.x;
    int y0 = blockIdx.y * 32;
    #pragma unroll
    for (int j = threadIdx.y; j < 32; j += 8)
        t[j][threadIdx.x] = in[(size_t)(y0 + j) * 1024 + x];
    __syncthreads();
    int xo  = blockIdx.y * 32 + threadIdx.x;
    int yo0 = blockIdx.x * 32;
    #pragma unroll
    for (int j = threadIdx.y; j < 32; j += 8)
        g_scratch[dstOff + (size_t)(yo0 + j) * 1024 + xo] = t[threadIdx.x][j];
}

// ---------------------------------------------------------------------------
// tokens -> bf16 hi/lo planes
// ---------------------------------------------------------------------------
__global__ __launch_bounds__(256) void tcnv_kernel(const float* __restrict__ tokens) {
    size_t idx4 = (size_t)blockIdx.x * 256u + threadIdx.x;
    float4 x = ((const float4*)tokens)[idx4];
    __nv_bfloat16 h0,h1,h2,h3,l0,l1,l2,l3;
    bsplit(x.x,h0,l0); bsplit(x.y,h1,l1); bsplit(x.z,h2,l2); bsplit(x.w,h3,l3);
    size_t k = idx4 * 4;
    *(__nv_bfloat162*)(g_tokh + k)     = __nv_bfloat162(h0, h1);
    *(__nv_bfloat162*)(g_tokh + k + 2) = __nv_bfloat162(h2, h3);
    *(__nv_bfloat162*)(g_tokl + k)     = __nv_bfloat162(l0, l1);
    *(__nv_bfloat162*)(g_tokl + k + 2) = __nv_bfloat162(l2, l3);
}

// ---------------------------------------------------------------------------
// split-convert to 2 planes: src (flat fp32) -> dh, dl
// ---------------------------------------------------------------------------
__global__ __launch_bounds__(256) void convw2_kernel(const float* __restrict__ src,
                                                     unsigned srcOff,
                                                     __nv_bfloat16* __restrict__ dh,
                                                     __nv_bfloat16* __restrict__ dl) {
    size_t idx4 = (size_t)blockIdx.x * 256u + threadIdx.x;
    const float* S = src ? src : (g_scratch + srcOff);
    float4 x = *(const float4*)(S + idx4 * 4);
    __nv_bfloat16 h0,h1,h2,h3,l0,l1,l2,l3;
    bsplit(x.x,h0,l0); bsplit(x.y,h1,l1); bsplit(x.z,h2,l2); bsplit(x.w,h3,l3);
    size_t k = idx4 * 4;
    *(__nv_bfloat162*)(dh + k)     = __nv_bfloat162(h0, h1);
    *(__nv_bfloat162*)(dh + k + 2) = __nv_bfloat162(h2, h3);
    *(__nv_bfloat162*)(dl + k)     = __nv_bfloat162(l0, l1);
    *(__nv_bfloat162*)(dl + k + 2) = __nv_bfloat162(l2, l3);
}

// ---------------------------------------------------------------------------
// gemv: out[row] = scale * dot(M[row, 0:len], v)
// ---------------------------------------------------------------------------
__global__ __launch_bounds__(256) void gemv_kernel(const float* __restrict__ M,
                                                   unsigned moff,
                                                   const float* __restrict__ v,
                                                   unsigned outoff, int len, float scale) {
    __shared__ float red[256];
    const float* Mr = (M ? M : g_scratch + moff) + (size_t)blockIdx.x * len;
    int tid = threadIdx.x;
    float p = 0.f;
    for (int i = tid * 4; i < len; i += 1024) {
        float4 a = *(const float4*)(Mr + i);
        float4 b = *(const float4*)(v + i);
        p += a.x*b.x + a.y*b.y + a.z*b.z + a.w*b.w;
    }
    red[tid] = p; __syncthreads();
    for (int o = 128; o > 0; o >>= 1) { if (tid < o) red[tid] += red[tid + o]; __syncthreads(); }
    if (tid == 0) g_scratch[outoff + blockIdx.x] = scale * red[0];
}

// ---------------------------------------------------------------------------
// 2-plane HMMA GEMM: C = (Ah+Al) (.) (Wh+Wl)^T  via Ah*Wh + Ah*Wl + Al*Wh.
// BM in {128, 64, 32}.  BN=64.  256 threads, 4-stage cp.async.
// ---------------------------------------------------------------------------
#define SAP 40

template<int BM>
__device__ __forceinline__ void gemm2_core(char* sm,
    const __nv_bfloat16* __restrict__ Ah, const __nv_bfloat16* __restrict__ Al,
    const __nv_bfloat16* __restrict__ Wh, const __nv_bfloat16* __restrict__ Wl,
    const float* __restrict__ bias, const float* __restrict__ bias2,
    float* Cout, __nv_bfloat16* ph, __nv_bfloat16* pl,
    int N, int K, int epi)
{
    constexpr int NW_M = BM / 32;          // warps along M
    constexpr int WTN  = BM / 4;           // warp tile N: 128->32, 64->16, 32->8
    constexpr int NT   = WTN / 8;
    constexpr uint32_t AP  = BM * SAP * 2;
    constexpr uint32_t WP  = 64 * SAP * 2;
    constexpr uint32_t STG = 2 * AP + 2 * WP;

    const int tid  = threadIdx.x;
    const int lane = tid & 31, wid = tid >> 5;
    const int wm = (wid % NW_M) * 32;
    const int wn = (wid / NW_M) * WTN;
    const int bn = blockIdx.x * 64, bm = blockIdx.y * BM;
    const int NC = K >> 5;

    const uint32_t smb = smem_u32(sm);

    const int lrow = tid >> 2, lch = (tid & 3) * 8;
    const uint32_t aoff  = (uint32_t)(lrow * SAP + lch) * 2;
    const uint32_t aoff1 = (uint32_t)((64 + lrow) * SAP + lch) * 2;
    const __nv_bfloat16* agh0 = Ah + (size_t)(bm + (lrow < BM ? lrow : 0)) * K + lch;
    const __nv_bfloat16* agl0 = Al + (size_t)(bm + (lrow < BM ? lrow : 0)) * K + lch;
    const __nv_bfloat16* agh1 = Ah + (size_t)(bm + 64 + lrow) * K + lch;
    const __nv_bfloat16* agl1 = Al + (size_t)(bm + 64 + lrow) * K + lch;
    const __nv_bfloat16* wgh  = Wh + (size_t)(bn + lrow) * K + lch;
    const __nv_bfloat16* wgl  = Wl + (size_t)(bn + lrow) * K + lch;

    const int a_row = wm + (lane & 15);
    const int a_col = (lane >> 4) * 8;
    // NT>=2 path (16 n-rows per ldm4)
    const int b_row = wn + ((lane >> 4) & 1) * 8 + (lane & 7);
    const int b_col = ((lane >> 3) & 1) * 8;
    // NT==1 path (8 n-rows, ldm2): lanes 0-7 -> k-half 0, lanes 8-15 -> k-half 1
    const int l2 = lane & 15;
    const int b_row1 = wn + (l2 & 7);
    const int b_col1 = ((l2 >> 3) & 1) * 8;

    float acc[2][NT][4];
    #pragma unroll
    for (int i = 0; i < 2; i++)
        #pragma unroll
        for (int j = 0; j < NT; j++)
            #pragma unroll
            for (int e = 0; e < 4; e++) acc[i][j][e] = 0.f;

    auto load_stage = [&](int st, int c) {
        const uint32_t S = smb + (uint32_t)st * STG;
        const int ko = c * 32;
        if (BM >= 64 || lrow < BM) {
            cp16s(S + aoff, agh0 + ko);
            cp16s(S + AP + aoff, agl0 + ko);
        }
        if (BM == 128) {
            cp16s(S + aoff1, agh1 + ko);
            cp16s(S + AP + aoff1, agl1 + ko);
        }
        cp16s(S + 2 * AP + aoff, wgh + ko);
        cp16s(S + 2 * AP + WP + aoff, wgl + ko);
        cpcommit();
    };

    load_stage(0, 0);
    load_stage(1, 1);
    load_stage(2, 2);

    for (int c = 0; c < NC; c++) {
        int bnd = NC - 1 - c; if (bnd > 2) bnd = 2;
        cpwait_n(bnd);
        __syncthreads();
        if (c + 3 < NC) load_stage((c + 3) & 3, c + 3);
        const uint32_t S = smb + (uint32_t)(c & 3) * STG;
        const uint32_t abh = S, abl = S + AP;
        const uint32_t wbh = S + 2 * AP, wbl = S + 2 * AP + WP;
        #pragma unroll
        for (int ks = 0; ks < 2; ks++) {
            uint32_t afh[2][4], afl[2][4], bfh[2][4], bfl[2][4];
            #pragma unroll
            for (int mt = 0; mt < 2; mt++) {
                uint32_t ao = (uint32_t)(((a_row + mt * 16) * SAP) + ks * 16 + a_col) * 2;
                ldm4(afh[mt], abh + ao);
                ldm4(afl[mt], abl + ao);
            }
            if (NT == 1) {
                uint32_t bo = (uint32_t)((b_row1 * SAP) + ks * 16 + b_col1) * 2;
                ldm2(bfh[0], wbh + bo);
                ldm2(bfl[0], wbl + bo);
            } else {
                #pragma unroll
                for (int nb = 0; nb < NT / 2; nb++) {
                    uint32_t bo = (uint32_t)(((b_row + nb * 16) * SAP) + ks * 16 + b_col) * 2;
                    ldm4(bfh[nb], wbh + bo);
                    ldm4(bfl[nb], wbl + bo);
                }
            }
            #pragma unroll
            for (int mt = 0; mt < 2; mt++)
                #pragma unroll
                for (int nt = 0; nt < NT; nt++) {
                    const uint32_t* bh = &bfh[nt >> 1][(nt & 1) * 2];
                    const uint32_t* bl = &bfl[nt >> 1][(nt & 1) * 2];
                    mma16816(acc[mt][nt], afh[mt], bh);
                    mma16816(acc[mt][nt], afh[mt], bl);
                    mma16816(acc[mt][nt], afl[mt], bh);
                }
        }
    }

    const int mrow = lane >> 2, ncol2 = (lane & 3) * 2;
    #pragma unroll
    for (int mt = 0; mt < 2; mt++) {
        #pragma unroll
        for (int h = 0; h < 2; h++) {
            const int m = bm + wm + mt * 16 + mrow + h * 8;
            float brow = 0.f;
            if (epi == 7) brow = g_scratch[OFF_BS + m];
            #pragma unroll
            for (int nt = 0; nt < NT; nt++) {
                const int n0 = bn + wn + nt * 8 + ncol2;
                float ox = acc[mt][nt][h * 2], oy = acc[mt][nt][h * 2 + 1];
                if (epi == 4) { ox *= SCALEF; oy *= SCALEF; }
                else if (epi == 6) { }
                else {
                    float2 bb = *(const float2*)(bias + n0);
                    if (epi == 7) {
                        float2 b2 = *(const float2*)(bias2 + n0);
                        ox += bb.x + brow * b2.x; oy += bb.y + brow * b2.y;
                    } else { ox += bb.x; oy += bb.y; }
                    if (epi == 2) { ox = geluf(ox); oy = geluf(oy); }
                    if (epi == 3) {
                        float2 c0 = *(const float2*)(Cout + (size_t)m * N + n0);
                        ox += c0.x; oy += c0.y;
                    }
                }
                if (Cout) *(float2*)(Cout + (size_t)m * N + n0) = make_float2(ox, oy);
                if (ph) {
                    __nv_bfloat16 hx, lx, hy, ly;
                    bsplit(ox, hx, lx); bsplit(oy, hy, ly);
                    *(__nv_bfloat162*)(ph + (size_t)m * N + n0) = __nv_bfloat162(hx, hy);
                    *(__nv_bfloat162*)(pl + (size_t)m * N + n0) = __nv_bfloat162(lx, ly);
                }
            }
        }
    }
}

template<int BM>
__global__ __launch_bounds__(256) void gemm2_k(const __nv_bfloat16* __restrict__ Ah,
                                               const __nv_bfloat16* __restrict__ Al,
                                               const __nv_bfloat16* __restrict__ Wh,
                                               const __nv_bfloat16* __restrict__ Wl,
                                               const float* __restrict__ bias,
                                               const float* __restrict__ bias2,
                                               float* Cout, __nv_bfloat16* ph, __nv_bfloat16* pl,
                                               int N, int K, int epi) {
    extern __shared__ char sm[];
    gemm2_core<BM>(sm, Ah, Al, Wh, Wl, bias, bias2, Cout, ph, pl, N, K, epi);
}

// merged GRU gemms
__global__ __launch_bounds__(256) void gru_gemm_k(const float* __restrict__ bih,
                                                  const float* __restrict__ bhh) {
    extern __shared__ char sm[];
    if (blockIdx.z == 0)
        gemm2_core<128>(sm, g_actAh, g_actAl, g_wVih, g_wVih + 3072u*1024u,
                        bih, g_scratch + OFF_BVW, g_scratch + OFF_GI,
                        nullptr, nullptr, 3072, 1024, 7);
    else
        gemm2_core<128>(sm, g_actSh, g_actSl, g_wHh, g_wHh + 3072u*1024u,
                        bhh, nullptr, g_scratch + OFF_GH,
                        nullptr, nullptr, 3072, 1024, 0);
}

// ---------------------------------------------------------------------------
// Single-read fused pass (256 threads): per 16-token group -- load tok strip
// once, logits (k split over 8 warps) + softmax + updates vs the SAME strip.
// U accumulated in registers across groups; one atomicAdd set per CTA.
// grid (32 chunks of 128 tokens, 16 b).
// ---------------------------------------------------------------------------
#define FP_SMEM 198144
__global__ __launch_bounds__(256) void fused_pass_kernel(float* __restrict__ attn_out,
                                                         int wlast) {
    extern __shared__ char sm[];
    __shared__ float Lg[8][16][17];
    __shared__ float Att32[16][17];                 // [token][slot]
    __shared__ __nv_bfloat16 ATh[16][24], ATl[16][24];  // [slot][token]
    __shared__ float cbs[16], rs[16];
    const int tid = threadIdx.x;
    const int lane = tid & 31, wid = tid >> 5;
    const int sc = blockIdx.x, b = blockIdx.y;

    const uint32_t smb = smem_u32(sm);
    const uint32_t Qh = smb, Ql = smb + 33024u;
    const uint32_t TB = smb + 66048u;               // 2 buffers x 66048

    if (tid < 16) { cbs[tid] = g_scratch[OFF_CB + b * 16 + tid]; rs[tid] = 0.f; }

    const size_t tokbase = ((size_t)b * 4096 + (size_t)sc * 128) * 1024;

    auto load_group = [&](int buf, int g) {
        const uint32_t Bs = TB + (uint32_t)buf * 66048u;
        #pragma unroll
        for (int i = 0; i < 8; i++) {
            int idx = tid + 256 * i;
            int row = idx >> 7, j = idx & 127;
            cp16s(Bs + (uint32_t)(row * 1032 + j * 8) * 2,
                  g_tokh + tokbase + (size_t)(g * 16 + row) * 1024 + j * 8);
            cp16s(Bs + 33024u + (uint32_t)(row * 1032 + j * 8) * 2,
                  g_tokl + tokbase + (size_t)(g * 16 + row) * 1024 + j * 8);
        }
        cpcommit();
    };

    // Q planes + first group
    {
        #pragma unroll
        for (int i = 0; i < 8; i++) {
            int id = tid + 256 * i;
            int row = id >> 7, j = id & 127;
            cp16s(Qh + (uint32_t)(row * 1032 + j * 8) * 2,
                  g_q2h + (size_t)(b * 16 + row) * 1024 + j * 8);
            cp16s(Ql + (uint32_t)(row * 1032 + j * 8) * 2,
                  g_q2l + (size_t)(b * 16 + row) * 1024 + j * 8);
        }
        cpcommit();
        load_group(0, 0);
    }

    // persistent U accumulators: warp wid owns d slice [wid*128, wid*128+128)
    float uacc[16][4];
    #pragma unroll
    for (int nt = 0; nt < 16; nt++)
        #pragma unroll
        for (int e = 0; e < 4; e++) uacc[nt][e] = 0.f;

    const int kw = wid * 128;               // this warp's k-slice
    const int a_r = lane & 15;              // token row
    const int a_c = (lane >> 4) * 8;
    const int b_r = ((lane >> 4) & 1) * 8 + (lane & 7);
    const int b_c = ((lane >> 3) & 1) * 8;
    const uint32_t ATHb = smem_u32(&ATh[0][0]);
    const uint32_t ATLb = smem_u32(&ATl[0][0]);
    const uint32_t at_off = (uint32_t)((lane & 15) * 24 + (lane >> 4) * 8) * 2;

    for (int g = 0; g < 8; g++) {
        cpwait_n(0);
        __syncthreads();
        if (g + 1 < 8) load_group((g + 1) & 1, g + 1);
        const uint32_t Bs = TB + (uint32_t)(g & 1) * 66048u;
        const uint32_t Bh = Bs, Bl = Bs + 33024u;

        // ---- logits: warp k-slice, m16 (tokens) x n16 (slots) ----
        float la[2][4];
        #pragma unroll
        for (int nt = 0; nt < 2; nt++)
            #pragma unroll
            for (int e = 0; e < 4; e++) la[nt][e] = 0.f;
        #pragma unroll
        for (int ks = 0; ks < 8; ks++) {
            const int col = kw + ks * 16;
            uint32_t afh[4], afl[4], bfh[4], bfl[4];
            uint32_t ao = (uint32_t)(a_r * 1032 + col + a_c) * 2;
            ldm4(afh, Bh + ao);
            ldm4(afl, Bl + ao);
            uint32_t bo = (uint32_t)(b_r * 1032 + col + b_c) * 2;
            ldm4(bfh, Qh + bo);
            ldm4(bfl, Ql + bo);
            #pragma unroll
            for (int nt = 0; nt < 2; nt++) {
                mma16816(la[nt], afh, &bfh[nt * 2]);
                mma16816(la[nt], afh, &bfl[nt * 2]);
                mma16816(la[nt], afl, &bfh[nt * 2]);
            }
        }
        #pragma unroll
        for (int nt = 0; nt < 2; nt++)
            #pragma unroll
            for (int e = 0; e < 4; e++) {
                int row = (lane >> 2) + (e >> 1) * 8;
                int col = nt * 8 + (lane & 3) * 2 + (e & 1);
                Lg[wid][row][col] = la[nt][e];
            }
        __syncthreads();

        // reduce over 8 warps (256 threads, one (tok, slot) each)
        {
            int tok = tid >> 4, s = tid & 15;
            float v = cbs[s];
            #pragma unroll
            for (int w = 0; w < 8; w++) v += Lg[w][tok][s];
            Att32[tok][s] = v;
        }
        __syncthreads();

        // softmax per token (threads 0..15)
        if (tid < 16) {
            float a[16];
            float mx = -1e30f;
            #pragma unroll
            for (int k = 0; k < 16; k++) { a[k] = Att32[tid][k]; mx = fmaxf(mx, a[k]); }
            float sum = 0.f;
            #pragma unroll
            for (int k = 0; k < 16; k++) { a[k] = __expf(a[k] - mx); sum += a[k]; }
            float inv = 1.0f / sum;
            #pragma unroll
            for (int k = 0; k < 16; k++) {
                a[k] *= inv;
                Att32[tid][k] = a[k];
                __nv_bfloat16 h, l; bsplit(a[k], h, l);
                ATh[k][tid] = h; ATl[k][tid] = l;
                if (wlast)
                    attn_out[(size_t)(b * 16 + k) * 4096 + (size_t)sc * 128 + g * 16 + tid] = a[k];
            }
        }
        __syncthreads();

        // rowsum partial (threads 16..31, slot = tid-16)
        if (tid >= 16 && tid < 32) {
            int s = tid - 16;
            float t = 0.f;
            #pragma unroll
            for (int tok = 0; tok < 16; tok++) t += Att32[tok][s];
            rs[s] += t;
        }

        // ---- updates: U[slots][d-slice] += attnT @ tok  (same strip) ----
        uint32_t ath[4], atl[4];
        ldm4(ath, ATHb + at_off);
        ldm4(atl, ATLb + at_off);
        #pragma unroll
        for (int nt = 0; nt < 16; nt++) {
            const int d0 = kw + nt * 8;
            uint32_t bh[2], bl[2];
            uint32_t bo = (uint32_t)((lane & 15) * 1032 + d0) * 2;
            ldm2t(bh, Bh + bo);
            ldm2t(bl, Bl + bo);
            mma16816(uacc[nt], ath, bh);
            mma16816(uacc[nt], ath, bl);
            mma16816(uacc[nt], atl, bh);
        }
    }

    __syncthreads();
    if (tid < 16)
        g_scratch[OFF_RP + (size_t)(b * 16 + tid) * 32 + sc] = rs[tid];

    // one atomic accumulation per CTA
    float* Ub = g_scratch + OFF_U + (size_t)(b * 16) * 1024;
    const int slot0 = lane >> 2;
    #pragma unroll
    for (int nt = 0; nt < 16; nt++) {
        const int d0 = kw + nt * 8 + (lane & 3) * 2;
        atomicAdd(&Ub[(size_t)slot0 * 1024 + d0],           uacc[nt][0]);
        atomicAdd(&Ub[(size_t)slot0 * 1024 + d0 + 1],       uacc[nt][1]);
        atomicAdd(&Ub[(size_t)(slot0 + 8) * 1024 + d0],     uacc[nt][2]);
        atomicAdd(&Ub[(size_t)(slot0 + 8) * 1024 + d0 + 1], uacc[nt][3]);
    }
}

// ---------------------------------------------------------------------------
// LayerNorm (slots) -> actA planes; docb=1: also cb + zero-U
// ---------------------------------------------------------------------------
__global__ __launch_bounds__(256) void ln_kernel(unsigned offX,
                                                 const float* __restrict__ g,
                                                 const float* __restrict__ bt,
                                                 int docb) {
    __shared__ float red[256];
    const float* X = g_scratch + offX;
    int row = blockIdx.x, tid = threadIdx.x;
    float4 x = ((const float4*)X)[row * 256 + tid];
    red[tid] = x.x + x.y + x.z + x.w;
    __syncthreads();
    for (int o = 128; o > 0; o >>= 1) { if (tid < o) red[tid] += red[tid + o]; __syncthreads(); }
    float mean = red[0] * (1.0f / 1024.0f);
    __syncthreads();
    float4 dx = { x.x - mean, x.y - mean, x.z - mean, x.w - mean };
    red[tid] = dx.x*dx.x + dx.y*dx.y + dx.z*dx.z + dx.w*dx.w;
    __syncthreads();
    for (int o = 128; o > 0; o >>= 1) { if (tid < o) red[tid] += red[tid + o]; __syncthreads(); }
    float rs = rsqrtf(red[0] * (1.0f / 1024.0f) + EPS_LN);
    float4 gg = ((const float4*)g)[tid], bb = ((const float4*)bt)[tid];
    float y[4] = { dx.x*rs*gg.x + bb.x, dx.y*rs*gg.y + bb.y,
                   dx.z*rs*gg.z + bb.z, dx.w*rs*gg.w + bb.w };
    size_t base = (size_t)row * 1024u + tid * 4;
    #pragma unroll
    for (int j = 0; j < 4; j++) {
        __nv_bfloat16 h, l; bsplit(y[j], h, l);
        g_actAh[base + j] = h; g_actAl[base + j] = l;
    }
    if (docb) {
        *(float4*)&g_scratch[OFF_U + base] = make_float4(0.f, 0.f, 0.f, 0.f);
        float p = 0.f;
        #pragma unroll
        for (int j = 0; j < 4; j++) p += y[j] * g_scratch[OFF_WCB + tid * 4 + j];
        __syncthreads();
        red[tid] = p; __syncthreads();
        for (int o = 128; o > 0; o >>= 1) { if (tid < o) red[tid] += red[tid + o]; __syncthreads(); }
        if (tid == 0)
            g_scratch[OFF_CB + row] = SCALEF * (red[0] + g_scratch[OFF_C0]);
    }
}

// ---------------------------------------------------------------------------
// reduceU (+rowsum): Un[row] = U[row]/rowsum -> actA planes; BS=brow
// ---------------------------------------------------------------------------
__global__ __launch_bounds__(256) void reduceU_kernel() {
    float* S = g_scratch;
    int row = blockIdx.x, tid = threadIdx.x;
    float s = 0.f;
    #pragma unroll
    for (int cc = 0; cc < 32; cc++) s += S[OFF_RP + (size_t)row * 32 + cc];
    float ri = 1.0f / (s + EPS_ATTN);
    if (tid == 0) S[OFF_BS + row] = s * ri;
    size_t base = (size_t)row * 1024u + tid * 4;
    float4 v = *(const float4*)&S[OFF_U + base];
    float y[4] = { v.x * ri, v.y * ri, v.z * ri, v.w * ri };
    #pragma unroll
    for (int j = 0; j < 4; j++) {
        __nv_bfloat16 h, l; bsplit(y[j], h, l);
        g_actAh[base + j] = h; g_actAl[base + j] = l;
    }
}

// ---------------------------------------------------------------------------
// Fused GRU combine + LayerNorm(mlp) -> slots, actA planes.  block = row.
// ---------------------------------------------------------------------------
__global__ __launch_bounds__(256) void gru_ln_kernel(const float* __restrict__ gm,
                                                     const float* __restrict__ bm) {
    __shared__ float red[256];
    float* S = g_scratch;
    int row = blockIdx.x, tid = threadIdx.x;
    size_t gb = (size_t)row * 3072 + tid * 4;
    float4 ir = *(const float4*)&S[OFF_GI + gb];
    float4 iz = *(const float4*)&S[OFF_GI + gb + 1024];
    float4 in_ = *(const float4*)&S[OFF_GI + gb + 2048];
    float4 hr = *(const float4*)&S[OFF_GH + gb];
    float4 hz = *(const float4*)&S[OFF_GH + gb + 1024];
    float4 hn = *(const float4*)&S[OFF_GH + gb + 2048];
    float4 sp = *(const float4*)&S[OFF_SLOTS + (size_t)row * 1024 + tid * 4];
    float ns[4];
    {
        float r0 = sigmf(ir.x + hr.x), z0 = sigmf(iz.x + hz.x);
        ns[0] = (1.f - z0) * tanhf(in_.x + r0 * hn.x) + z0 * sp.x;
        float r1 = sigmf(ir.y + hr.y), z1 = sigmf(iz.y + hz.y);
        ns[1] = (1.f - z1) * tanhf(in_.y + r1 * hn.y) + z1 * sp.y;
        float r2 = sigmf(ir.z + hr.z), z2 = sigmf(iz.z + hz.z);
        ns[2] = (1.f - z2) * tanhf(in_.z + r2 * hn.z) + z2 * sp.z;
        float r3 = sigmf(ir.w + hr.w), z3 = sigmf(iz.w + hz.w);
        ns[3] = (1.f - z3) * tanhf(in_.w + r3 * hn.w) + z3 * sp.w;
    }
    *(float4*)&S[OFF_SLOTS + (size_t)row * 1024 + tid * 4] =
        make_float4(ns[0], ns[1], ns[2], ns[3]);
    red[tid] = ns[0] + ns[1] + ns[2] + ns[3];
    __syncthreads();
    for (int o = 128; o > 0; o >>= 1) { if (tid < o) red[tid] += red[tid + o]; __syncthreads(); }
    float mean = red[0] * (1.0f / 1024.0f);
    __syncthreads();
    float dx[4] = { ns[0]-mean, ns[1]-mean, ns[2]-mean, ns[3]-mean };
    red[tid] = dx[0]*dx[0] + dx[1]*dx[1] + dx[2]*dx[2] + dx[3]*dx[3];
    __syncthreads();
    for (int o = 128; o > 0; o >>= 1) { if (tid < o) red[tid] += red[tid + o]; __syncthreads(); }
    float rs = rsqrtf(red[0] * (1.0f / 1024.0f) + EPS_LN);
    float4 gg = ((const float4*)gm)[tid], bb = ((const float4*)bm)[tid];
    float y[4] = { dx[0]*rs*gg.x + bb.x, dx[1]*rs*gg.y + bb.y,
                   dx[2]*rs*gg.z + bb.z, dx[3]*rs*gg.w + bb.w };
    size_t base = (size_t)row * 1024u + tid * 4;
    #pragma unroll
    for (int j = 0; j < 4; j++) {
        __nv_bfloat16 h, l; bsplit(y[j], h, l);
        g_actAh[base + j] = h; g_actAl[base + j] = l;
    }
}

// ---------------------------------------------------------------------------
// copy slots -> out
// ---------------------------------------------------------------------------
__global__ __launch_bounds__(256) void copy_out_kernel(float* __restrict__ out, int n) {
    int idx = blockIdx.x * 256 + threadIdx.x;
    if (idx < n) out[idx] = g_scratch[OFF_SLOTS + idx];
}

// ---------------------------------------------------------------------------
// host
// ---------------------------------------------------------------------------
#define SMEM128 (4 * (2*128 + 2*64) * SAP * 2)   /* 122880 */
#define SMEM64  (4 * (2*64 + 2*64) * SAP * 2)    /* 81920 */
#define SMEM32  (4 * (2*32 + 2*64) * SAP * 2)    /* 61440 */

extern "C" void kernel_launch(void* const* d_in, const int* in_sizes, int n_in,
                              void* d_out, int out_size) {
    const float* tokens = (const float*)d_in[0];
    const float* mu     = (const float*)d_in[1];
    const float* Wq  = (const float*)d_in[2];  const float* bq  = (const float*)d_in[3];
    const float* Wk  = (const float*)d_in[4];  const float* bk  = (const float*)d_in[5];
    const float* Wv  = (const float*)d_in[6];  const float* bv  = (const float*)d_in[7];
    const float* Wih = (const float*)d_in[8];  const float* bih = (const float*)d_in[9];
    const float* Whh = (const float*)d_in[10]; const float* bhh = (const float*)d_in[11];
    const float* W1  = (const float*)d_in[12]; const float* b1  = (const float*)d_in[13];
    const float* W2  = (const float*)d_in[14]; const float* b2  = (const float*)d_in[15];
    const float* gs  = (const float*)d_in[16]; const float* bs  = (const float*)d_in[17];
    const float* gm  = (const float*)d_in[18]; const float* bm  = (const float*)d_in[19];
    float* out = (float*)d_out;

    cudaFuncSetAttribute((const void*)gemm2_k<128>, cudaFuncAttributeMaxDynamicSharedMemorySize, SMEM128);
    cudaFuncSetAttribute((const void*)gemm2_k<64>,  cudaFuncAttributeMaxDynamicSharedMemorySize, SMEM64);
    cudaFuncSetAttribute((const void*)gemm2_k<32>,  cudaFuncAttributeMaxDynamicSharedMemorySize, SMEM32);
    cudaFuncSetAttribute((const void*)gru_gemm_k,   cudaFuncAttributeMaxDynamicSharedMemorySize, SMEM128);
    cudaFuncSetAttribute((const void*)fused_pass_kernel, cudaFuncAttributeMaxDynamicSharedMemorySize, FP_SMEM);

    __nv_bfloat16 *wMw, *wVih, *wHh, *w1, *w2, *wWqT, *wWkT, *wWvT, *wWihA;
    __nv_bfloat16 *actAh, *actAl, *actBh, *actBl, *q2h, *q2l, *actSh, *actSl;
    cudaGetSymbolAddress((void**)&wMw,   g_wMw);
    cudaGetSymbolAddress((void**)&wVih,  g_wVih);
    cudaGetSymbolAddress((void**)&wHh,   g_wHh);
    cudaGetSymbolAddress((void**)&w1,    g_w1);
    cudaGetSymbolAddress((void**)&w2,    g_w2);
    cudaGetSymbolAddress((void**)&wWqT,  g_wWqT);
    cudaGetSymbolAddress((void**)&wWkT,  g_wWkT);
    cudaGetSymbolAddress((void**)&wWvT,  g_wWvT);
    cudaGetSymbolAddress((void**)&wWihA, g_wWihA);
    cudaGetSymbolAddress((void**)&actAh, g_actAh);
    cudaGetSymbolAddress((void**)&actAl, g_actAl);
    cudaGetSymbolAddress((void**)&actBh, g_actBh);
    cudaGetSymbolAddress((void**)&actBl, g_actBl);
    cudaGetSymbolAddress((void**)&q2h, g_q2h);
    cudaGetSymbolAddress((void**)&q2l, g_q2l);
    cudaGetSymbolAddress((void**)&actSh, g_actSh);
    cudaGetSymbolAddress((void**)&actSl, g_actSl);
    float* scr;
    cudaGetSymbolAddress((void**)&scr, g_scratch);

    float* attnp = (out_size >= 1310720) ? (out + 262144) : (scr + OFF_ATTN);

    const size_t P1M = 1024u * 1024u;
    const size_t P3M = 3072u * 1024u;
    const size_t P4M = 4096u * 1024u;

    // ---- one-time ----
    transpose_kernel<<<dim3(32, 32), dim3(32, 8)>>>(Wk, OFF_WKT);
    transpose_kernel<<<dim3(32, 32), dim3(32, 8)>>>(Wq, OFF_WQT);
    transpose_kernel<<<dim3(32, 32), dim3(32, 8)>>>(Wv, OFF_WVT);
    tcnv_kernel<<<65536, 256>>>(tokens);
    convw2_kernel<<<1024, 256>>>(nullptr, OFF_WQT, wWqT, wWqT + P1M);
    convw2_kernel<<<1024, 256>>>(nullptr, OFF_WKT, wWkT, wWkT + P1M);
    convw2_kernel<<<1024, 256>>>(nullptr, OFF_WVT, wWvT, wWvT + P1M);
    convw2_kernel<<<3072, 256>>>(Wih, 0, wWihA, wWihA + P3M);
    gemv_kernel<<<1024, 256>>>(nullptr, OFF_WQT, bk, OFF_WCB, 1024, 1.0f);
    gemv_kernel<<<1024, 256>>>(nullptr, OFF_WKT, bq, OFF_V2, 1024, SCALEF);
    gemv_kernel<<<3072, 256>>>(Wih, 0, bv, OFF_BVW, 1024, 1.0f);
    gemv_kernel<<<1, 256>>>(bq, 0, bk, OFF_C0, 1024, 1.0f);
    gemm2_k<128><<<dim3(16, 8), 256, SMEM128>>>(wWkT, wWkT + P1M, wWqT, wWqT + P1M,
                                                nullptr, nullptr, scr + OFF_MFP,
                                                nullptr, nullptr, 1024, 1024, 4);
    gemm2_k<128><<<dim3(16, 24), 256, SMEM128>>>(wWihA, wWihA + P3M, wWvT, wWvT + P1M,
                                                 nullptr, nullptr, scr + OFF_WVIH,
                                                 nullptr, nullptr, 1024, 1024, 6);
    convw2_kernel<<<1024, 256>>>(nullptr, OFF_MFP,  wMw,  wMw + P1M);
    convw2_kernel<<<3072, 256>>>(nullptr, OFF_WVIH, wVih, wVih + P3M);
    convw2_kernel<<<3072, 256>>>(Whh, 0, wHh, wHh + P3M);
    convw2_kernel<<<4096, 256>>>(W1,  0, w1,  w1 + P4M);
    convw2_kernel<<<4096, 256>>>(W2,  0, w2,  w2 + P4M);
    init_slots_kernel<<<1024, 256>>>(mu);

    for (int it = 0; it < 3; it++) {
        ln_kernel<<<256, 256>>>(OFF_SLOTS, gs, bs, 1);
        // q2 = ln (.) Mw + v2 -> q2 planes   (BM=32, 128 blocks)
        gemm2_k<32><<<dim3(16, 8), 256, SMEM32>>>(actAh, actAl, wMw, wMw + P1M,
                                                  scr + OFF_V2, nullptr, nullptr,
                                                  q2h, q2l, 1024, 1024, 0);
        fused_pass_kernel<<<dim3(32, 16), 256, FP_SMEM>>>(attnp, it == 2 ? 1 : 0);
        reduceU_kernel<<<256, 256>>>();
        gru_gemm_k<<<dim3(48, 2, 2), 256, SMEM128>>>(bih, bhh);
        gru_ln_kernel<<<256, 256>>>(gm, bm);
        gemm2_k<128><<<dim3(64, 2), 256, SMEM128>>>(actAh, actAl, w1, w1 + P4M,
                                                    b1, nullptr, nullptr,
                                                    actBh, actBl, 4096, 1024, 2);
        // w2: K=4096, BM=32 -> 128 blocks
        gemm2_k<32><<<dim3(16, 8), 256, SMEM32>>>(actBh, actBl, w2, w2 + P4M,
                                                  b2, nullptr, scr + OFF_SLOTS,
                                                  actSh, actSl, 1024, 4096, 3);
    }

    int nslots = out_size < 262144 ? out_size : 262144;
    copy_out_kernel<<<1024, 256>>>(out, nslots);
}

// round 14
// speedup vs baseline: 2.7971x; 1.0234x over previous
#include <cuda_runtime.h>
#include <cuda_bf16.h>
#include <cstdint>
#include <cstddef>

// ---------------------------------------------------------------------------
// Problem sizes: B=16, S=4096, D=1024, K=16, ITERS=3
// ---------------------------------------------------------------------------
#define SCALEF   0.03125f        /* 1024^-0.5 */
#define EPS_LN   1e-5f
#define EPS_ATTN 1e-8f

// fp32 scratch offsets (floats)
#define OFF_SLOTS 0u
#define OFF_GI    1572864u
#define OFF_GH    2359296u
#define OFF_WQT   4194304u
#define OFF_WVT   5242880u
#define OFF_MFP   6291456u
#define OFF_WVIH  7340032u      /* 3145728 floats */
#define OFF_U     10485760u     /* 262144 floats (atomic accum) */
#define OFF_WCB   10747904u
#define OFF_V2    10748928u
#define OFF_BVW   10749952u
#define OFF_C0    10753024u
#define OFF_WKT   12582912u
#define OFF_CB    13631488u
#define OFF_BS    13631744u
#define OFF_RP    13632256u     /* 256 rows * 32 chunks */
#define OFF_ATTN  13640448u
#define SCRATCH_N 14689024u

__device__ float g_scratch[SCRATCH_N];

// bf16 2-plane weight buffers: [hi plane | lo plane], each N*K
__device__ __nv_bfloat16 g_wMw  [2u * 1024u * 1024u];
__device__ __nv_bfloat16 g_wVih [2u * 3072u * 1024u];
__device__ __nv_bfloat16 g_wHh  [2u * 3072u * 1024u];
__device__ __nv_bfloat16 g_w1   [2u * 4096u * 1024u];
__device__ __nv_bfloat16 g_w2   [2u * 1024u * 4096u];
// one-time composition operands
__device__ __nv_bfloat16 g_wWqT [2u * 1024u * 1024u];
__device__ __nv_bfloat16 g_wWkT [2u * 1024u * 1024u];
__device__ __nv_bfloat16 g_wWvT [2u * 1024u * 1024u];
__device__ __nv_bfloat16 g_wWihA[2u * 3072u * 1024u];
// activation plane pairs
__device__ __nv_bfloat16 g_actAh[256u * 1024u], g_actAl[256u * 1024u];
__device__ __nv_bfloat16 g_actSh[256u * 1024u], g_actSl[256u * 1024u];
__device__ __nv_bfloat16 g_actBh[256u * 4096u], g_actBl[256u * 4096u];
// token planes [b][s][d]
__device__ __nv_bfloat16 g_tokh [16u * 4096u * 1024u];
__device__ __nv_bfloat16 g_tokl [16u * 4096u * 1024u];
// q2 planes [256][1024]
__device__ __nv_bfloat16 g_q2h[256u * 1024u];
__device__ __nv_bfloat16 g_q2l[256u * 1024u];

__device__ __forceinline__ float geluf(float x) {
    return 0.5f * x * (1.0f + erff(x * 0.70710678118654752f));
}
__device__ __forceinline__ float sigmf(float x) {
    return 1.0f / (1.0f + __expf(-x));
}

__device__ __forceinline__ uint32_t smem_u32(const void* p) {
    uint32_t a;
    asm("{ .reg .u64 t; cvta.to.shared.u64 t, %1; cvt.u32.u64 %0, t; }" : "=r"(a) : "l"(p));
    return a;
}
__device__ __forceinline__ void cp16s(uint32_t daddr, const void* src) {
    asm volatile("cp.async.cg.shared.global [%0], [%1], 16;" :: "r"(daddr), "l"(src));
}
__device__ __forceinline__ void cpcommit() {
    asm volatile("cp.async.commit_group;" ::: "memory");
}
__device__ __forceinline__ void cpwait_n(int n) {
    if (n <= 0)      asm volatile("cp.async.wait_group 0;" ::: "memory");
    else if (n == 1) asm volatile("cp.async.wait_group 1;" ::: "memory");
    else             asm volatile("cp.async.wait_group 2;" ::: "memory");
}
__device__ __forceinline__ void ldm4(uint32_t* r, uint32_t addr) {
    asm volatile("ldmatrix.sync.aligned.m8n8.x4.shared.b16 {%0,%1,%2,%3}, [%4];"
        : "=r"(r[0]), "=r"(r[1]), "=r"(r[2]), "=r"(r[3]) : "r"(addr));
}
__device__ __forceinline__ void ldm2(uint32_t* r, uint32_t addr) {
    asm volatile("ldmatrix.sync.aligned.m8n8.x2.shared.b16 {%0,%1}, [%2];"
        : "=r"(r[0]), "=r"(r[1]) : "r"(addr));
}
__device__ __forceinline__ void ldm2t(uint32_t* r, uint32_t addr) {
    asm volatile("ldmatrix.sync.aligned.m8n8.x2.trans.shared.b16 {%0,%1}, [%2];"
        : "=r"(r[0]), "=r"(r[1]) : "r"(addr));
}
__device__ __forceinline__ void mma16816(float* c, const uint32_t* a, const uint32_t* b) {
    asm volatile(
        "mma.sync.aligned.m16n8k16.row.col.f32.bf16.bf16.f32 "
        "{%0,%1,%2,%3}, {%4,%5,%6,%7}, {%8,%9}, {%0,%1,%2,%3};"
        : "+f"(c[0]), "+f"(c[1]), "+f"(c[2]), "+f"(c[3])
        : "r"(a[0]), "r"(a[1]), "r"(a[2]), "r"(a[3]), "r"(b[0]), "r"(b[1]));
}

__device__ __forceinline__ void bsplit(float x, __nv_bfloat16& h, __nv_bfloat16& l) {
    h = __float2bfloat16_rn(x);
    l = __float2bfloat16_rn(x - __bfloat162float(h));
}

// ---------------------------------------------------------------------------
// init: slots = broadcast(slot_mu); emit actS planes (slots feed gh at it0)
// ---------------------------------------------------------------------------
__global__ __launch_bounds__(256) void init_slots_kernel(const float* __restrict__ mu) {
    unsigned idx = blockIdx.x * 256u + threadIdx.x;          // < 262144
    float x = mu[idx & 16383u];
    g_scratch[OFF_SLOTS + idx] = x;
    __nv_bfloat16 h, l; bsplit(x, h, l);
    g_actSh[idx] = h; g_actSl[idx] = l;
}

// ---------------------------------------------------------------------------
// transpose 1024x1024 fp32: in -> g_scratch[dstOff]
// ---------------------------------------------------------------------------
__global__ void transpose_kernel(const float* __restrict__ in, unsigned dstOff) {
    __shared__ float t[32][33];
    int x  = blockIdx.x * 32 + threadIdx.x;
    int y0 = blockIdx.y * 32;
    #pragma unroll
    for (int j = threadIdx.y; j < 32; j += 8)
        t[j][threadIdx.x] = in[(size_t)(y0 + j) * 1024 + x];
    __syncthreads();
    int xo  = blockIdx.y * 32 + threadIdx.x;
    int yo0 = blockIdx.x * 32;
    #pragma unroll
    for (int j = threadIdx.y; j < 32; j += 8)
        g_scratch[dstOff + (size_t)(yo0 + j) * 1024 + xo] = t[threadIdx.x][j];
}

// ---------------------------------------------------------------------------
// tokens -> bf16 hi/lo planes
// ---------------------------------------------------------------------------
__global__ __launch_bounds__(256) void tcnv_kernel(const float* __restrict__ tokens) {
    size_t idx4 = (size_t)blockIdx.x * 256u + threadIdx.x;
    float4 x = ((const float4*)tokens)[idx4];
    __nv_bfloat16 h0,h1,h2,h3,l0,l1,l2,l3;
    bsplit(x.x,h0,l0); bsplit(x.y,h1,l1); bsplit(x.z,h2,l2); bsplit(x.w,h3,l3);
    size_t k = idx4 * 4;
    *(__nv_bfloat162*)(g_tokh + k)     = __nv_bfloat162(h0, h1);
    *(__nv_bfloat162*)(g_tokh + k + 2) = __nv_bfloat162(h2, h3);
    *(__nv_bfloat162*)(g_tokl + k)     = __nv_bfloat162(l0, l1);
    *(__nv_bfloat162*)(g_tokl + k + 2) = __nv_bfloat162(l2, l3);
}

// ---------------------------------------------------------------------------
// split-convert to 2 planes: src (flat fp32) -> dh, dl
// ---------------------------------------------------------------------------
__global__ __launch_bounds__(256) void convw2_kernel(const float* __restrict__ src,
                                                     unsigned srcOff,
                                                     __nv_bfloat16* __restrict__ dh,
                                                     __nv_bfloat16* __restrict__ dl) {
    size_t idx4 = (size_t)blockIdx.x * 256u + threadIdx.x;
    const float* S = src ? src : (g_scratch + srcOff);
    float4 x = *(const float4*)(S + idx4 * 4);
    __nv_bfloat16 h0,h1,h2,h3,l0,l1,l2,l3;
    bsplit(x.x,h0,l0); bsplit(x.y,h1,l1); bsplit(x.z,h2,l2); bsplit(x.w,h3,l3);
    size_t k = idx4 * 4;
    *(__nv_bfloat162*)(dh + k)     = __nv_bfloat162(h0, h1);
    *(__nv_bfloat162*)(dh + k + 2) = __nv_bfloat162(h2, h3);
    *(__nv_bfloat162*)(dl + k)     = __nv_bfloat162(l0, l1);
    *(__nv_bfloat162*)(dl + k + 2) = __nv_bfloat162(l2, l3);
}

// ---------------------------------------------------------------------------
// gemv: out[row] = scale * dot(M[row, 0:len], v)
// ---------------------------------------------------------------------------
__global__ __launch_bounds__(256) void gemv_kernel(const float* __restrict__ M,
                                                   unsigned moff,
                                                   const float* __restrict__ v,
                                                   unsigned outoff, int len, float scale) {
    __shared__ float red[256];
    const float* Mr = (M ? M : g_scratch + moff) + (size_t)blockIdx.x * len;
    int tid = threadIdx.x;
    float p = 0.f;
    for (int i = tid * 4; i < len; i += 1024) {
        float4 a = *(const float4*)(Mr + i);
        float4 b = *(const float4*)(v + i);
        p += a.x*b.x + a.y*b.y + a.z*b.z + a.w*b.w;
    }
    red[tid] = p; __syncthreads();
    for (int o = 128; o > 0; o >>= 1) { if (tid < o) red[tid] += red[tid + o]; __syncthreads(); }
    if (tid == 0) g_scratch[outoff + blockIdx.x] = scale * red[0];
}

// ---------------------------------------------------------------------------
// 2-plane HMMA GEMM: C = (Ah+Al) (.) (Wh+Wl)^T  via Ah*Wh + Ah*Wl + Al*Wh.
// BM in {128, 64, 32}.  BN=64.  256 threads, 4-stage cp.async.
// epi==3 reads residual from Cres, writes to Cout.
// ---------------------------------------------------------------------------
#define SAP 40

template<int BM>
__device__ __forceinline__ void gemm2_core(char* sm,
    const __nv_bfloat16* __restrict__ Ah, const __nv_bfloat16* __restrict__ Al,
    const __nv_bfloat16* __restrict__ Wh, const __nv_bfloat16* __restrict__ Wl,
    const float* __restrict__ bias, const float* __restrict__ bias2,
    float* Cout, const float* __restrict__ Cres,
    __nv_bfloat16* ph, __nv_bfloat16* pl,
    int N, int K, int epi)
{
    constexpr int NW_M = BM / 32;          // warps along M
    constexpr int WTN  = BM / 4;           // warp tile N: 128->32, 64->16, 32->8
    constexpr int NT   = WTN / 8;
    constexpr uint32_t AP  = BM * SAP * 2;
    constexpr uint32_t WP  = 64 * SAP * 2;
    constexpr uint32_t STG = 2 * AP + 2 * WP;

    const int tid  = threadIdx.x;
    const int lane = tid & 31, wid = tid >> 5;
    const int wm = (wid % NW_M) * 32;
    const int wn = (wid / NW_M) * WTN;
    const int bn = blockIdx.x * 64, bm = blockIdx.y * BM;
    const int NC = K >> 5;

    const uint32_t smb = smem_u32(sm);

    const int lrow = tid >> 2, lch = (tid & 3) * 8;
    const uint32_t aoff  = (uint32_t)(lrow * SAP + lch) * 2;
    const uint32_t aoff1 = (uint32_t)((64 + lrow) * SAP + lch) * 2;
    const __nv_bfloat16* agh0 = Ah + (size_t)(bm + (lrow < BM ? lrow : 0)) * K + lch;
    const __nv_bfloat16* agl0 = Al + (size_t)(bm + (lrow < BM ? lrow : 0)) * K + lch;
    const __nv_bfloat16* agh1 = Ah + (size_t)(bm + 64 + lrow) * K + lch;
    const __nv_bfloat16* agl1 = Al + (size_t)(bm + 64 + lrow) * K + lch;
    const __nv_bfloat16* wgh  = Wh + (size_t)(bn + lrow) * K + lch;
    const __nv_bfloat16* wgl  = Wl + (size_t)(bn + lrow) * K + lch;

    const int a_row = wm + (lane & 15);
    const int a_col = (lane >> 4) * 8;
    const int b_row = wn + ((lane >> 4) & 1) * 8 + (lane & 7);
    const int b_col = ((lane >> 3) & 1) * 8;
    const int l2 = lane & 15;
    const int b_row1 = wn + (l2 & 7);
    const int b_col1 = ((l2 >> 3) & 1) * 8;

    float acc[2][NT][4];
    #pragma unroll
    for (int i = 0; i < 2; i++)
        #pragma unroll
        for (int j = 0; j < NT; j++)
            #pragma unroll
            for (int e = 0; e < 4; e++) acc[i][j][e] = 0.f;

    auto load_stage = [&](int st, int c) {
        const uint32_t S = smb + (uint32_t)st * STG;
        const int ko = c * 32;
        if (BM >= 64 || lrow < BM) {
            cp16s(S + aoff, agh0 + ko);
            cp16s(S + AP + aoff, agl0 + ko);
        }
        if (BM == 128) {
            cp16s(S + aoff1, agh1 + ko);
            cp16s(S + AP + aoff1, agl1 + ko);
        }
        cp16s(S + 2 * AP + aoff, wgh + ko);
        cp16s(S + 2 * AP + WP + aoff, wgl + ko);
        cpcommit();
    };

    load_stage(0, 0);
    load_stage(1, 1);
    load_stage(2, 2);

    for (int c = 0; c < NC; c++) {
        int bnd = NC - 1 - c; if (bnd > 2) bnd = 2;
        cpwait_n(bnd);
        __syncthreads();
        if (c + 3 < NC) load_stage((c + 3) & 3, c + 3);
        const uint32_t S = smb + (uint32_t)(c & 3) * STG;
        const uint32_t abh = S, abl = S + AP;
        const uint32_t wbh = S + 2 * AP, wbl = S + 2 * AP + WP;
        #pragma unroll
        for (int ks = 0; ks < 2; ks++) {
            uint32_t afh[2][4], afl[2][4], bfh[2][4], bfl[2][4];
            #pragma unroll
            for (int mt = 0; mt < 2; mt++) {
                uint32_t ao = (uint32_t)(((a_row + mt * 16) * SAP) + ks * 16 + a_col) * 2;
                ldm4(afh[mt], abh + ao);
                ldm4(afl[mt], abl + ao);
            }
            if (NT == 1) {
                uint32_t bo = (uint32_t)((b_row1 * SAP) + ks * 16 + b_col1) * 2;
                ldm2(bfh[0], wbh + bo);
                ldm2(bfl[0], wbl + bo);
            } else {
                #pragma unroll
                for (int nb = 0; nb < NT / 2; nb++) {
                    uint32_t bo = (uint32_t)(((b_row + nb * 16) * SAP) + ks * 16 + b_col) * 2;
                    ldm4(bfh[nb], wbh + bo);
                    ldm4(bfl[nb], wbl + bo);
                }
            }
            #pragma unroll
            for (int mt = 0; mt < 2; mt++)
                #pragma unroll
                for (int nt = 0; nt < NT; nt++) {
                    const uint32_t* bh = &bfh[nt >> 1][(nt & 1) * 2];
                    const uint32_t* bl = &bfl[nt >> 1][(nt & 1) * 2];
                    mma16816(acc[mt][nt], afh[mt], bh);
                    mma16816(acc[mt][nt], afh[mt], bl);
                    mma16816(acc[mt][nt], afl[mt], bh);
                }
        }
    }

    const int mrow = lane >> 2, ncol2 = (lane & 3) * 2;
    #pragma unroll
    for (int mt = 0; mt < 2; mt++) {
        #pragma unroll
        for (int h = 0; h < 2; h++) {
            const int m = bm + wm + mt * 16 + mrow + h * 8;
            float brow = 0.f;
            if (epi == 7) brow = g_scratch[OFF_BS + m];
            #pragma unroll
            for (int nt = 0; nt < NT; nt++) {
                const int n0 = bn + wn + nt * 8 + ncol2;
                float ox = acc[mt][nt][h * 2], oy = acc[mt][nt][h * 2 + 1];
                if (epi == 4) { ox *= SCALEF; oy *= SCALEF; }
                else if (epi == 6) { }
                else {
                    float2 bb = *(const float2*)(bias + n0);
                    if (epi == 7) {
                        float2 b2 = *(const float2*)(bias2 + n0);
                        ox += bb.x + brow * b2.x; oy += bb.y + brow * b2.y;
                    } else { ox += bb.x; oy += bb.y; }
                    if (epi == 2) { ox = geluf(ox); oy = geluf(oy); }
                    if (epi == 3) {
                        float2 c0 = *(const float2*)(Cres + (size_t)m * N + n0);
                        ox += c0.x; oy += c0.y;
                    }
                }
                if (Cout) *(float2*)(Cout + (size_t)m * N + n0) = make_float2(ox, oy);
                if (ph) {
                    __nv_bfloat16 hx, lx, hy, ly;
                    bsplit(ox, hx, lx); bsplit(oy, hy, ly);
                    *(__nv_bfloat162*)(ph + (size_t)m * N + n0) = __nv_bfloat162(hx, hy);
                    *(__nv_bfloat162*)(pl + (size_t)m * N + n0) = __nv_bfloat162(lx, ly);
                }
            }
        }
    }
}

template<int BM>
__global__ __launch_bounds__(256) void gemm2_k(const __nv_bfloat16* __restrict__ Ah,
                                               const __nv_bfloat16* __restrict__ Al,
                                               const __nv_bfloat16* __restrict__ Wh,
                                               const __nv_bfloat16* __restrict__ Wl,
                                               const float* __restrict__ bias,
                                               const float* __restrict__ bias2,
                                               float* Cout, const float* Cres,
                                               __nv_bfloat16* ph, __nv_bfloat16* pl,
                                               int N, int K, int epi) {
    extern __shared__ char sm[];
    gemm2_core<BM>(sm, Ah, Al, Wh, Wl, bias, bias2, Cout, Cres, ph, pl, N, K, epi);
}

// merged GRU gemms (BM=64: 2 CTAs/SM)
__global__ __launch_bounds__(256) void gru_gemm_k(const float* __restrict__ bih,
                                                  const float* __restrict__ bhh) {
    extern __shared__ char sm[];
    if (blockIdx.z == 0)
        gemm2_core<64>(sm, g_actAh, g_actAl, g_wVih, g_wVih + 3072u*1024u,
                       bih, g_scratch + OFF_BVW, g_scratch + OFF_GI, nullptr,
                       nullptr, nullptr, 3072, 1024, 7);
    else
        gemm2_core<64>(sm, g_actSh, g_actSl, g_wHh, g_wHh + 3072u*1024u,
                       bhh, nullptr, g_scratch + OFF_GH, nullptr,
                       nullptr, nullptr, 3072, 1024, 0);
}

// ---------------------------------------------------------------------------
// Single-read fused pass (256 threads): per 16-token group -- load tok strip
// once, logits (k split over 8 warps) + softmax + updates vs the SAME strip.
// U accumulated in registers across groups; one atomicAdd set per CTA.
// grid (32 chunks of 128 tokens, 16 b).
// ---------------------------------------------------------------------------
#define FP_SMEM 198144
__global__ __launch_bounds__(256) void fused_pass_kernel(float* __restrict__ attn_out,
                                                         int wlast) {
    extern __shared__ char sm[];
    __shared__ float Lg[8][16][17];
    __shared__ float Att32[16][17];                 // [token][slot]
    __shared__ __nv_bfloat16 ATh[16][24], ATl[16][24];  // [slot][token]
    __shared__ float cbs[16], rs[16];
    const int tid = threadIdx.x;
    const int lane = tid & 31, wid = tid >> 5;
    const int sc = blockIdx.x, b = blockIdx.y;

    const uint32_t smb = smem_u32(sm);
    const uint32_t Qh = smb, Ql = smb + 33024u;
    const uint32_t TB = smb + 66048u;               // 2 buffers x 66048

    if (tid < 16) { cbs[tid] = g_scratch[OFF_CB + b * 16 + tid]; rs[tid] = 0.f; }

    const size_t tokbase = ((size_t)b * 4096 + (size_t)sc * 128) * 1024;

    auto load_group = [&](int buf, int g) {
        const uint32_t Bs = TB + (uint32_t)buf * 66048u;
        #pragma unroll
        for (int i = 0; i < 8; i++) {
            int idx = tid + 256 * i;
            int row = idx >> 7, j = idx & 127;
            cp16s(Bs + (uint32_t)(row * 1032 + j * 8) * 2,
                  g_tokh + tokbase + (size_t)(g * 16 + row) * 1024 + j * 8);
            cp16s(Bs + 33024u + (uint32_t)(row * 1032 + j * 8) * 2,
                  g_tokl + tokbase + (size_t)(g * 16 + row) * 1024 + j * 8);
        }
        cpcommit();
    };

    // Q planes + first group
    {
        #pragma unroll
        for (int i = 0; i < 8; i++) {
            int id = tid + 256 * i;
            int row = id >> 7, j = id & 127;
            cp16s(Qh + (uint32_t)(row * 1032 + j * 8) * 2,
                  g_q2h + (size_t)(b * 16 + row) * 1024 + j * 8);
            cp16s(Ql + (uint32_t)(row * 1032 + j * 8) * 2,
                  g_q2l + (size_t)(b * 16 + row) * 1024 + j * 8);
        }
        cpcommit();
        load_group(0, 0);
    }

    // persistent U accumulators: warp wid owns d slice [wid*128, wid*128+128)
    float uacc[16][4];
    #pragma unroll
    for (int nt = 0; nt < 16; nt++)
        #pragma unroll
        for (int e = 0; e < 4; e++) uacc[nt][e] = 0.f;

    const int kw = wid * 128;               // this warp's k-slice
    const int a_r = lane & 15;              // token row
    const int a_c = (lane >> 4) * 8;
    const int b_r = ((lane >> 4) & 1) * 8 + (lane & 7);
    const int b_c = ((lane >> 3) & 1) * 8;
    const uint32_t ATHb = smem_u32(&ATh[0][0]);
    const uint32_t ATLb = smem_u32(&ATl[0][0]);
    const uint32_t at_off = (uint32_t)((lane & 15) * 24 + (lane >> 4) * 8) * 2;

    for (int g = 0; g < 8; g++) {
        cpwait_n(0);
        __syncthreads();
        if (g + 1 < 8) load_group((g + 1) & 1, g + 1);
        const uint32_t Bs = TB + (uint32_t)(g & 1) * 66048u;
        const uint32_t Bh = Bs, Bl = Bs + 33024u;

        // ---- logits: warp k-slice, m16 (tokens) x n16 (slots) ----
        float la[2][4];
        #pragma unroll
        for (int nt = 0; nt < 2; nt++)
            #pragma unroll
            for (int e = 0; e < 4; e++) la[nt][e] = 0.f;
        #pragma unroll
        for (int ks = 0; ks < 8; ks++) {
            const int col = kw + ks * 16;
            uint32_t afh[4], afl[4], bfh[4], bfl[4];
            uint32_t ao = (uint32_t)(a_r * 1032 + col + a_c) * 2;
            ldm4(afh, Bh + ao);
            ldm4(afl, Bl + ao);
            uint32_t bo = (uint32_t)(b_r * 1032 + col + b_c) * 2;
            ldm4(bfh, Qh + bo);
            ldm4(bfl, Ql + bo);
            #pragma unroll
            for (int nt = 0; nt < 2; nt++) {
                mma16816(la[nt], afh, &bfh[nt * 2]);
                mma16816(la[nt], afh, &bfl[nt * 2]);
                mma16816(la[nt], afl, &bfh[nt * 2]);
            }
        }
        #pragma unroll
        for (int nt = 0; nt < 2; nt++)
            #pragma unroll
            for (int e = 0; e < 4; e++) {
                int row = (lane >> 2) + (e >> 1) * 8;
                int col = nt * 8 + (lane & 3) * 2 + (e & 1);
                Lg[wid][row][col] = la[nt][e];
            }
        __syncthreads();

        // reduce over 8 warps (256 threads, one (tok, slot) each)
        {
            int tok = tid >> 4, s = tid & 15;
            float v = cbs[s];
            #pragma unroll
            for (int w = 0; w < 8; w++) v += Lg[w][tok][s];
            Att32[tok][s] = v;
        }
        __syncthreads();

        // softmax per token (threads 0..15)
        if (tid < 16) {
            float a[16];
            float mx = -1e30f;
            #pragma unroll
            for (int k = 0; k < 16; k++) { a[k] = Att32[tid][k]; mx = fmaxf(mx, a[k]); }
            float sum = 0.f;
            #pragma unroll
            for (int k = 0; k < 16; k++) { a[k] = __expf(a[k] - mx); sum += a[k]; }
            float inv = 1.0f / sum;
            #pragma unroll
            for (int k = 0; k < 16; k++) {
                a[k] *= inv;
                Att32[tid][k] = a[k];
                __nv_bfloat16 h, l; bsplit(a[k], h, l);
                ATh[k][tid] = h; ATl[k][tid] = l;
                if (wlast)
                    attn_out[(size_t)(b * 16 + k) * 4096 + (size_t)sc * 128 + g * 16 + tid] = a[k];
            }
        }
        __syncthreads();

        // rowsum partial (threads 16..31, slot = tid-16)
        if (tid >= 16 && tid < 32) {
            int s = tid - 16;
            float t = 0.f;
            #pragma unroll
            for (int tok = 0; tok < 16; tok++) t += Att32[tok][s];
            rs[s] += t;
        }

        // ---- updates: U[slots][d-slice] += attnT @ tok  (same strip) ----
        uint32_t ath[4], atl[4];
        ldm4(ath, ATHb + at_off);
        ldm4(atl, ATLb + at_off);
        #pragma unroll
        for (int nt = 0; nt < 16; nt++) {
            const int d0 = kw + nt * 8;
            uint32_t bh[2], bl[2];
            uint32_t bo = (uint32_t)((lane & 15) * 1032 + d0) * 2;
            ldm2t(bh, Bh + bo);
            ldm2t(bl, Bl + bo);
            mma16816(uacc[nt], ath, bh);
            mma16816(uacc[nt], ath, bl);
            mma16816(uacc[nt], atl, bh);
        }
    }

    __syncthreads();
    if (tid < 16)
        g_scratch[OFF_RP + (size_t)(b * 16 + tid) * 32 + sc] = rs[tid];

    // one atomic accumulation per CTA
    float* Ub = g_scratch + OFF_U + (size_t)(b * 16) * 1024;
    const int slot0 = lane >> 2;
    #pragma unroll
    for (int nt = 0; nt < 16; nt++) {
        const int d0 = kw + nt * 8 + (lane & 3) * 2;
        atomicAdd(&Ub[(size_t)slot0 * 1024 + d0],           uacc[nt][0]);
        atomicAdd(&Ub[(size_t)slot0 * 1024 + d0 + 1],       uacc[nt][1]);
        atomicAdd(&Ub[(size_t)(slot0 + 8) * 1024 + d0],     uacc[nt][2]);
        atomicAdd(&Ub[(size_t)(slot0 + 8) * 1024 + d0 + 1], uacc[nt][3]);
    }
}

// ---------------------------------------------------------------------------
// LayerNorm (slots) -> actA planes; docb=1: also cb + zero-U
// ---------------------------------------------------------------------------
__global__ __launch_bounds__(256) void ln_kernel(unsigned offX,
                                                 const float* __restrict__ g,
                                                 const float* __restrict__ bt,
                                                 int docb) {
    __shared__ float red[256];
    const float* X = g_scratch + offX;
    int row = blockIdx.x, tid = threadIdx.x;
    float4 x = ((const float4*)X)[row * 256 + tid];
    red[tid] = x.x + x.y + x.z + x.w;
    __syncthreads();
    for (int o = 128; o > 0; o >>= 1) { if (tid < o) red[tid] += red[tid + o]; __syncthreads(); }
    float mean = red[0] * (1.0f / 1024.0f);
    __syncthreads();
    float4 dx = { x.x - mean, x.y - mean, x.z - mean, x.w - mean };
    red[tid] = dx.x*dx.x + dx.y*dx.y + dx.z*dx.z + dx.w*dx.w;
    __syncthreads();
    for (int o = 128; o > 0; o >>= 1) { if (tid < o) red[tid] += red[tid + o]; __syncthreads(); }
    float rs = rsqrtf(red[0] * (1.0f / 1024.0f) + EPS_LN);
    float4 gg = ((const float4*)g)[tid], bb = ((const float4*)bt)[tid];
    float y[4] = { dx.x*rs*gg.x + bb.x, dx.y*rs*gg.y + bb.y,
                   dx.z*rs*gg.z + bb.z, dx.w*rs*gg.w + bb.w };
    size_t base = (size_t)row * 1024u + tid * 4;
    #pragma unroll
    for (int j = 0; j < 4; j++) {
        __nv_bfloat16 h, l; bsplit(y[j], h, l);
        g_actAh[base + j] = h; g_actAl[base + j] = l;
    }
    if (docb) {
        *(float4*)&g_scratch[OFF_U + base] = make_float4(0.f, 0.f, 0.f, 0.f);
        float p = 0.f;
        #pragma unroll
        for (int j = 0; j < 4; j++) p += y[j] * g_scratch[OFF_WCB + tid * 4 + j];
        __syncthreads();
        red[tid] = p; __syncthreads();
        for (int o = 128; o > 0; o >>= 1) { if (tid < o) red[tid] += red[tid + o]; __syncthreads(); }
        if (tid == 0)
            g_scratch[OFF_CB + row] = SCALEF * (red[0] + g_scratch[OFF_C0]);
    }
}

// ---------------------------------------------------------------------------
// reduceU (+rowsum): Un[row] = U[row]/rowsum -> actA planes; BS=brow
// ---------------------------------------------------------------------------
__global__ __launch_bounds__(256) void reduceU_kernel() {
    float* S = g_scratch;
    int row = blockIdx.x, tid = threadIdx.x;
    float s = 0.f;
    #pragma unroll
    for (int cc = 0; cc < 32; cc++) s += S[OFF_RP + (size_t)row * 32 + cc];
    float ri = 1.0f / (s + EPS_ATTN);
    if (tid == 0) S[OFF_BS + row] = s * ri;
    size_t base = (size_t)row * 1024u + tid * 4;
    float4 v = *(const float4*)&S[OFF_U + base];
    float y[4] = { v.x * ri, v.y * ri, v.z * ri, v.w * ri };
    #pragma unroll
    for (int j = 0; j < 4; j++) {
        __nv_bfloat16 h, l; bsplit(y[j], h, l);
        g_actAh[base + j] = h; g_actAl[base + j] = l;
    }
}

// ---------------------------------------------------------------------------
// Fused GRU combine + LayerNorm(mlp) -> slots, actA planes.  block = row.
// ---------------------------------------------------------------------------
__global__ __launch_bounds__(256) void gru_ln_kernel(const float* __restrict__ gm,
                                                     const float* __restrict__ bm) {
    __shared__ float red[256];
    float* S = g_scratch;
    int row = blockIdx.x, tid = threadIdx.x;
    size_t gb = (size_t)row * 3072 + tid * 4;
    float4 ir = *(const float4*)&S[OFF_GI + gb];
    float4 iz = *(const float4*)&S[OFF_GI + gb + 1024];
    float4 in_ = *(const float4*)&S[OFF_GI + gb + 2048];
    float4 hr = *(const float4*)&S[OFF_GH + gb];
    float4 hz = *(const float4*)&S[OFF_GH + gb + 1024];
    float4 hn = *(const float4*)&S[OFF_GH + gb + 2048];
    float4 sp = *(const float4*)&S[OFF_SLOTS + (size_t)row * 1024 + tid * 4];
    float ns[4];
    {
        float r0 = sigmf(ir.x + hr.x), z0 = sigmf(iz.x + hz.x);
        ns[0] = (1.f - z0) * tanhf(in_.x + r0 * hn.x) + z0 * sp.x;
        float r1 = sigmf(ir.y + hr.y), z1 = sigmf(iz.y + hz.y);
        ns[1] = (1.f - z1) * tanhf(in_.y + r1 * hn.y) + z1 * sp.y;
        float r2 = sigmf(ir.z + hr.z), z2 = sigmf(iz.z + hz.z);
        ns[2] = (1.f - z2) * tanhf(in_.z + r2 * hn.z) + z2 * sp.z;
        float r3 = sigmf(ir.w + hr.w), z3 = sigmf(iz.w + hz.w);
        ns[3] = (1.f - z3) * tanhf(in_.w + r3 * hn.w) + z3 * sp.w;
    }
    *(float4*)&S[OFF_SLOTS + (size_t)row * 1024 + tid * 4] =
        make_float4(ns[0], ns[1], ns[2], ns[3]);
    red[tid] = ns[0] + ns[1] + ns[2] + ns[3];
    __syncthreads();
    for (int o = 128; o > 0; o >>= 1) { if (tid < o) red[tid] += red[tid + o]; __syncthreads(); }
    float mean = red[0] * (1.0f / 1024.0f);
    __syncthreads();
    float dx[4] = { ns[0]-mean, ns[1]-mean, ns[2]-mean, ns[3]-mean };
    red[tid] = dx[0]*dx[0] + dx[1]*dx[1] + dx[2]*dx[2] + dx[3]*dx[3];
    __syncthreads();
    for (int o = 128; o > 0; o >>= 1) { if (tid < o) red[tid] += red[tid + o]; __syncthreads(); }
    float rs = rsqrtf(red[0] * (1.0f / 1024.0f) + EPS_LN);
    float4 gg = ((const float4*)gm)[tid], bb = ((const float4*)bm)[tid];
    float y[4] = { dx[0]*rs*gg.x + bb.x, dx[1]*rs*gg.y + bb.y,
                   dx[2]*rs*gg.z + bb.z, dx[3]*rs*gg.w + bb.w };
    size_t base = (size_t)row * 1024u + tid * 4;
    #pragma unroll
    for (int j = 0; j < 4; j++) {
        __nv_bfloat16 h, l; bsplit(y[j], h, l);
        g_actAh[base + j] = h; g_actAl[base + j] = l;
    }
}

// ---------------------------------------------------------------------------
// copy slots -> out (fallback only)
// ---------------------------------------------------------------------------
__global__ __launch_bounds__(256) void copy_out_kernel(float* __restrict__ out, int n) {
    int idx = blockIdx.x * 256 + threadIdx.x;
    if (idx < n) out[idx] = g_scratch[OFF_SLOTS + idx];
}

// ---------------------------------------------------------------------------
// host
// ---------------------------------------------------------------------------
#define SMEM128 (4 * (2*128 + 2*64) * SAP * 2)   /* 122880 */
#define SMEM64  (4 * (2*64 + 2*64) * SAP * 2)    /* 81920 */
#define SMEM32  (4 * (2*32 + 2*64) * SAP * 2)    /* 61440 */

extern "C" void kernel_launch(void* const* d_in, const int* in_sizes, int n_in,
                              void* d_out, int out_size) {
    const float* tokens = (const float*)d_in[0];
    const float* mu     = (const float*)d_in[1];
    const float* Wq  = (const float*)d_in[2];  const float* bq  = (const float*)d_in[3];
    const float* Wk  = (const float*)d_in[4];  const float* bk  = (const float*)d_in[5];
    const float* Wv  = (const float*)d_in[6];  const float* bv  = (const float*)d_in[7];
    const float* Wih = (const float*)d_in[8];  const float* bih = (const float*)d_in[9];
    const float* Whh = (const float*)d_in[10]; const float* bhh = (const float*)d_in[11];
    const float* W1  = (const float*)d_in[12]; const float* b1  = (const float*)d_in[13];
    const float* W2  = (const float*)d_in[14]; const float* b2  = (const float*)d_in[15];
    const float* gs  = (const float*)d_in[16]; const float* bs  = (const float*)d_in[17];
    const float* gm  = (const float*)d_in[18]; const float* bm  = (const float*)d_in[19];
    float* out = (float*)d_out;

    cudaFuncSetAttribute((const void*)gemm2_k<128>, cudaFuncAttributeMaxDynamicSharedMemorySize, SMEM128);
    cudaFuncSetAttribute((const void*)gemm2_k<64>,  cudaFuncAttributeMaxDynamicSharedMemorySize, SMEM64);
    cudaFuncSetAttribute((const void*)gemm2_k<32>,  cudaFuncAttributeMaxDynamicSharedMemorySize, SMEM32);
    cudaFuncSetAttribute((const void*)gru_gemm_k,   cudaFuncAttributeMaxDynamicSharedMemorySize, SMEM64);
    cudaFuncSetAttribute((const void*)fused_pass_kernel, cudaFuncAttributeMaxDynamicSharedMemorySize, FP_SMEM);

    __nv_bfloat16 *wMw, *wVih, *wHh, *w1, *w2, *wWqT, *wWkT, *wWvT, *wWihA;
    __nv_bfloat16 *actAh, *actAl, *actBh, *actBl, *q2h, *q2l, *actSh, *actSl;
    cudaGetSymbolAddress((void**)&wMw,   g_wMw);
    cudaGetSymbolAddress((void**)&wVih,  g_wVih);
    cudaGetSymbolAddress((void**)&wHh,   g_wHh);
    cudaGetSymbolAddress((void**)&w1,    g_w1);
    cudaGetSymbolAddress((void**)&w2,    g_w2);
    cudaGetSymbolAddress((void**)&wWqT,  g_wWqT);
    cudaGetSymbolAddress((void**)&wWkT,  g_wWkT);
    cudaGetSymbolAddress((void**)&wWvT,  g_wWvT);
    cudaGetSymbolAddress((void**)&wWihA, g_wWihA);
    cudaGetSymbolAddress((void**)&actAh, g_actAh);
    cudaGetSymbolAddress((void**)&actAl, g_actAl);
    cudaGetSymbolAddress((void**)&actBh, g_actBh);
    cudaGetSymbolAddress((void**)&actBl, g_actBl);
    cudaGetSymbolAddress((void**)&q2h, g_q2h);
    cudaGetSymbolAddress((void**)&q2l, g_q2l);
    cudaGetSymbolAddress((void**)&actSh, g_actSh);
    cudaGetSymbolAddress((void**)&actSl, g_actSl);
    float* scr;
    cudaGetSymbolAddress((void**)&scr, g_scratch);

    const int direct_out = (out_size >= 262144);
    float* attnp = (out_size >= 1310720) ? (out + 262144) : (scr + OFF_ATTN);

    const size_t P1M = 1024u * 1024u;
    const size_t P3M = 3072u * 1024u;
    const size_t P4M = 4096u * 1024u;

    // ---- one-time ----
    transpose_kernel<<<dim3(32, 32), dim3(32, 8)>>>(Wk, OFF_WKT);
    transpose_kernel<<<dim3(32, 32), dim3(32, 8)>>>(Wq, OFF_WQT);
    transpose_kernel<<<dim3(32, 32), dim3(32, 8)>>>(Wv, OFF_WVT);
    tcnv_kernel<<<65536, 256>>>(tokens);
    convw2_kernel<<<1024, 256>>>(nullptr, OFF_WQT, wWqT, wWqT + P1M);
    convw2_kernel<<<1024, 256>>>(nullptr, OFF_WKT, wWkT, wWkT + P1M);
    convw2_kernel<<<1024, 256>>>(nullptr, OFF_WVT, wWvT, wWvT + P1M);
    convw2_kernel<<<3072, 256>>>(Wih, 0, wWihA, wWihA + P3M);
    gemv_kernel<<<1024, 256>>>(nullptr, OFF_WQT, bk, OFF_WCB, 1024, 1.0f);
    gemv_kernel<<<1024, 256>>>(nullptr, OFF_WKT, bq, OFF_V2, 1024, SCALEF);
    gemv_kernel<<<3072, 256>>>(Wih, 0, bv, OFF_BVW, 1024, 1.0f);
    gemv_kernel<<<1, 256>>>(bq, 0, bk, OFF_C0, 1024, 1.0f);
    gemm2_k<128><<<dim3(16, 8), 256, SMEM128>>>(wWkT, wWkT + P1M, wWqT, wWqT + P1M,
                                                nullptr, nullptr, scr + OFF_MFP, nullptr,
                                                nullptr, nullptr, 1024, 1024, 4);
    gemm2_k<128><<<dim3(16, 24), 256, SMEM128>>>(wWihA, wWihA + P3M, wWvT, wWvT + P1M,
                                                 nullptr, nullptr, scr + OFF_WVIH, nullptr,
                                                 nullptr, nullptr, 1024, 1024, 6);
    convw2_kernel<<<1024, 256>>>(nullptr, OFF_MFP,  wMw,  wMw + P1M);
    convw2_kernel<<<3072, 256>>>(nullptr, OFF_WVIH, wVih, wVih + P3M);
    convw2_kernel<<<3072, 256>>>(Whh, 0, wHh, wHh + P3M);
    convw2_kernel<<<4096, 256>>>(W1,  0, w1,  w1 + P4M);
    convw2_kernel<<<4096, 256>>>(W2,  0, w2,  w2 + P4M);
    init_slots_kernel<<<1024, 256>>>(mu);

    for (int it = 0; it < 3; it++) {
        const int last = (it == 2);
        ln_kernel<<<256, 256>>>(OFF_SLOTS, gs, bs, 1);
        gemm2_k<32><<<dim3(16, 8), 256, SMEM32>>>(actAh, actAl, wMw, wMw + P1M,
                                                  scr + OFF_V2, nullptr, nullptr, nullptr,
                                                  q2h, q2l, 1024, 1024, 0);
        fused_pass_kernel<<<dim3(32, 16), 256, FP_SMEM>>>(attnp, last);
        reduceU_kernel<<<256, 256>>>();
        gru_gemm_k<<<dim3(48, 4, 2), 256, SMEM64>>>(bih, bhh);
        gru_ln_kernel<<<256, 256>>>(gm, bm);
        gemm2_k<64><<<dim3(64, 4), 256, SMEM64>>>(actAh, actAl, w1, w1 + P4M,
                                                  b1, nullptr, nullptr, nullptr,
                                                  actBh, actBl, 4096, 1024, 2);
        // w2: residual read from scratch slots; last iter writes directly to out
        float* w2dst = (last && direct_out) ? out : (scr + OFF_SLOTS);
        gemm2_k<32><<<dim3(16, 8), 256, SMEM32>>>(actBh, actBl, w2, w2 + P4M,
                                                  b2, nullptr, w2dst, scr + OFF_SLOTS,
                                                  last ? nullptr : actSh,
                                                  last ? nullptr : actSl,
                                                  1024, 4096, 3);
    }

    if (!direct_out) {
        int nslots = out_size < 262144 ? out_size : 262144;
        copy_out_kernel<<<1024, 256>>>(out, nslots);
    }
}

// round 15
// speedup vs baseline: 2.9647x; 1.0599x over previous
#include <cuda_runtime.h>
#include <cuda_bf16.h>
#include <cstdint>
#include <cstddef>

// ---------------------------------------------------------------------------
// Problem sizes: B=16, S=4096, D=1024, K=16, ITERS=3
// ---------------------------------------------------------------------------
#define SCALEF   0.03125f        /* 1024^-0.5 */
#define EPS_LN   1e-5f
#define EPS_ATTN 1e-8f

// fp32 scratch offsets (floats)
#define OFF_SLOTS 0u
#define OFF_GI    1572864u
#define OFF_GH    2359296u
#define OFF_WQT   4194304u
#define OFF_MFP   6291456u
#define OFF_U     10485760u     /* 262144 floats (atomic accum) */
#define OFF_WCB   10747904u
#define OFF_V2    10748928u
#define OFF_C0    10753024u
#define OFF_WKT   12582912u
#define OFF_CB    13631488u
#define OFF_BS    13631744u
#define OFF_RP    13632256u     /* 256 rows * 32 chunks */
#define OFF_ATTN  13640448u
#define SCRATCH_N 14689024u

__device__ float g_scratch[SCRATCH_N];

// bf16 2-plane weight buffers: [hi plane | lo plane], each N*K
__device__ __nv_bfloat16 g_wMw  [2u * 1024u * 1024u];
__device__ __nv_bfloat16 g_wV   [2u * 1024u * 1024u];
__device__ __nv_bfloat16 g_wIh  [2u * 3072u * 1024u];
__device__ __nv_bfloat16 g_wHh  [2u * 3072u * 1024u];
__device__ __nv_bfloat16 g_w1   [2u * 4096u * 1024u];
__device__ __nv_bfloat16 g_w2   [2u * 1024u * 4096u];
// one-time composition operands
__device__ __nv_bfloat16 g_wWqT [2u * 1024u * 1024u];
__device__ __nv_bfloat16 g_wWkT [2u * 1024u * 1024u];
// activation plane pairs
__device__ __nv_bfloat16 g_actAh[256u * 1024u], g_actAl[256u * 1024u];
__device__ __nv_bfloat16 g_actSh[256u * 1024u], g_actSl[256u * 1024u];
__device__ __nv_bfloat16 g_actBh[256u * 4096u], g_actBl[256u * 4096u];
// token planes [b][s][d]
__device__ __nv_bfloat16 g_tokh [16u * 4096u * 1024u];
__device__ __nv_bfloat16 g_tokl [16u * 4096u * 1024u];
// q2 planes [256][1024]
__device__ __nv_bfloat16 g_q2h[256u * 1024u];
__device__ __nv_bfloat16 g_q2l[256u * 1024u];

__device__ __forceinline__ float geluf(float x) {
    return 0.5f * x * (1.0f + erff(x * 0.70710678118654752f));
}
__device__ __forceinline__ float sigmf(float x) {
    return 1.0f / (1.0f + __expf(-x));
}

__device__ __forceinline__ uint32_t smem_u32(const void* p) {
    uint32_t a;
    asm("{ .reg .u64 t; cvta.to.shared.u64 t, %1; cvt.u32.u64 %0, t; }" : "=r"(a) : "l"(p));
    return a;
}
__device__ __forceinline__ void cp16s(uint32_t daddr, const void* src) {
    asm volatile("cp.async.cg.shared.global [%0], [%1], 16;" :: "r"(daddr), "l"(src));
}
__device__ __forceinline__ void cpcommit() {
    asm volatile("cp.async.commit_group;" ::: "memory");
}
__device__ __forceinline__ void cpwait_n(int n) {
    if (n <= 0)      asm volatile("cp.async.wait_group 0;" ::: "memory");
    else if (n == 1) asm volatile("cp.async.wait_group 1;" ::: "memory");
    else             asm volatile("cp.async.wait_group 2;" ::: "memory");
}
__device__ __forceinline__ void ldm4(uint32_t* r, uint32_t addr) {
    asm volatile("ldmatrix.sync.aligned.m8n8.x4.shared.b16 {%0,%1,%2,%3}, [%4];"
        : "=r"(r[0]), "=r"(r[1]), "=r"(r[2]), "=r"(r[3]) : "r"(addr));
}
__device__ __forceinline__ void ldm2(uint32_t* r, uint32_t addr) {
    asm volatile("ldmatrix.sync.aligned.m8n8.x2.shared.b16 {%0,%1}, [%2];"
        : "=r"(r[0]), "=r"(r[1]) : "r"(addr));
}
__device__ __forceinline__ void ldm2t(uint32_t* r, uint32_t addr) {
    asm volatile("ldmatrix.sync.aligned.m8n8.x2.trans.shared.b16 {%0,%1}, [%2];"
        : "=r"(r[0]), "=r"(r[1]) : "r"(addr));
}
__device__ __forceinline__ void mma16816(float* c, const uint32_t* a, const uint32_t* b) {
    asm volatile(
        "mma.sync.aligned.m16n8k16.row.col.f32.bf16.bf16.f32 "
        "{%0,%1,%2,%3}, {%4,%5,%6,%7}, {%8,%9}, {%0,%1,%2,%3};"
        : "+f"(c[0]), "+f"(c[1]), "+f"(c[2]), "+f"(c[3])
        : "r"(a[0]), "r"(a[1]), "r"(a[2]), "r"(a[3]), "r"(b[0]), "r"(b[1]));
}

__device__ __forceinline__ void bsplit(float x, __nv_bfloat16& h, __nv_bfloat16& l) {
    h = __float2bfloat16_rn(x);
    l = __float2bfloat16_rn(x - __bfloat162float(h));
}

// ---------------------------------------------------------------------------
// init: slots = broadcast(slot_mu); emit actS planes (slots feed gh at it0)
// ---------------------------------------------------------------------------
__global__ __launch_bounds__(256) void init_slots_kernel(const float* __restrict__ mu) {
    unsigned idx = blockIdx.x * 256u + threadIdx.x;          // < 262144
    float x = mu[idx & 16383u];
    g_scratch[OFF_SLOTS + idx] = x;
    __nv_bfloat16 h, l; bsplit(x, h, l);
    g_actSh[idx] = h; g_actSl[idx] = l;
}

// ---------------------------------------------------------------------------
// transpose 1024x1024 fp32: in -> g_scratch[dstOff]
// ---------------------------------------------------------------------------
__global__ void transpose_kernel(const float* __restrict__ in, unsigned dstOff) {
    __shared__ float t[32][33];
    int x  = blockIdx.x * 32 + threadIdx.x;
    int y0 = blockIdx.y * 32;
    #pragma unroll
    for (int j = threadIdx.y; j < 32; j += 8)
        t[j][threadIdx.x] = in[(size_t)(y0 + j) * 1024 + x];
    __syncthreads();
    int xo  = blockIdx.y * 32 + threadIdx.x;
    int yo0 = blockIdx.x * 32;
    #pragma unroll
    for (int j = threadIdx.y; j < 32; j += 8)
        g_scratch[dstOff + (size_t)(yo0 + j) * 1024 + xo] = t[threadIdx.x][j];
}

// ---------------------------------------------------------------------------
// tokens -> bf16 hi/lo planes
// ---------------------------------------------------------------------------
__global__ __launch_bounds__(256) void tcnv_kernel(const float* __restrict__ tokens) {
    size_t idx4 = (size_t)blockIdx.x * 256u + threadIdx.x;
    float4 x = ((const float4*)tokens)[idx4];
    __nv_bfloat16 h0,h1,h2,h3,l0,l1,l2,l3;
    bsplit(x.x,h0,l0); bsplit(x.y,h1,l1); bsplit(x.z,h2,l2); bsplit(x.w,h3,l3);
    size_t k = idx4 * 4;
    *(__nv_bfloat162*)(g_tokh + k)     = __nv_bfloat162(h0, h1);
    *(__nv_bfloat162*)(g_tokh + k + 2) = __nv_bfloat162(h2, h3);
    *(__nv_bfloat162*)(g_tokl + k)     = __nv_bfloat162(l0, l1);
    *(__nv_bfloat162*)(g_tokl + k + 2) = __nv_bfloat162(l2, l3);
}

// ---------------------------------------------------------------------------
// split-convert to 2 planes: src (flat fp32) -> dh, dl
// ---------------------------------------------------------------------------
__global__ __launch_bounds__(256) void convw2_kernel(const float* __restrict__ src,
                                                     unsigned srcOff,
                                                     __nv_bfloat16* __restrict__ dh,
                                                     __nv_bfloat16* __restrict__ dl) {
    size_t idx4 = (size_t)blockIdx.x * 256u + threadIdx.x;
    const float* S = src ? src : (g_scratch + srcOff);
    float4 x = *(const float4*)(S + idx4 * 4);
    __nv_bfloat16 h0,h1,h2,h3,l0,l1,l2,l3;
    bsplit(x.x,h0,l0); bsplit(x.y,h1,l1); bsplit(x.z,h2,l2); bsplit(x.w,h3,l3);
    size_t k = idx4 * 4;
    *(__nv_bfloat162*)(dh + k)     = __nv_bfloat162(h0, h1);
    *(__nv_bfloat162*)(dh + k + 2) = __nv_bfloat162(h2, h3);
    *(__nv_bfloat162*)(dl + k)     = __nv_bfloat162(l0, l1);
    *(__nv_bfloat162*)(dl + k + 2) = __nv_bfloat162(l2, l3);
}

// ---------------------------------------------------------------------------
// gemv: out[row] = scale * dot(M[row, 0:len], v)
// ---------------------------------------------------------------------------
__global__ __launch_bounds__(256) void gemv_kernel(const float* __restrict__ M,
                                                   unsigned moff,
                                                   const float* __restrict__ v,
                                                   unsigned outoff, int len, float scale) {
    __shared__ float red[256];
    const float* Mr = (M ? M : g_scratch + moff) + (size_t)blockIdx.x * len;
    int tid = threadIdx.x;
    float p = 0.f;
    for (int i = tid * 4; i < len; i += 1024) {
        float4 a = *(const float4*)(Mr + i);
        float4 b = *(const float4*)(v + i);
        p += a.x*b.x + a.y*b.y + a.z*b.z + a.w*b.w;
    }
    red[tid] = p; __syncthreads();
    for (int o = 128; o > 0; o >>= 1) { if (tid < o) red[tid] += red[tid + o]; __syncthreads(); }
    if (tid == 0) g_scratch[outoff + blockIdx.x] = scale * red[0];
}

// ---------------------------------------------------------------------------
// 2-plane HMMA GEMM: C = (Ah+Al) (.) (Wh+Wl)^T  via Ah*Wh + Ah*Wl + Al*Wh.
// BM in {128, 64, 32}.  BN=64.  256 threads, 4-stage cp.async.
// epi: 0=+bias 2=gelu(+bias) 3=+bias+res(Cres) 4=*SCALE 6=raw
//      7=+bias+brow*bias2  8=+brow*bias
// ---------------------------------------------------------------------------
#define SAP 40

template<int BM>
__device__ __forceinline__ void gemm2_core(char* sm,
    const __nv_bfloat16* __restrict__ Ah, const __nv_bfloat16* __restrict__ Al,
    const __nv_bfloat16* __restrict__ Wh, const __nv_bfloat16* __restrict__ Wl,
    const float* __restrict__ bias, const float* __restrict__ bias2,
    float* Cout, const float* __restrict__ Cres,
    __nv_bfloat16* ph, __nv_bfloat16* pl,
    int N, int K, int epi)
{
    constexpr int NW_M = BM / 32;          // warps along M
    constexpr int WTN  = BM / 4;           // warp tile N: 128->32, 64->16, 32->8
    constexpr int NT   = WTN / 8;
    constexpr uint32_t AP  = BM * SAP * 2;
    constexpr uint32_t WP  = 64 * SAP * 2;
    constexpr uint32_t STG = 2 * AP + 2 * WP;

    const int tid  = threadIdx.x;
    const int lane = tid & 31, wid = tid >> 5;
    const int wm = (wid % NW_M) * 32;
    const int wn = (wid / NW_M) * WTN;
    const int bn = blockIdx.x * 64, bm = blockIdx.y * BM;
    const int NC = K >> 5;

    const uint32_t smb = smem_u32(sm);

    const int lrow = tid >> 2, lch = (tid & 3) * 8;
    const uint32_t aoff  = (uint32_t)(lrow * SAP + lch) * 2;
    const uint32_t aoff1 = (uint32_t)((64 + lrow) * SAP + lch) * 2;
    const __nv_bfloat16* agh0 = Ah + (size_t)(bm + (lrow < BM ? lrow : 0)) * K + lch;
    const __nv_bfloat16* agl0 = Al + (size_t)(bm + (lrow < BM ? lrow : 0)) * K + lch;
    const __nv_bfloat16* agh1 = Ah + (size_t)(bm + 64 + lrow) * K + lch;
    const __nv_bfloat16* agl1 = Al + (size_t)(bm + 64 + lrow) * K + lch;
    const __nv_bfloat16* wgh  = Wh + (size_t)(bn + lrow) * K + lch;
    const __nv_bfloat16* wgl  = Wl + (size_t)(bn + lrow) * K + lch;

    const int a_row = wm + (lane & 15);
    const int a_col = (lane >> 4) * 8;
    const int b_row = wn + ((lane >> 4) & 1) * 8 + (lane & 7);
    const int b_col = ((lane >> 3) & 1) * 8;
    const int l2 = lane & 15;
    const int b_row1 = wn + (l2 & 7);
    const int b_col1 = ((l2 >> 3) & 1) * 8;

    float acc[2][NT][4];
    #pragma unroll
    for (int i = 0; i < 2; i++)
        #pragma unroll
        for (int j = 0; j < NT; j++)
            #pragma unroll
            for (int e = 0; e < 4; e++) acc[i][j][e] = 0.f;

    auto load_stage = [&](int st, int c) {
        const uint32_t S = smb + (uint32_t)st * STG;
        const int ko = c * 32;
        if (BM >= 64 || lrow < BM) {
            cp16s(S + aoff, agh0 + ko);
            cp16s(S + AP + aoff, agl0 + ko);
        }
        if (BM == 128) {
            cp16s(S + aoff1, agh1 + ko);
            cp16s(S + AP + aoff1, agl1 + ko);
        }
        cp16s(S + 2 * AP + aoff, wgh + ko);
        cp16s(S + 2 * AP + WP + aoff, wgl + ko);
        cpcommit();
    };

    load_stage(0, 0);
    load_stage(1, 1);
    load_stage(2, 2);

    for (int c = 0; c < NC; c++) {
        int bnd = NC - 1 - c; if (bnd > 2) bnd = 2;
        cpwait_n(bnd);
        __syncthreads();
        if (c + 3 < NC) load_stage((c + 3) & 3, c + 3);
        const uint32_t S = smb + (uint32_t)(c & 3) * STG;
        const uint32_t abh = S, abl = S + AP;
        const uint32_t wbh = S + 2 * AP, wbl = S + 2 * AP + WP;
        #pragma unroll
        for (int ks = 0; ks < 2; ks++) {
            uint32_t afh[2][4], afl[2][4], bfh[2][4], bfl[2][4];
            #pragma unroll
            for (int mt = 0; mt < 2; mt++) {
                uint32_t ao = (uint32_t)(((a_row + mt * 16) * SAP) + ks * 16 + a_col) * 2;
                ldm4(afh[mt], abh + ao);
                ldm4(afl[mt], abl + ao);
            }
            if (NT == 1) {
                uint32_t bo = (uint32_t)((b_row1 * SAP) + ks * 16 + b_col1) * 2;
                ldm2(bfh[0], wbh + bo);
                ldm2(bfl[0], wbl + bo);
            } else {
                #pragma unroll
                for (int nb = 0; nb < NT / 2; nb++) {
                    uint32_t bo = (uint32_t)(((b_row + nb * 16) * SAP) + ks * 16 + b_col) * 2;
                    ldm4(bfh[nb], wbh + bo);
                    ldm4(bfl[nb], wbl + bo);
                }
            }
            #pragma unroll
            for (int mt = 0; mt < 2; mt++)
                #pragma unroll
                for (int nt = 0; nt < NT; nt++) {
                    const uint32_t* bh = &bfh[nt >> 1][(nt & 1) * 2];
                    const uint32_t* bl = &bfl[nt >> 1][(nt & 1) * 2];
                    mma16816(acc[mt][nt], afh[mt], bh);
                    mma16816(acc[mt][nt], afh[mt], bl);
                    mma16816(acc[mt][nt], afl[mt], bh);
                }
        }
    }

    const int mrow = lane >> 2, ncol2 = (lane & 3) * 2;
    #pragma unroll
    for (int mt = 0; mt < 2; mt++) {
        #pragma unroll
        for (int h = 0; h < 2; h++) {
            const int m = bm + wm + mt * 16 + mrow + h * 8;
            float brow = 0.f;
            if (epi == 7 || epi == 8) brow = g_scratch[OFF_BS + m];
            #pragma unroll
            for (int nt = 0; nt < NT; nt++) {
                const int n0 = bn + wn + nt * 8 + ncol2;
                float ox = acc[mt][nt][h * 2], oy = acc[mt][nt][h * 2 + 1];
                if (epi == 4) { ox *= SCALEF; oy *= SCALEF; }
                else if (epi == 6) { }
                else {
                    float2 bb = *(const float2*)(bias + n0);
                    if (epi == 7) {
                        float2 b2 = *(const float2*)(bias2 + n0);
                        ox += bb.x + brow * b2.x; oy += bb.y + brow * b2.y;
                    } else if (epi == 8) {
                        ox += brow * bb.x; oy += brow * bb.y;
                    } else { ox += bb.x; oy += bb.y; }
                    if (epi == 2) { ox = geluf(ox); oy = geluf(oy); }
                    if (epi == 3) {
                        float2 c0 = *(const float2*)(Cres + (size_t)m * N + n0);
                        ox += c0.x; oy += c0.y;
                    }
                }
                if (Cout) *(float2*)(Cout + (size_t)m * N + n0) = make_float2(ox, oy);
                if (ph) {
                    __nv_bfloat16 hx, lx, hy, ly;
                    bsplit(ox, hx, lx); bsplit(oy, hy, ly);
                    *(__nv_bfloat162*)(ph + (size_t)m * N + n0) = __nv_bfloat162(hx, hy);
                    *(__nv_bfloat162*)(pl + (size_t)m * N + n0) = __nv_bfloat162(lx, ly);
                }
            }
        }
    }
}

template<int BM>
__global__ __launch_bounds__(256) void gemm2_k(const __nv_bfloat16* __restrict__ Ah,
                                               const __nv_bfloat16* __restrict__ Al,
                                               const __nv_bfloat16* __restrict__ Wh,
                                               const __nv_bfloat16* __restrict__ Wl,
                                               const float* __restrict__ bias,
                                               const float* __restrict__ bias2,
                                               float* Cout, const float* Cres,
                                               __nv_bfloat16* ph, __nv_bfloat16* pl,
                                               int N, int K, int epi) {
    extern __shared__ char sm[];
    gemm2_core<BM>(sm, Ah, Al, Wh, Wl, bias, bias2, Cout, Cres, ph, pl, N, K, epi);
}

// merged GRU gemms (BM=64: 2 CTAs/SM)
// z=0: gi = upd(actB planes) @ Wih^T + bih ; z=1: gh = slots(actS) @ Whh^T + bhh
__global__ __launch_bounds__(256) void gru_gemm_k(const float* __restrict__ bih,
                                                  const float* __restrict__ bhh) {
    extern __shared__ char sm[];
    if (blockIdx.z == 0)
        gemm2_core<64>(sm, g_actBh, g_actBl, g_wIh, g_wIh + 3072u*1024u,
                       bih, nullptr, g_scratch + OFF_GI, nullptr,
                       nullptr, nullptr, 3072, 1024, 0);
    else
        gemm2_core<64>(sm, g_actSh, g_actSl, g_wHh, g_wHh + 3072u*1024u,
                       bhh, nullptr, g_scratch + OFF_GH, nullptr,
                       nullptr, nullptr, 3072, 1024, 0);
}

// ---------------------------------------------------------------------------
// Single-read fused pass (256 threads): per 16-token group -- load tok strip
// once, logits (k split over 8 warps) + shfl softmax + updates vs SAME strip.
// U accumulated in registers across groups; one atomicAdd set per CTA.
// grid (32 chunks of 128 tokens, 16 b).
// ---------------------------------------------------------------------------
#define FP_SMEM 198144
__global__ __launch_bounds__(256) void fused_pass_kernel(float* __restrict__ attn_out,
                                                         int wlast) {
    extern __shared__ char sm[];
    __shared__ float Lg[8][16][17];
    __shared__ float Att32[16][17];                 // [token][slot]
    __shared__ __nv_bfloat16 ATh[16][24], ATl[16][24];  // [slot][token]
    __shared__ float cbs[16], rs[16];
    const int tid = threadIdx.x;
    const int lane = tid & 31, wid = tid >> 5;
    const int sc = blockIdx.x, b = blockIdx.y;

    const uint32_t smb = smem_u32(sm);
    const uint32_t Qh = smb, Ql = smb + 33024u;
    const uint32_t TB = smb + 66048u;               // 2 buffers x 66048

    if (tid < 16) { cbs[tid] = g_scratch[OFF_CB + b * 16 + tid]; rs[tid] = 0.f; }

    const size_t tokbase = ((size_t)b * 4096 + (size_t)sc * 128) * 1024;

    auto load_group = [&](int buf, int g) {
        const uint32_t Bs = TB + (uint32_t)buf * 66048u;
        #pragma unroll
        for (int i = 0; i < 8; i++) {
            int idx = tid + 256 * i;
            int row = idx >> 7, j = idx & 127;
            cp16s(Bs + (uint32_t)(row * 1032 + j * 8) * 2,
                  g_tokh + tokbase + (size_t)(g * 16 + row) * 1024 + j * 8);
            cp16s(Bs + 33024u + (uint32_t)(row * 1032 + j * 8) * 2,
                  g_tokl + tokbase + (size_t)(g * 16 + row) * 1024 + j * 8);
        }
        cpcommit();
    };

    // Q planes + first group
    {
        #pragma unroll
        for (int i = 0; i < 8; i++) {
            int id = tid + 256 * i;
            int row = id >> 7, j = id & 127;
            cp16s(Qh + (uint32_t)(row * 1032 + j * 8) * 2,
                  g_q2h + (size_t)(b * 16 + row) * 1024 + j * 8);
            cp16s(Ql + (uint32_t)(row * 1032 + j * 8) * 2,
                  g_q2l + (size_t)(b * 16 + row) * 1024 + j * 8);
        }
        cpcommit();
        load_group(0, 0);
    }

    // persistent U accumulators: warp wid owns d slice [wid*128, wid*128+128)
    float uacc[16][4];
    #pragma unroll
    for (int nt = 0; nt < 16; nt++)
        #pragma unroll
        for (int e = 0; e < 4; e++) uacc[nt][e] = 0.f;

    const int kw = wid * 128;               // this warp's k-slice
    const int a_r = lane & 15;              // token row
    const int a_c = (lane >> 4) * 8;
    const int b_r = ((lane >> 4) & 1) * 8 + (lane & 7);
    const int b_c = ((lane >> 3) & 1) * 8;
    const uint32_t ATHb = smem_u32(&ATh[0][0]);
    const uint32_t ATLb = smem_u32(&ATl[0][0]);
    const uint32_t at_off = (uint32_t)((lane & 15) * 24 + (lane >> 4) * 8) * 2;

    for (int g = 0; g < 8; g++) {
        cpwait_n(0);
        __syncthreads();
        if (g + 1 < 8) load_group((g + 1) & 1, g + 1);
        const uint32_t Bs = TB + (uint32_t)(g & 1) * 66048u;
        const uint32_t Bh = Bs, Bl = Bs + 33024u;

        // ---- logits: warp k-slice, m16 (tokens) x n16 (slots) ----
        float la[2][4];
        #pragma unroll
        for (int nt = 0; nt < 2; nt++)
            #pragma unroll
            for (int e = 0; e < 4; e++) la[nt][e] = 0.f;
        #pragma unroll
        for (int ks = 0; ks < 8; ks++) {
            const int col = kw + ks * 16;
            uint32_t afh[4], afl[4], bfh[4], bfl[4];
            uint32_t ao = (uint32_t)(a_r * 1032 + col + a_c) * 2;
            ldm4(afh, Bh + ao);
            ldm4(afl, Bl + ao);
            uint32_t bo = (uint32_t)(b_r * 1032 + col + b_c) * 2;
            ldm4(bfh, Qh + bo);
            ldm4(bfl, Ql + bo);
            #pragma unroll
            for (int nt = 0; nt < 2; nt++) {
                mma16816(la[nt], afh, &bfh[nt * 2]);
                mma16816(la[nt], afh, &bfl[nt * 2]);
                mma16816(la[nt], afl, &bfh[nt * 2]);
            }
        }
        #pragma unroll
        for (int nt = 0; nt < 2; nt++)
            #pragma unroll
            for (int e = 0; e < 4; e++) {
                int row = (lane >> 2) + (e >> 1) * 8;
                int col = nt * 8 + (lane & 3) * 2 + (e & 1);
                Lg[wid][row][col] = la[nt][e];
            }
        __syncthreads();

        // ---- fused reduce + parallel softmax (256 thr = 16 tok x 16 slot) ----
        {
            int tok = tid >> 4, s = tid & 15;
            float v = cbs[s];
            #pragma unroll
            for (int w = 0; w < 8; w++) v += Lg[w][tok][s];
            float mx = v;
            #pragma unroll
            for (int o = 8; o > 0; o >>= 1)
                mx = fmaxf(mx, __shfl_xor_sync(0xffffffffu, mx, o));
            float e = __expf(v - mx);
            float sum = e;
            #pragma unroll
            for (int o = 8; o > 0; o >>= 1)
                sum += __shfl_xor_sync(0xffffffffu, sum, o);
            float a = e / sum;
            Att32[tok][s] = a;
            __nv_bfloat16 h, l; bsplit(a, h, l);
            ATh[s][tok] = h; ATl[s][tok] = l;
            if (wlast)
                attn_out[(size_t)(b * 16 + s) * 4096 + (size_t)sc * 128 + g * 16 + tok] = a;
        }
        __syncthreads();

        // rowsum partial (threads 16..31, slot = tid-16)
        if (tid >= 16 && tid < 32) {
            int s = tid - 16;
            float t = 0.f;
            #pragma unroll
            for (int tok = 0; tok < 16; tok++) t += Att32[tok][s];
            rs[s] += t;
        }

        // ---- updates: U[slots][d-slice] += attnT @ tok  (same strip) ----
        uint32_t ath[4], atl[4];
        ldm4(ath, ATHb + at_off);
        ldm4(atl, ATLb + at_off);
        #pragma unroll
        for (int nt = 0; nt < 16; nt++) {
            const int d0 = kw + nt * 8;
            uint32_t bh[2], bl[2];
            uint32_t bo = (uint32_t)((lane & 15) * 1032 + d0) * 2;
            ldm2t(bh, Bh + bo);
            ldm2t(bl, Bl + bo);
            mma16816(uacc[nt], ath, bh);
            mma16816(uacc[nt], ath, bl);
            mma16816(uacc[nt], atl, bh);
        }
    }

    __syncthreads();
    if (tid < 16)
        g_scratch[OFF_RP + (size_t)(b * 16 + tid) * 32 + sc] = rs[tid];

    // one atomic accumulation per CTA
    float* Ub = g_scratch + OFF_U + (size_t)(b * 16) * 1024;
    const int slot0 = lane >> 2;
    #pragma unroll
    for (int nt = 0; nt < 16; nt++) {
        const int d0 = kw + nt * 8 + (lane & 3) * 2;
        atomicAdd(&Ub[(size_t)slot0 * 1024 + d0],           uacc[nt][0]);
        atomicAdd(&Ub[(size_t)slot0 * 1024 + d0 + 1],       uacc[nt][1]);
        atomicAdd(&Ub[(size_t)(slot0 + 8) * 1024 + d0],     uacc[nt][2]);
        atomicAdd(&Ub[(size_t)(slot0 + 8) * 1024 + d0 + 1], uacc[nt][3]);
    }
}

// ---------------------------------------------------------------------------
// LayerNorm (slots) -> actA planes; docb=1: also cb + zero-U
// ---------------------------------------------------------------------------
__global__ __launch_bounds__(256) void ln_kernel(unsigned offX,
                                                 const float* __restrict__ g,
                                                 const float* __restrict__ bt,
                                                 int docb) {
    __shared__ float red[256];
    const float* X = g_scratch + offX;
    int row = blockIdx.x, tid = threadIdx.x;
    float4 x = ((const float4*)X)[row * 256 + tid];
    red[tid] = x.x + x.y + x.z + x.w;
    __syncthreads();
    for (int o = 128; o > 0; o >>= 1) { if (tid < o) red[tid] += red[tid + o]; __syncthreads(); }
    float mean = red[0] * (1.0f / 1024.0f);
    __syncthreads();
    float4 dx = { x.x - mean, x.y - mean, x.z - mean, x.w - mean };
    red[tid] = dx.x*dx.x + dx.y*dx.y + dx.z*dx.z + dx.w*dx.w;
    __syncthreads();
    for (int o = 128; o > 0; o >>= 1) { if (tid < o) red[tid] += red[tid + o]; __syncthreads(); }
    float rs = rsqrtf(red[0] * (1.0f / 1024.0f) + EPS_LN);
    float4 gg = ((const float4*)g)[tid], bb = ((const float4*)bt)[tid];
    float y[4] = { dx.x*rs*gg.x + bb.x, dx.y*rs*gg.y + bb.y,
                   dx.z*rs*gg.z + bb.z, dx.w*rs*gg.w + bb.w };
    size_t base = (size_t)row * 1024u + tid * 4;
    #pragma unroll
    for (int j = 0; j < 4; j++) {
        __nv_bfloat16 h, l; bsplit(y[j], h, l);
        g_actAh[base + j] = h; g_actAl[base + j] = l;
    }
    if (docb) {
        *(float4*)&g_scratch[OFF_U + base] = make_float4(0.f, 0.f, 0.f, 0.f);
        float p = 0.f;
        #pragma unroll
        for (int j = 0; j < 4; j++) p += y[j] * g_scratch[OFF_WCB + tid * 4 + j];
        __syncthreads();
        red[tid] = p; __syncthreads();
        for (int o = 128; o > 0; o >>= 1) { if (tid < o) red[tid] += red[tid + o]; __syncthreads(); }
        if (tid == 0)
            g_scratch[OFF_CB + row] = SCALEF * (red[0] + g_scratch[OFF_C0]);
    }
}

// ---------------------------------------------------------------------------
// reduceU (+rowsum): Un[row] = U[row]/rowsum -> actA planes; BS=brow
// ---------------------------------------------------------------------------
__global__ __launch_bounds__(256) void reduceU_kernel() {
    float* S = g_scratch;
    int row = blockIdx.x, tid = threadIdx.x;
    float s = 0.f;
    #pragma unroll
    for (int cc = 0; cc < 32; cc++) s += S[OFF_RP + (size_t)row * 32 + cc];
    float ri = 1.0f / (s + EPS_ATTN);
    if (tid == 0) S[OFF_BS + row] = s * ri;
    size_t base = (size_t)row * 1024u + tid * 4;
    float4 v = *(const float4*)&S[OFF_U + base];
    float y[4] = { v.x * ri, v.y * ri, v.z * ri, v.w * ri };
    #pragma unroll
    for (int j = 0; j < 4; j++) {
        __nv_bfloat16 h, l; bsplit(y[j], h, l);
        g_actAh[base + j] = h; g_actAl[base + j] = l;
    }
}

// ---------------------------------------------------------------------------
// Fused GRU combine + LayerNorm(mlp) -> slots, actA planes.  block = row.
// ---------------------------------------------------------------------------
__global__ __launch_bounds__(256) void gru_ln_kernel(const float* __restrict__ gm,
                                                     const float* __restrict__ bm) {
    __shared__ float red[256];
    float* S = g_scratch;
    int row = blockIdx.x, tid = threadIdx.x;
    size_t gb = (size_t)row * 3072 + tid * 4;
    float4 ir = *(const float4*)&S[OFF_GI + gb];
    float4 iz = *(const float4*)&S[OFF_GI + gb + 1024];
    float4 in_ = *(const float4*)&S[OFF_GI + gb + 2048];
    float4 hr = *(const float4*)&S[OFF_GH + gb];
    float4 hz = *(const float4*)&S[OFF_GH + gb + 1024];
    float4 hn = *(const float4*)&S[OFF_GH + gb + 2048];
    float4 sp = *(const float4*)&S[OFF_SLOTS + (size_t)row * 1024 + tid * 4];
    float ns[4];
    {
        float r0 = sigmf(ir.x + hr.x), z0 = sigmf(iz.x + hz.x);
        ns[0] = (1.f - z0) * tanhf(in_.x + r0 * hn.x) + z0 * sp.x;
        float r1 = sigmf(ir.y + hr.y), z1 = sigmf(iz.y + hz.y);
        ns[1] = (1.f - z1) * tanhf(in_.y + r1 * hn.y) + z1 * sp.y;
        float r2 = sigmf(ir.z + hr.z), z2 = sigmf(iz.z + hz.z);
        ns[2] = (1.f - z2) * tanhf(in_.z + r2 * hn.z) + z2 * sp.z;
        float r3 = sigmf(ir.w + hr.w), z3 = sigmf(iz.w + hz.w);
        ns[3] = (1.f - z3) * tanhf(in_.w + r3 * hn.w) + z3 * sp.w;
    }
    *(float4*)&S[OFF_SLOTS + (size_t)row * 1024 + tid * 4] =
        make_float4(ns[0], ns[1], ns[2], ns[3]);
    red[tid] = ns[0] + ns[1] + ns[2] + ns[3];
    __syncthreads();
    for (int o = 128; o > 0; o >>= 1) { if (tid < o) red[tid] += red[tid + o]; __syncthreads(); }
    float mean = red[0] * (1.0f / 1024.0f);
    __syncthreads();
    float dx[4] = { ns[0]-mean, ns[1]-mean, ns[2]-mean, ns[3]-mean };
    red[tid] = dx[0]*dx[0] + dx[1]*dx[1] + dx[2]*dx[2] + dx[3]*dx[3];
    __syncthreads();
    for (int o = 128; o > 0; o >>= 1) { if (tid < o) red[tid] += red[tid + o]; __syncthreads(); }
    float rs = rsqrtf(red[0] * (1.0f / 1024.0f) + EPS_LN);
    float4 gg = ((const float4*)gm)[tid], bb = ((const float4*)bm)[tid];
    float y[4] = { dx[0]*rs*gg.x + bb.x, dx[1]*rs*gg.y + bb.y,
                   dx[2]*rs*gg.z + bb.z, dx[3]*rs*gg.w + bb.w };
    size_t base = (size_t)row * 1024u + tid * 4;
    #pragma unroll
    for (int j = 0; j < 4; j++) {
        __nv_bfloat16 h, l; bsplit(y[j], h, l);
        g_actAh[base + j] = h; g_actAl[base + j] = l;
    }
}

// ---------------------------------------------------------------------------
// copy slots -> out (fallback only)
// ---------------------------------------------------------------------------
__global__ __launch_bounds__(256) void copy_out_kernel(float* __restrict__ out, int n) {
    int idx = blockIdx.x * 256 + threadIdx.x;
    if (idx < n) out[idx] = g_scratch[OFF_SLOTS + idx];
}

// ---------------------------------------------------------------------------
// host
// ---------------------------------------------------------------------------
#define SMEM128 (4 * (2*128 + 2*64) * SAP * 2)   /* 122880 */
#define SMEM64  (4 * (2*64 + 2*64) * SAP * 2)    /* 81920 */
#define SMEM32  (4 * (2*32 + 2*64) * SAP * 2)    /* 61440 */

extern "C" void kernel_launch(void* const* d_in, const int* in_sizes, int n_in,
                              void* d_out, int out_size) {
    const float* tokens = (const float*)d_in[0];
    const float* mu     = (const float*)d_in[1];
    const float* Wq  = (const float*)d_in[2];  const float* bq  = (const float*)d_in[3];
    const float* Wk  = (const float*)d_in[4];  const float* bk  = (const float*)d_in[5];
    const float* Wv  = (const float*)d_in[6];  const float* bv  = (const float*)d_in[7];
    const float* Wih = (const float*)d_in[8];  const float* bih = (const float*)d_in[9];
    const float* Whh = (const float*)d_in[10]; const float* bhh = (const float*)d_in[11];
    const float* W1  = (const float*)d_in[12]; const float* b1  = (const float*)d_in[13];
    const float* W2  = (const float*)d_in[14]; const float* b2  = (const float*)d_in[15];
    const float* gs  = (const float*)d_in[16]; const float* bs  = (const float*)d_in[17];
    const float* gm  = (const float*)d_in[18]; const float* bm  = (const float*)d_in[19];
    float* out = (float*)d_out;

    cudaFuncSetAttribute((const void*)gemm2_k<128>, cudaFuncAttributeMaxDynamicSharedMemorySize, SMEM128);
    cudaFuncSetAttribute((const void*)gemm2_k<64>,  cudaFuncAttributeMaxDynamicSharedMemorySize, SMEM64);
    cudaFuncSetAttribute((const void*)gemm2_k<32>,  cudaFuncAttributeMaxDynamicSharedMemorySize, SMEM32);
    cudaFuncSetAttribute((const void*)gru_gemm_k,   cudaFuncAttributeMaxDynamicSharedMemorySize, SMEM64);
    cudaFuncSetAttribute((const void*)fused_pass_kernel, cudaFuncAttributeMaxDynamicSharedMemorySize, FP_SMEM);

    __nv_bfloat16 *wMw, *wV, *wIh, *wHh, *w1, *w2, *wWqT, *wWkT;
    __nv_bfloat16 *actAh, *actAl, *actBh, *actBl, *q2h, *q2l, *actSh, *actSl;
    cudaGetSymbolAddress((void**)&wMw,  g_wMw);
    cudaGetSymbolAddress((void**)&wV,   g_wV);
    cudaGetSymbolAddress((void**)&wIh,  g_wIh);
    cudaGetSymbolAddress((void**)&wHh,  g_wHh);
    cudaGetSymbolAddress((void**)&w1,   g_w1);
    cudaGetSymbolAddress((void**)&w2,   g_w2);
    cudaGetSymbolAddress((void**)&wWqT, g_wWqT);
    cudaGetSymbolAddress((void**)&wWkT, g_wWkT);
    cudaGetSymbolAddress((void**)&actAh, g_actAh);
    cudaGetSymbolAddress((void**)&actAl, g_actAl);
    cudaGetSymbolAddress((void**)&actBh, g_actBh);
    cudaGetSymbolAddress((void**)&actBl, g_actBl);
    cudaGetSymbolAddress((void**)&q2h, g_q2h);
    cudaGetSymbolAddress((void**)&q2l, g_q2l);
    cudaGetSymbolAddress((void**)&actSh, g_actSh);
    cudaGetSymbolAddress((void**)&actSl, g_actSl);
    float* scr;
    cudaGetSymbolAddress((void**)&scr, g_scratch);

    const int direct_out = (out_size >= 262144);
    float* attnp = (out_size >= 1310720) ? (out + 262144) : (scr + OFF_ATTN);

    const size_t P1M = 1024u * 1024u;
    const size_t P3M = 3072u * 1024u;
    const size_t P4M = 4096u * 1024u;

    // ---- one-time ----
    transpose_kernel<<<dim3(32, 32), dim3(32, 8)>>>(Wk, OFF_WKT);
    transpose_kernel<<<dim3(32, 32), dim3(32, 8)>>>(Wq, OFF_WQT);
    tcnv_kernel<<<65536, 256>>>(tokens);
    convw2_kernel<<<1024, 256>>>(nullptr, OFF_WQT, wWqT, wWqT + P1M);
    convw2_kernel<<<1024, 256>>>(nullptr, OFF_WKT, wWkT, wWkT + P1M);
    convw2_kernel<<<1024, 256>>>(Wv,  0, wV,  wV + P1M);
    convw2_kernel<<<3072, 256>>>(Wih, 0, wIh, wIh + P3M);
    gemv_kernel<<<1024, 256>>>(nullptr, OFF_WQT, bk, OFF_WCB, 1024, 1.0f);
    gemv_kernel<<<1024, 256>>>(nullptr, OFF_WKT, bq, OFF_V2, 1024, SCALEF);
    gemv_kernel<<<1, 256>>>(bq, 0, bk, OFF_C0, 1024, 1.0f);
    // Mw = SCALE * WkT (.) WqT^T   [1024 x 1024]
    gemm2_k<128><<<dim3(16, 8), 256, SMEM128>>>(wWkT, wWkT + P1M, wWqT, wWqT + P1M,
                                                nullptr, nullptr, scr + OFF_MFP, nullptr,
                                                nullptr, nullptr, 1024, 1024, 4);
    convw2_kernel<<<1024, 256>>>(nullptr, OFF_MFP, wMw, wMw + P1M);
    convw2_kernel<<<3072, 256>>>(Whh, 0, wHh, wHh + P3M);
    convw2_kernel<<<4096, 256>>>(W1,  0, w1,  w1 + P4M);
    convw2_kernel<<<4096, 256>>>(W2,  0, w2,  w2 + P4M);
    init_slots_kernel<<<1024, 256>>>(mu);

    for (int it = 0; it < 3; it++) {
        const int last = (it == 2);
        ln_kernel<<<256, 256>>>(OFF_SLOTS, gs, bs, 1);
        gemm2_k<32><<<dim3(16, 8), 256, SMEM32>>>(actAh, actAl, wMw, wMw + P1M,
                                                  scr + OFF_V2, nullptr, nullptr, nullptr,
                                                  q2h, q2l, 1024, 1024, 0);
        fused_pass_kernel<<<dim3(32, 16), 256, FP_SMEM>>>(attnp, last);
        reduceU_kernel<<<256, 256>>>();
        // upd = Un @ Wv^T + brow*bv  -> actB planes
        gemm2_k<32><<<dim3(16, 8), 256, SMEM32>>>(actAh, actAl, wV, wV + P1M,
                                                  bv, nullptr, nullptr, nullptr,
                                                  actBh, actBl, 1024, 1024, 8);
        gru_gemm_k<<<dim3(48, 4, 2), 256, SMEM64>>>(bih, bhh);
        gru_ln_kernel<<<256, 256>>>(gm, bm);
        gemm2_k<64><<<dim3(64, 4), 256, SMEM64>>>(actAh, actAl, w1, w1 + P4M,
                                                  b1, nullptr, nullptr, nullptr,
                                                  actBh, actBl, 4096, 1024, 2);
        float* w2dst = (last && direct_out) ? out : (scr + OFF_SLOTS);
        gemm2_k<32><<<dim3(16, 8), 256, SMEM32>>>(actBh, actBl, w2, w2 + P4M,
                                                  b2, nullptr, w2dst, scr + OFF_SLOTS,
                                                  last ? nullptr : actSh,
                                                  last ? nullptr : actSl,
                                                  1024, 4096, 3);
    }

    if (!direct_out) {
        int nslots = out_size < 262144 ? out_size : 262144;
        copy_out_kernel<<<1024, 256>>>(out, nslots);
    }
}